// round 7
// baseline (speedup 1.0000x reference)
#include <cuda_runtime.h>
#include <cuda_bf16.h>
#include <math.h>
#include <stdint.h>

// ---------------------------------------------------------------------------
// PointNet++ encoder forward. B=2048 clouds, N=1024 pts, 6 ch.
// All MLP stages on HMMA (mma.sync bf16x3 split, fp32 accumulate).
// ---------------------------------------------------------------------------

#define B_TOT 2048
#define N1    1024
#define M1    32
#define M2    16
#define NSMP  32

__device__ int   g_fps1 [B_TOT * M1];
__device__ float g_nx1  [B_TOT * M1 * 3];
__device__ int   g_ball1[B_TOT * M1 * NSMP];
__device__ float g_f1   [B_TOT * M1 * 128];
__device__ int   g_fps2 [B_TOT * M2];
__device__ float g_nx2  [B_TOT * M2 * 3];
__device__ int   g_ball2[B_TOT * M2 * NSMP];
__device__ float g_f2   [B_TOT * M2 * 256];
__device__ float g_g    [B_TOT * 768];

// Pre-split weights: [N][Kpad] bf16, hi block then lo block.
__device__ __align__(16) __nv_bfloat16 g_w10b[2 * 64 * 16];
__device__ __align__(16) __nv_bfloat16 g_w11b[2 * 64 * 64];
__device__ __align__(16) __nv_bfloat16 g_w12b[2 * 128 * 64];
__device__ __align__(16) __nv_bfloat16 g_w20b[2 * 128 * 152];
__device__ __align__(16) __nv_bfloat16 g_w21b[2 * 128 * 136];
__device__ __align__(16) __nv_bfloat16 g_w22b[2 * 256 * 136];
__device__ __align__(16) __nv_bfloat16 g_w30b[2 * 256 * 272];
__device__ __align__(16) __nv_bfloat16 g_w31b[2 * 512 * 272];
__device__ __align__(16) __nv_bfloat16 g_w32b[2 * 768 * 528];
// Head intermediate activations (32768 samples x 512), bf16 hi/lo.
#define HOFF 16777216
__device__ __align__(16) __nv_bfloat16 g_h1[2 * 32768 * 512];

// ---- packed f32x2 helpers (FC kernel) ----------------------------------------
typedef unsigned long long ull_t;
__device__ __forceinline__ ull_t dup2(float v) {
    ull_t r; unsigned u = __float_as_uint(v);
    asm("mov.b64 %0, {%1, %1};" : "=l"(r) : "r"(u));
    return r;
}
__device__ __forceinline__ float2 unpk(ull_t p) {
    unsigned lo, hi;
    asm("mov.b64 {%0, %1}, %2;" : "=r"(lo), "=r"(hi) : "l"(p));
    return make_float2(__uint_as_float(lo), __uint_as_float(hi));
}
#define FMA2(d, a, b, c) \
    asm("fma.rn.f32x2 %0, %1, %2, %3;" : "=l"(d) : "l"(a), "l"(b), "l"(c))

#define BNS_F 0.99999500003749968f   // 1/sqrt(1+1e-5)

// ---- mma.sync / ldmatrix helpers --------------------------------------------
__device__ __forceinline__ uint32_t smem_to_u32(const void* p) {
    uint32_t a;
    asm("{ .reg .u64 t; cvta.to.shared.u64 t, %1; cvt.u32.u64 %0, t; }"
        : "=r"(a) : "l"(p));
    return a;
}
#define LDSM4(r, a) \
    asm volatile("ldmatrix.sync.aligned.m8n8.x4.shared.b16 {%0,%1,%2,%3}, [%4];" \
                 : "=r"((r)[0]), "=r"((r)[1]), "=r"((r)[2]), "=r"((r)[3]) : "r"(a))

__device__ __forceinline__ void mma_bf16(float* c, const uint32_t* a,
                                         const uint32_t* b) {
    asm volatile(
        "mma.sync.aligned.m16n8k16.row.col.f32.bf16.bf16.f32 "
        "{%0,%1,%2,%3}, {%4,%5,%6,%7}, {%8,%9}, {%0,%1,%2,%3};"
        : "+f"(c[0]), "+f"(c[1]), "+f"(c[2]), "+f"(c[3])
        : "r"(a[0]), "r"(a[1]), "r"(a[2]), "r"(a[3]), "r"(b[0]), "r"(b[1]));
}

__device__ __forceinline__ uint32_t pack_hi(float v0, float v1, uint32_t* lo) {
    __nv_bfloat162 hh = __floats2bfloat162_rn(v0, v1);
    __nv_bfloat162 ll = __floats2bfloat162_rn(v0 - __bfloat162float(hh.x),
                                              v1 - __bfloat162float(hh.y));
    *lo = *(const uint32_t*)&ll;
    return *(const uint32_t*)&hh;
}

extern __shared__ float dynsmem[];

// Generalized bf16x3 GEMM pass (mapping identical to the validated SA2 one).
template <int KS, int PN>
__device__ __forceinline__ void gp_t(uint32_t aBase, uint32_t aHalf, uint32_t aStride,
                                     uint32_t bBase, uint32_t bHalf, uint32_t bStride,
                                     int mrow, int nbase, int lane,
                                     float (&c)[2 * PN][4]) {
    const uint32_t aAddr = aBase + (uint32_t)(mrow + (lane & 15)) * aStride +
                           (uint32_t)((lane >> 4) << 4);
    const uint32_t nrow  = (lane & 7) + ((lane >> 4) << 3);
    const uint32_t kcolB = ((lane >> 3) & 1) << 4;
    const uint32_t bAddr = bBase + (uint32_t)(nbase + nrow) * bStride + kcolB;
    #pragma unroll 1
    for (int ks = 0; ks < KS; ++ks) {
        uint32_t ah[4], al[4];
        LDSM4(ah, aAddr + ks * 32);
        LDSM4(al, aAddr + aHalf + ks * 32);
        #pragma unroll
        for (int p = 0; p < PN; ++p) {
            uint32_t bh[4], bl[4];
            const uint32_t ba = bAddr + (uint32_t)p * 16u * bStride + ks * 32;
            LDSM4(bh, ba);
            LDSM4(bl, ba + bHalf);
            mma_bf16(c[2*p],   ah, bh);
            mma_bf16(c[2*p],   ah, bl);
            mma_bf16(c[2*p],   al, bh);
            mma_bf16(c[2*p+1], ah, bh + 2);
            mma_bf16(c[2*p+1], ah, bl + 2);
            mma_bf16(c[2*p+1], al, bh + 2);
        }
    }
}

// Epilogue: bias+BNS+relu, split bf16 hi/lo into smem for next layer.
template <int PN>
__device__ __forceinline__ void epi_t(char* smem, uint32_t outOff, uint32_t outHalf,
                                      uint32_t outStride, const float* bias, int cbase,
                                      float (&c)[2 * PN][4], int mrow, int lane) {
    const int r0  = mrow + (lane >> 2);
    const int ccb = 2 * (lane & 3);
    #pragma unroll
    for (int f = 0; f < 2 * PN; ++f) {
        const int col = cbase + (f >> 1) * 16 + (f & 1) * 8 + ccb;
        const float bv0 = bias[col], bv1 = bias[col + 1];
        const float v00 = fmaxf((c[f][0] + bv0) * BNS_F, 0.0f);
        const float v01 = fmaxf((c[f][1] + bv1) * BNS_F, 0.0f);
        const float v10 = fmaxf((c[f][2] + bv0) * BNS_F, 0.0f);
        const float v11 = fmaxf((c[f][3] + bv1) * BNS_F, 0.0f);
        uint32_t l0, l1;
        const uint32_t h0 = pack_hi(v00, v01, &l0);
        const uint32_t h1 = pack_hi(v10, v11, &l1);
        const uint32_t o0 = outOff + (uint32_t)r0 * outStride + (uint32_t)col * 2u;
        const uint32_t o1 = o0 + 8u * outStride;
        *(uint32_t*)(smem + o0) = h0;
        *(uint32_t*)(smem + o0 + outHalf) = l0;
        *(uint32_t*)(smem + o1) = h1;
        *(uint32_t*)(smem + o1 + outHalf) = l1;
    }
}

// Stage weights (hi/lo) from separate global offsets into smem.
__device__ __forceinline__ void stage_w2(char* smem, uint32_t off,
                                         const __nv_bfloat16* srcHi,
                                         const __nv_bfloat16* srcLo, int halfBytes) {
    float4* dh = (float4*)(smem + off);
    float4* dl = (float4*)(smem + off + halfBytes);
    const float4* sh = (const float4*)srcHi;
    const float4* sl = (const float4*)srcLo;
    const int n16 = halfBytes / 16;
    for (int i = threadIdx.x; i < n16; i += 256) { dh[i] = sh[i]; dl[i] = sl[i]; }
}

// ---------------------------------------------------------------------------
// FPS stage 1 + 2, ball query (unchanged, index-exact).
// ---------------------------------------------------------------------------
__global__ void fps1_kernel(const float* __restrict__ x,
                            int* __restrict__ fidx, float* __restrict__ nxyz) {
    __shared__ float swv[32];
    __shared__ int   swi[32];
    __shared__ float cur[3];
    __shared__ int   slast;
    const int b = blockIdx.x;
    const int t = threadIdx.x;
    const int warp = t >> 5, lane = t & 31;
    const float* p = x + ((size_t)b * N1 + t) * 6;
    const float px = p[0], py = p[1], pz = p[2];
    float dist = 1e10f;
    if (t == 0) {
        fidx[b * M1] = 0;
        float* o = nxyz + (size_t)b * M1 * 3;
        o[0] = px; o[1] = py; o[2] = pz;
    }
    int last = 0;
    for (int it = 1; it < M1; ++it) {
        if (t == last) { cur[0] = px; cur[1] = py; cur[2] = pz; }
        __syncthreads();
        float dx = __fsub_rn(px, cur[0]);
        float dy = __fsub_rn(py, cur[1]);
        float dz = __fsub_rn(pz, cur[2]);
        float d  = __fadd_rn(__fadd_rn(__fmul_rn(dx, dx), __fmul_rn(dy, dy)),
                             __fmul_rn(dz, dz));
        dist = fminf(dist, d);
        float v = dist; int vi = t;
        #pragma unroll
        for (int off = 16; off; off >>= 1) {
            float v2 = __shfl_xor_sync(0xffffffffu, v, off);
            int   i2 = __shfl_xor_sync(0xffffffffu, vi, off);
            if (v2 > v || (v2 == v && i2 < vi)) { v = v2; vi = i2; }
        }
        if (lane == 0) { swv[warp] = v; swi[warp] = vi; }
        __syncthreads();
        if (warp == 0) {
            float wv = swv[lane]; int wi = swi[lane];
            #pragma unroll
            for (int off = 16; off; off >>= 1) {
                float v2 = __shfl_xor_sync(0xffffffffu, wv, off);
                int   i2 = __shfl_xor_sync(0xffffffffu, wi, off);
                if (v2 > wv || (v2 == wv && i2 < wi)) { wv = v2; wi = i2; }
            }
            if (lane == 0) { slast = wi; fidx[b * M1 + it] = wi; }
        }
        __syncthreads();
        last = slast;
        if (t == last) {
            float* o = nxyz + ((size_t)b * M1 + it) * 3;
            o[0] = px; o[1] = py; o[2] = pz;
        }
    }
}

__global__ void fps2_kernel(const float* __restrict__ pts,
                            int* __restrict__ fidx, float* __restrict__ nxyz) {
    const int gw   = (blockIdx.x * blockDim.x + threadIdx.x) >> 5;
    const int lane = threadIdx.x & 31;
    if (gw >= B_TOT) return;
    const float* pb = pts + (size_t)gw * M1 * 3;
    const float px = pb[lane * 3 + 0], py = pb[lane * 3 + 1], pz = pb[lane * 3 + 2];
    float dist = 1e10f;
    if (lane == 0) {
        fidx[gw * M2] = 0;
        float* o = nxyz + (size_t)gw * M2 * 3;
        o[0] = px; o[1] = py; o[2] = pz;
    }
    int last = 0;
    for (int it = 1; it < M2; ++it) {
        const float cx = __shfl_sync(0xffffffffu, px, last);
        const float cy = __shfl_sync(0xffffffffu, py, last);
        const float cz = __shfl_sync(0xffffffffu, pz, last);
        float dx = __fsub_rn(px, cx), dy = __fsub_rn(py, cy), dz = __fsub_rn(pz, cz);
        float d  = __fadd_rn(__fadd_rn(__fmul_rn(dx, dx), __fmul_rn(dy, dy)),
                             __fmul_rn(dz, dz));
        dist = fminf(dist, d);
        float v = dist; int vi = lane;
        #pragma unroll
        for (int off = 16; off; off >>= 1) {
            float v2 = __shfl_xor_sync(0xffffffffu, v, off);
            int   i2 = __shfl_xor_sync(0xffffffffu, vi, off);
            if (v2 > v || (v2 == v && i2 < vi)) { v = v2; vi = i2; }
        }
        last = vi;
        if (lane == 0) fidx[gw * M2 + it] = last;
        if (lane == last) {
            float* o = nxyz + ((size_t)gw * M2 + it) * 3;
            o[0] = px; o[1] = py; o[2] = pz;
        }
    }
}

__global__ void ball_kernel(const float* __restrict__ pts, int pstride,
                            const float* __restrict__ centers,
                            int M, int N, float r2, int* __restrict__ out) {
    const int gw   = (blockIdx.x * blockDim.x + threadIdx.x) >> 5;
    const int lane = threadIdx.x & 31;
    if (gw >= B_TOT * M) return;
    const int b = gw / M;
    const float* c = centers + (size_t)gw * 3;
    const float cx = c[0], cy = c[1], cz = c[2];
    const float cn = __fadd_rn(__fadd_rn(__fmul_rn(cx, cx), __fmul_rn(cy, cy)),
                               __fmul_rn(cz, cz));
    int* o = out + (size_t)gw * NSMP;
    int cnt = 0, first = -1;
    for (int base = 0; base < N && cnt < NSMP; base += 32) {
        const float* pp = pts + ((size_t)b * N + base + lane) * pstride;
        const float px = pp[0], py = pp[1], pz = pp[2];
        const float pn = __fadd_rn(__fadd_rn(__fmul_rn(px, px), __fmul_rn(py, py)),
                                   __fmul_rn(pz, pz));
        const float dt = __fadd_rn(__fadd_rn(__fmul_rn(cx, px), __fmul_rn(cy, py)),
                                   __fmul_rn(cz, pz));
        const float d2 = __fsub_rn(__fadd_rn(cn, pn), __fmul_rn(2.0f, dt));
        const bool hit = d2 < r2;
        const unsigned mask = __ballot_sync(0xffffffffu, hit);
        if (first < 0 && mask) first = base + __ffs(mask) - 1;
        const int pos = cnt + __popc(mask & ((1u << lane) - 1u));
        if (hit && pos < NSMP) o[pos] = base + lane;
        cnt += __popc(mask);
    }
    if (cnt > NSMP) cnt = NSMP;
    for (int k = cnt + lane; k < NSMP; k += 32) o[k] = first;
}

// ---------------------------------------------------------------------------
// Weight prep: transpose to [N][Kpad], split bf16 hi/lo.
// ---------------------------------------------------------------------------
__global__ void prep_t_kernel(const float* __restrict__ w,
                              __nv_bfloat16* __restrict__ out,
                              int Cin, int Cout, int Kpad) {
    const int total = Cout * Kpad;
    for (int idx = blockIdx.x * blockDim.x + threadIdx.x; idx < total;
         idx += gridDim.x * blockDim.x) {
        const int n = idx / Kpad, kp = idx % Kpad;
        const float v = (kp < Cin) ? w[(size_t)kp * Cout + n] : 0.0f;
        const __nv_bfloat16 hi = __float2bfloat16(v);
        const __nv_bfloat16 lo = __float2bfloat16(v - __bfloat162float(hi));
        out[idx] = hi;
        out[total + idx] = lo;
    }
}

// ---------------------------------------------------------------------------
// SA1 HMMA: 4 centers/block (M=128), MLP 6(p16)->64->64->128, fused max.
// smem: A0 hi@0/lo@4096 (str32); A1 hi@8192/lo@24576 (str128);
//       A2 hi@40960/lo@57344 (str128); B@73728 (<=32KB); part@106496; bias@110592.
// ---------------------------------------------------------------------------
#define S1_A0   0u
#define S1_A1   8192u
#define S1_A2   40960u
#define S1_B    73728u
#define S1_PART 106496u
#define S1_BIAS 110592u
#define S1_SMEM 111616

__global__ void __launch_bounds__(256)
sa1m_kernel(const float* __restrict__ x, const float* __restrict__ nx1,
            const int* __restrict__ ball,
            const float* __restrict__ b0_, const float* __restrict__ b1_,
            const float* __restrict__ b2_, float* __restrict__ out) {
    char* smem = (char*)dynsmem;
    const uint32_t su = smem_to_u32(smem);
    const int tid = threadIdx.x;
    const int wid = tid >> 5, lane = tid & 31;
    const int mrow = wid * 16;
    float* bias = (float*)(smem + S1_BIAS);
    float* part = (float*)(smem + S1_PART);
    const int bm0 = blockIdx.x * 4;
    const int b   = bm0 / M1;

    if (tid < 64) { bias[tid] = b0_[tid]; bias[64 + tid] = b1_[tid]; }
    if (tid < 128) bias[128 + tid] = b2_[tid];

    // Gather A0: 128 rows x 16 cols (6 real).
    if (tid < 128) {
        const int row = tid;
        const int center = bm0 + (row >> 5);
        const int p = ball[center * NSMP + (row & 31)];
        const float* xr  = x + ((size_t)b * N1 + p) * 6;
        const float* ctr = nx1 + (size_t)center * 3;
        uint32_t* dh = (uint32_t*)(smem + S1_A0 + row * 32);
        uint32_t* dl = (uint32_t*)(smem + S1_A0 + 4096 + row * 32);
        #pragma unroll
        for (int j = 0; j < 8; ++j) {
            const int k = 2 * j;
            float v0 = 0.0f, v1 = 0.0f;
            if (k < 6)     v0 = (k < 3)     ? xr[k] - ctr[k]         : xr[k];
            if (k + 1 < 6) v1 = (k + 1 < 3) ? xr[k + 1] - ctr[k + 1] : xr[k + 1];
            uint32_t lo;
            dh[j] = pack_hi(v0, v1, &lo);
            dl[j] = lo;
        }
    }
    stage_w2(smem, S1_B, g_w10b, g_w10b + 64 * 16, 2048);
    __syncthreads();

    {   // L0: K=16 (1 ks), N=64
        float c[8][4];
        #pragma unroll
        for (int f = 0; f < 8; ++f)
            #pragma unroll
            for (int j = 0; j < 4; ++j) c[f][j] = 0.0f;
        gp_t<1, 4>(su + S1_A0, 4096u, 32u, su + S1_B, 2048u, 32u, mrow, 0, lane, c);
        epi_t<4>(smem, S1_A1, 16384u, 128u, bias, 0, c, mrow, lane);
    }
    __syncthreads();
    stage_w2(smem, S1_B, g_w11b, g_w11b + 64 * 64, 8192);
    __syncthreads();

    {   // L1: K=64 (4 ks), N=64
        float c[8][4];
        #pragma unroll
        for (int f = 0; f < 8; ++f)
            #pragma unroll
            for (int j = 0; j < 4; ++j) c[f][j] = 0.0f;
        gp_t<4, 4>(su + S1_A1, 16384u, 128u, su + S1_B, 8192u, 128u, mrow, 0, lane, c);
        epi_t<4>(smem, S1_A2, 16384u, 128u, bias + 64, 0, c, mrow, lane);
    }
    __syncthreads();
    stage_w2(smem, S1_B, g_w12b, g_w12b + 128 * 64, 16384);
    __syncthreads();

    {   // L2: K=64, N=128 + fused max over 32 rows/center
        float c[16][4];
        #pragma unroll
        for (int f = 0; f < 16; ++f)
            #pragma unroll
            for (int j = 0; j < 4; ++j) c[f][j] = 0.0f;
        gp_t<4, 8>(su + S1_A2, 16384u, 128u, su + S1_B, 16384u, 128u, mrow, 0, lane, c);
        #pragma unroll
        for (int f = 0; f < 16; ++f) {
            float m0 = fmaxf(c[f][0], c[f][2]);
            float m1 = fmaxf(c[f][1], c[f][3]);
            #pragma unroll
            for (int off = 4; off <= 16; off <<= 1) {
                m0 = fmaxf(m0, __shfl_xor_sync(0xffffffffu, m0, off));
                m1 = fmaxf(m1, __shfl_xor_sync(0xffffffffu, m1, off));
            }
            if (lane < 4) {
                const int cc = (f >> 1) * 16 + (f & 1) * 8 + 2 * lane;
                part[wid * 128 + cc] = m0;
                part[wid * 128 + cc + 1] = m1;
            }
        }
        __syncthreads();
        for (int i = tid; i < 512; i += 256) {
            const int ci = i >> 7, n = i & 127;
            const float v = fmaxf(part[(2 * ci) * 128 + n],
                                  part[(2 * ci + 1) * 128 + n]);
            out[(size_t)(bm0 + ci) * 128 + n] =
                fmaxf((v + bias[128 + n]) * BNS_F, 0.0f);
        }
    }
}

// ---------------------------------------------------------------------------
// SA2 HMMA (validated R5, unchanged).
// ---------------------------------------------------------------------------
#define A_OFF     0u
#define HALF_A    38912u
#define B_OFF     77824u
#define HALF_B    69632u
#define PART_OFF  217088u
#define BIAS_OFF  221184u
#define SA2M_SMEM 223232

__device__ __forceinline__ void stage_b(char* smem, const __nv_bfloat16* src,
                                        int halfBytes) {
    float4* dh = (float4*)(smem + B_OFF);
    float4* dl = (float4*)(smem + B_OFF + HALF_B);
    const float4* sh = (const float4*)src;
    const float4* sl = (const float4*)((const char*)src + halfBytes);
    const int n16 = halfBytes / 16;
    for (int i = threadIdx.x; i < n16; i += 256) { dh[i] = sh[i]; dl[i] = sl[i]; }
}

template <int KS>
__device__ __forceinline__ void gemm_pass(uint32_t su, uint32_t aStride,
                                          uint32_t bStride, int nBase, int mw,
                                          int lane, float (&c)[16][4]) {
    const uint32_t aAddr = su + A_OFF + (uint32_t)(mw + (lane & 15)) * aStride +
                           (uint32_t)((lane >> 4) << 4);
    const uint32_t nrow  = (lane & 7) + ((lane >> 4) << 3);
    const uint32_t kcolB = ((lane >> 3) & 1) << 4;
    const uint32_t bAddr = su + B_OFF + (uint32_t)(nBase + nrow) * bStride + kcolB;
    #pragma unroll 1
    for (int ks = 0; ks < KS; ++ks) {
        uint32_t ah[4], al[4];
        LDSM4(ah, aAddr + ks * 32);
        LDSM4(al, aAddr + HALF_A + ks * 32);
        #pragma unroll
        for (int p = 0; p < 8; ++p) {
            uint32_t bh[4], bl[4];
            const uint32_t ba = bAddr + (uint32_t)p * 16u * bStride + ks * 32;
            LDSM4(bh, ba);
            LDSM4(bl, ba + HALF_B);
            mma_bf16(c[2*p],     ah, bh);
            mma_bf16(c[2*p],     ah, bl);
            mma_bf16(c[2*p],     al, bh);
            mma_bf16(c[2*p+1],   ah, bh + 2);
            mma_bf16(c[2*p+1],   ah, bl + 2);
            mma_bf16(c[2*p+1],   al, bh + 2);
        }
    }
}

__device__ __forceinline__ void epi_dense(char* smem, const float* bs, int boff,
                                          float (&c)[16][4], int mw, int lane) {
    const int r0  = mw + (lane >> 2);
    const int ccb = 2 * (lane & 3);
    #pragma unroll
    for (int f = 0; f < 16; ++f) {
        const int cc = (f >> 1) * 16 + (f & 1) * 8 + ccb;
        const float bv0 = bs[boff + cc], bv1 = bs[boff + cc + 1];
        const float v00 = fmaxf((c[f][0] + bv0) * BNS_F, 0.0f);
        const float v01 = fmaxf((c[f][1] + bv1) * BNS_F, 0.0f);
        const float v10 = fmaxf((c[f][2] + bv0) * BNS_F, 0.0f);
        const float v11 = fmaxf((c[f][3] + bv1) * BNS_F, 0.0f);
        uint32_t l0, l1;
        const uint32_t h0 = pack_hi(v00, v01, &l0);
        const uint32_t h1 = pack_hi(v10, v11, &l1);
        const uint32_t o0 = (uint32_t)r0 * 272u + (uint32_t)cc * 2u;
        const uint32_t o1 = o0 + 8u * 272u;
        *(uint32_t*)(smem + o0) = h0;
        *(uint32_t*)(smem + HALF_A + o0) = l0;
        *(uint32_t*)(smem + o1) = h1;
        *(uint32_t*)(smem + HALF_A + o1) = l1;
    }
}

__global__ void __launch_bounds__(256)
sa2m_kernel(const float* __restrict__ nx1, const float* __restrict__ f1,
            const float* __restrict__ nx2, const int* __restrict__ ball,
            const float* __restrict__ b0_, const float* __restrict__ b1_,
            const float* __restrict__ b2_, float* __restrict__ out) {
    char* smem = (char*)dynsmem;
    const uint32_t su = smem_to_u32(smem);
    const int tid = threadIdx.x;
    const int wid = tid >> 5, lane = tid & 31;
    const int mw  = wid * 16;
    float* bs = (float*)(smem + BIAS_OFF);
    float* part = (float*)(smem + PART_OFF);

    const int bm0 = blockIdx.x * 4;
    const int b   = bm0 / M2;

    if (tid < 128) { bs[tid] = b0_[tid]; bs[128 + tid] = b1_[tid]; }
    bs[256 + tid] = b2_[tid];

    {
        const int row = tid >> 1, seg = tid & 1;
        const int center = bm0 + (row >> 5);
        const int p = ball[center * NSMP + (row & 31)];
        const float* nx1r = nx1 + ((size_t)b * M1 + p) * 3;
        const float* ctr  = nx2 + (size_t)center * 3;
        const float* f1r  = f1 + ((size_t)b * M1 + p) * 128;
        #pragma unroll 1
        for (int i = 0; i < 36; ++i) {
            const int k = seg * 72 + 2 * i;
            float v0, v1;
            if (k < 3)        v0 = nx1r[k] - ctr[k];
            else if (k < 131) v0 = f1r[k - 3];
            else              v0 = 0.0f;
            const int k1 = k + 1;
            if (k1 < 3)        v1 = nx1r[k1] - ctr[k1];
            else if (k1 < 131) v1 = f1r[k1 - 3];
            else               v1 = 0.0f;
            uint32_t lo;
            const uint32_t hi = pack_hi(v0, v1, &lo);
            const uint32_t off = (uint32_t)row * 304u + (uint32_t)k * 2u;
            *(uint32_t*)(smem + off) = hi;
            *(uint32_t*)(smem + HALF_A + off) = lo;
        }
    }
    stage_b(smem, g_w20b, 128 * 152 * 2);
    __syncthreads();

    float c[16][4];
    #pragma unroll
    for (int f = 0; f < 16; ++f)
        #pragma unroll
        for (int j = 0; j < 4; ++j) c[f][j] = 0.0f;
    gemm_pass<9>(su, 304u, 304u, 0, mw, lane, c);
    __syncthreads();
    epi_dense(smem, bs, 0, c, mw, lane);
    stage_b(smem, g_w21b, 128 * 136 * 2);
    __syncthreads();

    #pragma unroll
    for (int f = 0; f < 16; ++f)
        #pragma unroll
        for (int j = 0; j < 4; ++j) c[f][j] = 0.0f;
    gemm_pass<8>(su, 272u, 272u, 0, mw, lane, c);
    __syncthreads();
    epi_dense(smem, bs, 128, c, mw, lane);
    stage_b(smem, g_w22b, 256 * 136 * 2);
    __syncthreads();

    #pragma unroll 1
    for (int h = 0; h < 2; ++h) {
        #pragma unroll
        for (int f = 0; f < 16; ++f)
            #pragma unroll
            for (int j = 0; j < 4; ++j) c[f][j] = 0.0f;
        gemm_pass<8>(su, 272u, 272u, h * 128, mw, lane, c);
        #pragma unroll
        for (int f = 0; f < 16; ++f) {
            float m0 = fmaxf(c[f][0], c[f][2]);
            float m1 = fmaxf(c[f][1], c[f][3]);
            #pragma unroll
            for (int off = 4; off <= 16; off <<= 1) {
                m0 = fmaxf(m0, __shfl_xor_sync(0xffffffffu, m0, off));
                m1 = fmaxf(m1, __shfl_xor_sync(0xffffffffu, m1, off));
            }
            if (lane < 4) {
                const int cc = (f >> 1) * 16 + (f & 1) * 8 + 2 * lane;
                part[wid * 128 + cc] = m0;
                part[wid * 128 + cc + 1] = m1;
            }
        }
        __syncthreads();
        for (int i = tid; i < 512; i += 256) {
            const int ci = i >> 7, n = i & 127;
            const float v = fmaxf(part[(2 * ci) * 128 + n],
                                  part[(2 * ci + 1) * 128 + n]);
            out[(size_t)(bm0 + ci) * 256 + h * 128 + n] =
                fmaxf((v + bs[256 + h * 128 + n]) * BNS_F, 0.0f);
        }
        __syncthreads();
    }
}

// ---------------------------------------------------------------------------
// Head H_a: 4 batches/block (M=64). L0 259(p272)->256, L1 256(p272)->512.
// L1 output -> g_h1 (global bf16 hi/lo).
// ---------------------------------------------------------------------------
#define HA_A0   0u
#define HA_A0H  34816u
#define HA_A1   69632u
#define HA_A1H  34816u
#define HA_B    139264u
#define HA_BH   34816u
#define HA_BIAS 208896u
#define HA_SMEM 211968

__global__ void __launch_bounds__(256)
ha_kernel(const float* __restrict__ nx2, const float* __restrict__ f2,
          const float* __restrict__ b30, const float* __restrict__ b31) {
    char* smem = (char*)dynsmem;
    const uint32_t su = smem_to_u32(smem);
    const int tid = threadIdx.x;
    const int wid = tid >> 5, lane = tid & 31;
    const int mrow = (wid & 3) * 16;
    const int nb   = (wid >> 2) * 32;
    float* bias0 = (float*)(smem + HA_BIAS);
    float* bias1 = bias0 + 256;

    bias0[tid] = b30[tid];
    for (int i = tid; i < 512; i += 256) bias1[i] = b31[i];

    // Gather A0: 64 rows x 272 cols (259 real: xyz2 | f2).
    {
        const int row = tid >> 2, q = tid & 3;
        const int sg = blockIdx.x * 64 + row;
        const float* nx2r = nx2 + (size_t)sg * 3;
        const float* f2r  = f2 + (size_t)sg * 256;
        #pragma unroll 1
        for (int j = 0; j < 34; ++j) {
            const int k = q * 68 + 2 * j;
            const float v0 = (k < 3) ? nx2r[k] : (k < 259 ? f2r[k - 3] : 0.0f);
            const int k1 = k + 1;
            const float v1 = (k1 < 3) ? nx2r[k1] : (k1 < 259 ? f2r[k1 - 3] : 0.0f);
            uint32_t lo;
            const uint32_t hi = pack_hi(v0, v1, &lo);
            const uint32_t off = (uint32_t)row * 544u + (uint32_t)k * 2u;
            *(uint32_t*)(smem + HA_A0 + off) = hi;
            *(uint32_t*)(smem + HA_A0 + HA_A0H + off) = lo;
        }
        if (q == 0) {  // zero A1 pad cols 256..271
            uint32_t* zh = (uint32_t*)(smem + HA_A1 + row * 544 + 512);
            uint32_t* zl = (uint32_t*)(smem + HA_A1 + HA_A1H + row * 544 + 512);
            #pragma unroll
            for (int j = 0; j < 8; ++j) { zh[j] = 0; zl[j] = 0; }
        }
    }

    // L0: K=272 (17 ks), N=256 in 4 chunks of 64.
    #pragma unroll 1
    for (int chunk = 0; chunk < 4; ++chunk) {
        stage_w2(smem, HA_B, g_w30b + chunk * 64 * 272,
                 g_w30b + 256 * 272 + chunk * 64 * 272, HA_BH);
        __syncthreads();
        float c[4][4];
        #pragma unroll
        for (int f = 0; f < 4; ++f)
            #pragma unroll
            for (int j = 0; j < 4; ++j) c[f][j] = 0.0f;
        gp_t<17, 2>(su + HA_A0, HA_A0H, 544u, su + HA_B, HA_BH, 544u,
                    mrow, nb, lane, c);
        epi_t<2>(smem, HA_A1, HA_A1H, 544u, bias0, chunk * 64 + nb, c, mrow, lane);
        __syncthreads();
    }

    // L1: K=272 (17 ks, cols 256..271 zero), N=512 in 8 chunks of 64 -> g_h1.
    #pragma unroll 1
    for (int chunk = 0; chunk < 8; ++chunk) {
        stage_w2(smem, HA_B, g_w31b + chunk * 64 * 272,
                 g_w31b + 512 * 272 + chunk * 64 * 272, HA_BH);
        __syncthreads();
        float c[4][4];
        #pragma unroll
        for (int f = 0; f < 4; ++f)
            #pragma unroll
            for (int j = 0; j < 4; ++j) c[f][j] = 0.0f;
        gp_t<17, 2>(su + HA_A1, HA_A1H, 544u, su + HA_B, HA_BH, 544u,
                    mrow, nb, lane, c);
        const int r0 = mrow + (lane >> 2);
        const size_t s0 = (size_t)blockIdx.x * 64 + r0;
        #pragma unroll
        for (int f = 0; f < 4; ++f) {
            const int col = chunk * 64 + nb + (f >> 1) * 16 + (f & 1) * 8 +
                            2 * (lane & 3);
            const float bv0 = bias1[col], bv1 = bias1[col + 1];
            const float v00 = fmaxf((c[f][0] + bv0) * BNS_F, 0.0f);
            const float v01 = fmaxf((c[f][1] + bv1) * BNS_F, 0.0f);
            const float v10 = fmaxf((c[f][2] + bv0) * BNS_F, 0.0f);
            const float v11 = fmaxf((c[f][3] + bv1) * BNS_F, 0.0f);
            uint32_t l0, l1;
            const uint32_t h0 = pack_hi(v00, v01, &l0);
            const uint32_t h1 = pack_hi(v10, v11, &l1);
            const size_t o0 = s0 * 512 + col;
            const size_t o1 = (s0 + 8) * 512 + col;
            *(uint32_t*)(g_h1 + o0) = h0;
            *(uint32_t*)(g_h1 + HOFF + o0) = l0;
            *(uint32_t*)(g_h1 + o1) = h1;
            *(uint32_t*)(g_h1 + HOFF + o1) = l1;
        }
        __syncthreads();
    }
}

// ---------------------------------------------------------------------------
// Head H_b: 4 batches/block (M=64). L2 512(p528)->768, fused max over 16 -> g.
// ---------------------------------------------------------------------------
#define HB_A    0u
#define HB_AH   67584u
#define HB_B    135168u
#define HB_BH   33792u
#define HB_BIAS 202752u
#define HB_SMEM 205824

__global__ void __launch_bounds__(256)
hb_kernel(const float* __restrict__ b32, float* __restrict__ gout) {
    char* smem = (char*)dynsmem;
    const uint32_t su = smem_to_u32(smem);
    const int tid = threadIdx.x;
    const int wid = tid >> 5, lane = tid & 31;
    const int mtile = wid & 3, h = wid >> 2;
    const int mrow = mtile * 16, nb = h * 16;
    float* bias = (float*)(smem + HB_BIAS);

    for (int i = tid; i < 768; i += 256) bias[i] = b32[i];

    // Load A: 64 rows x 512 cols from g_h1 (pad 512..527 zero), stride 1056B.
    {
        const int row = tid >> 2, q = tid & 3;
        const size_t sg = (size_t)blockIdx.x * 64 + row;
        const float4* srcH = (const float4*)(g_h1 + sg * 512) + q * 16;
        const float4* srcL = (const float4*)(g_h1 + HOFF + sg * 512) + q * 16;
        float4* dH = (float4*)(smem + HB_A + row * 1056 + q * 256);
        float4* dL = (float4*)(smem + HB_A + HB_AH + row * 1056 + q * 256);
        #pragma unroll
        for (int j = 0; j < 16; ++j) { dH[j] = srcH[j]; dL[j] = srcL[j]; }
        if (q == 3) {
            float4 z = make_float4(0.f, 0.f, 0.f, 0.f);
            float4* zh = (float4*)(smem + HB_A + row * 1056 + 1024);
            float4* zl = (float4*)(smem + HB_A + HB_AH + row * 1056 + 1024);
            zh[0] = z; zh[1] = z; zl[0] = z; zl[1] = z;
        }
    }

    // 24 chunks of N=32; K=528 (33 ks).
    #pragma unroll 1
    for (int chunk = 0; chunk < 24; ++chunk) {
        stage_w2(smem, HB_B, g_w32b + chunk * 32 * 528,
                 g_w32b + 768 * 528 + chunk * 32 * 528, HB_BH);
        __syncthreads();
        float c[2][4];
        #pragma unroll
        for (int f = 0; f < 2; ++f)
            #pragma unroll
            for (int j = 0; j < 4; ++j) c[f][j] = 0.0f;
        gp_t<33, 1>(su + HB_A, HB_AH, 1056u, su + HB_B, HB_BH, 1056u,
                    mrow, nb, lane, c);
        #pragma unroll
        for (int f = 0; f < 2; ++f) {
            float m0 = fmaxf(c[f][0], c[f][2]);
            float m1 = fmaxf(c[f][1], c[f][3]);
            #pragma unroll
            for (int off = 4; off <= 16; off <<= 1) {
                m0 = fmaxf(m0, __shfl_xor_sync(0xffffffffu, m0, off));
                m1 = fmaxf(m1, __shfl_xor_sync(0xffffffffu, m1, off));
            }
            if (lane < 4) {
                const int col = chunk * 32 + nb + f * 8 + 2 * lane;
                const int bg = blockIdx.x * 4 + mtile;
                gout[(size_t)bg * 768 + col] =
                    fmaxf((m0 + bias[col]) * BNS_F, 0.0f);
                gout[(size_t)bg * 768 + col + 1] =
                    fmaxf((m1 + bias[col + 1]) * BNS_F, 0.0f);
            }
        }
        __syncthreads();
    }
}

// ---------------------------------------------------------------------------
// FC: 16 batches/block share fc_w loads.
// ---------------------------------------------------------------------------
__global__ void __launch_bounds__(192)
fc_kernel(const float* __restrict__ g_in, const float* __restrict__ fcw,
          const float* __restrict__ fcb, float* __restrict__ out) {
    constexpr int FCB = 16, C = 768, NT = 192;
    __shared__ float gs[FCB * C];
    const int b0 = blockIdx.x * FCB;
    for (int i = threadIdx.x; i < FCB * C; i += NT)
        gs[i] = g_in[(size_t)b0 * C + i];
    __syncthreads();
    const int og = threadIdx.x;
    const float4 bv = *reinterpret_cast<const float4*>(fcb + 4 * og);
    ull_t a01[FCB], a23[FCB];
    #pragma unroll
    for (int i = 0; i < FCB; ++i) { a01[i] = 0ull; a23[i] = 0ull; }
    const float* wp = fcw + 4 * og;
    #pragma unroll 2
    for (int k = 0; k < C; ++k) {
        const ulonglong2 wq =
            *reinterpret_cast<const ulonglong2*>(wp + (size_t)k * C);
        #pragma unroll
        for (int i = 0; i < FCB; ++i) {
            const ull_t hh = dup2(gs[i * C + k]);
            FMA2(a01[i], hh, wq.x, a01[i]);
            FMA2(a23[i], hh, wq.y, a23[i]);
        }
    }
    #pragma unroll
    for (int i = 0; i < FCB; ++i) {
        const float2 p0 = unpk(a01[i]);
        const float2 p1 = unpk(a23[i]);
        float4 r = make_float4(p0.x + bv.x, p0.y + bv.y, p1.x + bv.z, p1.y + bv.w);
        *reinterpret_cast<float4*>(out + (size_t)(b0 + i) * C + 4 * og) = r;
    }
}

// ---------------------------------------------------------------------------
// Host launcher
// ---------------------------------------------------------------------------
extern "C" void kernel_launch(void* const* d_in, const int* in_sizes, int n_in,
                              void* d_out, int out_size) {
    const float* x   = (const float*)d_in[0];
    const float* w10 = (const float*)d_in[1];  const float* b10 = (const float*)d_in[2];
    const float* w11 = (const float*)d_in[3];  const float* b11 = (const float*)d_in[4];
    const float* w12 = (const float*)d_in[5];  const float* b12 = (const float*)d_in[6];
    const float* w20 = (const float*)d_in[7];  const float* b20 = (const float*)d_in[8];
    const float* w21 = (const float*)d_in[9];  const float* b21 = (const float*)d_in[10];
    const float* w22 = (const float*)d_in[11]; const float* b22 = (const float*)d_in[12];
    const float* w30 = (const float*)d_in[13]; const float* b30 = (const float*)d_in[14];
    const float* w31 = (const float*)d_in[15]; const float* b31 = (const float*)d_in[16];
    const float* w32 = (const float*)d_in[17]; const float* b32 = (const float*)d_in[18];
    const float* fcw = (const float*)d_in[19]; const float* fcb = (const float*)d_in[20];
    float* out = (float*)d_out;

    int *fps1p, *ball1p, *fps2p, *ball2p;
    float *nx1p, *f1p, *nx2p, *f2p, *gp;
    __nv_bfloat16 *w10bp, *w11bp, *w12bp, *w20bp, *w21bp, *w22bp, *w30bp, *w31bp, *w32bp;
    cudaGetSymbolAddress((void**)&fps1p,  g_fps1);
    cudaGetSymbolAddress((void**)&nx1p,   g_nx1);
    cudaGetSymbolAddress((void**)&ball1p, g_ball1);
    cudaGetSymbolAddress((void**)&f1p,    g_f1);
    cudaGetSymbolAddress((void**)&fps2p,  g_fps2);
    cudaGetSymbolAddress((void**)&nx2p,   g_nx2);
    cudaGetSymbolAddress((void**)&ball2p, g_ball2);
    cudaGetSymbolAddress((void**)&f2p,    g_f2);
    cudaGetSymbolAddress((void**)&gp,     g_g);
    cudaGetSymbolAddress((void**)&w10bp,  g_w10b);
    cudaGetSymbolAddress((void**)&w11bp,  g_w11b);
    cudaGetSymbolAddress((void**)&w12bp,  g_w12b);
    cudaGetSymbolAddress((void**)&w20bp,  g_w20b);
    cudaGetSymbolAddress((void**)&w21bp,  g_w21b);
    cudaGetSymbolAddress((void**)&w22bp,  g_w22b);
    cudaGetSymbolAddress((void**)&w30bp,  g_w30b);
    cudaGetSymbolAddress((void**)&w31bp,  g_w31b);
    cudaGetSymbolAddress((void**)&w32bp,  g_w32b);

    cudaFuncSetAttribute(sa1m_kernel, cudaFuncAttributeMaxDynamicSharedMemorySize, S1_SMEM);
    cudaFuncSetAttribute(sa2m_kernel, cudaFuncAttributeMaxDynamicSharedMemorySize, SA2M_SMEM);
    cudaFuncSetAttribute(ha_kernel,   cudaFuncAttributeMaxDynamicSharedMemorySize, HA_SMEM);
    cudaFuncSetAttribute(hb_kernel,   cudaFuncAttributeMaxDynamicSharedMemorySize, HB_SMEM);

    // Weight prep (deterministic; part of the graph)
    prep_t_kernel<<<4, 256>>>(w10, w10bp, 6, 64, 16);
    prep_t_kernel<<<16, 256>>>(w11, w11bp, 64, 64, 64);
    prep_t_kernel<<<32, 256>>>(w12, w12bp, 64, 128, 64);
    prep_t_kernel<<<76, 256>>>(w20, w20bp, 131, 128, 152);
    prep_t_kernel<<<68, 256>>>(w21, w21bp, 128, 128, 136);
    prep_t_kernel<<<136, 256>>>(w22, w22bp, 128, 256, 136);
    prep_t_kernel<<<272, 256>>>(w30, w30bp, 259, 256, 272);
    prep_t_kernel<<<512, 256>>>(w31, w31bp, 256, 512, 272);
    prep_t_kernel<<<512, 256>>>(w32, w32bp, 512, 768, 528);

    // SA1
    fps1_kernel<<<B_TOT, 1024>>>(x, fps1p, nx1p);
    ball_kernel<<<(B_TOT * M1 * 32 + 255) / 256, 256>>>(
        x, 6, nx1p, M1, N1, (float)(0.2 * 0.2), ball1p);
    sa1m_kernel<<<B_TOT * M1 / 4, 256, S1_SMEM>>>(x, nx1p, ball1p,
                                                  b10, b11, b12, f1p);
    // SA2
    fps2_kernel<<<(B_TOT * 32 + 127) / 128, 128>>>(nx1p, fps2p, nx2p);
    ball_kernel<<<(B_TOT * M2 * 32 + 255) / 256, 256>>>(
        nx1p, 3, nx2p, M2, M1, (float)(0.4 * 0.4), ball2p);
    sa2m_kernel<<<B_TOT * M2 / 4, 256, SA2M_SMEM>>>(nx1p, f1p, nx2p, ball2p,
                                                    b20, b21, b22, f2p);
    // Head + FC
    ha_kernel<<<B_TOT / 4, 256, HA_SMEM>>>(nx2p, f2p, b30, b31);
    hb_kernel<<<B_TOT / 4, 256, HB_SMEM>>>(b32, gp);
    fc_kernel<<<B_TOT / 16, 192>>>(gp, fcw, fcb, out);
}

// round 8
// speedup vs baseline: 1.0620x; 1.0620x over previous
#include <cuda_runtime.h>
#include <cuda_bf16.h>
#include <math.h>
#include <stdint.h>

// ---------------------------------------------------------------------------
// PointNet++ encoder forward. B=2048 clouds, N=1024 pts, 6 ch.
// All MLP stages on HMMA (mma.sync bf16x3 split, fp32 accumulate).
// Head = generic tiled GEMM (BM64 x BN128, K-chunked), max fused in L2.
// ---------------------------------------------------------------------------

#define B_TOT 2048
#define N1    1024
#define M1    32
#define M2    16
#define NSMP  32

__device__ int   g_fps1 [B_TOT * M1];
__device__ float g_nx1  [B_TOT * M1 * 3];
__device__ int   g_ball1[B_TOT * M1 * NSMP];
__device__ float g_f1   [B_TOT * M1 * 128];
__device__ int   g_fps2 [B_TOT * M2];
__device__ float g_nx2  [B_TOT * M2 * 3];
__device__ int   g_ball2[B_TOT * M2 * NSMP];
__device__ float g_f2   [B_TOT * M2 * 256];
__device__ float g_g    [B_TOT * 768];

// Pre-split weights: [N][Kpad] bf16, hi block then lo block.
__device__ __align__(16) __nv_bfloat16 g_w10b[2 * 64 * 16];
__device__ __align__(16) __nv_bfloat16 g_w11b[2 * 64 * 64];
__device__ __align__(16) __nv_bfloat16 g_w12b[2 * 128 * 64];
__device__ __align__(16) __nv_bfloat16 g_w20b[2 * 128 * 152];
__device__ __align__(16) __nv_bfloat16 g_w21b[2 * 128 * 136];
__device__ __align__(16) __nv_bfloat16 g_w22b[2 * 256 * 136];
__device__ __align__(16) __nv_bfloat16 g_w30b[2 * 256 * 288];
__device__ __align__(16) __nv_bfloat16 g_w31b[2 * 512 * 256];
__device__ __align__(16) __nv_bfloat16 g_w32b[2 * 768 * 512];

// Head activations, [32768 rows][Kpad] bf16, hi block then lo block.
#define A0HALF ((size_t)32768 * 288)
#define H0HALF ((size_t)32768 * 256)
#define H1HALF ((size_t)32768 * 512)
__device__ __align__(16) __nv_bfloat16 g_a0[2 * 32768 * 288];
__device__ __align__(16) __nv_bfloat16 g_h0[2 * 32768 * 256];
__device__ __align__(16) __nv_bfloat16 g_h1[2 * 32768 * 512];

// ---- packed f32x2 helpers (FC kernel) ----------------------------------------
typedef unsigned long long ull_t;
__device__ __forceinline__ ull_t dup2(float v) {
    ull_t r; unsigned u = __float_as_uint(v);
    asm("mov.b64 %0, {%1, %1};" : "=l"(r) : "r"(u));
    return r;
}
__device__ __forceinline__ float2 unpk(ull_t p) {
    unsigned lo, hi;
    asm("mov.b64 {%0, %1}, %2;" : "=r"(lo), "=r"(hi) : "l"(p));
    return make_float2(__uint_as_float(lo), __uint_as_float(hi));
}
#define FMA2(d, a, b, c) \
    asm("fma.rn.f32x2 %0, %1, %2, %3;" : "=l"(d) : "l"(a), "l"(b), "l"(c))

#define BNS_F 0.99999500003749968f   // 1/sqrt(1+1e-5)

// ---- mma.sync / ldmatrix helpers --------------------------------------------
__device__ __forceinline__ uint32_t smem_to_u32(const void* p) {
    uint32_t a;
    asm("{ .reg .u64 t; cvta.to.shared.u64 t, %1; cvt.u32.u64 %0, t; }"
        : "=r"(a) : "l"(p));
    return a;
}
#define LDSM4(r, a) \
    asm volatile("ldmatrix.sync.aligned.m8n8.x4.shared.b16 {%0,%1,%2,%3}, [%4];" \
                 : "=r"((r)[0]), "=r"((r)[1]), "=r"((r)[2]), "=r"((r)[3]) : "r"(a))

__device__ __forceinline__ void mma_bf16(float* c, const uint32_t* a,
                                         const uint32_t* b) {
    asm volatile(
        "mma.sync.aligned.m16n8k16.row.col.f32.bf16.bf16.f32 "
        "{%0,%1,%2,%3}, {%4,%5,%6,%7}, {%8,%9}, {%0,%1,%2,%3};"
        : "+f"(c[0]), "+f"(c[1]), "+f"(c[2]), "+f"(c[3])
        : "r"(a[0]), "r"(a[1]), "r"(a[2]), "r"(a[3]), "r"(b[0]), "r"(b[1]));
}

__device__ __forceinline__ uint32_t pack_hi(float v0, float v1, uint32_t* lo) {
    __nv_bfloat162 hh = __floats2bfloat162_rn(v0, v1);
    __nv_bfloat162 ll = __floats2bfloat162_rn(v0 - __bfloat162float(hh.x),
                                              v1 - __bfloat162float(hh.y));
    *lo = *(const uint32_t*)&ll;
    return *(const uint32_t*)&hh;
}

extern __shared__ float dynsmem[];

// Generalized bf16x3 GEMM pass (fragment mapping validated in R5).
template <int KS, int PN>
__device__ __forceinline__ void gp_t(uint32_t aBase, uint32_t aHalf, uint32_t aStride,
                                     uint32_t bBase, uint32_t bHalf, uint32_t bStride,
                                     int mrow, int nbase, int lane,
                                     float (&c)[2 * PN][4]) {
    const uint32_t aAddr = aBase + (uint32_t)(mrow + (lane & 15)) * aStride +
                           (uint32_t)((lane >> 4) << 4);
    const uint32_t nrow  = (lane & 7) + ((lane >> 4) << 3);
    const uint32_t kcolB = ((lane >> 3) & 1) << 4;
    const uint32_t bAddr = bBase + (uint32_t)(nbase + nrow) * bStride + kcolB;
    #pragma unroll 1
    for (int ks = 0; ks < KS; ++ks) {
        uint32_t ah[4], al[4];
        LDSM4(ah, aAddr + ks * 32);
        LDSM4(al, aAddr + aHalf + ks * 32);
        #pragma unroll
        for (int p = 0; p < PN; ++p) {
            uint32_t bh[4], bl[4];
            const uint32_t ba = bAddr + (uint32_t)p * 16u * bStride + ks * 32;
            LDSM4(bh, ba);
            LDSM4(bl, ba + bHalf);
            mma_bf16(c[2*p],   ah, bh);
            mma_bf16(c[2*p],   ah, bl);
            mma_bf16(c[2*p],   al, bh);
            mma_bf16(c[2*p+1], ah, bh + 2);
            mma_bf16(c[2*p+1], ah, bl + 2);
            mma_bf16(c[2*p+1], al, bh + 2);
        }
    }
}

// Epilogue into smem (bias+BNS+relu, bf16 hi/lo split).
template <int PN>
__device__ __forceinline__ void epi_t(char* smem, uint32_t outOff, uint32_t outHalf,
                                      uint32_t outStride, const float* bias, int cbase,
                                      float (&c)[2 * PN][4], int mrow, int lane) {
    const int r0  = mrow + (lane >> 2);
    const int ccb = 2 * (lane & 3);
    #pragma unroll
    for (int f = 0; f < 2 * PN; ++f) {
        const int col = cbase + (f >> 1) * 16 + (f & 1) * 8 + ccb;
        const float bv0 = bias[col], bv1 = bias[col + 1];
        const float v00 = fmaxf((c[f][0] + bv0) * BNS_F, 0.0f);
        const float v01 = fmaxf((c[f][1] + bv1) * BNS_F, 0.0f);
        const float v10 = fmaxf((c[f][2] + bv0) * BNS_F, 0.0f);
        const float v11 = fmaxf((c[f][3] + bv1) * BNS_F, 0.0f);
        uint32_t l0, l1;
        const uint32_t h0 = pack_hi(v00, v01, &l0);
        const uint32_t h1 = pack_hi(v10, v11, &l1);
        const uint32_t o0 = outOff + (uint32_t)r0 * outStride + (uint32_t)col * 2u;
        const uint32_t o1 = o0 + 8u * outStride;
        *(uint32_t*)(smem + o0) = h0;
        *(uint32_t*)(smem + o0 + outHalf) = l0;
        *(uint32_t*)(smem + o1) = h1;
        *(uint32_t*)(smem + o1 + outHalf) = l1;
    }
}

__device__ __forceinline__ void stage_w2(char* smem, uint32_t off,
                                         const __nv_bfloat16* srcHi,
                                         const __nv_bfloat16* srcLo, int halfBytes) {
    float4* dh = (float4*)(smem + off);
    float4* dl = (float4*)(smem + off + halfBytes);
    const float4* sh = (const float4*)srcHi;
    const float4* sl = (const float4*)srcLo;
    const int n16 = halfBytes / 16;
    for (int i = threadIdx.x; i < n16; i += 256) { dh[i] = sh[i]; dl[i] = sl[i]; }
}

// ---------------------------------------------------------------------------
// Merged weight prep: transpose to [N][Kpad], split bf16 hi/lo, all 9 weights.
// ---------------------------------------------------------------------------
__device__ __forceinline__ void prep_one(const float* w, __nv_bfloat16* out,
                                         int idx, int Cin, int Cout, int Kpad) {
    const int n = idx / Kpad, kp = idx % Kpad;
    const float v = (kp < Cin) ? w[(size_t)kp * Cout + n] : 0.0f;
    const __nv_bfloat16 hi = __float2bfloat16(v);
    const __nv_bfloat16 lo = __float2bfloat16(v - __bfloat162float(hi));
    out[idx] = hi;
    out[Cout * Kpad + idx] = lo;
}

__global__ void prep_all_kernel(const float* w10, const float* w11, const float* w12,
                                const float* w20, const float* w21, const float* w22,
                                const float* w30, const float* w31, const float* w32) {
    // segment sizes
    const int s0 = 64*16, s1 = 64*64, s2 = 128*64, s3 = 128*152, s4 = 128*136,
              s5 = 256*136, s6 = 256*288, s7 = 512*256, s8 = 768*512;
    const int total = s0+s1+s2+s3+s4+s5+s6+s7+s8;
    for (int i = blockIdx.x * blockDim.x + threadIdx.x; i < total;
         i += gridDim.x * blockDim.x) {
        int idx = i;
        if (idx < s0) { prep_one(w10, g_w10b, idx, 6, 64, 16); continue; }   idx -= s0;
        if (idx < s1) { prep_one(w11, g_w11b, idx, 64, 64, 64); continue; }  idx -= s1;
        if (idx < s2) { prep_one(w12, g_w12b, idx, 64, 128, 64); continue; } idx -= s2;
        if (idx < s3) { prep_one(w20, g_w20b, idx, 131, 128, 152); continue; } idx -= s3;
        if (idx < s4) { prep_one(w21, g_w21b, idx, 128, 128, 136); continue; } idx -= s4;
        if (idx < s5) { prep_one(w22, g_w22b, idx, 128, 256, 136); continue; } idx -= s5;
        if (idx < s6) { prep_one(w30, g_w30b, idx, 259, 256, 288); continue; } idx -= s6;
        if (idx < s7) { prep_one(w31, g_w31b, idx, 256, 512, 256); continue; } idx -= s7;
        prep_one(w32, g_w32b, idx, 512, 768, 512);
    }
}

// ---------------------------------------------------------------------------
// FPS + ball (index-exact, unchanged).
// ---------------------------------------------------------------------------
__global__ void fps1_kernel(const float* __restrict__ x,
                            int* __restrict__ fidx, float* __restrict__ nxyz) {
    __shared__ float swv[32];
    __shared__ int   swi[32];
    __shared__ float cur[3];
    __shared__ int   slast;
    const int b = blockIdx.x;
    const int t = threadIdx.x;
    const int warp = t >> 5, lane = t & 31;
    const float* p = x + ((size_t)b * N1 + t) * 6;
    const float px = p[0], py = p[1], pz = p[2];
    float dist = 1e10f;
    if (t == 0) {
        fidx[b * M1] = 0;
        float* o = nxyz + (size_t)b * M1 * 3;
        o[0] = px; o[1] = py; o[2] = pz;
    }
    int last = 0;
    for (int it = 1; it < M1; ++it) {
        if (t == last) { cur[0] = px; cur[1] = py; cur[2] = pz; }
        __syncthreads();
        float dx = __fsub_rn(px, cur[0]);
        float dy = __fsub_rn(py, cur[1]);
        float dz = __fsub_rn(pz, cur[2]);
        float d  = __fadd_rn(__fadd_rn(__fmul_rn(dx, dx), __fmul_rn(dy, dy)),
                             __fmul_rn(dz, dz));
        dist = fminf(dist, d);
        float v = dist; int vi = t;
        #pragma unroll
        for (int off = 16; off; off >>= 1) {
            float v2 = __shfl_xor_sync(0xffffffffu, v, off);
            int   i2 = __shfl_xor_sync(0xffffffffu, vi, off);
            if (v2 > v || (v2 == v && i2 < vi)) { v = v2; vi = i2; }
        }
        if (lane == 0) { swv[warp] = v; swi[warp] = vi; }
        __syncthreads();
        if (warp == 0) {
            float wv = swv[lane]; int wi = swi[lane];
            #pragma unroll
            for (int off = 16; off; off >>= 1) {
                float v2 = __shfl_xor_sync(0xffffffffu, wv, off);
                int   i2 = __shfl_xor_sync(0xffffffffu, wi, off);
                if (v2 > wv || (v2 == wv && i2 < wi)) { wv = v2; wi = i2; }
            }
            if (lane == 0) { slast = wi; fidx[b * M1 + it] = wi; }
        }
        __syncthreads();
        last = slast;
        if (t == last) {
            float* o = nxyz + ((size_t)b * M1 + it) * 3;
            o[0] = px; o[1] = py; o[2] = pz;
        }
    }
}

__global__ void fps2_kernel(const float* __restrict__ pts,
                            int* __restrict__ fidx, float* __restrict__ nxyz) {
    const int gw   = (blockIdx.x * blockDim.x + threadIdx.x) >> 5;
    const int lane = threadIdx.x & 31;
    if (gw >= B_TOT) return;
    const float* pb = pts + (size_t)gw * M1 * 3;
    const float px = pb[lane * 3 + 0], py = pb[lane * 3 + 1], pz = pb[lane * 3 + 2];
    float dist = 1e10f;
    if (lane == 0) {
        fidx[gw * M2] = 0;
        float* o = nxyz + (size_t)gw * M2 * 3;
        o[0] = px; o[1] = py; o[2] = pz;
    }
    int last = 0;
    for (int it = 1; it < M2; ++it) {
        const float cx = __shfl_sync(0xffffffffu, px, last);
        const float cy = __shfl_sync(0xffffffffu, py, last);
        const float cz = __shfl_sync(0xffffffffu, pz, last);
        float dx = __fsub_rn(px, cx), dy = __fsub_rn(py, cy), dz = __fsub_rn(pz, cz);
        float d  = __fadd_rn(__fadd_rn(__fmul_rn(dx, dx), __fmul_rn(dy, dy)),
                             __fmul_rn(dz, dz));
        dist = fminf(dist, d);
        float v = dist; int vi = lane;
        #pragma unroll
        for (int off = 16; off; off >>= 1) {
            float v2 = __shfl_xor_sync(0xffffffffu, v, off);
            int   i2 = __shfl_xor_sync(0xffffffffu, vi, off);
            if (v2 > v || (v2 == v && i2 < vi)) { v = v2; vi = i2; }
        }
        last = vi;
        if (lane == 0) fidx[gw * M2 + it] = last;
        if (lane == last) {
            float* o = nxyz + ((size_t)gw * M2 + it) * 3;
            o[0] = px; o[1] = py; o[2] = pz;
        }
    }
}

__global__ void ball_kernel(const float* __restrict__ pts, int pstride,
                            const float* __restrict__ centers,
                            int M, int N, float r2, int* __restrict__ out) {
    const int gw   = (blockIdx.x * blockDim.x + threadIdx.x) >> 5;
    const int lane = threadIdx.x & 31;
    if (gw >= B_TOT * M) return;
    const int b = gw / M;
    const float* c = centers + (size_t)gw * 3;
    const float cx = c[0], cy = c[1], cz = c[2];
    const float cn = __fadd_rn(__fadd_rn(__fmul_rn(cx, cx), __fmul_rn(cy, cy)),
                               __fmul_rn(cz, cz));
    int* o = out + (size_t)gw * NSMP;
    int cnt = 0, first = -1;
    for (int base = 0; base < N && cnt < NSMP; base += 32) {
        const float* pp = pts + ((size_t)b * N + base + lane) * pstride;
        const float px = pp[0], py = pp[1], pz = pp[2];
        const float pn = __fadd_rn(__fadd_rn(__fmul_rn(px, px), __fmul_rn(py, py)),
                                   __fmul_rn(pz, pz));
        const float dt = __fadd_rn(__fadd_rn(__fmul_rn(cx, px), __fmul_rn(cy, py)),
                                   __fmul_rn(cz, pz));
        const float d2 = __fsub_rn(__fadd_rn(cn, pn), __fmul_rn(2.0f, dt));
        const bool hit = d2 < r2;
        const unsigned mask = __ballot_sync(0xffffffffu, hit);
        if (first < 0 && mask) first = base + __ffs(mask) - 1;
        const int pos = cnt + __popc(mask & ((1u << lane) - 1u));
        if (hit && pos < NSMP) o[pos] = base + lane;
        cnt += __popc(mask);
    }
    if (cnt > NSMP) cnt = NSMP;
    for (int k = cnt + lane; k < NSMP; k += 32) o[k] = first;
}

// ---------------------------------------------------------------------------
// SA1 HMMA: 4 centers/block (M=128), MLP 6(p16)->64->64->128, fused max.
// ---------------------------------------------------------------------------
#define S1_A0   0u
#define S1_A1   8192u
#define S1_A2   40960u
#define S1_B    73728u
#define S1_PART 106496u
#define S1_BIAS 110592u
#define S1_SMEM 111616

__global__ void __launch_bounds__(256)
sa1m_kernel(const float* __restrict__ x, const float* __restrict__ nx1,
            const int* __restrict__ ball,
            const float* __restrict__ b0_, const float* __restrict__ b1_,
            const float* __restrict__ b2_, float* __restrict__ out) {
    char* smem = (char*)dynsmem;
    const uint32_t su = smem_to_u32(smem);
    const int tid = threadIdx.x;
    const int wid = tid >> 5, lane = tid & 31;
    const int mrow = wid * 16;
    float* bias = (float*)(smem + S1_BIAS);
    float* part = (float*)(smem + S1_PART);
    const int bm0 = blockIdx.x * 4;
    const int b   = bm0 / M1;

    if (tid < 64) { bias[tid] = b0_[tid]; bias[64 + tid] = b1_[tid]; }
    if (tid < 128) bias[128 + tid] = b2_[tid];

    if (tid < 128) {
        const int row = tid;
        const int center = bm0 + (row >> 5);
        const int p = ball[center * NSMP + (row & 31)];
        const float* xr  = x + ((size_t)b * N1 + p) * 6;
        const float* ctr = nx1 + (size_t)center * 3;
        uint32_t* dh = (uint32_t*)(smem + S1_A0 + row * 32);
        uint32_t* dl = (uint32_t*)(smem + S1_A0 + 4096 + row * 32);
        #pragma unroll
        for (int j = 0; j < 8; ++j) {
            const int k = 2 * j;
            float v0 = 0.0f, v1 = 0.0f;
            if (k < 6)     v0 = (k < 3)     ? xr[k] - ctr[k]         : xr[k];
            if (k + 1 < 6) v1 = (k + 1 < 3) ? xr[k + 1] - ctr[k + 1] : xr[k + 1];
            uint32_t lo;
            dh[j] = pack_hi(v0, v1, &lo);
            dl[j] = lo;
        }
    }
    stage_w2(smem, S1_B, g_w10b, g_w10b + 64 * 16, 2048);
    __syncthreads();

    {
        float c[8][4];
        #pragma unroll
        for (int f = 0; f < 8; ++f)
            #pragma unroll
            for (int j = 0; j < 4; ++j) c[f][j] = 0.0f;
        gp_t<1, 4>(su + S1_A0, 4096u, 32u, su + S1_B, 2048u, 32u, mrow, 0, lane, c);
        epi_t<4>(smem, S1_A1, 16384u, 128u, bias, 0, c, mrow, lane);
    }
    __syncthreads();
    stage_w2(smem, S1_B, g_w11b, g_w11b + 64 * 64, 8192);
    __syncthreads();

    {
        float c[8][4];
        #pragma unroll
        for (int f = 0; f < 8; ++f)
            #pragma unroll
            for (int j = 0; j < 4; ++j) c[f][j] = 0.0f;
        gp_t<4, 4>(su + S1_A1, 16384u, 128u, su + S1_B, 8192u, 128u, mrow, 0, lane, c);
        epi_t<4>(smem, S1_A2, 16384u, 128u, bias + 64, 0, c, mrow, lane);
    }
    __syncthreads();
    stage_w2(smem, S1_B, g_w12b, g_w12b + 128 * 64, 16384);
    __syncthreads();

    {
        float c[16][4];
        #pragma unroll
        for (int f = 0; f < 16; ++f)
            #pragma unroll
            for (int j = 0; j < 4; ++j) c[f][j] = 0.0f;
        gp_t<4, 8>(su + S1_A2, 16384u, 128u, su + S1_B, 16384u, 128u, mrow, 0, lane, c);
        #pragma unroll
        for (int f = 0; f < 16; ++f) {
            float m0 = fmaxf(c[f][0], c[f][2]);
            float m1 = fmaxf(c[f][1], c[f][3]);
            #pragma unroll
            for (int off = 4; off <= 16; off <<= 1) {
                m0 = fmaxf(m0, __shfl_xor_sync(0xffffffffu, m0, off));
                m1 = fmaxf(m1, __shfl_xor_sync(0xffffffffu, m1, off));
            }
            if (lane < 4) {
                const int cc = (f >> 1) * 16 + (f & 1) * 8 + 2 * lane;
                part[wid * 128 + cc] = m0;
                part[wid * 128 + cc + 1] = m1;
            }
        }
        __syncthreads();
        for (int i = tid; i < 512; i += 256) {
            const int ci = i >> 7, n = i & 127;
            const float v = fmaxf(part[(2 * ci) * 128 + n],
                                  part[(2 * ci + 1) * 128 + n]);
            out[(size_t)(bm0 + ci) * 128 + n] =
                fmaxf((v + bias[128 + n]) * BNS_F, 0.0f);
        }
    }
}

// ---------------------------------------------------------------------------
// SA2 HMMA (validated R5, unchanged).
// ---------------------------------------------------------------------------
#define A_OFF     0u
#define HALF_A    38912u
#define B_OFF     77824u
#define HALF_B    69632u
#define PART_OFF  217088u
#define BIAS_OFF  221184u
#define SA2M_SMEM 223232

__device__ __forceinline__ void stage_b(char* smem, const __nv_bfloat16* src,
                                        int halfBytes) {
    float4* dh = (float4*)(smem + B_OFF);
    float4* dl = (float4*)(smem + B_OFF + HALF_B);
    const float4* sh = (const float4*)src;
    const float4* sl = (const float4*)((const char*)src + halfBytes);
    const int n16 = halfBytes / 16;
    for (int i = threadIdx.x; i < n16; i += 256) { dh[i] = sh[i]; dl[i] = sl[i]; }
}

template <int KS>
__device__ __forceinline__ void gemm_pass(uint32_t su, uint32_t aStride,
                                          uint32_t bStride, int nBase, int mw,
                                          int lane, float (&c)[16][4]) {
    const uint32_t aAddr = su + A_OFF + (uint32_t)(mw + (lane & 15)) * aStride +
                           (uint32_t)((lane >> 4) << 4);
    const uint32_t nrow  = (lane & 7) + ((lane >> 4) << 3);
    const uint32_t kcolB = ((lane >> 3) & 1) << 4;
    const uint32_t bAddr = su + B_OFF + (uint32_t)(nBase + nrow) * bStride + kcolB;
    #pragma unroll 1
    for (int ks = 0; ks < KS; ++ks) {
        uint32_t ah[4], al[4];
        LDSM4(ah, aAddr + ks * 32);
        LDSM4(al, aAddr + HALF_A + ks * 32);
        #pragma unroll
        for (int p = 0; p < 8; ++p) {
            uint32_t bh[4], bl[4];
            const uint32_t ba = bAddr + (uint32_t)p * 16u * bStride + ks * 32;
            LDSM4(bh, ba);
            LDSM4(bl, ba + HALF_B);
            mma_bf16(c[2*p],     ah, bh);
            mma_bf16(c[2*p],     ah, bl);
            mma_bf16(c[2*p],     al, bh);
            mma_bf16(c[2*p+1],   ah, bh + 2);
            mma_bf16(c[2*p+1],   ah, bl + 2);
            mma_bf16(c[2*p+1],   al, bh + 2);
        }
    }
}

__device__ __forceinline__ void epi_dense(char* smem, const float* bs, int boff,
                                          float (&c)[16][4], int mw, int lane) {
    const int r0  = mw + (lane >> 2);
    const int ccb = 2 * (lane & 3);
    #pragma unroll
    for (int f = 0; f < 16; ++f) {
        const int cc = (f >> 1) * 16 + (f & 1) * 8 + ccb;
        const float bv0 = bs[boff + cc], bv1 = bs[boff + cc + 1];
        const float v00 = fmaxf((c[f][0] + bv0) * BNS_F, 0.0f);
        const float v01 = fmaxf((c[f][1] + bv1) * BNS_F, 0.0f);
        const float v10 = fmaxf((c[f][2] + bv0) * BNS_F, 0.0f);
        const float v11 = fmaxf((c[f][3] + bv1) * BNS_F, 0.0f);
        uint32_t l0, l1;
        const uint32_t h0 = pack_hi(v00, v01, &l0);
        const uint32_t h1 = pack_hi(v10, v11, &l1);
        const uint32_t o0 = (uint32_t)r0 * 272u + (uint32_t)cc * 2u;
        const uint32_t o1 = o0 + 8u * 272u;
        *(uint32_t*)(smem + o0) = h0;
        *(uint32_t*)(smem + HALF_A + o0) = l0;
        *(uint32_t*)(smem + o1) = h1;
        *(uint32_t*)(smem + HALF_A + o1) = l1;
    }
}

__global__ void __launch_bounds__(256)
sa2m_kernel(const float* __restrict__ nx1, const float* __restrict__ f1,
            const float* __restrict__ nx2, const int* __restrict__ ball,
            const float* __restrict__ b0_, const float* __restrict__ b1_,
            const float* __restrict__ b2_, float* __restrict__ out) {
    char* smem = (char*)dynsmem;
    const uint32_t su = smem_to_u32(smem);
    const int tid = threadIdx.x;
    const int wid = tid >> 5, lane = tid & 31;
    const int mw  = wid * 16;
    float* bs = (float*)(smem + BIAS_OFF);
    float* part = (float*)(smem + PART_OFF);

    const int bm0 = blockIdx.x * 4;
    const int b   = bm0 / M2;

    if (tid < 128) { bs[tid] = b0_[tid]; bs[128 + tid] = b1_[tid]; }
    bs[256 + tid] = b2_[tid];

    {
        const int row = tid >> 1, seg = tid & 1;
        const int center = bm0 + (row >> 5);
        const int p = ball[center * NSMP + (row & 31)];
        const float* nx1r = nx1 + ((size_t)b * M1 + p) * 3;
        const float* ctr  = nx2 + (size_t)center * 3;
        const float* f1r  = f1 + ((size_t)b * M1 + p) * 128;
        #pragma unroll 1
        for (int i = 0; i < 36; ++i) {
            const int k = seg * 72 + 2 * i;
            float v0, v1;
            if (k < 3)        v0 = nx1r[k] - ctr[k];
            else if (k < 131) v0 = f1r[k - 3];
            else              v0 = 0.0f;
            const int k1 = k + 1;
            if (k1 < 3)        v1 = nx1r[k1] - ctr[k1];
            else if (k1 < 131) v1 = f1r[k1 - 3];
            else               v1 = 0.0f;
            uint32_t lo;
            const uint32_t hi = pack_hi(v0, v1, &lo);
            const uint32_t off = (uint32_t)row * 304u + (uint32_t)k * 2u;
            *(uint32_t*)(smem + off) = hi;
            *(uint32_t*)(smem + HALF_A + off) = lo;
        }
    }
    stage_b(smem, g_w20b, 128 * 152 * 2);
    __syncthreads();

    float c[16][4];
    #pragma unroll
    for (int f = 0; f < 16; ++f)
        #pragma unroll
        for (int j = 0; j < 4; ++j) c[f][j] = 0.0f;
    gemm_pass<9>(su, 304u, 304u, 0, mw, lane, c);
    __syncthreads();
    epi_dense(smem, bs, 0, c, mw, lane);
    stage_b(smem, g_w21b, 128 * 136 * 2);
    __syncthreads();

    #pragma unroll
    for (int f = 0; f < 16; ++f)
        #pragma unroll
        for (int j = 0; j < 4; ++j) c[f][j] = 0.0f;
    gemm_pass<8>(su, 272u, 272u, 0, mw, lane, c);
    __syncthreads();
    epi_dense(smem, bs, 128, c, mw, lane);
    stage_b(smem, g_w22b, 256 * 136 * 2);
    __syncthreads();

    #pragma unroll 1
    for (int h = 0; h < 2; ++h) {
        #pragma unroll
        for (int f = 0; f < 16; ++f)
            #pragma unroll
            for (int j = 0; j < 4; ++j) c[f][j] = 0.0f;
        gemm_pass<8>(su, 272u, 272u, h * 128, mw, lane, c);
        #pragma unroll
        for (int f = 0; f < 16; ++f) {
            float m0 = fmaxf(c[f][0], c[f][2]);
            float m1 = fmaxf(c[f][1], c[f][3]);
            #pragma unroll
            for (int off = 4; off <= 16; off <<= 1) {
                m0 = fmaxf(m0, __shfl_xor_sync(0xffffffffu, m0, off));
                m1 = fmaxf(m1, __shfl_xor_sync(0xffffffffu, m1, off));
            }
            if (lane < 4) {
                const int cc = (f >> 1) * 16 + (f & 1) * 8 + 2 * lane;
                part[wid * 128 + cc] = m0;
                part[wid * 128 + cc + 1] = m1;
            }
        }
        __syncthreads();
        for (int i = tid; i < 512; i += 256) {
            const int ci = i >> 7, n = i & 127;
            const float v = fmaxf(part[(2 * ci) * 128 + n],
                                  part[(2 * ci + 1) * 128 + n]);
            out[(size_t)(bm0 + ci) * 256 + h * 128 + n] =
                fmaxf((v + bs[256 + h * 128 + n]) * BNS_F, 0.0f);
        }
        __syncthreads();
    }
}

// ---------------------------------------------------------------------------
// Head input gather: rows [32768][288] bf16 hi/lo; cols 0-2 xyz2, 3-258 f2, pad 0.
// ---------------------------------------------------------------------------
__global__ void gather_a0_kernel(const float* __restrict__ nx2,
                                 const float* __restrict__ f2) {
    const int row = blockIdx.x * blockDim.x + threadIdx.x;
    if (row >= 32768) return;
    const float* nr = nx2 + (size_t)row * 3;
    const float* fr = f2 + (size_t)row * 256;
    uint32_t* dh = (uint32_t*)(g_a0 + (size_t)row * 288);
    uint32_t* dl = (uint32_t*)(g_a0 + A0HALF + (size_t)row * 288);
    #pragma unroll 4
    for (int j = 0; j < 144; ++j) {
        const int k = 2 * j;
        float v0, v1;
        if (k < 3)        v0 = nr[k];
        else if (k < 259) v0 = fr[k - 3];
        else              v0 = 0.0f;
        const int k1 = k + 1;
        if (k1 < 3)        v1 = nr[k1];
        else if (k1 < 259) v1 = fr[k1 - 3];
        else               v1 = 0.0f;
        uint32_t lo;
        dh[j] = pack_hi(v0, v1, &lo);
        dl[j] = lo;
    }
}

// ---------------------------------------------------------------------------
// Generic tiled GEMM: C[64 x 128] tile, K chunked by 32 from global.
// A: [32768][Kpad] bf16 hi/lo. B: [Nout][Kpad] bf16 hi/lo.
// smem: A 2x5120 @0 (stride 80), B 2x10240 @10240 (stride 80), bias @30720.
// MODE 0: dense out (bias+relu, bf16 hi/lo -> O[row][KpadO]).
// MODE 1: max over 16 rows (=1 batch/warp-mtile) -> gout fp32 [batch][768].
// ---------------------------------------------------------------------------
#define GM_BIAS 30720u
#define GM_SMEM 31232

template <int MODE>
__global__ void __launch_bounds__(256, 2)
gemm_kernel(const __nv_bfloat16* __restrict__ A, size_t aHalf, int Kpad, int KC,
            const __nv_bfloat16* __restrict__ Bw, size_t bHalf,
            const float* __restrict__ biasG,
            __nv_bfloat16* __restrict__ O, size_t oHalf, int KpadO,
            float* __restrict__ gout) {
    char* smem = (char*)dynsmem;
    const uint32_t su = smem_to_u32(smem);
    const int tid = threadIdx.x;
    const int wid = tid >> 5, lane = tid & 31;
    const int Mbase = blockIdx.x * 64;
    const int Nbase = blockIdx.y * 128;
    float* bias = (float*)(smem + GM_BIAS);
    if (tid < 128) bias[tid] = biasG[Nbase + tid];

    float c[8][4];
    #pragma unroll
    for (int f = 0; f < 8; ++f)
        #pragma unroll
        for (int j = 0; j < 4; ++j) c[f][j] = 0.0f;

    #pragma unroll 1
    for (int kc = 0; kc < KC; ++kc) {
        if (kc) __syncthreads();
        // stage A chunk: 64 rows x 32 cols, hi+lo
        {
            const int row = tid >> 2, q = tid & 3;
            const int half = q >> 1, seg = q & 1;
            const uint4* s = (const uint4*)(A + (size_t)half * aHalf +
                                            (size_t)(Mbase + row) * Kpad +
                                            kc * 32 + seg * 16);
            uint4* d = (uint4*)(smem + half * 5120 + row * 80 + seg * 32);
            d[0] = s[0]; d[1] = s[1];
        }
        // stage B chunk: 128 rows x 32 cols, hi+lo
        #pragma unroll
        for (int it = 0; it < 2; ++it) {
            const int t2 = tid + it * 256;
            const int row = t2 >> 2, q = t2 & 3;
            const int half = q >> 1, seg = q & 1;
            const uint4* s = (const uint4*)(Bw + (size_t)half * bHalf +
                                            (size_t)(Nbase + row) * Kpad +
                                            kc * 32 + seg * 16);
            uint4* d = (uint4*)(smem + 10240 + half * 10240 + row * 80 + seg * 32);
            d[0] = s[0]; d[1] = s[1];
        }
        __syncthreads();
        gp_t<2, 4>(su, 5120u, 80u, su + 10240u, 10240u, 80u,
                   (wid & 3) * 16, (wid >> 2) * 64, lane, c);
    }

    if (MODE == 0) {
        const int r0 = Mbase + (wid & 3) * 16 + (lane >> 2);
        const int cb = (wid >> 2) * 64 + 2 * (lane & 3);
        #pragma unroll
        for (int f = 0; f < 8; ++f) {
            const int cl = cb + (f >> 1) * 16 + (f & 1) * 8;   // local col
            const int col = Nbase + cl;
            const float bv0 = bias[cl], bv1 = bias[cl + 1];
            const float v00 = fmaxf((c[f][0] + bv0) * BNS_F, 0.0f);
            const float v01 = fmaxf((c[f][1] + bv1) * BNS_F, 0.0f);
            const float v10 = fmaxf((c[f][2] + bv0) * BNS_F, 0.0f);
            const float v11 = fmaxf((c[f][3] + bv1) * BNS_F, 0.0f);
            uint32_t l0, l1;
            const uint32_t h0 = pack_hi(v00, v01, &l0);
            const uint32_t h1 = pack_hi(v10, v11, &l1);
            *(uint32_t*)(O + (size_t)r0 * KpadO + col) = h0;
            *(uint32_t*)(O + oHalf + (size_t)r0 * KpadO + col) = l0;
            *(uint32_t*)(O + (size_t)(r0 + 8) * KpadO + col) = h1;
            *(uint32_t*)(O + oHalf + (size_t)(r0 + 8) * KpadO + col) = l1;
        }
    } else {
        const int batch = blockIdx.x * 4 + (wid & 3);
        const int cb = (wid >> 2) * 64;
        #pragma unroll
        for (int f = 0; f < 8; ++f) {
            float m0 = fmaxf(c[f][0], c[f][2]);
            float m1 = fmaxf(c[f][1], c[f][3]);
            #pragma unroll
            for (int off = 4; off <= 16; off <<= 1) {
                m0 = fmaxf(m0, __shfl_xor_sync(0xffffffffu, m0, off));
                m1 = fmaxf(m1, __shfl_xor_sync(0xffffffffu, m1, off));
            }
            if (lane < 4) {
                const int cl = cb + (f >> 1) * 16 + (f & 1) * 8 + 2 * lane;
                const int col = Nbase + cl;
                gout[(size_t)batch * 768 + col] =
                    fmaxf((m0 + bias[cl]) * BNS_F, 0.0f);
                gout[(size_t)batch * 768 + col + 1] =
                    fmaxf((m1 + bias[cl + 1]) * BNS_F, 0.0f);
            }
        }
    }
}

// ---------------------------------------------------------------------------
// FC: 16 batches/block share fc_w loads.
// ---------------------------------------------------------------------------
__global__ void __launch_bounds__(192)
fc_kernel(const float* __restrict__ g_in, const float* __restrict__ fcw,
          const float* __restrict__ fcb, float* __restrict__ out) {
    constexpr int FCB = 16, C = 768, NT = 192;
    __shared__ float gs[FCB * C];
    const int b0 = blockIdx.x * FCB;
    for (int i = threadIdx.x; i < FCB * C; i += NT)
        gs[i] = g_in[(size_t)b0 * C + i];
    __syncthreads();
    const int og = threadIdx.x;
    const float4 bv = *reinterpret_cast<const float4*>(fcb + 4 * og);
    ull_t a01[FCB], a23[FCB];
    #pragma unroll
    for (int i = 0; i < FCB; ++i) { a01[i] = 0ull; a23[i] = 0ull; }
    const float* wp = fcw + 4 * og;
    #pragma unroll 2
    for (int k = 0; k < C; ++k) {
        const ulonglong2 wq =
            *reinterpret_cast<const ulonglong2*>(wp + (size_t)k * C);
        #pragma unroll
        for (int i = 0; i < FCB; ++i) {
            const ull_t hh = dup2(gs[i * C + k]);
            FMA2(a01[i], hh, wq.x, a01[i]);
            FMA2(a23[i], hh, wq.y, a23[i]);
        }
    }
    #pragma unroll
    for (int i = 0; i < FCB; ++i) {
        const float2 p0 = unpk(a01[i]);
        const float2 p1 = unpk(a23[i]);
        float4 r = make_float4(p0.x + bv.x, p0.y + bv.y, p1.x + bv.z, p1.y + bv.w);
        *reinterpret_cast<float4*>(out + (size_t)(b0 + i) * C + 4 * og) = r;
    }
}

// ---------------------------------------------------------------------------
// Host launcher
// ---------------------------------------------------------------------------
extern "C" void kernel_launch(void* const* d_in, const int* in_sizes, int n_in,
                              void* d_out, int out_size) {
    const float* x   = (const float*)d_in[0];
    const float* w10 = (const float*)d_in[1];  const float* b10 = (const float*)d_in[2];
    const float* w11 = (const float*)d_in[3];  const float* b11 = (const float*)d_in[4];
    const float* w12 = (const float*)d_in[5];  const float* b12 = (const float*)d_in[6];
    const float* w20 = (const float*)d_in[7];  const float* b20 = (const float*)d_in[8];
    const float* w21 = (const float*)d_in[9];  const float* b21 = (const float*)d_in[10];
    const float* w22 = (const float*)d_in[11]; const float* b22 = (const float*)d_in[12];
    const float* w30 = (const float*)d_in[13]; const float* b30 = (const float*)d_in[14];
    const float* w31 = (const float*)d_in[15]; const float* b31 = (const float*)d_in[16];
    const float* w32 = (const float*)d_in[17]; const float* b32 = (const float*)d_in[18];
    const float* fcw = (const float*)d_in[19]; const float* fcb = (const float*)d_in[20];
    float* out = (float*)d_out;

    int *fps1p, *ball1p, *fps2p, *ball2p;
    float *nx1p, *f1p, *nx2p, *f2p, *gp;
    __nv_bfloat16 *a0p, *h0p, *h1p, *w30bp, *w31bp, *w32bp;
    cudaGetSymbolAddress((void**)&fps1p,  g_fps1);
    cudaGetSymbolAddress((void**)&nx1p,   g_nx1);
    cudaGetSymbolAddress((void**)&ball1p, g_ball1);
    cudaGetSymbolAddress((void**)&f1p,    g_f1);
    cudaGetSymbolAddress((void**)&fps2p,  g_fps2);
    cudaGetSymbolAddress((void**)&nx2p,   g_nx2);
    cudaGetSymbolAddress((void**)&ball2p, g_ball2);
    cudaGetSymbolAddress((void**)&f2p,    g_f2);
    cudaGetSymbolAddress((void**)&gp,     g_g);
    cudaGetSymbolAddress((void**)&a0p,    g_a0);
    cudaGetSymbolAddress((void**)&h0p,    g_h0);
    cudaGetSymbolAddress((void**)&h1p,    g_h1);
    cudaGetSymbolAddress((void**)&w30bp,  g_w30b);
    cudaGetSymbolAddress((void**)&w31bp,  g_w31b);
    cudaGetSymbolAddress((void**)&w32bp,  g_w32b);

    cudaFuncSetAttribute(sa1m_kernel, cudaFuncAttributeMaxDynamicSharedMemorySize, S1_SMEM);
    cudaFuncSetAttribute(sa2m_kernel, cudaFuncAttributeMaxDynamicSharedMemorySize, SA2M_SMEM);

    // 1: weight prep (single kernel)
    prep_all_kernel<<<1024, 256>>>(w10, w11, w12, w20, w21, w22, w30, w31, w32);
    // 2-3: FPS1 + ball1
    fps1_kernel<<<B_TOT, 1024>>>(x, fps1p, nx1p);
    ball_kernel<<<(B_TOT * M1 * 32 + 255) / 256, 256>>>(
        x, 6, nx1p, M1, N1, (float)(0.2 * 0.2), ball1p);
    // 4: SA1 (this launch slot gets profiled by ncu)
    sa1m_kernel<<<B_TOT * M1 / 4, 256, S1_SMEM>>>(x, nx1p, ball1p,
                                                  b10, b11, b12, f1p);
    // 5-7: FPS2 + ball2 + SA2
    fps2_kernel<<<(B_TOT * 32 + 127) / 128, 128>>>(nx1p, fps2p, nx2p);
    ball_kernel<<<(B_TOT * M2 * 32 + 255) / 256, 256>>>(
        nx1p, 3, nx2p, M2, M1, (float)(0.4 * 0.4), ball2p);
    sa2m_kernel<<<B_TOT * M2 / 4, 256, SA2M_SMEM>>>(nx1p, f1p, nx2p, ball2p,
                                                    b20, b21, b22, f2p);
    // 8: head input gather
    gather_a0_kernel<<<32768 / 256, 256>>>(nx2p, f2p);
    // 9-11: head GEMMs (L0 259p288->256, L1 256->512, L2 512->768 + max)
    gemm_kernel<0><<<dim3(512, 2), 256, GM_SMEM>>>(
        a0p, A0HALF, 288, 9, w30bp, (size_t)256 * 288, b30,
        h0p, H0HALF, 256, nullptr);
    gemm_kernel<0><<<dim3(512, 4), 256, GM_SMEM>>>(
        h0p, H0HALF, 256, 8, w31bp, (size_t)512 * 256, b31,
        h1p, H1HALF, 512, nullptr);
    gemm_kernel<1><<<dim3(512, 6), 256, GM_SMEM>>>(
        h1p, H1HALF, 512, 16, w32bp, (size_t)768 * 512, b32,
        nullptr, 0, 0, gp);
    // 12: FC
    fc_kernel<<<B_TOT / 16, 192>>>(gp, fcw, fcb, out);
}

// round 10
// speedup vs baseline: 1.1027x; 1.0384x over previous
#include <cuda_runtime.h>
#include <cuda_bf16.h>
#include <math.h>
#include <stdint.h>

// ---------------------------------------------------------------------------
// PointNet++ encoder forward. B=2048 clouds, N=1024 pts, 6 ch.
// All MLP stages on HMMA (mma.sync bf16x3 split, fp32 accumulate) with
// cp.async-pipelined weight staging.
// ---------------------------------------------------------------------------

#define B_TOT 2048
#define N1    1024
#define M1    32
#define M2    16
#define NSMP  32

__device__ int   g_fps1 [B_TOT * M1];
__device__ float g_nx1  [B_TOT * M1 * 3];
__device__ int   g_ball1[B_TOT * M1 * NSMP];
__device__ float g_f1   [B_TOT * M1 * 128];
__device__ int   g_fps2 [B_TOT * M2];
__device__ float g_nx2  [B_TOT * M2 * 3];
__device__ int   g_ball2[B_TOT * M2 * NSMP];
__device__ float g_f2   [B_TOT * M2 * 256];
__device__ float g_g    [B_TOT * 768];

// Pre-split weights: [N][Kpad] bf16, hi block then lo block.
__device__ __align__(16) __nv_bfloat16 g_w11b[2 * 64 * 64];
__device__ __align__(16) __nv_bfloat16 g_w12b[2 * 128 * 64];
__device__ __align__(16) __nv_bfloat16 g_w20b[2 * 128 * 152];
__device__ __align__(16) __nv_bfloat16 g_w21b[2 * 128 * 136];
__device__ __align__(16) __nv_bfloat16 g_w22b[2 * 256 * 136];
__device__ __align__(16) __nv_bfloat16 g_w30b[2 * 256 * 288];
__device__ __align__(16) __nv_bfloat16 g_w31b[2 * 512 * 256];
__device__ __align__(16) __nv_bfloat16 g_w32b[2 * 768 * 512];

// Head activations, [32768 rows][Kpad] bf16, hi block then lo block.
#define A0HALF ((size_t)32768 * 288)
#define H0HALF ((size_t)32768 * 256)
#define H1HALF ((size_t)32768 * 512)
__device__ __align__(16) __nv_bfloat16 g_a0[2 * 32768 * 288];
__device__ __align__(16) __nv_bfloat16 g_h0[2 * 32768 * 256];
__device__ __align__(16) __nv_bfloat16 g_h1[2 * 32768 * 512];

// ---- packed f32x2 helpers (FC kernel) ----------------------------------------
typedef unsigned long long ull_t;
__device__ __forceinline__ ull_t dup2(float v) {
    ull_t r; unsigned u = __float_as_uint(v);
    asm("mov.b64 %0, {%1, %1};" : "=l"(r) : "r"(u));
    return r;
}
__device__ __forceinline__ float2 unpk(ull_t p) {
    unsigned lo, hi;
    asm("mov.b64 {%0, %1}, %2;" : "=r"(lo), "=r"(hi) : "l"(p));
    return make_float2(__uint_as_float(lo), __uint_as_float(hi));
}
#define FMA2(d, a, b, c) \
    asm("fma.rn.f32x2 %0, %1, %2, %3;" : "=l"(d) : "l"(a), "l"(b), "l"(c))

#define BNS_F 0.99999500003749968f   // 1/sqrt(1+1e-5)

// ---- mma.sync / ldmatrix / cp.async helpers ----------------------------------
__device__ __forceinline__ uint32_t smem_to_u32(const void* p) {
    uint32_t a;
    asm("{ .reg .u64 t; cvta.to.shared.u64 t, %1; cvt.u32.u64 %0, t; }"
        : "=r"(a) : "l"(p));
    return a;
}
#define LDSM4(r, a) \
    asm volatile("ldmatrix.sync.aligned.m8n8.x4.shared.b16 {%0,%1,%2,%3}, [%4];" \
                 : "=r"((r)[0]), "=r"((r)[1]), "=r"((r)[2]), "=r"((r)[3]) : "r"(a))

__device__ __forceinline__ void mma_bf16(float* c, const uint32_t* a,
                                         const uint32_t* b) {
    asm volatile(
        "mma.sync.aligned.m16n8k16.row.col.f32.bf16.bf16.f32 "
        "{%0,%1,%2,%3}, {%4,%5,%6,%7}, {%8,%9}, {%0,%1,%2,%3};"
        : "+f"(c[0]), "+f"(c[1]), "+f"(c[2]), "+f"(c[3])
        : "r"(a[0]), "r"(a[1]), "r"(a[2]), "r"(a[3]), "r"(b[0]), "r"(b[1]));
}

#define CP_A16(dst, src) \
    asm volatile("cp.async.cg.shared.global [%0], [%1], 16;" \
                 :: "r"(dst), "l"(src) : "memory")
#define CP_COMMIT() asm volatile("cp.async.commit_group;" ::: "memory")
#define CP_WAIT0()  asm volatile("cp.async.wait_group 0;" ::: "memory")
#define CP_WAIT1()  asm volatile("cp.async.wait_group 1;" ::: "memory")

// linear async copy, 256 threads
__device__ __forceinline__ void cp_copy(uint32_t dst, const void* src, int bytes) {
    const char* s = (const char*)src;
    for (int i = threadIdx.x * 16; i < bytes; i += 256 * 16)
        CP_A16(dst + i, s + i);
}

__device__ __forceinline__ uint32_t pack_hi(float v0, float v1, uint32_t* lo) {
    __nv_bfloat162 hh = __floats2bfloat162_rn(v0, v1);
    __nv_bfloat162 ll = __floats2bfloat162_rn(v0 - __bfloat162float(hh.x),
                                              v1 - __bfloat162float(hh.y));
    *lo = *(const uint32_t*)&ll;
    return *(const uint32_t*)&hh;
}

extern __shared__ float dynsmem[];

// Generalized bf16x3 GEMM pass (fragment mapping validated R5).
template <int KS, int PN>
__device__ __forceinline__ void gp_t(uint32_t aBase, uint32_t aHalf, uint32_t aStride,
                                     uint32_t bBase, uint32_t bHalf, uint32_t bStride,
                                     int mrow, int nbase, int lane,
                                     float (&c)[2 * PN][4]) {
    const uint32_t aAddr = aBase + (uint32_t)(mrow + (lane & 15)) * aStride +
                           (uint32_t)((lane >> 4) << 4);
    const uint32_t nrow  = (lane & 7) + ((lane >> 4) << 3);
    const uint32_t kcolB = ((lane >> 3) & 1) << 4;
    const uint32_t bAddr = bBase + (uint32_t)(nbase + nrow) * bStride + kcolB;
    #pragma unroll 1
    for (int ks = 0; ks < KS; ++ks) {
        uint32_t ah[4], al[4];
        LDSM4(ah, aAddr + ks * 32);
        LDSM4(al, aAddr + aHalf + ks * 32);
        #pragma unroll
        for (int p = 0; p < PN; ++p) {
            uint32_t bh[4], bl[4];
            const uint32_t ba = bAddr + (uint32_t)p * 16u * bStride + ks * 32;
            LDSM4(bh, ba);
            LDSM4(bl, ba + bHalf);
            mma_bf16(c[2*p],   ah, bh);
            mma_bf16(c[2*p],   ah, bl);
            mma_bf16(c[2*p],   al, bh);
            mma_bf16(c[2*p+1], ah, bh + 2);
            mma_bf16(c[2*p+1], ah, bl + 2);
            mma_bf16(c[2*p+1], al, bh + 2);
        }
    }
}

// Epilogue into smem (bias+BNS+relu, bf16 hi/lo split).
template <int PN>
__device__ __forceinline__ void epi_t(char* smem, uint32_t outOff, uint32_t outHalf,
                                      uint32_t outStride, const float* bias, int cbase,
                                      float (&c)[2 * PN][4], int mrow, int lane) {
    const int r0  = mrow + (lane >> 2);
    const int ccb = 2 * (lane & 3);
    #pragma unroll
    for (int f = 0; f < 2 * PN; ++f) {
        const int col = cbase + (f >> 1) * 16 + (f & 1) * 8 + ccb;
        const float bv0 = bias[col], bv1 = bias[col + 1];
        const float v00 = fmaxf((c[f][0] + bv0) * BNS_F, 0.0f);
        const float v01 = fmaxf((c[f][1] + bv1) * BNS_F, 0.0f);
        const float v10 = fmaxf((c[f][2] + bv0) * BNS_F, 0.0f);
        const float v11 = fmaxf((c[f][3] + bv1) * BNS_F, 0.0f);
        uint32_t l0, l1;
        const uint32_t h0 = pack_hi(v00, v01, &l0);
        const uint32_t h1 = pack_hi(v10, v11, &l1);
        const uint32_t o0 = outOff + (uint32_t)r0 * outStride + (uint32_t)col * 2u;
        const uint32_t o1 = o0 + 8u * outStride;
        *(uint32_t*)(smem + o0) = h0;
        *(uint32_t*)(smem + o0 + outHalf) = l0;
        *(uint32_t*)(smem + o1) = h1;
        *(uint32_t*)(smem + o1 + outHalf) = l1;
    }
}

// ---------------------------------------------------------------------------
// Merged weight prep: transpose to [N][Kpad], split bf16 hi/lo.
// ---------------------------------------------------------------------------
__device__ __forceinline__ void prep_one(const float* w, __nv_bfloat16* out,
                                         int idx, int Cin, int Cout, int Kpad) {
    const int n = idx / Kpad, kp = idx % Kpad;
    const float v = (kp < Cin) ? w[(size_t)kp * Cout + n] : 0.0f;
    const __nv_bfloat16 hi = __float2bfloat16(v);
    const __nv_bfloat16 lo = __float2bfloat16(v - __bfloat162float(hi));
    out[idx] = hi;
    out[Cout * Kpad + idx] = lo;
}

__global__ void prep_all_kernel(const float* w11, const float* w12,
                                const float* w20, const float* w21, const float* w22,
                                const float* w30, const float* w31, const float* w32) {
    const int s1 = 64*64, s2 = 128*64, s3 = 128*152, s4 = 128*136,
              s5 = 256*136, s6 = 256*288, s7 = 512*256, s8 = 768*512;
    const int total = s1+s2+s3+s4+s5+s6+s7+s8;
    for (int i = blockIdx.x * blockDim.x + threadIdx.x; i < total;
         i += gridDim.x * blockDim.x) {
        int idx = i;
        if (idx < s1) { prep_one(w11, g_w11b, idx, 64, 64, 64); continue; }  idx -= s1;
        if (idx < s2) { prep_one(w12, g_w12b, idx, 64, 128, 64); continue; } idx -= s2;
        if (idx < s3) { prep_one(w20, g_w20b, idx, 131, 128, 152); continue; } idx -= s3;
        if (idx < s4) { prep_one(w21, g_w21b, idx, 128, 128, 136); continue; } idx -= s4;
        if (idx < s5) { prep_one(w22, g_w22b, idx, 128, 256, 136); continue; } idx -= s5;
        if (idx < s6) { prep_one(w30, g_w30b, idx, 259, 256, 288); continue; } idx -= s6;
        if (idx < s7) { prep_one(w31, g_w31b, idx, 256, 512, 256); continue; } idx -= s7;
        prep_one(w32, g_w32b, idx, 512, 768, 512);
    }
}

// ---------------------------------------------------------------------------
// FPS + ball (index-exact, unchanged).
// ---------------------------------------------------------------------------
__global__ void fps1_kernel(const float* __restrict__ x,
                            int* __restrict__ fidx, float* __restrict__ nxyz) {
    __shared__ float swv[32];
    __shared__ int   swi[32];
    __shared__ float cur[3];
    __shared__ int   slast;
    const int b = blockIdx.x;
    const int t = threadIdx.x;
    const int warp = t >> 5, lane = t & 31;
    const float* p = x + ((size_t)b * N1 + t) * 6;
    const float px = p[0], py = p[1], pz = p[2];
    float dist = 1e10f;
    if (t == 0) {
        fidx[b * M1] = 0;
        float* o = nxyz + (size_t)b * M1 * 3;
        o[0] = px; o[1] = py; o[2] = pz;
    }
    int last = 0;
    for (int it = 1; it < M1; ++it) {
        if (t == last) { cur[0] = px; cur[1] = py; cur[2] = pz; }
        __syncthreads();
        float dx = __fsub_rn(px, cur[0]);
        float dy = __fsub_rn(py, cur[1]);
        float dz = __fsub_rn(pz, cur[2]);
        float d  = __fadd_rn(__fadd_rn(__fmul_rn(dx, dx), __fmul_rn(dy, dy)),
                             __fmul_rn(dz, dz));
        dist = fminf(dist, d);
        float v = dist; int vi = t;
        #pragma unroll
        for (int off = 16; off; off >>= 1) {
            float v2 = __shfl_xor_sync(0xffffffffu, v, off);
            int   i2 = __shfl_xor_sync(0xffffffffu, vi, off);
            if (v2 > v || (v2 == v && i2 < vi)) { v = v2; vi = i2; }
        }
        if (lane == 0) { swv[warp] = v; swi[warp] = vi; }
        __syncthreads();
        if (warp == 0) {
            float wv = swv[lane]; int wi = swi[lane];
            #pragma unroll
            for (int off = 16; off; off >>= 1) {
                float v2 = __shfl_xor_sync(0xffffffffu, wv, off);
                int   i2 = __shfl_xor_sync(0xffffffffu, wi, off);
                if (v2 > wv || (v2 == wv && i2 < wi)) { wv = v2; wi = i2; }
            }
            if (lane == 0) { slast = wi; fidx[b * M1 + it] = wi; }
        }
        __syncthreads();
        last = slast;
        if (t == last) {
            float* o = nxyz + ((size_t)b * M1 + it) * 3;
            o[0] = px; o[1] = py; o[2] = pz;
        }
    }
}

__global__ void fps2_kernel(const float* __restrict__ pts,
                            int* __restrict__ fidx, float* __restrict__ nxyz) {
    const int gw   = (blockIdx.x * blockDim.x + threadIdx.x) >> 5;
    const int lane = threadIdx.x & 31;
    if (gw >= B_TOT) return;
    const float* pb = pts + (size_t)gw * M1 * 3;
    const float px = pb[lane * 3 + 0], py = pb[lane * 3 + 1], pz = pb[lane * 3 + 2];
    float dist = 1e10f;
    if (lane == 0) {
        fidx[gw * M2] = 0;
        float* o = nxyz + (size_t)gw * M2 * 3;
        o[0] = px; o[1] = py; o[2] = pz;
    }
    int last = 0;
    for (int it = 1; it < M2; ++it) {
        const float cx = __shfl_sync(0xffffffffu, px, last);
        const float cy = __shfl_sync(0xffffffffu, py, last);
        const float cz = __shfl_sync(0xffffffffu, pz, last);
        float dx = __fsub_rn(px, cx), dy = __fsub_rn(py, cy), dz = __fsub_rn(pz, cz);
        float d  = __fadd_rn(__fadd_rn(__fmul_rn(dx, dx), __fmul_rn(dy, dy)),
                             __fmul_rn(dz, dz));
        dist = fminf(dist, d);
        float v = dist; int vi = lane;
        #pragma unroll
        for (int off = 16; off; off >>= 1) {
            float v2 = __shfl_xor_sync(0xffffffffu, v, off);
            int   i2 = __shfl_xor_sync(0xffffffffu, vi, off);
            if (v2 > v || (v2 == v && i2 < vi)) { v = v2; vi = i2; }
        }
        last = vi;
        if (lane == 0) fidx[gw * M2 + it] = last;
        if (lane == last) {
            float* o = nxyz + ((size_t)gw * M2 + it) * 3;
            o[0] = px; o[1] = py; o[2] = pz;
        }
    }
}

__global__ void ball_kernel(const float* __restrict__ pts, int pstride,
                            const float* __restrict__ centers,
                            int M, int N, float r2, int* __restrict__ out) {
    const int gw   = (blockIdx.x * blockDim.x + threadIdx.x) >> 5;
    const int lane = threadIdx.x & 31;
    if (gw >= B_TOT * M) return;
    const int b = gw / M;
    const float* c = centers + (size_t)gw * 3;
    const float cx = c[0], cy = c[1], cz = c[2];
    const float cn = __fadd_rn(__fadd_rn(__fmul_rn(cx, cx), __fmul_rn(cy, cy)),
                               __fmul_rn(cz, cz));
    int* o = out + (size_t)gw * NSMP;
    int cnt = 0, first = -1;
    for (int base = 0; base < N && cnt < NSMP; base += 32) {
        const float* pp = pts + ((size_t)b * N + base + lane) * pstride;
        const float px = pp[0], py = pp[1], pz = pp[2];
        const float pn = __fadd_rn(__fadd_rn(__fmul_rn(px, px), __fmul_rn(py, py)),
                                   __fmul_rn(pz, pz));
        const float dt = __fadd_rn(__fadd_rn(__fmul_rn(cx, px), __fmul_rn(cy, py)),
                                   __fmul_rn(cz, pz));
        const float d2 = __fsub_rn(__fadd_rn(cn, pn), __fmul_rn(2.0f, dt));
        const bool hit = d2 < r2;
        const unsigned mask = __ballot_sync(0xffffffffu, hit);
        if (first < 0 && mask) first = base + __ffs(mask) - 1;
        const int pos = cnt + __popc(mask & ((1u << lane) - 1u));
        if (hit && pos < NSMP) o[pos] = base + lane;
        cnt += __popc(mask);
    }
    if (cnt > NSMP) cnt = NSMP;
    for (int k = cnt + lane; k < NSMP; k += 32) o[k] = first;
}

// ---------------------------------------------------------------------------
// SA1: 4 centers/block (M=128). L0 scalar in gather (K=6); L1/L2 HMMA.
// ---------------------------------------------------------------------------
#define S1_A1   0u
#define S1_A2   32768u
#define S1_B1   65536u
#define S1_B2   81920u
#define S1_PART 65536u
#define S1_BIAS 114688u
#define S1_SMEM 115456

__global__ void __launch_bounds__(256)
sa1m_kernel(const float* __restrict__ x, const float* __restrict__ nx1,
            const int* __restrict__ ball,
            const float* __restrict__ w0g, const float* __restrict__ b0g,
            const float* __restrict__ b1_, const float* __restrict__ b2_,
            float* __restrict__ out) {
    char* smem = (char*)dynsmem;
    const uint32_t su = smem_to_u32(smem);
    const int tid = threadIdx.x;
    const int wid = tid >> 5, lane = tid & 31;
    const int mrow = wid * 16;
    float* bias = (float*)(smem + S1_BIAS);
    float* part = (float*)(smem + S1_PART);
    const int bm0 = blockIdx.x * 4;
    const int b   = bm0 / M1;

    cp_copy(su + S1_B1, g_w11b, 8192);
    cp_copy(su + S1_B1 + 8192, g_w11b + 64 * 64, 8192);
    cp_copy(su + S1_B2, g_w12b, 16384);
    cp_copy(su + S1_B2 + 16384, g_w12b + 128 * 64, 16384);
    CP_COMMIT();

    if (tid < 64)  bias[tid] = b1_[tid];
    if (tid < 128) bias[64 + tid] = b2_[tid];

    {
        const int row = tid >> 1, seg = tid & 1;
        const int center = bm0 + (row >> 5);
        const int p = ball[center * NSMP + (row & 31)];
        const float* xr  = x + ((size_t)b * N1 + p) * 6;
        const float* ctr = nx1 + (size_t)center * 3;
        float in[6];
        #pragma unroll
        for (int k = 0; k < 6; ++k)
            in[k] = (k < 3) ? xr[k] - ctr[k] : xr[k];
        uint32_t* dh = (uint32_t*)(smem + S1_A1 + row * 128 + seg * 64);
        uint32_t* dl = (uint32_t*)(smem + S1_A1 + 16384 + row * 128 + seg * 64);
        #pragma unroll 4
        for (int j = 0; j < 16; ++j) {
            const int c0 = seg * 32 + 2 * j;
            float a0 = b0g[c0], a1 = b0g[c0 + 1];
            #pragma unroll
            for (int k = 0; k < 6; ++k) {
                a0 = fmaf(in[k], w0g[k * 64 + c0], a0);
                a1 = fmaf(in[k], w0g[k * 64 + c0 + 1], a1);
            }
            const float v0 = fmaxf(a0 * BNS_F, 0.0f);
            const float v1 = fmaxf(a1 * BNS_F, 0.0f);
            uint32_t lo;
            dh[j] = pack_hi(v0, v1, &lo);
            dl[j] = lo;
        }
    }
    CP_WAIT0();
    __syncthreads();

    {   // L1: K=64 (4 ks), N=64
        float c[8][4];
        #pragma unroll
        for (int f = 0; f < 8; ++f)
            #pragma unroll
            for (int j = 0; j < 4; ++j) c[f][j] = 0.0f;
        gp_t<4, 4>(su + S1_A1, 16384u, 128u, su + S1_B1, 8192u, 128u, mrow, 0, lane, c);
        epi_t<4>(smem, S1_A2, 16384u, 128u, bias, 0, c, mrow, lane);
    }
    __syncthreads();

    {   // L2: K=64, N=128 + fused max over 32 rows/center
        float c[16][4];
        #pragma unroll
        for (int f = 0; f < 16; ++f)
            #pragma unroll
            for (int j = 0; j < 4; ++j) c[f][j] = 0.0f;
        gp_t<4, 8>(su + S1_A2, 16384u, 128u, su + S1_B2, 16384u, 128u, mrow, 0, lane, c);
        #pragma unroll
        for (int f = 0; f < 16; ++f) {
            float m0 = fmaxf(c[f][0], c[f][2]);
            float m1 = fmaxf(c[f][1], c[f][3]);
            #pragma unroll
            for (int off = 4; off <= 16; off <<= 1) {
                m0 = fmaxf(m0, __shfl_xor_sync(0xffffffffu, m0, off));
                m1 = fmaxf(m1, __shfl_xor_sync(0xffffffffu, m1, off));
            }
            if (lane < 4) {
                const int cc = (f >> 1) * 16 + (f & 1) * 8 + 2 * lane;
                part[wid * 128 + cc] = m0;
                part[wid * 128 + cc + 1] = m1;
            }
        }
        __syncthreads();
        for (int i = tid; i < 512; i += 256) {
            const int ci = i >> 7, n = i & 127;
            const float v = fmaxf(part[(2 * ci) * 128 + n],
                                  part[(2 * ci + 1) * 128 + n]);
            out[(size_t)(bm0 + ci) * 128 + n] =
                fmaxf((v + bias[64 + n]) * BNS_F, 0.0f);
        }
    }
}

// ---------------------------------------------------------------------------
// SA2: 4 centers/block (M=128), cp.async-prefetched weights.
// ---------------------------------------------------------------------------
#define A2_A      0u
#define A2_AH     38912u
#define A2_B0     77824u
#define A2_B1     155648u
#define A2_BIAS   225280u
#define A2_PART   227328u
#define SA2M_SMEM 231424

__global__ void __launch_bounds__(256)
sa2m_kernel(const float* __restrict__ nx1, const float* __restrict__ f1,
            const float* __restrict__ nx2, const int* __restrict__ ball,
            const float* __restrict__ b0_, const float* __restrict__ b1_,
            const float* __restrict__ b2_, float* __restrict__ out) {
    char* smem = (char*)dynsmem;
    const uint32_t su = smem_to_u32(smem);
    const int tid = threadIdx.x;
    const int wid = tid >> 5, lane = tid & 31;
    const int mw  = wid * 16;
    float* bs = (float*)(smem + A2_BIAS);
    float* part = (float*)(smem + A2_PART);
    const int bm0 = blockIdx.x * 4;
    const int b   = bm0 / M2;

    cp_copy(su + A2_B0, g_w20b, 38912);
    cp_copy(su + A2_B0 + 38912, g_w20b + 128 * 152, 38912);
    CP_COMMIT();
    cp_copy(su + A2_B1, g_w21b, 34816);
    cp_copy(su + A2_B1 + 34816, g_w21b + 128 * 136, 34816);
    CP_COMMIT();

    if (tid < 128) { bs[tid] = b0_[tid]; bs[128 + tid] = b1_[tid]; }
    bs[256 + tid] = b2_[tid];

    {
        const int row = tid >> 1, seg = tid & 1;
        const int center = bm0 + (row >> 5);
        const int p = ball[center * NSMP + (row & 31)];
        const float* nx1r = nx1 + ((size_t)b * M1 + p) * 3;
        const float* ctr  = nx2 + (size_t)center * 3;
        const float* f1r  = f1 + ((size_t)b * M1 + p) * 128;
        #pragma unroll 1
        for (int i = 0; i < 36; ++i) {
            const int k = seg * 72 + 2 * i;
            float v0, v1;
            if (k < 3)        v0 = nx1r[k] - ctr[k];
            else if (k < 131) v0 = f1r[k - 3];
            else              v0 = 0.0f;
            const int k1 = k + 1;
            if (k1 < 3)        v1 = nx1r[k1] - ctr[k1];
            else if (k1 < 131) v1 = f1r[k1 - 3];
            else               v1 = 0.0f;
            uint32_t lo;
            const uint32_t hi = pack_hi(v0, v1, &lo);
            const uint32_t off = (uint32_t)row * 304u + (uint32_t)k * 2u;
            *(uint32_t*)(smem + A2_A + off) = hi;
            *(uint32_t*)(smem + A2_A + A2_AH + off) = lo;
        }
    }
    CP_WAIT1();
    __syncthreads();

    float c[16][4];
    // Layer 0: K=144 (9 ks), N=128
    #pragma unroll
    for (int f = 0; f < 16; ++f)
        #pragma unroll
        for (int j = 0; j < 4; ++j) c[f][j] = 0.0f;
    gp_t<9, 8>(su + A2_A, A2_AH, 304u, su + A2_B0, 38912u, 304u, mw, 0, lane, c);
    __syncthreads();
    cp_copy(su + A2_B0, g_w22b, 34816);
    cp_copy(su + A2_B0 + 34816, g_w22b + 256 * 136, 34816);
    CP_COMMIT();
    epi_t<8>(smem, A2_A, A2_AH, 272u, bs, 0, c, mw, lane);
    CP_WAIT1();
    __syncthreads();

    // Layer 1: K=128 (8 ks), N=128
    #pragma unroll
    for (int f = 0; f < 16; ++f)
        #pragma unroll
        for (int j = 0; j < 4; ++j) c[f][j] = 0.0f;
    gp_t<8, 8>(su + A2_A, A2_AH, 272u, su + A2_B1, 34816u, 272u, mw, 0, lane, c);
    __syncthreads();
    cp_copy(su + A2_B1, g_w22b + 128 * 136, 34816);
    cp_copy(su + A2_B1 + 34816, g_w22b + 256 * 136 + 128 * 136, 34816);
    CP_COMMIT();
    epi_t<8>(smem, A2_A, A2_AH, 272u, bs + 128, 0, c, mw, lane);
    CP_WAIT1();
    __syncthreads();

    // Layer 2: K=128, N=256 in two halves; fused max over 32 rows/center.
    #pragma unroll 1
    for (int h = 0; h < 2; ++h) {
        const uint32_t bBase = h ? (su + A2_B1) : (su + A2_B0);
        #pragma unroll
        for (int f = 0; f < 16; ++f)
            #pragma unroll
            for (int j = 0; j < 4; ++j) c[f][j] = 0.0f;
        gp_t<8, 8>(su + A2_A, A2_AH, 272u, bBase, 34816u, 272u, mw, 0, lane, c);
        #pragma unroll
        for (int f = 0; f < 16; ++f) {
            float m0 = fmaxf(c[f][0], c[f][2]);
            float m1 = fmaxf(c[f][1], c[f][3]);
            #pragma unroll
            for (int off = 4; off <= 16; off <<= 1) {
                m0 = fmaxf(m0, __shfl_xor_sync(0xffffffffu, m0, off));
                m1 = fmaxf(m1, __shfl_xor_sync(0xffffffffu, m1, off));
            }
            if (lane < 4) {
                const int cc = (f >> 1) * 16 + (f & 1) * 8 + 2 * lane;
                part[wid * 128 + cc] = m0;
                part[wid * 128 + cc + 1] = m1;
            }
        }
        __syncthreads();
        for (int i = tid; i < 512; i += 256) {
            const int ci = i >> 7, n = i & 127;
            const float v = fmaxf(part[(2 * ci) * 128 + n],
                                  part[(2 * ci + 1) * 128 + n]);
            out[(size_t)(bm0 + ci) * 256 + h * 128 + n] =
                fmaxf((v + bs[256 + h * 128 + n]) * BNS_F, 0.0f);
        }
        if (h == 0) CP_WAIT0();
        __syncthreads();
    }
}

// ---------------------------------------------------------------------------
// Head input gather.
// ---------------------------------------------------------------------------
__global__ void gather_a0_kernel(const float* __restrict__ nx2,
                                 const float* __restrict__ f2) {
    const int row = blockIdx.x * blockDim.x + threadIdx.x;
    if (row >= 32768) return;
    const float* nr = nx2 + (size_t)row * 3;
    const float* fr = f2 + (size_t)row * 256;
    uint32_t* dh = (uint32_t*)(g_a0 + (size_t)row * 288);
    uint32_t* dl = (uint32_t*)(g_a0 + A0HALF + (size_t)row * 288);
    #pragma unroll 4
    for (int j = 0; j < 144; ++j) {
        const int k = 2 * j;
        float v0, v1;
        if (k < 3)        v0 = nr[k];
        else if (k < 259) v0 = fr[k - 3];
        else              v0 = 0.0f;
        const int k1 = k + 1;
        if (k1 < 3)        v1 = nr[k1];
        else if (k1 < 259) v1 = fr[k1 - 3];
        else               v1 = 0.0f;
        uint32_t lo;
        dh[j] = pack_hi(v0, v1, &lo);
        dl[j] = lo;
    }
}

// ---------------------------------------------------------------------------
// Pipelined tiled GEMM: C[64 x 128], K chunked by 32, double-buffered cp.async.
// ---------------------------------------------------------------------------
#define GM_BUF  30720u
#define GM_BIAS 61440u
#define GM_SMEM 61952

__device__ __forceinline__ void gm_load(uint32_t bufBase,
                                        const __nv_bfloat16* A, size_t aHalf,
                                        const __nv_bfloat16* Bw, size_t bHalf,
                                        int Kpad, int Mbase, int Nbase, int kc) {
    const int tid = threadIdx.x;
    {
        const int row = tid >> 2, q = tid & 3;
        const int half = q >> 1, seg = q & 1;
        const char* s = (const char*)(A + (size_t)half * aHalf +
                                      (size_t)(Mbase + row) * Kpad + kc * 32 + seg * 16);
        const uint32_t d = bufBase + half * 5120u + row * 80u + seg * 32u;
        CP_A16(d, s);
        CP_A16(d + 16, s + 16);
    }
    #pragma unroll
    for (int it = 0; it < 2; ++it) {
        const int t2 = tid + it * 256;
        const int row = t2 >> 2, q = t2 & 3;
        const int half = q >> 1, seg = q & 1;
        const char* s = (const char*)(Bw + (size_t)half * bHalf +
                                      (size_t)(Nbase + row) * Kpad + kc * 32 + seg * 16);
        const uint32_t d = bufBase + 10240u + half * 10240u + row * 80u + seg * 32u;
        CP_A16(d, s);
        CP_A16(d + 16, s + 16);
    }
}

template <int MODE>
__global__ void __launch_bounds__(256, 2)
gemm_kernel(const __nv_bfloat16* __restrict__ A, size_t aHalf, int Kpad, int KC,
            const __nv_bfloat16* __restrict__ Bw, size_t bHalf,
            const float* __restrict__ biasG,
            __nv_bfloat16* __restrict__ O, size_t oHalf, int KpadO,
            float* __restrict__ gout) {
    char* smem = (char*)dynsmem;
    const uint32_t su = smem_to_u32(smem);
    const int tid = threadIdx.x;
    const int wid = tid >> 5, lane = tid & 31;
    const int Mbase = blockIdx.x * 64;
    const int Nbase = blockIdx.y * 128;
    float* bias = (float*)(smem + GM_BIAS);

    gm_load(su, A, aHalf, Bw, bHalf, Kpad, Mbase, Nbase, 0);
    CP_COMMIT();
    if (tid < 128) bias[tid] = biasG[Nbase + tid];

    float c[8][4];
    #pragma unroll
    for (int f = 0; f < 8; ++f)
        #pragma unroll
        for (int j = 0; j < 4; ++j) c[f][j] = 0.0f;

    #pragma unroll 1
    for (int kc = 0; kc < KC; ++kc) {
        CP_WAIT0();
        __syncthreads();
        if (kc + 1 < KC) {
            gm_load(su + ((kc + 1) & 1) * GM_BUF, A, aHalf, Bw, bHalf,
                    Kpad, Mbase, Nbase, kc + 1);
            CP_COMMIT();
        }
        const uint32_t buf = su + (kc & 1) * GM_BUF;
        gp_t<2, 4>(buf, 5120u, 80u, buf + 10240u, 10240u, 80u,
                   (wid & 3) * 16, (wid >> 2) * 64, lane, c);
    }

    if (MODE == 0) {
        const int r0 = Mbase + (wid & 3) * 16 + (lane >> 2);
        const int cb = (wid >> 2) * 64 + 2 * (lane & 3);
        #pragma unroll
        for (int f = 0; f < 8; ++f) {
            const int cl = cb + (f >> 1) * 16 + (f & 1) * 8;
            const int col = Nbase + cl;
            const float bv0 = bias[cl], bv1 = bias[cl + 1];
            const float v00 = fmaxf((c[f][0] + bv0) * BNS_F, 0.0f);
            const float v01 = fmaxf((c[f][1] + bv1) * BNS_F, 0.0f);
            const float v10 = fmaxf((c[f][2] + bv0) * BNS_F, 0.0f);
            const float v11 = fmaxf((c[f][3] + bv1) * BNS_F, 0.0f);
            uint32_t l0, l1;
            const uint32_t h0 = pack_hi(v00, v01, &l0);
            const uint32_t h1 = pack_hi(v10, v11, &l1);
            *(uint32_t*)(O + (size_t)r0 * KpadO + col) = h0;
            *(uint32_t*)(O + oHalf + (size_t)r0 * KpadO + col) = l0;
            *(uint32_t*)(O + (size_t)(r0 + 8) * KpadO + col) = h1;
            *(uint32_t*)(O + oHalf + (size_t)(r0 + 8) * KpadO + col) = l1;
        }
    } else {
        const int batch = blockIdx.x * 4 + (wid & 3);
        const int cb = (wid >> 2) * 64;
        #pragma unroll
        for (int f = 0; f < 8; ++f) {
            float m0 = fmaxf(c[f][0], c[f][2]);
            float m1 = fmaxf(c[f][1], c[f][3]);
            #pragma unroll
            for (int off = 4; off <= 16; off <<= 1) {
                m0 = fmaxf(m0, __shfl_xor_sync(0xffffffffu, m0, off));
                m1 = fmaxf(m1, __shfl_xor_sync(0xffffffffu, m1, off));
            }
            if (lane < 4) {
                const int cl = cb + (f >> 1) * 16 + (f & 1) * 8 + 2 * lane;
                const int col = Nbase + cl;
                gout[(size_t)batch * 768 + col] =
                    fmaxf((m0 + bias[cl]) * BNS_F, 0.0f);
                gout[(size_t)batch * 768 + col + 1] =
                    fmaxf((m1 + bias[cl + 1]) * BNS_F, 0.0f);
            }
        }
    }
}

// ---------------------------------------------------------------------------
// FC: 16 batches/block share fc_w loads.
// ---------------------------------------------------------------------------
__global__ void __launch_bounds__(192)
fc_kernel(const float* __restrict__ g_in, const float* __restrict__ fcw,
          const float* __restrict__ fcb, float* __restrict__ out) {
    constexpr int FCB = 16, C = 768, NT = 192;
    __shared__ float gs[FCB * C];
    const int b0 = blockIdx.x * FCB;
    for (int i = threadIdx.x; i < FCB * C; i += NT)
        gs[i] = g_in[(size_t)b0 * C + i];
    __syncthreads();
    const int og = threadIdx.x;
    const float4 bv = *reinterpret_cast<const float4*>(fcb + 4 * og);
    ull_t a01[FCB], a23[FCB];
    #pragma unroll
    for (int i = 0; i < FCB; ++i) { a01[i] = 0ull; a23[i] = 0ull; }
    const float* wp = fcw + 4 * og;
    #pragma unroll 2
    for (int k = 0; k < C; ++k) {
        const ulonglong2 wq =
            *reinterpret_cast<const ulonglong2*>(wp + (size_t)k * C);
        #pragma unroll
        for (int i = 0; i < FCB; ++i) {
            const ull_t hh = dup2(gs[i * C + k]);
            FMA2(a01[i], hh, wq.x, a01[i]);
            FMA2(a23[i], hh, wq.y, a23[i]);
        }
    }
    #pragma unroll
    for (int i = 0; i < FCB; ++i) {
        const float2 p0 = unpk(a01[i]);
        const float2 p1 = unpk(a23[i]);
        float4 r = make_float4(p0.x + bv.x, p0.y + bv.y, p1.x + bv.z, p1.y + bv.w);
        *reinterpret_cast<float4*>(out + (size_t)(b0 + i) * C + 4 * og) = r;
    }
}

// ---------------------------------------------------------------------------
// Host launcher
// ---------------------------------------------------------------------------
extern "C" void kernel_launch(void* const* d_in, const int* in_sizes, int n_in,
                              void* d_out, int out_size) {
    const float* x   = (const float*)d_in[0];
    const float* w10 = (const float*)d_in[1];  const float* b10 = (const float*)d_in[2];
    const float* w11 = (const float*)d_in[3];  const float* b11 = (const float*)d_in[4];
    const float* w12 = (const float*)d_in[5];  const float* b12 = (const float*)d_in[6];
    const float* w20 = (const float*)d_in[7];  const float* b20 = (const float*)d_in[8];
    const float* w21 = (const float*)d_in[9];  const float* b21 = (const float*)d_in[10];
    const float* w22 = (const float*)d_in[11]; const float* b22 = (const float*)d_in[12];
    const float* w30 = (const float*)d_in[13]; const float* b30 = (const float*)d_in[14];
    const float* w31 = (const float*)d_in[15]; const float* b31 = (const float*)d_in[16];
    const float* w32 = (const float*)d_in[17]; const float* b32 = (const float*)d_in[18];
    const float* fcw = (const float*)d_in[19]; const float* fcb = (const float*)d_in[20];
    float* out = (float*)d_out;

    int *fps1p, *ball1p, *fps2p, *ball2p;
    float *nx1p, *f1p, *nx2p, *f2p, *gp;
    __nv_bfloat16 *a0p, *h0p, *h1p, *w30bp, *w31bp, *w32bp;
    cudaGetSymbolAddress((void**)&fps1p,  g_fps1);
    cudaGetSymbolAddress((void**)&nx1p,   g_nx1);
    cudaGetSymbolAddress((void**)&ball1p, g_ball1);
    cudaGetSymbolAddress((void**)&f1p,    g_f1);
    cudaGetSymbolAddress((void**)&fps2p,  g_fps2);
    cudaGetSymbolAddress((void**)&nx2p,   g_nx2);
    cudaGetSymbolAddress((void**)&ball2p, g_ball2);
    cudaGetSymbolAddress((void**)&f2p,    g_f2);
    cudaGetSymbolAddress((void**)&gp,     g_g);
    cudaGetSymbolAddress((void**)&a0p,    g_a0);
    cudaGetSymbolAddress((void**)&h0p,    g_h0);
    cudaGetSymbolAddress((void**)&h1p,    g_h1);
    cudaGetSymbolAddress((void**)&w30bp,  g_w30b);
    cudaGetSymbolAddress((void**)&w31bp,  g_w31b);
    cudaGetSymbolAddress((void**)&w32bp,  g_w32b);

    cudaFuncSetAttribute(sa1m_kernel, cudaFuncAttributeMaxDynamicSharedMemorySize, S1_SMEM);
    cudaFuncSetAttribute(sa2m_kernel, cudaFuncAttributeMaxDynamicSharedMemorySize, SA2M_SMEM);
    cudaFuncSetAttribute(gemm_kernel<0>, cudaFuncAttributeMaxDynamicSharedMemorySize, GM_SMEM);
    cudaFuncSetAttribute(gemm_kernel<1>, cudaFuncAttributeMaxDynamicSharedMemorySize, GM_SMEM);

    // 1: weight prep
    prep_all_kernel<<<1024, 256>>>(w11, w12, w20, w21, w22, w30, w31, w32);
    // 2-3: FPS1 + ball1
    fps1_kernel<<<B_TOT, 1024>>>(x, fps1p, nx1p);
    ball_kernel<<<(B_TOT * M1 * 32 + 255) / 256, 256>>>(
        x, 6, nx1p, M1, N1, (float)(0.2 * 0.2), ball1p);
    // 4: SA1
    sa1m_kernel<<<B_TOT * M1 / 4, 256, S1_SMEM>>>(x, nx1p, ball1p,
                                                  w10, b10, b11, b12, f1p);
    // 5-7: FPS2 + ball2 + SA2
    fps2_kernel<<<(B_TOT * 32 + 127) / 128, 128>>>(nx1p, fps2p, nx2p);
    ball_kernel<<<(B_TOT * M2 * 32 + 255) / 256, 256>>>(
        nx1p, 3, nx2p, M2, M1, (float)(0.4 * 0.4), ball2p);
    sa2m_kernel<<<B_TOT * M2 / 4, 256, SA2M_SMEM>>>(nx1p, f1p, nx2p, ball2p,
                                                    b20, b21, b22, f2p);
    // 8: head input gather
    gather_a0_kernel<<<32768 / 256, 256>>>(nx2p, f2p);
    // 9-11: head GEMMs
    gemm_kernel<0><<<dim3(512, 2), 256, GM_SMEM>>>(
        a0p, A0HALF, 288, 9, w30bp, (size_t)256 * 288, b30,
        h0p, H0HALF, 256, nullptr);
    gemm_kernel<0><<<dim3(512, 4), 256, GM_SMEM>>>(
        h0p, H0HALF, 256, 8, w31bp, (size_t)512 * 256, b31,
        h1p, H1HALF, 512, nullptr);
    gemm_kernel<1><<<dim3(512, 6), 256, GM_SMEM>>>(
        h1p, H1HALF, 512, 16, w32bp, (size_t)768 * 512, b32,
        nullptr, 0, 0, gp);
    // 12: FC
    fc_kernel<<<B_TOT / 16, 192>>>(gp, fcw, fcb, out);
}

// round 11
// speedup vs baseline: 1.5136x; 1.3726x over previous
#include <cuda_runtime.h>
#include <cuda_fp16.h>
#include <math.h>
#include <stdint.h>

// ---------------------------------------------------------------------------
// PointNet++ encoder forward. B=2048 clouds, N=1024 pts, 6 ch.
// All MLP stages on HMMA fp16x2: activations split hi/lo (Dekker), weights
// single fp16, fp32 accumulate. 2 MMAs per logical k-step.
// ---------------------------------------------------------------------------

#define B_TOT 2048
#define N1    1024
#define M1    32
#define M2    16
#define NSMP  32

__device__ int   g_fps1 [B_TOT * M1];
__device__ float g_nx1  [B_TOT * M1 * 3];
__device__ int   g_ball1[B_TOT * M1 * NSMP];
__device__ float g_f1   [B_TOT * M1 * 128];
__device__ int   g_fps2 [B_TOT * M2];
__device__ float g_nx2  [B_TOT * M2 * 3];
__device__ int   g_ball2[B_TOT * M2 * NSMP];
__device__ float g_f2   [B_TOT * M2 * 256];
__device__ float g_g    [B_TOT * 768];

// Weights: [N][Kpad] fp16 (single precision-split NOT needed for weights).
__device__ __align__(16) __half g_w11h[64 * 64];
__device__ __align__(16) __half g_w12h[128 * 64];
__device__ __align__(16) __half g_w20h[128 * 152];
__device__ __align__(16) __half g_w21h[128 * 136];
__device__ __align__(16) __half g_w22h[256 * 136];
__device__ __align__(16) __half g_w30h[256 * 288];
__device__ __align__(16) __half g_w31h[512 * 256];
__device__ __align__(16) __half g_w32h[768 * 512];

// Head activations, [32768 rows][Kpad] fp16, hi block then lo block.
#define A0HALF ((size_t)32768 * 288)
#define H0HALF ((size_t)32768 * 256)
#define H1HALF ((size_t)32768 * 512)
__device__ __align__(16) __half g_a0[2 * 32768 * 288];
__device__ __align__(16) __half g_h0[2 * 32768 * 256];
__device__ __align__(16) __half g_h1[2 * 32768 * 512];

// ---- packed f32x2 helpers (FC kernel) ----------------------------------------
typedef unsigned long long ull_t;
__device__ __forceinline__ ull_t dup2(float v) {
    ull_t r; unsigned u = __float_as_uint(v);
    asm("mov.b64 %0, {%1, %1};" : "=l"(r) : "r"(u));
    return r;
}
__device__ __forceinline__ float2 unpk(ull_t p) {
    unsigned lo, hi;
    asm("mov.b64 {%0, %1}, %2;" : "=r"(lo), "=r"(hi) : "l"(p));
    return make_float2(__uint_as_float(lo), __uint_as_float(hi));
}
#define FMA2(d, a, b, c) \
    asm("fma.rn.f32x2 %0, %1, %2, %3;" : "=l"(d) : "l"(a), "l"(b), "l"(c))

#define BNS_F 0.99999500003749968f   // 1/sqrt(1+1e-5)

// ---- mma.sync / ldmatrix / cp.async helpers ----------------------------------
__device__ __forceinline__ uint32_t smem_to_u32(const void* p) {
    uint32_t a;
    asm("{ .reg .u64 t; cvta.to.shared.u64 t, %1; cvt.u32.u64 %0, t; }"
        : "=r"(a) : "l"(p));
    return a;
}
#define LDSM4(r, a) \
    asm volatile("ldmatrix.sync.aligned.m8n8.x4.shared.b16 {%0,%1,%2,%3}, [%4];" \
                 : "=r"((r)[0]), "=r"((r)[1]), "=r"((r)[2]), "=r"((r)[3]) : "r"(a))

__device__ __forceinline__ void mma_f16(float* c, const uint32_t* a,
                                        const uint32_t* b) {
    asm volatile(
        "mma.sync.aligned.m16n8k16.row.col.f32.f16.f16.f32 "
        "{%0,%1,%2,%3}, {%4,%5,%6,%7}, {%8,%9}, {%0,%1,%2,%3};"
        : "+f"(c[0]), "+f"(c[1]), "+f"(c[2]), "+f"(c[3])
        : "r"(a[0]), "r"(a[1]), "r"(a[2]), "r"(a[3]), "r"(b[0]), "r"(b[1]));
}

#define CP_A16(dst, src) \
    asm volatile("cp.async.cg.shared.global [%0], [%1], 16;" \
                 :: "r"(dst), "l"(src) : "memory")
#define CP_COMMIT() asm volatile("cp.async.commit_group;" ::: "memory")
#define CP_WAIT0()  asm volatile("cp.async.wait_group 0;" ::: "memory")
#define CP_WAIT1()  asm volatile("cp.async.wait_group 1;" ::: "memory")

__device__ __forceinline__ void cp_copy(uint32_t dst, const void* src, int bytes) {
    const char* s = (const char*)src;
    for (int i = threadIdx.x * 16; i < bytes; i += 256 * 16)
        CP_A16(dst + i, s + i);
}

// fp16 Dekker split: returns packed half2 hi, writes packed half2 lo.
__device__ __forceinline__ uint32_t pack_hi(float v0, float v1, uint32_t* lo) {
    __half2 hh = __floats2half2_rn(v0, v1);
    __half2 ll = __floats2half2_rn(v0 - __low2float(hh), v1 - __high2float(hh));
    *lo = *(const uint32_t*)&ll;
    return *(const uint32_t*)&hh;
}

extern __shared__ float dynsmem[];

// fp16x2 GEMM pass: A split hi/lo, B single. 2 MMAs per (p, half-n).
template <int KS, int PN>
__device__ __forceinline__ void gp_t(uint32_t aBase, uint32_t aHalf, uint32_t aStride,
                                     uint32_t bBase, uint32_t bStride,
                                     int mrow, int nbase, int lane,
                                     float (&c)[2 * PN][4]) {
    const uint32_t aAddr = aBase + (uint32_t)(mrow + (lane & 15)) * aStride +
                           (uint32_t)((lane >> 4) << 4);
    const uint32_t nrow  = (lane & 7) + ((lane >> 4) << 3);
    const uint32_t kcolB = ((lane >> 3) & 1) << 4;
    const uint32_t bAddr = bBase + (uint32_t)(nbase + nrow) * bStride + kcolB;
    #pragma unroll 1
    for (int ks = 0; ks < KS; ++ks) {
        uint32_t ah[4], al[4];
        LDSM4(ah, aAddr + ks * 32);
        LDSM4(al, aAddr + aHalf + ks * 32);
        #pragma unroll
        for (int p = 0; p < PN; ++p) {
            uint32_t bh[4];
            LDSM4(bh, bAddr + (uint32_t)p * 16u * bStride + ks * 32);
            mma_f16(c[2*p],   ah, bh);
            mma_f16(c[2*p],   al, bh);
            mma_f16(c[2*p+1], ah, bh + 2);
            mma_f16(c[2*p+1], al, bh + 2);
        }
    }
}

// Epilogue into smem (bias+BNS+relu, fp16 hi/lo split).
template <int PN>
__device__ __forceinline__ void epi_t(char* smem, uint32_t outOff, uint32_t outHalf,
                                      uint32_t outStride, const float* bias, int cbase,
                                      float (&c)[2 * PN][4], int mrow, int lane) {
    const int r0  = mrow + (lane >> 2);
    const int ccb = 2 * (lane & 3);
    #pragma unroll
    for (int f = 0; f < 2 * PN; ++f) {
        const int col = cbase + (f >> 1) * 16 + (f & 1) * 8 + ccb;
        const float bv0 = bias[col], bv1 = bias[col + 1];
        const float v00 = fmaxf((c[f][0] + bv0) * BNS_F, 0.0f);
        const float v01 = fmaxf((c[f][1] + bv1) * BNS_F, 0.0f);
        const float v10 = fmaxf((c[f][2] + bv0) * BNS_F, 0.0f);
        const float v11 = fmaxf((c[f][3] + bv1) * BNS_F, 0.0f);
        uint32_t l0, l1;
        const uint32_t h0 = pack_hi(v00, v01, &l0);
        const uint32_t h1 = pack_hi(v10, v11, &l1);
        const uint32_t o0 = outOff + (uint32_t)r0 * outStride + (uint32_t)col * 2u;
        const uint32_t o1 = o0 + 8u * outStride;
        *(uint32_t*)(smem + o0) = h0;
        *(uint32_t*)(smem + o0 + outHalf) = l0;
        *(uint32_t*)(smem + o1) = h1;
        *(uint32_t*)(smem + o1 + outHalf) = l1;
    }
}

// ---------------------------------------------------------------------------
// Merged weight prep: transpose to [N][Kpad], single fp16.
// ---------------------------------------------------------------------------
__device__ __forceinline__ void prep_one(const float* w, __half* out,
                                         int idx, int Cin, int Cout, int Kpad) {
    const int n = idx / Kpad, kp = idx % Kpad;
    const float v = (kp < Cin) ? w[(size_t)kp * Cout + n] : 0.0f;
    out[idx] = __float2half_rn(v);
}

__global__ void prep_all_kernel(const float* w11, const float* w12,
                                const float* w20, const float* w21, const float* w22,
                                const float* w30, const float* w31, const float* w32) {
    const int s1 = 64*64, s2 = 128*64, s3 = 128*152, s4 = 128*136,
              s5 = 256*136, s6 = 256*288, s7 = 512*256, s8 = 768*512;
    const int total = s1+s2+s3+s4+s5+s6+s7+s8;
    for (int i = blockIdx.x * blockDim.x + threadIdx.x; i < total;
         i += gridDim.x * blockDim.x) {
        int idx = i;
        if (idx < s1) { prep_one(w11, g_w11h, idx, 64, 64, 64); continue; }  idx -= s1;
        if (idx < s2) { prep_one(w12, g_w12h, idx, 64, 128, 64); continue; } idx -= s2;
        if (idx < s3) { prep_one(w20, g_w20h, idx, 131, 128, 152); continue; } idx -= s3;
        if (idx < s4) { prep_one(w21, g_w21h, idx, 128, 128, 136); continue; } idx -= s4;
        if (idx < s5) { prep_one(w22, g_w22h, idx, 128, 256, 136); continue; } idx -= s5;
        if (idx < s6) { prep_one(w30, g_w30h, idx, 259, 256, 288); continue; } idx -= s6;
        if (idx < s7) { prep_one(w31, g_w31h, idx, 256, 512, 256); continue; } idx -= s7;
        prep_one(w32, g_w32h, idx, 512, 768, 512);
    }
}

// ---------------------------------------------------------------------------
// FPS + ball (index-exact, unchanged).
// ---------------------------------------------------------------------------
__global__ void fps1_kernel(const float* __restrict__ x,
                            int* __restrict__ fidx, float* __restrict__ nxyz) {
    __shared__ float swv[32];
    __shared__ int   swi[32];
    __shared__ float cur[3];
    __shared__ int   slast;
    const int b = blockIdx.x;
    const int t = threadIdx.x;
    const int warp = t >> 5, lane = t & 31;
    const float* p = x + ((size_t)b * N1 + t) * 6;
    const float px = p[0], py = p[1], pz = p[2];
    float dist = 1e10f;
    if (t == 0) {
        fidx[b * M1] = 0;
        float* o = nxyz + (size_t)b * M1 * 3;
        o[0] = px; o[1] = py; o[2] = pz;
    }
    int last = 0;
    for (int it = 1; it < M1; ++it) {
        if (t == last) { cur[0] = px; cur[1] = py; cur[2] = pz; }
        __syncthreads();
        float dx = __fsub_rn(px, cur[0]);
        float dy = __fsub_rn(py, cur[1]);
        float dz = __fsub_rn(pz, cur[2]);
        float d  = __fadd_rn(__fadd_rn(__fmul_rn(dx, dx), __fmul_rn(dy, dy)),
                             __fmul_rn(dz, dz));
        dist = fminf(dist, d);
        float v = dist; int vi = t;
        #pragma unroll
        for (int off = 16; off; off >>= 1) {
            float v2 = __shfl_xor_sync(0xffffffffu, v, off);
            int   i2 = __shfl_xor_sync(0xffffffffu, vi, off);
            if (v2 > v || (v2 == v && i2 < vi)) { v = v2; vi = i2; }
        }
        if (lane == 0) { swv[warp] = v; swi[warp] = vi; }
        __syncthreads();
        if (warp == 0) {
            float wv = swv[lane]; int wi = swi[lane];
            #pragma unroll
            for (int off = 16; off; off >>= 1) {
                float v2 = __shfl_xor_sync(0xffffffffu, wv, off);
                int   i2 = __shfl_xor_sync(0xffffffffu, wi, off);
                if (v2 > wv || (v2 == wv && i2 < wi)) { wv = v2; wi = i2; }
            }
            if (lane == 0) { slast = wi; fidx[b * M1 + it] = wi; }
        }
        __syncthreads();
        last = slast;
        if (t == last) {
            float* o = nxyz + ((size_t)b * M1 + it) * 3;
            o[0] = px; o[1] = py; o[2] = pz;
        }
    }
}

__global__ void fps2_kernel(const float* __restrict__ pts,
                            int* __restrict__ fidx, float* __restrict__ nxyz) {
    const int gw   = (blockIdx.x * blockDim.x + threadIdx.x) >> 5;
    const int lane = threadIdx.x & 31;
    if (gw >= B_TOT) return;
    const float* pb = pts + (size_t)gw * M1 * 3;
    const float px = pb[lane * 3 + 0], py = pb[lane * 3 + 1], pz = pb[lane * 3 + 2];
    float dist = 1e10f;
    if (lane == 0) {
        fidx[gw * M2] = 0;
        float* o = nxyz + (size_t)gw * M2 * 3;
        o[0] = px; o[1] = py; o[2] = pz;
    }
    int last = 0;
    for (int it = 1; it < M2; ++it) {
        const float cx = __shfl_sync(0xffffffffu, px, last);
        const float cy = __shfl_sync(0xffffffffu, py, last);
        const float cz = __shfl_sync(0xffffffffu, pz, last);
        float dx = __fsub_rn(px, cx), dy = __fsub_rn(py, cy), dz = __fsub_rn(pz, cz);
        float d  = __fadd_rn(__fadd_rn(__fmul_rn(dx, dx), __fmul_rn(dy, dy)),
                             __fmul_rn(dz, dz));
        dist = fminf(dist, d);
        float v = dist; int vi = lane;
        #pragma unroll
        for (int off = 16; off; off >>= 1) {
            float v2 = __shfl_xor_sync(0xffffffffu, v, off);
            int   i2 = __shfl_xor_sync(0xffffffffu, vi, off);
            if (v2 > v || (v2 == v && i2 < vi)) { v = v2; vi = i2; }
        }
        last = vi;
        if (lane == 0) fidx[gw * M2 + it] = last;
        if (lane == last) {
            float* o = nxyz + ((size_t)gw * M2 + it) * 3;
            o[0] = px; o[1] = py; o[2] = pz;
        }
    }
}

__global__ void ball_kernel(const float* __restrict__ pts, int pstride,
                            const float* __restrict__ centers,
                            int M, int N, float r2, int* __restrict__ out) {
    const int gw   = (blockIdx.x * blockDim.x + threadIdx.x) >> 5;
    const int lane = threadIdx.x & 31;
    if (gw >= B_TOT * M) return;
    const int b = gw / M;
    const float* c = centers + (size_t)gw * 3;
    const float cx = c[0], cy = c[1], cz = c[2];
    const float cn = __fadd_rn(__fadd_rn(__fmul_rn(cx, cx), __fmul_rn(cy, cy)),
                               __fmul_rn(cz, cz));
    int* o = out + (size_t)gw * NSMP;
    int cnt = 0, first = -1;
    for (int base = 0; base < N && cnt < NSMP; base += 32) {
        const float* pp = pts + ((size_t)b * N + base + lane) * pstride;
        const float px = pp[0], py = pp[1], pz = pp[2];
        const float pn = __fadd_rn(__fadd_rn(__fmul_rn(px, px), __fmul_rn(py, py)),
                                   __fmul_rn(pz, pz));
        const float dt = __fadd_rn(__fadd_rn(__fmul_rn(cx, px), __fmul_rn(cy, py)),
                                   __fmul_rn(cz, pz));
        const float d2 = __fsub_rn(__fadd_rn(cn, pn), __fmul_rn(2.0f, dt));
        const bool hit = d2 < r2;
        const unsigned mask = __ballot_sync(0xffffffffu, hit);
        if (first < 0 && mask) first = base + __ffs(mask) - 1;
        const int pos = cnt + __popc(mask & ((1u << lane) - 1u));
        if (hit && pos < NSMP) o[pos] = base + lane;
        cnt += __popc(mask);
    }
    if (cnt > NSMP) cnt = NSMP;
    for (int k = cnt + lane; k < NSMP; k += 32) o[k] = first;
}

// ---------------------------------------------------------------------------
// SA1: 4 centers/block (M=128). L0 scalar (w0 staged in smem); L1/L2 HMMA.
// A1 hi@0/lo@16384 (str 128B); A2 hi@32768/lo@49152; B1@65536 (8192);
// B2@73728 (16384); w0s@90112 (1536); bias@91648 (768). part overlays A1.
// ---------------------------------------------------------------------------
#define S1_A1   0u
#define S1_A2   32768u
#define S1_B1   65536u
#define S1_B2   73728u
#define S1_W0   90112u
#define S1_BIAS 91648u
#define S1_SMEM 92416

__global__ void __launch_bounds__(256)
sa1m_kernel(const float* __restrict__ x, const float* __restrict__ nx1,
            const int* __restrict__ ball,
            const float* __restrict__ w0g, const float* __restrict__ b0g,
            const float* __restrict__ b1_, const float* __restrict__ b2_,
            float* __restrict__ out) {
    char* smem = (char*)dynsmem;
    const uint32_t su = smem_to_u32(smem);
    const int tid = threadIdx.x;
    const int wid = tid >> 5, lane = tid & 31;
    const int mrow = wid * 16;
    float* w0s  = (float*)(smem + S1_W0);
    float* bias = (float*)(smem + S1_BIAS);
    float* part = (float*)smem;          // overlays A1 (dead by then)
    const int bm0 = blockIdx.x * 4;
    const int b   = bm0 / M1;

    cp_copy(su + S1_B1, g_w11h, 8192);
    cp_copy(su + S1_B2, g_w12h, 16384);
    CP_COMMIT();

    for (int i = tid; i < 384; i += 256) w0s[i] = w0g[i];
    if (tid < 64)  { w0s[384 + tid] = b0g[tid]; bias[tid] = b1_[tid]; }
    if (tid < 128) bias[64 + tid] = b2_[tid];
    __syncthreads();

    // Gather + scalar L0 (fp32 exact): 2 threads per row, 32 cols each.
    {
        const int row = tid >> 1, seg = tid & 1;
        const int center = bm0 + (row >> 5);
        const int p = ball[center * NSMP + (row & 31)];
        const float* xr  = x + ((size_t)b * N1 + p) * 6;
        const float* ctr = nx1 + (size_t)center * 3;
        float in[6];
        #pragma unroll
        for (int k = 0; k < 6; ++k)
            in[k] = (k < 3) ? xr[k] - ctr[k] : xr[k];
        uint32_t* dh = (uint32_t*)(smem + S1_A1 + row * 128 + seg * 64);
        uint32_t* dl = (uint32_t*)(smem + S1_A1 + 16384 + row * 128 + seg * 64);
        #pragma unroll 4
        for (int j = 0; j < 16; ++j) {
            const int c0 = seg * 32 + 2 * j;
            float a0 = w0s[384 + c0], a1 = w0s[384 + c0 + 1];
            #pragma unroll
            for (int k = 0; k < 6; ++k) {
                a0 = fmaf(in[k], w0s[k * 64 + c0], a0);
                a1 = fmaf(in[k], w0s[k * 64 + c0 + 1], a1);
            }
            const float v0 = fmaxf(a0 * BNS_F, 0.0f);
            const float v1 = fmaxf(a1 * BNS_F, 0.0f);
            uint32_t lo;
            dh[j] = pack_hi(v0, v1, &lo);
            dl[j] = lo;
        }
    }
    CP_WAIT0();
    __syncthreads();

    {   // L1: K=64 (4 ks), N=64
        float c[8][4];
        #pragma unroll
        for (int f = 0; f < 8; ++f)
            #pragma unroll
            for (int j = 0; j < 4; ++j) c[f][j] = 0.0f;
        gp_t<4, 4>(su + S1_A1, 16384u, 128u, su + S1_B1, 128u, mrow, 0, lane, c);
        epi_t<4>(smem, S1_A2, 16384u, 128u, bias, 0, c, mrow, lane);
    }
    __syncthreads();

    {   // L2: K=64, N=128 + fused max over 32 rows/center
        float c[16][4];
        #pragma unroll
        for (int f = 0; f < 16; ++f)
            #pragma unroll
            for (int j = 0; j < 4; ++j) c[f][j] = 0.0f;
        gp_t<4, 8>(su + S1_A2, 16384u, 128u, su + S1_B2, 128u, mrow, 0, lane, c);
        __syncthreads();   // A1 region now reused as part[]
        #pragma unroll
        for (int f = 0; f < 16; ++f) {
            float m0 = fmaxf(c[f][0], c[f][2]);
            float m1 = fmaxf(c[f][1], c[f][3]);
            #pragma unroll
            for (int off = 4; off <= 16; off <<= 1) {
                m0 = fmaxf(m0, __shfl_xor_sync(0xffffffffu, m0, off));
                m1 = fmaxf(m1, __shfl_xor_sync(0xffffffffu, m1, off));
            }
            if (lane < 4) {
                const int cc = (f >> 1) * 16 + (f & 1) * 8 + 2 * lane;
                part[wid * 128 + cc] = m0;
                part[wid * 128 + cc + 1] = m1;
            }
        }
        __syncthreads();
        for (int i = tid; i < 512; i += 256) {
            const int ci = i >> 7, n = i & 127;
            const float v = fmaxf(part[(2 * ci) * 128 + n],
                                  part[(2 * ci + 1) * 128 + n]);
            out[(size_t)(bm0 + ci) * 128 + n] =
                fmaxf((v + bias[64 + n]) * BNS_F, 0.0f);
        }
    }
}

// ---------------------------------------------------------------------------
// SA2: 4 centers/block (M=128), cp.async-prefetched fp16 weights.
// A hi@0/lo@38912 (304B stride); B0@77824 (38912); B1@116736 (34816);
// bias@151552 (2048); part@153600 (4096).
// ---------------------------------------------------------------------------
#define A2_A      0u
#define A2_AH     38912u
#define A2_B0     77824u
#define A2_B1     116736u
#define A2_BIAS   151552u
#define A2_PART   153600u
#define SA2M_SMEM 157696

__global__ void __launch_bounds__(256)
sa2m_kernel(const float* __restrict__ nx1, const float* __restrict__ f1,
            const float* __restrict__ nx2, const int* __restrict__ ball,
            const float* __restrict__ b0_, const float* __restrict__ b1_,
            const float* __restrict__ b2_, float* __restrict__ out) {
    char* smem = (char*)dynsmem;
    const uint32_t su = smem_to_u32(smem);
    const int tid = threadIdx.x;
    const int wid = tid >> 5, lane = tid & 31;
    const int mw  = wid * 16;
    float* bs = (float*)(smem + A2_BIAS);
    float* part = (float*)(smem + A2_PART);
    const int bm0 = blockIdx.x * 4;
    const int b   = bm0 / M2;

    cp_copy(su + A2_B0, g_w20h, 38912);
    CP_COMMIT();
    cp_copy(su + A2_B1, g_w21h, 34816);
    CP_COMMIT();

    if (tid < 128) { bs[tid] = b0_[tid]; bs[128 + tid] = b1_[tid]; }
    bs[256 + tid] = b2_[tid];

    // Gather A(L0): 128 rows x 144 cols, fp16 hi/lo, stride 304B.
    {
        const int row = tid >> 1, seg = tid & 1;
        const int center = bm0 + (row >> 5);
        const int p = ball[center * NSMP + (row & 31)];
        const float* nx1r = nx1 + ((size_t)b * M1 + p) * 3;
        const float* ctr  = nx2 + (size_t)center * 3;
        const float* f1r  = f1 + ((size_t)b * M1 + p) * 128;
        #pragma unroll 1
        for (int i = 0; i < 36; ++i) {
            const int k = seg * 72 + 2 * i;
            float v0, v1;
            if (k < 3)        v0 = nx1r[k] - ctr[k];
            else if (k < 131) v0 = f1r[k - 3];
            else              v0 = 0.0f;
            const int k1 = k + 1;
            if (k1 < 3)        v1 = nx1r[k1] - ctr[k1];
            else if (k1 < 131) v1 = f1r[k1 - 3];
            else               v1 = 0.0f;
            uint32_t lo;
            const uint32_t hi = pack_hi(v0, v1, &lo);
            const uint32_t off = (uint32_t)row * 304u + (uint32_t)k * 2u;
            *(uint32_t*)(smem + A2_A + off) = hi;
            *(uint32_t*)(smem + A2_A + A2_AH + off) = lo;
        }
    }
    CP_WAIT1();
    __syncthreads();

    float c[16][4];
    // Layer 0: K=144 (9 ks), N=128
    #pragma unroll
    for (int f = 0; f < 16; ++f)
        #pragma unroll
        for (int j = 0; j < 4; ++j) c[f][j] = 0.0f;
    gp_t<9, 8>(su + A2_A, A2_AH, 304u, su + A2_B0, 304u, mw, 0, lane, c);
    __syncthreads();
    cp_copy(su + A2_B0, g_w22h, 34816);                 // B2 rows 0..127
    CP_COMMIT();
    epi_t<8>(smem, A2_A, A2_AH, 272u, bs, 0, c, mw, lane);
    CP_WAIT1();
    __syncthreads();

    // Layer 1: K=128 (8 ks), N=128
    #pragma unroll
    for (int f = 0; f < 16; ++f)
        #pragma unroll
        for (int j = 0; j < 4; ++j) c[f][j] = 0.0f;
    gp_t<8, 8>(su + A2_A, A2_AH, 272u, su + A2_B1, 272u, mw, 0, lane, c);
    __syncthreads();
    cp_copy(su + A2_B1, g_w22h + 128 * 136, 34816);     // B2 rows 128..255
    CP_COMMIT();
    epi_t<8>(smem, A2_A, A2_AH, 272u, bs + 128, 0, c, mw, lane);
    CP_WAIT1();
    __syncthreads();

    // Layer 2: K=128, N=256 in two halves; fused max over 32 rows/center.
    #pragma unroll 1
    for (int h = 0; h < 2; ++h) {
        const uint32_t bBase = h ? (su + A2_B1) : (su + A2_B0);
        #pragma unroll
        for (int f = 0; f < 16; ++f)
            #pragma unroll
            for (int j = 0; j < 4; ++j) c[f][j] = 0.0f;
        gp_t<8, 8>(su + A2_A, A2_AH, 272u, bBase, 272u, mw, 0, lane, c);
        #pragma unroll
        for (int f = 0; f < 16; ++f) {
            float m0 = fmaxf(c[f][0], c[f][2]);
            float m1 = fmaxf(c[f][1], c[f][3]);
            #pragma unroll
            for (int off = 4; off <= 16; off <<= 1) {
                m0 = fmaxf(m0, __shfl_xor_sync(0xffffffffu, m0, off));
                m1 = fmaxf(m1, __shfl_xor_sync(0xffffffffu, m1, off));
            }
            if (lane < 4) {
                const int cc = (f >> 1) * 16 + (f & 1) * 8 + 2 * lane;
                part[wid * 128 + cc] = m0;
                part[wid * 128 + cc + 1] = m1;
            }
        }
        __syncthreads();
        for (int i = tid; i < 512; i += 256) {
            const int ci = i >> 7, n = i & 127;
            const float v = fmaxf(part[(2 * ci) * 128 + n],
                                  part[(2 * ci + 1) * 128 + n]);
            out[(size_t)(bm0 + ci) * 256 + h * 128 + n] =
                fmaxf((v + bs[256 + h * 128 + n]) * BNS_F, 0.0f);
        }
        if (h == 0) CP_WAIT0();
        __syncthreads();
    }
}

// ---------------------------------------------------------------------------
// Head input gather (fp16 hi/lo).
// ---------------------------------------------------------------------------
__global__ void gather_a0_kernel(const float* __restrict__ nx2,
                                 const float* __restrict__ f2) {
    const int row = blockIdx.x * blockDim.x + threadIdx.x;
    if (row >= 32768) return;
    const float* nr = nx2 + (size_t)row * 3;
    const float* fr = f2 + (size_t)row * 256;
    uint32_t* dh = (uint32_t*)(g_a0 + (size_t)row * 288);
    uint32_t* dl = (uint32_t*)(g_a0 + A0HALF + (size_t)row * 288);
    #pragma unroll 4
    for (int j = 0; j < 144; ++j) {
        const int k = 2 * j;
        float v0, v1;
        if (k < 3)        v0 = nr[k];
        else if (k < 259) v0 = fr[k - 3];
        else              v0 = 0.0f;
        const int k1 = k + 1;
        if (k1 < 3)        v1 = nr[k1];
        else if (k1 < 259) v1 = fr[k1 - 3];
        else               v1 = 0.0f;
        uint32_t lo;
        dh[j] = pack_hi(v0, v1, &lo);
        dl[j] = lo;
    }
}

// ---------------------------------------------------------------------------
// Pipelined tiled GEMM: C[64 x 128], K chunked by 32, double-buffered cp.async.
// buf = [A hi 5120 | A lo 5120 | B 10240] x 2 (stride 80); bias @40960.
// ---------------------------------------------------------------------------
#define GM_BUF  20480u
#define GM_BIAS 40960u
#define GM_SMEM 41472

__device__ __forceinline__ void gm_load(uint32_t bufBase,
                                        const __half* A, size_t aHalf,
                                        const __half* Bw,
                                        int Kpad, int Mbase, int Nbase, int kc) {
    const int tid = threadIdx.x;
    {   // A: 64 rows x 2 halves x 64B; 2 threads per (row,half), 32B each
        const int task = tid >> 1, prt = tid & 1;
        const int row = task & 63, half = task >> 6;
        const char* s = (const char*)(A + (size_t)half * aHalf +
                                      (size_t)(Mbase + row) * Kpad + kc * 32) + prt * 32;
        const uint32_t d = bufBase + half * 5120u + row * 80u + prt * 32u;
        CP_A16(d, s);
        CP_A16(d + 16, s + 16);
    }
    {   // B: 128 rows x 64B; 2 threads per row, 32B each
        const int row = tid >> 1, prt = tid & 1;
        const char* s = (const char*)(Bw + (size_t)(Nbase + row) * Kpad + kc * 32)
                        + prt * 32;
        const uint32_t d = bufBase + 10240u + row * 80u + prt * 32u;
        CP_A16(d, s);
        CP_A16(d + 16, s + 16);
    }
}

template <int MODE>
__global__ void __launch_bounds__(256, 2)
gemm_kernel(const __half* __restrict__ A, size_t aHalf, int Kpad, int KC,
            const __half* __restrict__ Bw,
            const float* __restrict__ biasG,
            __half* __restrict__ O, size_t oHalf, int KpadO,
            float* __restrict__ gout) {
    char* smem = (char*)dynsmem;
    const uint32_t su = smem_to_u32(smem);
    const int tid = threadIdx.x;
    const int wid = tid >> 5, lane = tid & 31;
    const int Mbase = blockIdx.x * 64;
    const int Nbase = blockIdx.y * 128;
    float* bias = (float*)(smem + GM_BIAS);

    gm_load(su, A, aHalf, Bw, Kpad, Mbase, Nbase, 0);
    CP_COMMIT();
    if (tid < 128) bias[tid] = biasG[Nbase + tid];

    float c[8][4];
    #pragma unroll
    for (int f = 0; f < 8; ++f)
        #pragma unroll
        for (int j = 0; j < 4; ++j) c[f][j] = 0.0f;

    #pragma unroll 1
    for (int kc = 0; kc < KC; ++kc) {
        CP_WAIT0();
        __syncthreads();
        if (kc + 1 < KC) {
            gm_load(su + ((kc + 1) & 1) * GM_BUF, A, aHalf, Bw,
                    Kpad, Mbase, Nbase, kc + 1);
            CP_COMMIT();
        }
        const uint32_t buf = su + (kc & 1) * GM_BUF;
        gp_t<2, 4>(buf, 5120u, 80u, buf + 10240u, 80u,
                   (wid & 3) * 16, (wid >> 2) * 64, lane, c);
    }

    if (MODE == 0) {
        const int r0 = Mbase + (wid & 3) * 16 + (lane >> 2);
        const int cb = (wid >> 2) * 64 + 2 * (lane & 3);
        #pragma unroll
        for (int f = 0; f < 8; ++f) {
            const int cl = cb + (f >> 1) * 16 + (f & 1) * 8;
            const int col = Nbase + cl;
            const float bv0 = bias[cl], bv1 = bias[cl + 1];
            const float v00 = fmaxf((c[f][0] + bv0) * BNS_F, 0.0f);
            const float v01 = fmaxf((c[f][1] + bv1) * BNS_F, 0.0f);
            const float v10 = fmaxf((c[f][2] + bv0) * BNS_F, 0.0f);
            const float v11 = fmaxf((c[f][3] + bv1) * BNS_F, 0.0f);
            uint32_t l0, l1;
            const uint32_t h0 = pack_hi(v00, v01, &l0);
            const uint32_t h1 = pack_hi(v10, v11, &l1);
            *(uint32_t*)(O + (size_t)r0 * KpadO + col) = h0;
            *(uint32_t*)(O + oHalf + (size_t)r0 * KpadO + col) = l0;
            *(uint32_t*)(O + (size_t)(r0 + 8) * KpadO + col) = h1;
            *(uint32_t*)(O + oHalf + (size_t)(r0 + 8) * KpadO + col) = l1;
        }
    } else {
        const int batch = blockIdx.x * 4 + (wid & 3);
        const int cb = (wid >> 2) * 64;
        #pragma unroll
        for (int f = 0; f < 8; ++f) {
            float m0 = fmaxf(c[f][0], c[f][2]);
            float m1 = fmaxf(c[f][1], c[f][3]);
            #pragma unroll
            for (int off = 4; off <= 16; off <<= 1) {
                m0 = fmaxf(m0, __shfl_xor_sync(0xffffffffu, m0, off));
                m1 = fmaxf(m1, __shfl_xor_sync(0xffffffffu, m1, off));
            }
            if (lane < 4) {
                const int cl = cb + (f >> 1) * 16 + (f & 1) * 8 + 2 * lane;
                const int col = Nbase + cl;
                gout[(size_t)batch * 768 + col] =
                    fmaxf((m0 + bias[cl]) * BNS_F, 0.0f);
                gout[(size_t)batch * 768 + col + 1] =
                    fmaxf((m1 + bias[cl + 1]) * BNS_F, 0.0f);
            }
        }
    }
}

// ---------------------------------------------------------------------------
// FC: 16 batches/block share fc_w loads.
// ---------------------------------------------------------------------------
__global__ void __launch_bounds__(192)
fc_kernel(const float* __restrict__ g_in, const float* __restrict__ fcw,
          const float* __restrict__ fcb, float* __restrict__ out) {
    constexpr int FCB = 16, C = 768, NT = 192;
    __shared__ float gs[FCB * C];
    const int b0 = blockIdx.x * FCB;
    for (int i = threadIdx.x; i < FCB * C; i += NT)
        gs[i] = g_in[(size_t)b0 * C + i];
    __syncthreads();
    const int og = threadIdx.x;
    const float4 bv = *reinterpret_cast<const float4*>(fcb + 4 * og);
    ull_t a01[FCB], a23[FCB];
    #pragma unroll
    for (int i = 0; i < FCB; ++i) { a01[i] = 0ull; a23[i] = 0ull; }
    const float* wp = fcw + 4 * og;
    #pragma unroll 2
    for (int k = 0; k < C; ++k) {
        const ulonglong2 wq =
            *reinterpret_cast<const ulonglong2*>(wp + (size_t)k * C);
        #pragma unroll
        for (int i = 0; i < FCB; ++i) {
            const ull_t hh = dup2(gs[i * C + k]);
            FMA2(a01[i], hh, wq.x, a01[i]);
            FMA2(a23[i], hh, wq.y, a23[i]);
        }
    }
    #pragma unroll
    for (int i = 0; i < FCB; ++i) {
        const float2 p0 = unpk(a01[i]);
        const float2 p1 = unpk(a23[i]);
        float4 r = make_float4(p0.x + bv.x, p0.y + bv.y, p1.x + bv.z, p1.y + bv.w);
        *reinterpret_cast<float4*>(out + (size_t)(b0 + i) * C + 4 * og) = r;
    }
}

// ---------------------------------------------------------------------------
// Host launcher
// ---------------------------------------------------------------------------
extern "C" void kernel_launch(void* const* d_in, const int* in_sizes, int n_in,
                              void* d_out, int out_size) {
    const float* x   = (const float*)d_in[0];
    const float* w10 = (const float*)d_in[1];  const float* b10 = (const float*)d_in[2];
    const float* w11 = (const float*)d_in[3];  const float* b11 = (const float*)d_in[4];
    const float* w12 = (const float*)d_in[5];  const float* b12 = (const float*)d_in[6];
    const float* w20 = (const float*)d_in[7];  const float* b20 = (const float*)d_in[8];
    const float* w21 = (const float*)d_in[9];  const float* b21 = (const float*)d_in[10];
    const float* w22 = (const float*)d_in[11]; const float* b22 = (const float*)d_in[12];
    const float* w30 = (const float*)d_in[13]; const float* b30 = (const float*)d_in[14];
    const float* w31 = (const float*)d_in[15]; const float* b31 = (const float*)d_in[16];
    const float* w32 = (const float*)d_in[17]; const float* b32 = (const float*)d_in[18];
    const float* fcw = (const float*)d_in[19]; const float* fcb = (const float*)d_in[20];
    float* out = (float*)d_out;

    int *fps1p, *ball1p, *fps2p, *ball2p;
    float *nx1p, *f1p, *nx2p, *f2p, *gp;
    __half *a0p, *h0p, *h1p, *w30hp, *w31hp, *w32hp;
    cudaGetSymbolAddress((void**)&fps1p,  g_fps1);
    cudaGetSymbolAddress((void**)&nx1p,   g_nx1);
    cudaGetSymbolAddress((void**)&ball1p, g_ball1);
    cudaGetSymbolAddress((void**)&f1p,    g_f1);
    cudaGetSymbolAddress((void**)&fps2p,  g_fps2);
    cudaGetSymbolAddress((void**)&nx2p,   g_nx2);
    cudaGetSymbolAddress((void**)&ball2p, g_ball2);
    cudaGetSymbolAddress((void**)&f2p,    g_f2);
    cudaGetSymbolAddress((void**)&gp,     g_g);
    cudaGetSymbolAddress((void**)&a0p,    g_a0);
    cudaGetSymbolAddress((void**)&h0p,    g_h0);
    cudaGetSymbolAddress((void**)&h1p,    g_h1);
    cudaGetSymbolAddress((void**)&w30hp,  g_w30h);
    cudaGetSymbolAddress((void**)&w31hp,  g_w31h);
    cudaGetSymbolAddress((void**)&w32hp,  g_w32h);

    cudaFuncSetAttribute(sa1m_kernel, cudaFuncAttributeMaxDynamicSharedMemorySize, S1_SMEM);
    cudaFuncSetAttribute(sa2m_kernel, cudaFuncAttributeMaxDynamicSharedMemorySize, SA2M_SMEM);
    cudaFuncSetAttribute(gemm_kernel<0>, cudaFuncAttributeMaxDynamicSharedMemorySize, GM_SMEM);
    cudaFuncSetAttribute(gemm_kernel<1>, cudaFuncAttributeMaxDynamicSharedMemorySize, GM_SMEM);

    // 1: weight prep
    prep_all_kernel<<<1024, 256>>>(w11, w12, w20, w21, w22, w30, w31, w32);
    // 2-3: FPS1 + ball1
    fps1_kernel<<<B_TOT, 1024>>>(x, fps1p, nx1p);
    ball_kernel<<<(B_TOT * M1 * 32 + 255) / 256, 256>>>(
        x, 6, nx1p, M1, N1, (float)(0.2 * 0.2), ball1p);
    // 4: SA1
    sa1m_kernel<<<B_TOT * M1 / 4, 256, S1_SMEM>>>(x, nx1p, ball1p,
                                                  w10, b10, b11, b12, f1p);
    // 5-7: FPS2 + ball2 + SA2
    fps2_kernel<<<(B_TOT * 32 + 127) / 128, 128>>>(nx1p, fps2p, nx2p);
    ball_kernel<<<(B_TOT * M2 * 32 + 255) / 256, 256>>>(
        nx1p, 3, nx2p, M2, M1, (float)(0.4 * 0.4), ball2p);
    sa2m_kernel<<<B_TOT * M2 / 4, 256, SA2M_SMEM>>>(nx1p, f1p, nx2p, ball2p,
                                                    b20, b21, b22, f2p);
    // 8: head input gather
    gather_a0_kernel<<<32768 / 256, 256>>>(nx2p, f2p);
    // 9-11: head GEMMs
    gemm_kernel<0><<<dim3(512, 2), 256, GM_SMEM>>>(
        a0p, A0HALF, 288, 9, w30hp, b30, h0p, H0HALF, 256, nullptr);
    gemm_kernel<0><<<dim3(512, 4), 256, GM_SMEM>>>(
        h0p, H0HALF, 256, 8, w31hp, b31, h1p, H1HALF, 512, nullptr);
    gemm_kernel<1><<<dim3(512, 6), 256, GM_SMEM>>>(
        h1p, H1HALF, 512, 16, w32hp, b32, nullptr, 0, 0, gp);
    // 12: FC
    fc_kernel<<<B_TOT / 16, 192>>>(gp, fcw, fcb, out);
}

// round 12
// speedup vs baseline: 1.8369x; 1.2136x over previous
#include <cuda_runtime.h>
#include <cuda_fp16.h>
#include <math.h>
#include <stdint.h>

// ---------------------------------------------------------------------------
// PointNet++ encoder forward. B=2048 clouds, N=1024 pts, 6 ch.
// All MLP stages on HMMA fp16 (single precision both operands, fp32 accum).
// 1 MMA per logical k-step. Index paths (fps/ball) exact fp32.
// ---------------------------------------------------------------------------

#define B_TOT 2048
#define N1    1024
#define M1    32
#define M2    16
#define NSMP  32

__device__ int   g_fps1 [B_TOT * M1];
__device__ float g_nx1  [B_TOT * M1 * 3];
__device__ int   g_ball1[B_TOT * M1 * NSMP];
__device__ float g_f1   [B_TOT * M1 * 128];
__device__ int   g_fps2 [B_TOT * M2];
__device__ float g_nx2  [B_TOT * M2 * 3];
__device__ int   g_ball2[B_TOT * M2 * NSMP];
__device__ float g_f2   [B_TOT * M2 * 256];
__device__ float g_g    [B_TOT * 768];

// Weights: [N][Kpad] fp16.
__device__ __align__(16) __half g_w11h[64 * 64];
__device__ __align__(16) __half g_w12h[128 * 64];
__device__ __align__(16) __half g_w20h[128 * 152];
__device__ __align__(16) __half g_w21h[128 * 136];
__device__ __align__(16) __half g_w22h[256 * 136];
__device__ __align__(16) __half g_w30h[256 * 288];
__device__ __align__(16) __half g_w31h[512 * 256];
__device__ __align__(16) __half g_w32h[768 * 512];

// Head activations, [32768 rows][Kpad] fp16.
__device__ __align__(16) __half g_a0[32768 * 288];
__device__ __align__(16) __half g_h0[32768 * 256];
__device__ __align__(16) __half g_h1[32768 * 512];

// ---- packed f32x2 helpers (FC kernel) ----------------------------------------
typedef unsigned long long ull_t;
__device__ __forceinline__ ull_t dup2(float v) {
    ull_t r; unsigned u = __float_as_uint(v);
    asm("mov.b64 %0, {%1, %1};" : "=l"(r) : "r"(u));
    return r;
}
__device__ __forceinline__ float2 unpk(ull_t p) {
    unsigned lo, hi;
    asm("mov.b64 {%0, %1}, %2;" : "=r"(lo), "=r"(hi) : "l"(p));
    return make_float2(__uint_as_float(lo), __uint_as_float(hi));
}
#define FMA2(d, a, b, c) \
    asm("fma.rn.f32x2 %0, %1, %2, %3;" : "=l"(d) : "l"(a), "l"(b), "l"(c))

#define BNS_F 0.99999500003749968f   // 1/sqrt(1+1e-5)

// ---- mma.sync / ldmatrix / cp.async helpers ----------------------------------
__device__ __forceinline__ uint32_t smem_to_u32(const void* p) {
    uint32_t a;
    asm("{ .reg .u64 t; cvta.to.shared.u64 t, %1; cvt.u32.u64 %0, t; }"
        : "=r"(a) : "l"(p));
    return a;
}
#define LDSM4(r, a) \
    asm volatile("ldmatrix.sync.aligned.m8n8.x4.shared.b16 {%0,%1,%2,%3}, [%4];" \
                 : "=r"((r)[0]), "=r"((r)[1]), "=r"((r)[2]), "=r"((r)[3]) : "r"(a))

__device__ __forceinline__ void mma_f16(float* c, const uint32_t* a,
                                        const uint32_t* b) {
    asm volatile(
        "mma.sync.aligned.m16n8k16.row.col.f32.f16.f16.f32 "
        "{%0,%1,%2,%3}, {%4,%5,%6,%7}, {%8,%9}, {%0,%1,%2,%3};"
        : "+f"(c[0]), "+f"(c[1]), "+f"(c[2]), "+f"(c[3])
        : "r"(a[0]), "r"(a[1]), "r"(a[2]), "r"(a[3]), "r"(b[0]), "r"(b[1]));
}

#define CP_A16(dst, src) \
    asm volatile("cp.async.cg.shared.global [%0], [%1], 16;" \
                 :: "r"(dst), "l"(src) : "memory")
#define CP_COMMIT() asm volatile("cp.async.commit_group;" ::: "memory")
#define CP_WAIT0()  asm volatile("cp.async.wait_group 0;" ::: "memory")
#define CP_WAIT1()  asm volatile("cp.async.wait_group 1;" ::: "memory")

__device__ __forceinline__ void cp_copy(uint32_t dst, const void* src, int bytes) {
    const char* s = (const char*)src;
    for (int i = threadIdx.x * 16; i < bytes; i += 256 * 16)
        CP_A16(dst + i, s + i);
}

__device__ __forceinline__ uint32_t pk2h(float v0, float v1) {
    __half2 h = __floats2half2_rn(v0, v1);
    return *(const uint32_t*)&h;
}

extern __shared__ float dynsmem[];

// fp16 GEMM pass: 1 MMA per (p, half-n) per k-step.
template <int KS, int PN>
__device__ __forceinline__ void gp_t(uint32_t aBase, uint32_t aStride,
                                     uint32_t bBase, uint32_t bStride,
                                     int mrow, int nbase, int lane,
                                     float (&c)[2 * PN][4]) {
    const uint32_t aAddr = aBase + (uint32_t)(mrow + (lane & 15)) * aStride +
                           (uint32_t)((lane >> 4) << 4);
    const uint32_t nrow  = (lane & 7) + ((lane >> 4) << 3);
    const uint32_t kcolB = ((lane >> 3) & 1) << 4;
    const uint32_t bAddr = bBase + (uint32_t)(nbase + nrow) * bStride + kcolB;
    #pragma unroll 1
    for (int ks = 0; ks < KS; ++ks) {
        uint32_t ah[4];
        LDSM4(ah, aAddr + ks * 32);
        #pragma unroll
        for (int p = 0; p < PN; ++p) {
            uint32_t bh[4];
            LDSM4(bh, bAddr + (uint32_t)p * 16u * bStride + ks * 32);
            mma_f16(c[2*p],   ah, bh);
            mma_f16(c[2*p+1], ah, bh + 2);
        }
    }
}

// Epilogue into smem (bias+BNS+relu, fp16).
template <int PN>
__device__ __forceinline__ void epi_t(char* smem, uint32_t outOff,
                                      uint32_t outStride, const float* bias, int cbase,
                                      float (&c)[2 * PN][4], int mrow, int lane) {
    const int r0  = mrow + (lane >> 2);
    const int ccb = 2 * (lane & 3);
    #pragma unroll
    for (int f = 0; f < 2 * PN; ++f) {
        const int col = cbase + (f >> 1) * 16 + (f & 1) * 8 + ccb;
        const float bv0 = bias[col], bv1 = bias[col + 1];
        const float v00 = fmaxf((c[f][0] + bv0) * BNS_F, 0.0f);
        const float v01 = fmaxf((c[f][1] + bv1) * BNS_F, 0.0f);
        const float v10 = fmaxf((c[f][2] + bv0) * BNS_F, 0.0f);
        const float v11 = fmaxf((c[f][3] + bv1) * BNS_F, 0.0f);
        const uint32_t o0 = outOff + (uint32_t)r0 * outStride + (uint32_t)col * 2u;
        const uint32_t o1 = o0 + 8u * outStride;
        *(uint32_t*)(smem + o0) = pk2h(v00, v01);
        *(uint32_t*)(smem + o1) = pk2h(v10, v11);
    }
}

// ---------------------------------------------------------------------------
// Merged weight prep: transpose to [N][Kpad], fp16.
// ---------------------------------------------------------------------------
__device__ __forceinline__ void prep_one(const float* w, __half* out,
                                         int idx, int Cin, int Cout, int Kpad) {
    const int n = idx / Kpad, kp = idx % Kpad;
    const float v = (kp < Cin) ? w[(size_t)kp * Cout + n] : 0.0f;
    out[idx] = __float2half_rn(v);
}

__global__ void prep_all_kernel(const float* w11, const float* w12,
                                const float* w20, const float* w21, const float* w22,
                                const float* w30, const float* w31, const float* w32) {
    const int s1 = 64*64, s2 = 128*64, s3 = 128*152, s4 = 128*136,
              s5 = 256*136, s6 = 256*288, s7 = 512*256, s8 = 768*512;
    const int total = s1+s2+s3+s4+s5+s6+s7+s8;
    for (int i = blockIdx.x * blockDim.x + threadIdx.x; i < total;
         i += gridDim.x * blockDim.x) {
        int idx = i;
        if (idx < s1) { prep_one(w11, g_w11h, idx, 64, 64, 64); continue; }  idx -= s1;
        if (idx < s2) { prep_one(w12, g_w12h, idx, 64, 128, 64); continue; } idx -= s2;
        if (idx < s3) { prep_one(w20, g_w20h, idx, 131, 128, 152); continue; } idx -= s3;
        if (idx < s4) { prep_one(w21, g_w21h, idx, 128, 128, 136); continue; } idx -= s4;
        if (idx < s5) { prep_one(w22, g_w22h, idx, 128, 256, 136); continue; } idx -= s5;
        if (idx < s6) { prep_one(w30, g_w30h, idx, 259, 256, 288); continue; } idx -= s6;
        if (idx < s7) { prep_one(w31, g_w31h, idx, 256, 512, 256); continue; } idx -= s7;
        prep_one(w32, g_w32h, idx, 512, 768, 512);
    }
}

// ---------------------------------------------------------------------------
// FPS + ball (index-exact, unchanged).
// ---------------------------------------------------------------------------
__global__ void fps1_kernel(const float* __restrict__ x,
                            int* __restrict__ fidx, float* __restrict__ nxyz) {
    __shared__ float swv[32];
    __shared__ int   swi[32];
    __shared__ float cur[3];
    __shared__ int   slast;
    const int b = blockIdx.x;
    const int t = threadIdx.x;
    const int warp = t >> 5, lane = t & 31;
    const float* p = x + ((size_t)b * N1 + t) * 6;
    const float px = p[0], py = p[1], pz = p[2];
    float dist = 1e10f;
    if (t == 0) {
        fidx[b * M1] = 0;
        float* o = nxyz + (size_t)b * M1 * 3;
        o[0] = px; o[1] = py; o[2] = pz;
    }
    int last = 0;
    for (int it = 1; it < M1; ++it) {
        if (t == last) { cur[0] = px; cur[1] = py; cur[2] = pz; }
        __syncthreads();
        float dx = __fsub_rn(px, cur[0]);
        float dy = __fsub_rn(py, cur[1]);
        float dz = __fsub_rn(pz, cur[2]);
        float d  = __fadd_rn(__fadd_rn(__fmul_rn(dx, dx), __fmul_rn(dy, dy)),
                             __fmul_rn(dz, dz));
        dist = fminf(dist, d);
        float v = dist; int vi = t;
        #pragma unroll
        for (int off = 16; off; off >>= 1) {
            float v2 = __shfl_xor_sync(0xffffffffu, v, off);
            int   i2 = __shfl_xor_sync(0xffffffffu, vi, off);
            if (v2 > v || (v2 == v && i2 < vi)) { v = v2; vi = i2; }
        }
        if (lane == 0) { swv[warp] = v; swi[warp] = vi; }
        __syncthreads();
        if (warp == 0) {
            float wv = swv[lane]; int wi = swi[lane];
            #pragma unroll
            for (int off = 16; off; off >>= 1) {
                float v2 = __shfl_xor_sync(0xffffffffu, wv, off);
                int   i2 = __shfl_xor_sync(0xffffffffu, wi, off);
                if (v2 > wv || (v2 == wv && i2 < wi)) { wv = v2; wi = i2; }
            }
            if (lane == 0) { slast = wi; fidx[b * M1 + it] = wi; }
        }
        __syncthreads();
        last = slast;
        if (t == last) {
            float* o = nxyz + ((size_t)b * M1 + it) * 3;
            o[0] = px; o[1] = py; o[2] = pz;
        }
    }
}

__global__ void fps2_kernel(const float* __restrict__ pts,
                            int* __restrict__ fidx, float* __restrict__ nxyz) {
    const int gw   = (blockIdx.x * blockDim.x + threadIdx.x) >> 5;
    const int lane = threadIdx.x & 31;
    if (gw >= B_TOT) return;
    const float* pb = pts + (size_t)gw * M1 * 3;
    const float px = pb[lane * 3 + 0], py = pb[lane * 3 + 1], pz = pb[lane * 3 + 2];
    float dist = 1e10f;
    if (lane == 0) {
        fidx[gw * M2] = 0;
        float* o = nxyz + (size_t)gw * M2 * 3;
        o[0] = px; o[1] = py; o[2] = pz;
    }
    int last = 0;
    for (int it = 1; it < M2; ++it) {
        const float cx = __shfl_sync(0xffffffffu, px, last);
        const float cy = __shfl_sync(0xffffffffu, py, last);
        const float cz = __shfl_sync(0xffffffffu, pz, last);
        float dx = __fsub_rn(px, cx), dy = __fsub_rn(py, cy), dz = __fsub_rn(pz, cz);
        float d  = __fadd_rn(__fadd_rn(__fmul_rn(dx, dx), __fmul_rn(dy, dy)),
                             __fmul_rn(dz, dz));
        dist = fminf(dist, d);
        float v = dist; int vi = lane;
        #pragma unroll
        for (int off = 16; off; off >>= 1) {
            float v2 = __shfl_xor_sync(0xffffffffu, v, off);
            int   i2 = __shfl_xor_sync(0xffffffffu, vi, off);
            if (v2 > v || (v2 == v && i2 < vi)) { v = v2; vi = i2; }
        }
        last = vi;
        if (lane == 0) fidx[gw * M2 + it] = last;
        if (lane == last) {
            float* o = nxyz + ((size_t)gw * M2 + it) * 3;
            o[0] = px; o[1] = py; o[2] = pz;
        }
    }
}

__global__ void ball_kernel(const float* __restrict__ pts, int pstride,
                            const float* __restrict__ centers,
                            int M, int N, float r2, int* __restrict__ out) {
    const int gw   = (blockIdx.x * blockDim.x + threadIdx.x) >> 5;
    const int lane = threadIdx.x & 31;
    if (gw >= B_TOT * M) return;
    const int b = gw / M;
    const float* c = centers + (size_t)gw * 3;
    const float cx = c[0], cy = c[1], cz = c[2];
    const float cn = __fadd_rn(__fadd_rn(__fmul_rn(cx, cx), __fmul_rn(cy, cy)),
                               __fmul_rn(cz, cz));
    int* o = out + (size_t)gw * NSMP;
    int cnt = 0, first = -1;
    for (int base = 0; base < N && cnt < NSMP; base += 32) {
        const float* pp = pts + ((size_t)b * N + base + lane) * pstride;
        const float px = pp[0], py = pp[1], pz = pp[2];
        const float pn = __fadd_rn(__fadd_rn(__fmul_rn(px, px), __fmul_rn(py, py)),
                                   __fmul_rn(pz, pz));
        const float dt = __fadd_rn(__fadd_rn(__fmul_rn(cx, px), __fmul_rn(cy, py)),
                                   __fmul_rn(cz, pz));
        const float d2 = __fsub_rn(__fadd_rn(cn, pn), __fmul_rn(2.0f, dt));
        const bool hit = d2 < r2;
        const unsigned mask = __ballot_sync(0xffffffffu, hit);
        if (first < 0 && mask) first = base + __ffs(mask) - 1;
        const int pos = cnt + __popc(mask & ((1u << lane) - 1u));
        if (hit && pos < NSMP) o[pos] = base + lane;
        cnt += __popc(mask);
    }
    if (cnt > NSMP) cnt = NSMP;
    for (int k = cnt + lane; k < NSMP; k += 32) o[k] = first;
}

// ---------------------------------------------------------------------------
// SA1: 4 centers/block (M=128). L0 scalar fp32 (w0 in smem); L1/L2 HMMA.
// A1@0 (16384, str128); A2@16384; B1@32768 (8192); B2@40960 (16384);
// w0s@57344 (1536); bias@58880 (768). part overlays A1.
// ---------------------------------------------------------------------------
#define S1_A1   0u
#define S1_A2   16384u
#define S1_B1   32768u
#define S1_B2   40960u
#define S1_W0   57344u
#define S1_BIAS 58880u
#define S1_SMEM 59648

__global__ void __launch_bounds__(256)
sa1m_kernel(const float* __restrict__ x, const float* __restrict__ nx1,
            const int* __restrict__ ball,
            const float* __restrict__ w0g, const float* __restrict__ b0g,
            const float* __restrict__ b1_, const float* __restrict__ b2_,
            float* __restrict__ out) {
    char* smem = (char*)dynsmem;
    const uint32_t su = smem_to_u32(smem);
    const int tid = threadIdx.x;
    const int wid = tid >> 5, lane = tid & 31;
    const int mrow = wid * 16;
    float* w0s  = (float*)(smem + S1_W0);
    float* bias = (float*)(smem + S1_BIAS);
    float* part = (float*)smem;          // overlays A1 (dead by then)
    const int bm0 = blockIdx.x * 4;
    const int b   = bm0 / M1;

    cp_copy(su + S1_B1, g_w11h, 8192);
    cp_copy(su + S1_B2, g_w12h, 16384);
    CP_COMMIT();

    for (int i = tid; i < 384; i += 256) w0s[i] = w0g[i];
    if (tid < 64)  { w0s[384 + tid] = b0g[tid]; bias[tid] = b1_[tid]; }
    if (tid < 128) bias[64 + tid] = b2_[tid];
    __syncthreads();

    // Gather + scalar L0 (fp32 exact): 2 threads per row, 32 cols each.
    {
        const int row = tid >> 1, seg = tid & 1;
        const int center = bm0 + (row >> 5);
        const int p = ball[center * NSMP + (row & 31)];
        const float* xr  = x + ((size_t)b * N1 + p) * 6;
        const float* ctr = nx1 + (size_t)center * 3;
        float in[6];
        #pragma unroll
        for (int k = 0; k < 6; ++k)
            in[k] = (k < 3) ? xr[k] - ctr[k] : xr[k];
        uint32_t* dh = (uint32_t*)(smem + S1_A1 + row * 128 + seg * 64);
        #pragma unroll 4
        for (int j = 0; j < 16; ++j) {
            const int c0 = seg * 32 + 2 * j;
            float a0 = w0s[384 + c0], a1 = w0s[384 + c0 + 1];
            #pragma unroll
            for (int k = 0; k < 6; ++k) {
                a0 = fmaf(in[k], w0s[k * 64 + c0], a0);
                a1 = fmaf(in[k], w0s[k * 64 + c0 + 1], a1);
            }
            dh[j] = pk2h(fmaxf(a0 * BNS_F, 0.0f), fmaxf(a1 * BNS_F, 0.0f));
        }
    }
    CP_WAIT0();
    __syncthreads();

    {   // L1: K=64 (4 ks), N=64
        float c[8][4];
        #pragma unroll
        for (int f = 0; f < 8; ++f)
            #pragma unroll
            for (int j = 0; j < 4; ++j) c[f][j] = 0.0f;
        gp_t<4, 4>(su + S1_A1, 128u, su + S1_B1, 128u, mrow, 0, lane, c);
        epi_t<4>(smem, S1_A2, 128u, bias, 0, c, mrow, lane);
    }
    __syncthreads();

    {   // L2: K=64, N=128 + fused max over 32 rows/center
        float c[16][4];
        #pragma unroll
        for (int f = 0; f < 16; ++f)
            #pragma unroll
            for (int j = 0; j < 4; ++j) c[f][j] = 0.0f;
        gp_t<4, 8>(su + S1_A2, 128u, su + S1_B2, 128u, mrow, 0, lane, c);
        __syncthreads();   // A1 region now reused as part[]
        #pragma unroll
        for (int f = 0; f < 16; ++f) {
            float m0 = fmaxf(c[f][0], c[f][2]);
            float m1 = fmaxf(c[f][1], c[f][3]);
            #pragma unroll
            for (int off = 4; off <= 16; off <<= 1) {
                m0 = fmaxf(m0, __shfl_xor_sync(0xffffffffu, m0, off));
                m1 = fmaxf(m1, __shfl_xor_sync(0xffffffffu, m1, off));
            }
            if (lane < 4) {
                const int cc = (f >> 1) * 16 + (f & 1) * 8 + 2 * lane;
                part[wid * 128 + cc] = m0;
                part[wid * 128 + cc + 1] = m1;
            }
        }
        __syncthreads();
        for (int i = tid; i < 512; i += 256) {
            const int ci = i >> 7, n = i & 127;
            const float v = fmaxf(part[(2 * ci) * 128 + n],
                                  part[(2 * ci + 1) * 128 + n]);
            out[(size_t)(bm0 + ci) * 128 + n] =
                fmaxf((v + bias[64 + n]) * BNS_F, 0.0f);
        }
    }
}

// ---------------------------------------------------------------------------
// SA2: 4 centers/block (M=128), cp.async-prefetched fp16 weights.
// A@0 (38912, str304); B0@38912 (38912); B1@77824 (34816);
// bias@112640 (2048); part@114688 (4096).
// ---------------------------------------------------------------------------
#define A2_A      0u
#define A2_B0     38912u
#define A2_B1     77824u
#define A2_BIAS   112640u
#define A2_PART   114688u
#define SA2M_SMEM 118784

__global__ void __launch_bounds__(256)
sa2m_kernel(const float* __restrict__ nx1, const float* __restrict__ f1,
            const float* __restrict__ nx2, const int* __restrict__ ball,
            const float* __restrict__ b0_, const float* __restrict__ b1_,
            const float* __restrict__ b2_, float* __restrict__ out) {
    char* smem = (char*)dynsmem;
    const uint32_t su = smem_to_u32(smem);
    const int tid = threadIdx.x;
    const int wid = tid >> 5, lane = tid & 31;
    const int mw  = wid * 16;
    float* bs = (float*)(smem + A2_BIAS);
    float* part = (float*)(smem + A2_PART);
    const int bm0 = blockIdx.x * 4;
    const int b   = bm0 / M2;

    cp_copy(su + A2_B0, g_w20h, 38912);
    CP_COMMIT();
    cp_copy(su + A2_B1, g_w21h, 34816);
    CP_COMMIT();

    if (tid < 128) { bs[tid] = b0_[tid]; bs[128 + tid] = b1_[tid]; }
    bs[256 + tid] = b2_[tid];

    // Gather A(L0): 128 rows x 144 cols, fp16, stride 304B.
    {
        const int row = tid >> 1, seg = tid & 1;
        const int center = bm0 + (row >> 5);
        const int p = ball[center * NSMP + (row & 31)];
        const float* nx1r = nx1 + ((size_t)b * M1 + p) * 3;
        const float* ctr  = nx2 + (size_t)center * 3;
        const float* f1r  = f1 + ((size_t)b * M1 + p) * 128;
        #pragma unroll 1
        for (int i = 0; i < 36; ++i) {
            const int k = seg * 72 + 2 * i;
            float v0, v1;
            if (k < 3)        v0 = nx1r[k] - ctr[k];
            else if (k < 131) v0 = f1r[k - 3];
            else              v0 = 0.0f;
            const int k1 = k + 1;
            if (k1 < 3)        v1 = nx1r[k1] - ctr[k1];
            else if (k1 < 131) v1 = f1r[k1 - 3];
            else               v1 = 0.0f;
            *(uint32_t*)(smem + A2_A + (uint32_t)row * 304u + (uint32_t)k * 2u) =
                pk2h(v0, v1);
        }
    }
    CP_WAIT1();
    __syncthreads();

    float c[16][4];
    // Layer 0: K=144 (9 ks), N=128
    #pragma unroll
    for (int f = 0; f < 16; ++f)
        #pragma unroll
        for (int j = 0; j < 4; ++j) c[f][j] = 0.0f;
    gp_t<9, 8>(su + A2_A, 304u, su + A2_B0, 304u, mw, 0, lane, c);
    __syncthreads();
    cp_copy(su + A2_B0, g_w22h, 34816);                 // B2 rows 0..127
    CP_COMMIT();
    epi_t<8>(smem, A2_A, 272u, bs, 0, c, mw, lane);
    CP_WAIT1();
    __syncthreads();

    // Layer 1: K=128 (8 ks), N=128
    #pragma unroll
    for (int f = 0; f < 16; ++f)
        #pragma unroll
        for (int j = 0; j < 4; ++j) c[f][j] = 0.0f;
    gp_t<8, 8>(su + A2_A, 272u, su + A2_B1, 272u, mw, 0, lane, c);
    __syncthreads();
    cp_copy(su + A2_B1, g_w22h + 128 * 136, 34816);     // B2 rows 128..255
    CP_COMMIT();
    epi_t<8>(smem, A2_A, 272u, bs + 128, 0, c, mw, lane);
    CP_WAIT1();
    __syncthreads();

    // Layer 2: K=128, N=256 in two halves; fused max over 32 rows/center.
    #pragma unroll 1
    for (int h = 0; h < 2; ++h) {
        const uint32_t bBase = h ? (su + A2_B1) : (su + A2_B0);
        #pragma unroll
        for (int f = 0; f < 16; ++f)
            #pragma unroll
            for (int j = 0; j < 4; ++j) c[f][j] = 0.0f;
        gp_t<8, 8>(su + A2_A, 272u, bBase, 272u, mw, 0, lane, c);
        #pragma unroll
        for (int f = 0; f < 16; ++f) {
            float m0 = fmaxf(c[f][0], c[f][2]);
            float m1 = fmaxf(c[f][1], c[f][3]);
            #pragma unroll
            for (int off = 4; off <= 16; off <<= 1) {
                m0 = fmaxf(m0, __shfl_xor_sync(0xffffffffu, m0, off));
                m1 = fmaxf(m1, __shfl_xor_sync(0xffffffffu, m1, off));
            }
            if (lane < 4) {
                const int cc = (f >> 1) * 16 + (f & 1) * 8 + 2 * lane;
                part[wid * 128 + cc] = m0;
                part[wid * 128 + cc + 1] = m1;
            }
        }
        __syncthreads();
        for (int i = tid; i < 512; i += 256) {
            const int ci = i >> 7, n = i & 127;
            const float v = fmaxf(part[(2 * ci) * 128 + n],
                                  part[(2 * ci + 1) * 128 + n]);
            out[(size_t)(bm0 + ci) * 256 + h * 128 + n] =
                fmaxf((v + bs[256 + h * 128 + n]) * BNS_F, 0.0f);
        }
        if (h == 0) CP_WAIT0();
        __syncthreads();
    }
}

// ---------------------------------------------------------------------------
// Head input gather (fp16).
// ---------------------------------------------------------------------------
__global__ void gather_a0_kernel(const float* __restrict__ nx2,
                                 const float* __restrict__ f2) {
    const int row = blockIdx.x * blockDim.x + threadIdx.x;
    if (row >= 32768) return;
    const float* nr = nx2 + (size_t)row * 3;
    const float* fr = f2 + (size_t)row * 256;
    uint32_t* dh = (uint32_t*)(g_a0 + (size_t)row * 288);
    #pragma unroll 4
    for (int j = 0; j < 144; ++j) {
        const int k = 2 * j;
        float v0, v1;
        if (k < 3)        v0 = nr[k];
        else if (k < 259) v0 = fr[k - 3];
        else              v0 = 0.0f;
        const int k1 = k + 1;
        if (k1 < 3)        v1 = nr[k1];
        else if (k1 < 259) v1 = fr[k1 - 3];
        else               v1 = 0.0f;
        dh[j] = pk2h(v0, v1);
    }
}

// ---------------------------------------------------------------------------
// Pipelined tiled GEMM: C[64 x 128], K chunked by 32, double-buffered cp.async.
// buf = [A 5120 | B 10240] x 2 (stride 80); bias @30720.
// ---------------------------------------------------------------------------
#define GM_BUF  15360u
#define GM_BIAS 30720u
#define GM_SMEM 31232

__device__ __forceinline__ void gm_load(uint32_t bufBase,
                                        const __half* A, const __half* Bw,
                                        int Kpad, int Mbase, int Nbase, int kc) {
    const int tid = threadIdx.x;
    if (tid < 128) {   // A: 64 rows x 64B; 2 threads/row, 32B each
        const int row = tid >> 1, prt = tid & 1;
        const char* s = (const char*)(A + (size_t)(Mbase + row) * Kpad + kc * 32)
                        + prt * 32;
        const uint32_t d = bufBase + row * 80u + prt * 32u;
        CP_A16(d, s);
        CP_A16(d + 16, s + 16);
    }
    {   // B: 128 rows x 64B; 2 threads/row, 32B each
        const int row = tid >> 1, prt = tid & 1;
        const char* s = (const char*)(Bw + (size_t)(Nbase + row) * Kpad + kc * 32)
                        + prt * 32;
        const uint32_t d = bufBase + 5120u + row * 80u + prt * 32u;
        CP_A16(d, s);
        CP_A16(d + 16, s + 16);
    }
}

template <int MODE>
__global__ void __launch_bounds__(256, 2)
gemm_kernel(const __half* __restrict__ A, int Kpad, int KC,
            const __half* __restrict__ Bw,
            const float* __restrict__ biasG,
            __half* __restrict__ O, int KpadO,
            float* __restrict__ gout) {
    char* smem = (char*)dynsmem;
    const uint32_t su = smem_to_u32(smem);
    const int tid = threadIdx.x;
    const int wid = tid >> 5, lane = tid & 31;
    const int Mbase = blockIdx.x * 64;
    const int Nbase = blockIdx.y * 128;
    float* bias = (float*)(smem + GM_BIAS);

    gm_load(su, A, Bw, Kpad, Mbase, Nbase, 0);
    CP_COMMIT();
    if (tid < 128) bias[tid] = biasG[Nbase + tid];

    float c[8][4];
    #pragma unroll
    for (int f = 0; f < 8; ++f)
        #pragma unroll
        for (int j = 0; j < 4; ++j) c[f][j] = 0.0f;

    #pragma unroll 1
    for (int kc = 0; kc < KC; ++kc) {
        CP_WAIT0();
        __syncthreads();
        if (kc + 1 < KC) {
            gm_load(su + ((kc + 1) & 1) * GM_BUF, A, Bw, Kpad, Mbase, Nbase, kc + 1);
            CP_COMMIT();
        }
        const uint32_t buf = su + (kc & 1) * GM_BUF;
        gp_t<2, 4>(buf, 80u, buf + 5120u, 80u,
                   (wid & 3) * 16, (wid >> 2) * 64, lane, c);
    }

    if (MODE == 0) {
        const int r0 = Mbase + (wid & 3) * 16 + (lane >> 2);
        const int cb = (wid >> 2) * 64 + 2 * (lane & 3);
        #pragma unroll
        for (int f = 0; f < 8; ++f) {
            const int cl = cb + (f >> 1) * 16 + (f & 1) * 8;
            const int col = Nbase + cl;
            const float bv0 = bias[cl], bv1 = bias[cl + 1];
            const float v00 = fmaxf((c[f][0] + bv0) * BNS_F, 0.0f);
            const float v01 = fmaxf((c[f][1] + bv1) * BNS_F, 0.0f);
            const float v10 = fmaxf((c[f][2] + bv0) * BNS_F, 0.0f);
            const float v11 = fmaxf((c[f][3] + bv1) * BNS_F, 0.0f);
            *(uint32_t*)(O + (size_t)r0 * KpadO + col) = pk2h(v00, v01);
            *(uint32_t*)(O + (size_t)(r0 + 8) * KpadO + col) = pk2h(v10, v11);
        }
    } else {
        const int batch = blockIdx.x * 4 + (wid & 3);
        const int cb = (wid >> 2) * 64;
        #pragma unroll
        for (int f = 0; f < 8; ++f) {
            float m0 = fmaxf(c[f][0], c[f][2]);
            float m1 = fmaxf(c[f][1], c[f][3]);
            #pragma unroll
            for (int off = 4; off <= 16; off <<= 1) {
                m0 = fmaxf(m0, __shfl_xor_sync(0xffffffffu, m0, off));
                m1 = fmaxf(m1, __shfl_xor_sync(0xffffffffu, m1, off));
            }
            if (lane < 4) {
                const int cl = cb + (f >> 1) * 16 + (f & 1) * 8 + 2 * lane;
                const int col = Nbase + cl;
                gout[(size_t)batch * 768 + col] =
                    fmaxf((m0 + bias[cl]) * BNS_F, 0.0f);
                gout[(size_t)batch * 768 + col + 1] =
                    fmaxf((m1 + bias[cl + 1]) * BNS_F, 0.0f);
            }
        }
    }
}

// ---------------------------------------------------------------------------
// FC: 16 batches/block share fc_w loads.
// ---------------------------------------------------------------------------
__global__ void __launch_bounds__(192)
fc_kernel(const float* __restrict__ g_in, const float* __restrict__ fcw,
          const float* __restrict__ fcb, float* __restrict__ out) {
    constexpr int FCB = 16, C = 768, NT = 192;
    __shared__ float gs[FCB * C];
    const int b0 = blockIdx.x * FCB;
    for (int i = threadIdx.x; i < FCB * C; i += NT)
        gs[i] = g_in[(size_t)b0 * C + i];
    __syncthreads();
    const int og = threadIdx.x;
    const float4 bv = *reinterpret_cast<const float4*>(fcb + 4 * og);
    ull_t a01[FCB], a23[FCB];
    #pragma unroll
    for (int i = 0; i < FCB; ++i) { a01[i] = 0ull; a23[i] = 0ull; }
    const float* wp = fcw + 4 * og;
    #pragma unroll 2
    for (int k = 0; k < C; ++k) {
        const ulonglong2 wq =
            *reinterpret_cast<const ulonglong2*>(wp + (size_t)k * C);
        #pragma unroll
        for (int i = 0; i < FCB; ++i) {
            const ull_t hh = dup2(gs[i * C + k]);
            FMA2(a01[i], hh, wq.x, a01[i]);
            FMA2(a23[i], hh, wq.y, a23[i]);
        }
    }
    #pragma unroll
    for (int i = 0; i < FCB; ++i) {
        const float2 p0 = unpk(a01[i]);
        const float2 p1 = unpk(a23[i]);
        float4 r = make_float4(p0.x + bv.x, p0.y + bv.y, p1.x + bv.z, p1.y + bv.w);
        *reinterpret_cast<float4*>(out + (size_t)(b0 + i) * C + 4 * og) = r;
    }
}

// ---------------------------------------------------------------------------
// Host launcher
// ---------------------------------------------------------------------------
extern "C" void kernel_launch(void* const* d_in, const int* in_sizes, int n_in,
                              void* d_out, int out_size) {
    const float* x   = (const float*)d_in[0];
    const float* w10 = (const float*)d_in[1];  const float* b10 = (const float*)d_in[2];
    const float* w11 = (const float*)d_in[3];  const float* b11 = (const float*)d_in[4];
    const float* w12 = (const float*)d_in[5];  const float* b12 = (const float*)d_in[6];
    const float* w20 = (const float*)d_in[7];  const float* b20 = (const float*)d_in[8];
    const float* w21 = (const float*)d_in[9];  const float* b21 = (const float*)d_in[10];
    const float* w22 = (const float*)d_in[11]; const float* b22 = (const float*)d_in[12];
    const float* w30 = (const float*)d_in[13]; const float* b30 = (const float*)d_in[14];
    const float* w31 = (const float*)d_in[15]; const float* b31 = (const float*)d_in[16];
    const float* w32 = (const float*)d_in[17]; const float* b32 = (const float*)d_in[18];
    const float* fcw = (const float*)d_in[19]; const float* fcb = (const float*)d_in[20];
    float* out = (float*)d_out;

    int *fps1p, *ball1p, *fps2p, *ball2p;
    float *nx1p, *f1p, *nx2p, *f2p, *gp;
    __half *a0p, *h0p, *h1p, *w30hp, *w31hp, *w32hp;
    cudaGetSymbolAddress((void**)&fps1p,  g_fps1);
    cudaGetSymbolAddress((void**)&nx1p,   g_nx1);
    cudaGetSymbolAddress((void**)&ball1p, g_ball1);
    cudaGetSymbolAddress((void**)&f1p,    g_f1);
    cudaGetSymbolAddress((void**)&fps2p,  g_fps2);
    cudaGetSymbolAddress((void**)&nx2p,   g_nx2);
    cudaGetSymbolAddress((void**)&ball2p, g_ball2);
    cudaGetSymbolAddress((void**)&f2p,    g_f2);
    cudaGetSymbolAddress((void**)&gp,     g_g);
    cudaGetSymbolAddress((void**)&a0p,    g_a0);
    cudaGetSymbolAddress((void**)&h0p,    g_h0);
    cudaGetSymbolAddress((void**)&h1p,    g_h1);
    cudaGetSymbolAddress((void**)&w30hp,  g_w30h);
    cudaGetSymbolAddress((void**)&w31hp,  g_w31h);
    cudaGetSymbolAddress((void**)&w32hp,  g_w32h);

    cudaFuncSetAttribute(sa1m_kernel, cudaFuncAttributeMaxDynamicSharedMemorySize, S1_SMEM);
    cudaFuncSetAttribute(sa2m_kernel, cudaFuncAttributeMaxDynamicSharedMemorySize, SA2M_SMEM);
    cudaFuncSetAttribute(gemm_kernel<0>, cudaFuncAttributeMaxDynamicSharedMemorySize, GM_SMEM);
    cudaFuncSetAttribute(gemm_kernel<1>, cudaFuncAttributeMaxDynamicSharedMemorySize, GM_SMEM);

    // 1: weight prep
    prep_all_kernel<<<1024, 256>>>(w11, w12, w20, w21, w22, w30, w31, w32);
    // 2-3: FPS1 + ball1
    fps1_kernel<<<B_TOT, 1024>>>(x, fps1p, nx1p);
    ball_kernel<<<(B_TOT * M1 * 32 + 255) / 256, 256>>>(
        x, 6, nx1p, M1, N1, (float)(0.2 * 0.2), ball1p);
    // 4: SA1
    sa1m_kernel<<<B_TOT * M1 / 4, 256, S1_SMEM>>>(x, nx1p, ball1p,
                                                  w10, b10, b11, b12, f1p);
    // 5-7: FPS2 + ball2 + SA2
    fps2_kernel<<<(B_TOT * 32 + 127) / 128, 128>>>(nx1p, fps2p, nx2p);
    ball_kernel<<<(B_TOT * M2 * 32 + 255) / 256, 256>>>(
        nx1p, 3, nx2p, M2, M1, (float)(0.4 * 0.4), ball2p);
    sa2m_kernel<<<B_TOT * M2 / 4, 256, SA2M_SMEM>>>(nx1p, f1p, nx2p, ball2p,
                                                    b20, b21, b22, f2p);
    // 8: head input gather
    gather_a0_kernel<<<32768 / 256, 256>>>(nx2p, f2p);
    // 9-11: head GEMMs
    gemm_kernel<0><<<dim3(512, 2), 256, GM_SMEM>>>(
        a0p, 288, 9, w30hp, b30, h0p, 256, nullptr);
    gemm_kernel<0><<<dim3(512, 4), 256, GM_SMEM>>>(
        h0p, 256, 8, w31hp, b31, h1p, 512, nullptr);
    gemm_kernel<1><<<dim3(512, 6), 256, GM_SMEM>>>(
        h1p, 512, 16, w32hp, b32, nullptr, 0, gp);
    // 12: FC
    fc_kernel<<<B_TOT / 16, 192>>>(gp, fcw, fcb, out);
}

// round 13
// speedup vs baseline: 1.8799x; 1.0234x over previous
#include <cuda_runtime.h>
#include <cuda_fp16.h>
#include <math.h>
#include <stdint.h>

// ---------------------------------------------------------------------------
// PointNet++ encoder forward. B=2048 clouds, N=1024 pts, 6 ch.
// MLP stages on HMMA fp16 (fp32 accum). Index paths exact fp32.
// ---------------------------------------------------------------------------

#define B_TOT 2048
#define N1    1024
#define M1    32
#define M2    16
#define NSMP  32

__device__ float g_nx1  [B_TOT * M1 * 3];
__device__ int   g_ball1[B_TOT * M1 * NSMP];
__device__ float g_f1   [B_TOT * M1 * 128];
__device__ float g_nx2  [B_TOT * M2 * 3];
__device__ int   g_ball2[B_TOT * M2 * NSMP];
__device__ float g_f2   [B_TOT * M2 * 256];
__device__ float g_g    [B_TOT * 768];

// Weights: [N][Kpad] fp16.
__device__ __align__(16) __half g_w11h[64 * 64];
__device__ __align__(16) __half g_w12h[128 * 64];
__device__ __align__(16) __half g_w20h[128 * 152];
__device__ __align__(16) __half g_w21h[128 * 136];
__device__ __align__(16) __half g_w22h[256 * 136];
__device__ __align__(16) __half g_w30h[256 * 288];
__device__ __align__(16) __half g_w31h[512 * 256];
__device__ __align__(16) __half g_w32h[768 * 512];

// Head activations, [32768 rows][Kpad] fp16.
__device__ __align__(16) __half g_a0[32768 * 288];
__device__ __align__(16) __half g_h0[32768 * 256];
__device__ __align__(16) __half g_h1[32768 * 512];

// ---- packed f32x2 helpers (FC kernel) ----------------------------------------
typedef unsigned long long ull_t;
__device__ __forceinline__ ull_t dup2(float v) {
    ull_t r; unsigned u = __float_as_uint(v);
    asm("mov.b64 %0, {%1, %1};" : "=l"(r) : "r"(u));
    return r;
}
__device__ __forceinline__ float2 unpk(ull_t p) {
    unsigned lo, hi;
    asm("mov.b64 {%0, %1}, %2;" : "=r"(lo), "=r"(hi) : "l"(p));
    return make_float2(__uint_as_float(lo), __uint_as_float(hi));
}
#define FMA2(d, a, b, c) \
    asm("fma.rn.f32x2 %0, %1, %2, %3;" : "=l"(d) : "l"(a), "l"(b), "l"(c))

#define BNS_F 0.99999500003749968f   // 1/sqrt(1+1e-5)

// ---- mma.sync / ldmatrix / cp.async helpers ----------------------------------
__device__ __forceinline__ uint32_t smem_to_u32(const void* p) {
    uint32_t a;
    asm("{ .reg .u64 t; cvta.to.shared.u64 t, %1; cvt.u32.u64 %0, t; }"
        : "=r"(a) : "l"(p));
    return a;
}
#define LDSM4(r, a) \
    asm volatile("ldmatrix.sync.aligned.m8n8.x4.shared.b16 {%0,%1,%2,%3}, [%4];" \
                 : "=r"((r)[0]), "=r"((r)[1]), "=r"((r)[2]), "=r"((r)[3]) : "r"(a))

__device__ __forceinline__ void mma_f16(float* c, const uint32_t* a,
                                        const uint32_t* b) {
    asm volatile(
        "mma.sync.aligned.m16n8k16.row.col.f32.f16.f16.f32 "
        "{%0,%1,%2,%3}, {%4,%5,%6,%7}, {%8,%9}, {%0,%1,%2,%3};"
        : "+f"(c[0]), "+f"(c[1]), "+f"(c[2]), "+f"(c[3])
        : "r"(a[0]), "r"(a[1]), "r"(a[2]), "r"(a[3]), "r"(b[0]), "r"(b[1]));
}

#define CP_A16(dst, src) \
    asm volatile("cp.async.cg.shared.global [%0], [%1], 16;" \
                 :: "r"(dst), "l"(src) : "memory")
#define CP_COMMIT() asm volatile("cp.async.commit_group;" ::: "memory")
#define CP_WAIT0()  asm volatile("cp.async.wait_group 0;" ::: "memory")
#define CP_WAIT1()  asm volatile("cp.async.wait_group 1;" ::: "memory")

__device__ __forceinline__ void cp_copy(uint32_t dst, const void* src, int bytes) {
    const char* s = (const char*)src;
    for (int i = threadIdx.x * 16; i < bytes; i += 256 * 16)
        CP_A16(dst + i, s + i);
}

__device__ __forceinline__ uint32_t pk2h(float v0, float v1) {
    __half2 h = __floats2half2_rn(v0, v1);
    return *(const uint32_t*)&h;
}

extern __shared__ float dynsmem[];

// fp16 GEMM pass.
template <int KS, int PN>
__device__ __forceinline__ void gp_t(uint32_t aBase, uint32_t aStride,
                                     uint32_t bBase, uint32_t bStride,
                                     int mrow, int nbase, int lane,
                                     float (&c)[2 * PN][4]) {
    const uint32_t aAddr = aBase + (uint32_t)(mrow + (lane & 15)) * aStride +
                           (uint32_t)((lane >> 4) << 4);
    const uint32_t nrow  = (lane & 7) + ((lane >> 4) << 3);
    const uint32_t kcolB = ((lane >> 3) & 1) << 4;
    const uint32_t bAddr = bBase + (uint32_t)(nbase + nrow) * bStride + kcolB;
    #pragma unroll 1
    for (int ks = 0; ks < KS; ++ks) {
        uint32_t ah[4];
        LDSM4(ah, aAddr + ks * 32);
        #pragma unroll
        for (int p = 0; p < PN; ++p) {
            uint32_t bh[4];
            LDSM4(bh, bAddr + (uint32_t)p * 16u * bStride + ks * 32);
            mma_f16(c[2*p],   ah, bh);
            mma_f16(c[2*p+1], ah, bh + 2);
        }
    }
}

// Epilogue into smem (bias+BNS+relu, fp16).
template <int PN>
__device__ __forceinline__ void epi_t(char* smem, uint32_t outOff,
                                      uint32_t outStride, const float* bias, int cbase,
                                      float (&c)[2 * PN][4], int mrow, int lane) {
    const int r0  = mrow + (lane >> 2);
    const int ccb = 2 * (lane & 3);
    #pragma unroll
    for (int f = 0; f < 2 * PN; ++f) {
        const int col = cbase + (f >> 1) * 16 + (f & 1) * 8 + ccb;
        const float bv0 = bias[col], bv1 = bias[col + 1];
        const float v00 = fmaxf((c[f][0] + bv0) * BNS_F, 0.0f);
        const float v01 = fmaxf((c[f][1] + bv1) * BNS_F, 0.0f);
        const float v10 = fmaxf((c[f][2] + bv0) * BNS_F, 0.0f);
        const float v11 = fmaxf((c[f][3] + bv1) * BNS_F, 0.0f);
        const uint32_t o0 = outOff + (uint32_t)r0 * outStride + (uint32_t)col * 2u;
        const uint32_t o1 = o0 + 8u * outStride;
        *(uint32_t*)(smem + o0) = pk2h(v00, v01);
        *(uint32_t*)(smem + o1) = pk2h(v10, v11);
    }
}

// ---------------------------------------------------------------------------
// Merged weight prep.
// ---------------------------------------------------------------------------
__device__ __forceinline__ void prep_one(const float* w, __half* out,
                                         int idx, int Cin, int Cout, int Kpad) {
    const int n = idx / Kpad, kp = idx % Kpad;
    const float v = (kp < Cin) ? w[(size_t)kp * Cout + n] : 0.0f;
    out[idx] = __float2half_rn(v);
}

__global__ void prep_all_kernel(const float* w11, const float* w12,
                                const float* w20, const float* w21, const float* w22,
                                const float* w30, const float* w31, const float* w32) {
    const int s1 = 64*64, s2 = 128*64, s3 = 128*152, s4 = 128*136,
              s5 = 256*136, s6 = 256*288, s7 = 512*256, s8 = 768*512;
    const int total = s1+s2+s3+s4+s5+s6+s7+s8;
    for (int i = blockIdx.x * blockDim.x + threadIdx.x; i < total;
         i += gridDim.x * blockDim.x) {
        int idx = i;
        if (idx < s1) { prep_one(w11, g_w11h, idx, 64, 64, 64); continue; }  idx -= s1;
        if (idx < s2) { prep_one(w12, g_w12h, idx, 64, 128, 64); continue; } idx -= s2;
        if (idx < s3) { prep_one(w20, g_w20h, idx, 131, 128, 152); continue; } idx -= s3;
        if (idx < s4) { prep_one(w21, g_w21h, idx, 128, 128, 136); continue; } idx -= s4;
        if (idx < s5) { prep_one(w22, g_w22h, idx, 128, 256, 136); continue; } idx -= s5;
        if (idx < s6) { prep_one(w30, g_w30h, idx, 259, 256, 288); continue; } idx -= s6;
        if (idx < s7) { prep_one(w31, g_w31h, idx, 256, 512, 256); continue; } idx -= s7;
        prep_one(w32, g_w32h, idx, 512, 768, 512);
    }
}

// ---------------------------------------------------------------------------
// FPS stage 1: 512 threads, 2 points/thread, 2 syncs/iter (redundant final
// reduce in every warp). Math identical to reference.
// ---------------------------------------------------------------------------
__global__ void __launch_bounds__(512)
fps1_kernel(const float* __restrict__ x, float* __restrict__ nxyz) {
    __shared__ float swv[16];
    __shared__ int   swi[16];
    __shared__ float cur[3];
    const int b = blockIdx.x;
    const int t = threadIdx.x;
    const int warp = t >> 5, lane = t & 31;
    const float* p0 = x + ((size_t)b * N1 + t) * 6;
    const float* p1 = p0 + 512 * 6;
    const float px0 = p0[0], py0 = p0[1], pz0 = p0[2];
    const float px1 = p1[0], py1 = p1[1], pz1 = p1[2];
    float d0 = 1e10f, d1 = 1e10f;
    if (t == 0) {
        float* o = nxyz + (size_t)b * M1 * 3;
        o[0] = px0; o[1] = py0; o[2] = pz0;
    }
    int last = 0;
    for (int it = 1; it < M1; ++it) {
        if (t == (last & 511)) {
            if (last < 512) { cur[0] = px0; cur[1] = py0; cur[2] = pz0; }
            else            { cur[0] = px1; cur[1] = py1; cur[2] = pz1; }
        }
        __syncthreads();
        const float cx = cur[0], cy = cur[1], cz = cur[2];
        {
            float dx = __fsub_rn(px0, cx), dy = __fsub_rn(py0, cy),
                  dz = __fsub_rn(pz0, cz);
            d0 = fminf(d0, __fadd_rn(__fadd_rn(__fmul_rn(dx, dx), __fmul_rn(dy, dy)),
                                     __fmul_rn(dz, dz)));
        }
        {
            float dx = __fsub_rn(px1, cx), dy = __fsub_rn(py1, cy),
                  dz = __fsub_rn(pz1, cz);
            d1 = fminf(d1, __fadd_rn(__fadd_rn(__fmul_rn(dx, dx), __fmul_rn(dy, dy)),
                                     __fmul_rn(dz, dz)));
        }
        float v; int vi;
        if (d0 >= d1) { v = d0; vi = t; } else { v = d1; vi = t + 512; }
        #pragma unroll
        for (int off = 16; off; off >>= 1) {
            float v2 = __shfl_xor_sync(0xffffffffu, v, off);
            int   i2 = __shfl_xor_sync(0xffffffffu, vi, off);
            if (v2 > v || (v2 == v && i2 < vi)) { v = v2; vi = i2; }
        }
        if (lane == 0) { swv[warp] = v; swi[warp] = vi; }
        __syncthreads();
        float wv = (lane < 16) ? swv[lane] : -1.0e30f;
        int   wi = (lane < 16) ? swi[lane] : 0x7fffffff;
        #pragma unroll
        for (int off = 16; off; off >>= 1) {
            float v2 = __shfl_xor_sync(0xffffffffu, wv, off);
            int   i2 = __shfl_xor_sync(0xffffffffu, wi, off);
            if (v2 > wv || (v2 == wv && i2 < wi)) { wv = v2; wi = i2; }
        }
        last = wi;
        if (t == (last & 511)) {
            float* o = nxyz + ((size_t)b * M1 + it) * 3;
            if (last < 512) { o[0] = px0; o[1] = py0; o[2] = pz0; }
            else            { o[0] = px1; o[1] = py1; o[2] = pz1; }
        }
    }
}

// ---------------------------------------------------------------------------
// FPS stage 2: warp per batch (unchanged math).
// ---------------------------------------------------------------------------
__global__ void fps2_kernel(const float* __restrict__ pts,
                            float* __restrict__ nxyz) {
    const int gw   = (blockIdx.x * blockDim.x + threadIdx.x) >> 5;
    const int lane = threadIdx.x & 31;
    if (gw >= B_TOT) return;
    const float* pb = pts + (size_t)gw * M1 * 3;
    const float px = pb[lane * 3 + 0], py = pb[lane * 3 + 1], pz = pb[lane * 3 + 2];
    float dist = 1e10f;
    if (lane == 0) {
        float* o = nxyz + (size_t)gw * M2 * 3;
        o[0] = px; o[1] = py; o[2] = pz;
    }
    int last = 0;
    for (int it = 1; it < M2; ++it) {
        const float cx = __shfl_sync(0xffffffffu, px, last);
        const float cy = __shfl_sync(0xffffffffu, py, last);
        const float cz = __shfl_sync(0xffffffffu, pz, last);
        float dx = __fsub_rn(px, cx), dy = __fsub_rn(py, cy), dz = __fsub_rn(pz, cz);
        float d  = __fadd_rn(__fadd_rn(__fmul_rn(dx, dx), __fmul_rn(dy, dy)),
                             __fmul_rn(dz, dz));
        dist = fminf(dist, d);
        float v = dist; int vi = lane;
        #pragma unroll
        for (int off = 16; off; off >>= 1) {
            float v2 = __shfl_xor_sync(0xffffffffu, v, off);
            int   i2 = __shfl_xor_sync(0xffffffffu, vi, off);
            if (v2 > v || (v2 == v && i2 < vi)) { v = v2; vi = i2; }
        }
        last = vi;
        if (lane == last) {
            float* o = nxyz + ((size_t)gw * M2 + it) * 3;
            o[0] = px; o[1] = py; o[2] = pz;
        }
    }
}

// ---------------------------------------------------------------------------
// Ball query 1: block per batch, xyz staged in smem, warp per center.
// Exact same fp ops as before (expanded distance form).
// ---------------------------------------------------------------------------
__global__ void __launch_bounds__(1024)
ball1_kernel(const float* __restrict__ x, const float* __restrict__ centers,
             int* __restrict__ out) {
    __shared__ float xs[N1], ys[N1], zs[N1];
    const int b = blockIdx.x, t = threadIdx.x;
    const float* p = x + ((size_t)b * N1 + t) * 6;
    xs[t] = p[0]; ys[t] = p[1]; zs[t] = p[2];
    __syncthreads();
    const int wid = t >> 5, lane = t & 31;
    const float* c = centers + ((size_t)b * M1 + wid) * 3;
    const float cx = c[0], cy = c[1], cz = c[2];
    const float cn = __fadd_rn(__fadd_rn(__fmul_rn(cx, cx), __fmul_rn(cy, cy)),
                               __fmul_rn(cz, cz));
    const float r2 = (float)(0.2 * 0.2);
    int* o = out + ((size_t)b * M1 + wid) * NSMP;
    int cnt = 0, first = -1;
    for (int base = 0; base < N1 && cnt < NSMP; base += 32) {
        const float px = xs[base + lane], py = ys[base + lane], pz = zs[base + lane];
        const float pn = __fadd_rn(__fadd_rn(__fmul_rn(px, px), __fmul_rn(py, py)),
                                   __fmul_rn(pz, pz));
        const float dt = __fadd_rn(__fadd_rn(__fmul_rn(cx, px), __fmul_rn(cy, py)),
                                   __fmul_rn(cz, pz));
        const float d2 = __fsub_rn(__fadd_rn(cn, pn), __fmul_rn(2.0f, dt));
        const bool hit = d2 < r2;
        const unsigned mask = __ballot_sync(0xffffffffu, hit);
        if (first < 0 && mask) first = base + __ffs(mask) - 1;
        const int pos = cnt + __popc(mask & ((1u << lane) - 1u));
        if (hit && pos < NSMP) o[pos] = base + lane;
        cnt += __popc(mask);
    }
    if (cnt > NSMP) cnt = NSMP;
    for (int k = cnt + lane; k < NSMP; k += 32) o[k] = first;
}

// ---------------------------------------------------------------------------
// Ball query 2: block per batch (512 thr), 32 points staged, warp per center.
// ---------------------------------------------------------------------------
__global__ void __launch_bounds__(512)
ball2_kernel(const float* __restrict__ pts, const float* __restrict__ centers,
             int* __restrict__ out) {
    __shared__ float xs[M1], ys[M1], zs[M1];
    const int b = blockIdx.x, t = threadIdx.x;
    if (t < M1) {
        const float* p = pts + ((size_t)b * M1 + t) * 3;
        xs[t] = p[0]; ys[t] = p[1]; zs[t] = p[2];
    }
    __syncthreads();
    const int wid = t >> 5, lane = t & 31;
    const float* c = centers + ((size_t)b * M2 + wid) * 3;
    const float cx = c[0], cy = c[1], cz = c[2];
    const float cn = __fadd_rn(__fadd_rn(__fmul_rn(cx, cx), __fmul_rn(cy, cy)),
                               __fmul_rn(cz, cz));
    const float r2 = (float)(0.4 * 0.4);
    int* o = out + ((size_t)b * M2 + wid) * NSMP;
    const float px = xs[lane], py = ys[lane], pz = zs[lane];
    const float pn = __fadd_rn(__fadd_rn(__fmul_rn(px, px), __fmul_rn(py, py)),
                               __fmul_rn(pz, pz));
    const float dt = __fadd_rn(__fadd_rn(__fmul_rn(cx, px), __fmul_rn(cy, py)),
                               __fmul_rn(cz, pz));
    const float d2 = __fsub_rn(__fadd_rn(cn, pn), __fmul_rn(2.0f, dt));
    const bool hit = d2 < r2;
    const unsigned mask = __ballot_sync(0xffffffffu, hit);
    const int first = mask ? (__ffs(mask) - 1) : -1;
    const int pos = __popc(mask & ((1u << lane) - 1u));
    if (hit) o[pos] = lane;
    const int cnt = __popc(mask);
    for (int k = cnt + lane; k < NSMP; k += 32) o[k] = first;
}

// ---------------------------------------------------------------------------
// SA1: 4 centers/block (M=128). L0 scalar fp32 (w0 in smem); L1/L2 HMMA.
// ---------------------------------------------------------------------------
#define S1_A1   0u
#define S1_A2   16384u
#define S1_B1   32768u
#define S1_B2   40960u
#define S1_W0   57344u
#define S1_BIAS 58880u
#define S1_SMEM 59648

__global__ void __launch_bounds__(256)
sa1m_kernel(const float* __restrict__ x, const float* __restrict__ nx1,
            const int* __restrict__ ball,
            const float* __restrict__ w0g, const float* __restrict__ b0g,
            const float* __restrict__ b1_, const float* __restrict__ b2_,
            float* __restrict__ out) {
    char* smem = (char*)dynsmem;
    const uint32_t su = smem_to_u32(smem);
    const int tid = threadIdx.x;
    const int wid = tid >> 5, lane = tid & 31;
    const int mrow = wid * 16;
    float* w0s  = (float*)(smem + S1_W0);
    float* bias = (float*)(smem + S1_BIAS);
    float* part = (float*)smem;          // overlays A1 (dead by then)
    const int bm0 = blockIdx.x * 4;
    const int b   = bm0 / M1;

    cp_copy(su + S1_B1, g_w11h, 8192);
    cp_copy(su + S1_B2, g_w12h, 16384);
    CP_COMMIT();

    for (int i = tid; i < 384; i += 256) w0s[i] = w0g[i];
    if (tid < 64)  { w0s[384 + tid] = b0g[tid]; bias[tid] = b1_[tid]; }
    if (tid < 128) bias[64 + tid] = b2_[tid];
    __syncthreads();

    {
        const int row = tid >> 1, seg = tid & 1;
        const int center = bm0 + (row >> 5);
        const int p = ball[center * NSMP + (row & 31)];
        const float* xr  = x + ((size_t)b * N1 + p) * 6;
        const float* ctr = nx1 + (size_t)center * 3;
        float in[6];
        #pragma unroll
        for (int k = 0; k < 6; ++k)
            in[k] = (k < 3) ? xr[k] - ctr[k] : xr[k];
        uint32_t* dh = (uint32_t*)(smem + S1_A1 + row * 128 + seg * 64);
        #pragma unroll 4
        for (int j = 0; j < 16; ++j) {
            const int c0 = seg * 32 + 2 * j;
            float a0 = w0s[384 + c0], a1 = w0s[384 + c0 + 1];
            #pragma unroll
            for (int k = 0; k < 6; ++k) {
                a0 = fmaf(in[k], w0s[k * 64 + c0], a0);
                a1 = fmaf(in[k], w0s[k * 64 + c0 + 1], a1);
            }
            dh[j] = pk2h(fmaxf(a0 * BNS_F, 0.0f), fmaxf(a1 * BNS_F, 0.0f));
        }
    }
    CP_WAIT0();
    __syncthreads();

    {   // L1: K=64 (4 ks), N=64
        float c[8][4];
        #pragma unroll
        for (int f = 0; f < 8; ++f)
            #pragma unroll
            for (int j = 0; j < 4; ++j) c[f][j] = 0.0f;
        gp_t<4, 4>(su + S1_A1, 128u, su + S1_B1, 128u, mrow, 0, lane, c);
        epi_t<4>(smem, S1_A2, 128u, bias, 0, c, mrow, lane);
    }
    __syncthreads();

    {   // L2: K=64, N=128 + fused max over 32 rows/center
        float c[16][4];
        #pragma unroll
        for (int f = 0; f < 16; ++f)
            #pragma unroll
            for (int j = 0; j < 4; ++j) c[f][j] = 0.0f;
        gp_t<4, 8>(su + S1_A2, 128u, su + S1_B2, 128u, mrow, 0, lane, c);
        __syncthreads();
        #pragma unroll
        for (int f = 0; f < 16; ++f) {
            float m0 = fmaxf(c[f][0], c[f][2]);
            float m1 = fmaxf(c[f][1], c[f][3]);
            #pragma unroll
            for (int off = 4; off <= 16; off <<= 1) {
                m0 = fmaxf(m0, __shfl_xor_sync(0xffffffffu, m0, off));
                m1 = fmaxf(m1, __shfl_xor_sync(0xffffffffu, m1, off));
            }
            if (lane < 4) {
                const int cc = (f >> 1) * 16 + (f & 1) * 8 + 2 * lane;
                part[wid * 128 + cc] = m0;
                part[wid * 128 + cc + 1] = m1;
            }
        }
        __syncthreads();
        for (int i = tid; i < 512; i += 256) {
            const int ci = i >> 7, n = i & 127;
            const float v = fmaxf(part[(2 * ci) * 128 + n],
                                  part[(2 * ci + 1) * 128 + n]);
            out[(size_t)(bm0 + ci) * 128 + n] =
                fmaxf((v + bias[64 + n]) * BNS_F, 0.0f);
        }
    }
}

// ---------------------------------------------------------------------------
// SA2: 4 centers/block (M=128), cp.async-prefetched fp16 weights.
// ---------------------------------------------------------------------------
#define A2_A      0u
#define A2_B0     38912u
#define A2_B1     77824u
#define A2_BIAS   112640u
#define A2_PART   114688u
#define SA2M_SMEM 118784

__global__ void __launch_bounds__(256)
sa2m_kernel(const float* __restrict__ nx1, const float* __restrict__ f1,
            const float* __restrict__ nx2, const int* __restrict__ ball,
            const float* __restrict__ b0_, const float* __restrict__ b1_,
            const float* __restrict__ b2_, float* __restrict__ out) {
    char* smem = (char*)dynsmem;
    const uint32_t su = smem_to_u32(smem);
    const int tid = threadIdx.x;
    const int wid = tid >> 5, lane = tid & 31;
    const int mw  = wid * 16;
    float* bs = (float*)(smem + A2_BIAS);
    float* part = (float*)(smem + A2_PART);
    const int bm0 = blockIdx.x * 4;
    const int b   = bm0 / M2;

    cp_copy(su + A2_B0, g_w20h, 38912);
    CP_COMMIT();
    cp_copy(su + A2_B1, g_w21h, 34816);
    CP_COMMIT();

    if (tid < 128) { bs[tid] = b0_[tid]; bs[128 + tid] = b1_[tid]; }
    bs[256 + tid] = b2_[tid];

    {
        const int row = tid >> 1, seg = tid & 1;
        const int center = bm0 + (row >> 5);
        const int p = ball[center * NSMP + (row & 31)];
        const float* nx1r = nx1 + ((size_t)b * M1 + p) * 3;
        const float* ctr  = nx2 + (size_t)center * 3;
        const float* f1r  = f1 + ((size_t)b * M1 + p) * 128;
        #pragma unroll 1
        for (int i = 0; i < 36; ++i) {
            const int k = seg * 72 + 2 * i;
            float v0, v1;
            if (k < 3)        v0 = nx1r[k] - ctr[k];
            else if (k < 131) v0 = f1r[k - 3];
            else              v0 = 0.0f;
            const int k1 = k + 1;
            if (k1 < 3)        v1 = nx1r[k1] - ctr[k1];
            else if (k1 < 131) v1 = f1r[k1 - 3];
            else               v1 = 0.0f;
            *(uint32_t*)(smem + A2_A + (uint32_t)row * 304u + (uint32_t)k * 2u) =
                pk2h(v0, v1);
        }
    }
    CP_WAIT1();
    __syncthreads();

    float c[16][4];
    #pragma unroll
    for (int f = 0; f < 16; ++f)
        #pragma unroll
        for (int j = 0; j < 4; ++j) c[f][j] = 0.0f;
    gp_t<9, 8>(su + A2_A, 304u, su + A2_B0, 304u, mw, 0, lane, c);
    __syncthreads();
    cp_copy(su + A2_B0, g_w22h, 34816);
    CP_COMMIT();
    epi_t<8>(smem, A2_A, 272u, bs, 0, c, mw, lane);
    CP_WAIT1();
    __syncthreads();

    #pragma unroll
    for (int f = 0; f < 16; ++f)
        #pragma unroll
        for (int j = 0; j < 4; ++j) c[f][j] = 0.0f;
    gp_t<8, 8>(su + A2_A, 272u, su + A2_B1, 272u, mw, 0, lane, c);
    __syncthreads();
    cp_copy(su + A2_B1, g_w22h + 128 * 136, 34816);
    CP_COMMIT();
    epi_t<8>(smem, A2_A, 272u, bs + 128, 0, c, mw, lane);
    CP_WAIT1();
    __syncthreads();

    #pragma unroll 1
    for (int h = 0; h < 2; ++h) {
        const uint32_t bBase = h ? (su + A2_B1) : (su + A2_B0);
        #pragma unroll
        for (int f = 0; f < 16; ++f)
            #pragma unroll
            for (int j = 0; j < 4; ++j) c[f][j] = 0.0f;
        gp_t<8, 8>(su + A2_A, 272u, bBase, 272u, mw, 0, lane, c);
        #pragma unroll
        for (int f = 0; f < 16; ++f) {
            float m0 = fmaxf(c[f][0], c[f][2]);
            float m1 = fmaxf(c[f][1], c[f][3]);
            #pragma unroll
            for (int off = 4; off <= 16; off <<= 1) {
                m0 = fmaxf(m0, __shfl_xor_sync(0xffffffffu, m0, off));
                m1 = fmaxf(m1, __shfl_xor_sync(0xffffffffu, m1, off));
            }
            if (lane < 4) {
                const int cc = (f >> 1) * 16 + (f & 1) * 8 + 2 * lane;
                part[wid * 128 + cc] = m0;
                part[wid * 128 + cc + 1] = m1;
            }
        }
        __syncthreads();
        for (int i = tid; i < 512; i += 256) {
            const int ci = i >> 7, n = i & 127;
            const float v = fmaxf(part[(2 * ci) * 128 + n],
                                  part[(2 * ci + 1) * 128 + n]);
            out[(size_t)(bm0 + ci) * 256 + h * 128 + n] =
                fmaxf((v + bs[256 + h * 128 + n]) * BNS_F, 0.0f);
        }
        if (h == 0) CP_WAIT0();
        __syncthreads();
    }
}

// ---------------------------------------------------------------------------
// Head input gather (fp16).
// ---------------------------------------------------------------------------
__global__ void gather_a0_kernel(const float* __restrict__ nx2,
                                 const float* __restrict__ f2) {
    const int row = blockIdx.x * blockDim.x + threadIdx.x;
    if (row >= 32768) return;
    const float* nr = nx2 + (size_t)row * 3;
    const float* fr = f2 + (size_t)row * 256;
    uint32_t* dh = (uint32_t*)(g_a0 + (size_t)row * 288);
    #pragma unroll 4
    for (int j = 0; j < 144; ++j) {
        const int k = 2 * j;
        float v0, v1;
        if (k < 3)        v0 = nr[k];
        else if (k < 259) v0 = fr[k - 3];
        else              v0 = 0.0f;
        const int k1 = k + 1;
        if (k1 < 3)        v1 = nr[k1];
        else if (k1 < 259) v1 = fr[k1 - 3];
        else               v1 = 0.0f;
        dh[j] = pk2h(v0, v1);
    }
}

// ---------------------------------------------------------------------------
// Pipelined tiled GEMM (fp16): C[64 x 128], K chunked by 32, double-buffered.
// ---------------------------------------------------------------------------
#define GM_BUF  15360u
#define GM_BIAS 30720u
#define GM_SMEM 31232

__device__ __forceinline__ void gm_load(uint32_t bufBase,
                                        const __half* A, const __half* Bw,
                                        int Kpad, int Mbase, int Nbase, int kc) {
    const int tid = threadIdx.x;
    if (tid < 128) {
        const int row = tid >> 1, prt = tid & 1;
        const char* s = (const char*)(A + (size_t)(Mbase + row) * Kpad + kc * 32)
                        + prt * 32;
        const uint32_t d = bufBase + row * 80u + prt * 32u;
        CP_A16(d, s);
        CP_A16(d + 16, s + 16);
    }
    {
        const int row = tid >> 1, prt = tid & 1;
        const char* s = (const char*)(Bw + (size_t)(Nbase + row) * Kpad + kc * 32)
                        + prt * 32;
        const uint32_t d = bufBase + 5120u + row * 80u + prt * 32u;
        CP_A16(d, s);
        CP_A16(d + 16, s + 16);
    }
}

template <int MODE>
__global__ void __launch_bounds__(256, 2)
gemm_kernel(const __half* __restrict__ A, int Kpad, int KC,
            const __half* __restrict__ Bw,
            const float* __restrict__ biasG,
            __half* __restrict__ O, int KpadO,
            float* __restrict__ gout) {
    char* smem = (char*)dynsmem;
    const uint32_t su = smem_to_u32(smem);
    const int tid = threadIdx.x;
    const int wid = tid >> 5, lane = tid & 31;
    const int Mbase = blockIdx.x * 64;
    const int Nbase = blockIdx.y * 128;
    float* bias = (float*)(smem + GM_BIAS);

    gm_load(su, A, Bw, Kpad, Mbase, Nbase, 0);
    CP_COMMIT();
    if (tid < 128) bias[tid] = biasG[Nbase + tid];

    float c[8][4];
    #pragma unroll
    for (int f = 0; f < 8; ++f)
        #pragma unroll
        for (int j = 0; j < 4; ++j) c[f][j] = 0.0f;

    #pragma unroll 1
    for (int kc = 0; kc < KC; ++kc) {
        CP_WAIT0();
        __syncthreads();
        if (kc + 1 < KC) {
            gm_load(su + ((kc + 1) & 1) * GM_BUF, A, Bw, Kpad, Mbase, Nbase, kc + 1);
            CP_COMMIT();
        }
        const uint32_t buf = su + (kc & 1) * GM_BUF;
        gp_t<2, 4>(buf, 80u, buf + 5120u, 80u,
                   (wid & 3) * 16, (wid >> 2) * 64, lane, c);
    }

    if (MODE == 0) {
        const int r0 = Mbase + (wid & 3) * 16 + (lane >> 2);
        const int cb = (wid >> 2) * 64 + 2 * (lane & 3);
        #pragma unroll
        for (int f = 0; f < 8; ++f) {
            const int cl = cb + (f >> 1) * 16 + (f & 1) * 8;
            const int col = Nbase + cl;
            const float bv0 = bias[cl], bv1 = bias[cl + 1];
            const float v00 = fmaxf((c[f][0] + bv0) * BNS_F, 0.0f);
            const float v01 = fmaxf((c[f][1] + bv1) * BNS_F, 0.0f);
            const float v10 = fmaxf((c[f][2] + bv0) * BNS_F, 0.0f);
            const float v11 = fmaxf((c[f][3] + bv1) * BNS_F, 0.0f);
            *(uint32_t*)(O + (size_t)r0 * KpadO + col) = pk2h(v00, v01);
            *(uint32_t*)(O + (size_t)(r0 + 8) * KpadO + col) = pk2h(v10, v11);
        }
    } else {
        const int batch = blockIdx.x * 4 + (wid & 3);
        const int cb = (wid >> 2) * 64;
        #pragma unroll
        for (int f = 0; f < 8; ++f) {
            float m0 = fmaxf(c[f][0], c[f][2]);
            float m1 = fmaxf(c[f][1], c[f][3]);
            #pragma unroll
            for (int off = 4; off <= 16; off <<= 1) {
                m0 = fmaxf(m0, __shfl_xor_sync(0xffffffffu, m0, off));
                m1 = fmaxf(m1, __shfl_xor_sync(0xffffffffu, m1, off));
            }
            if (lane < 4) {
                const int cl = cb + (f >> 1) * 16 + (f & 1) * 8 + 2 * lane;
                const int col = Nbase + cl;
                gout[(size_t)batch * 768 + col] =
                    fmaxf((m0 + bias[cl]) * BNS_F, 0.0f);
                gout[(size_t)batch * 768 + col + 1] =
                    fmaxf((m1 + bias[cl + 1]) * BNS_F, 0.0f);
            }
        }
    }
}

// ---------------------------------------------------------------------------
// FC: 16 batches/block share fc_w loads.
// ---------------------------------------------------------------------------
__global__ void __launch_bounds__(192)
fc_kernel(const float* __restrict__ g_in, const float* __restrict__ fcw,
          const float* __restrict__ fcb, float* __restrict__ out) {
    constexpr int FCB = 16, C = 768, NT = 192;
    __shared__ float gs[FCB * C];
    const int b0 = blockIdx.x * FCB;
    for (int i = threadIdx.x; i < FCB * C; i += NT)
        gs[i] = g_in[(size_t)b0 * C + i];
    __syncthreads();
    const int og = threadIdx.x;
    const float4 bv = *reinterpret_cast<const float4*>(fcb + 4 * og);
    ull_t a01[FCB], a23[FCB];
    #pragma unroll
    for (int i = 0; i < FCB; ++i) { a01[i] = 0ull; a23[i] = 0ull; }
    const float* wp = fcw + 4 * og;
    #pragma unroll 2
    for (int k = 0; k < C; ++k) {
        const ulonglong2 wq =
            *reinterpret_cast<const ulonglong2*>(wp + (size_t)k * C);
        #pragma unroll
        for (int i = 0; i < FCB; ++i) {
            const ull_t hh = dup2(gs[i * C + k]);
            FMA2(a01[i], hh, wq.x, a01[i]);
            FMA2(a23[i], hh, wq.y, a23[i]);
        }
    }
    #pragma unroll
    for (int i = 0; i < FCB; ++i) {
        const float2 p0 = unpk(a01[i]);
        const float2 p1 = unpk(a23[i]);
        float4 r = make_float4(p0.x + bv.x, p0.y + bv.y, p1.x + bv.z, p1.y + bv.w);
        *reinterpret_cast<float4*>(out + (size_t)(b0 + i) * C + 4 * og) = r;
    }
}

// ---------------------------------------------------------------------------
// Host launcher
// ---------------------------------------------------------------------------
extern "C" void kernel_launch(void* const* d_in, const int* in_sizes, int n_in,
                              void* d_out, int out_size) {
    const float* x   = (const float*)d_in[0];
    const float* w10 = (const float*)d_in[1];  const float* b10 = (const float*)d_in[2];
    const float* w11 = (const float*)d_in[3];  const float* b11 = (const float*)d_in[4];
    const float* w12 = (const float*)d_in[5];  const float* b12 = (const float*)d_in[6];
    const float* w20 = (const float*)d_in[7];  const float* b20 = (const float*)d_in[8];
    const float* w21 = (const float*)d_in[9];  const float* b21 = (const float*)d_in[10];
    const float* w22 = (const float*)d_in[11]; const float* b22 = (const float*)d_in[12];
    const float* w30 = (const float*)d_in[13]; const float* b30 = (const float*)d_in[14];
    const float* w31 = (const float*)d_in[15]; const float* b31 = (const float*)d_in[16];
    const float* w32 = (const float*)d_in[17]; const float* b32 = (const float*)d_in[18];
    const float* fcw = (const float*)d_in[19]; const float* fcb = (const float*)d_in[20];
    float* out = (float*)d_out;

    int *ball1p, *ball2p;
    float *nx1p, *f1p, *nx2p, *f2p, *gp;
    __half *a0p, *h0p, *h1p, *w30hp, *w31hp, *w32hp;
    cudaGetSymbolAddress((void**)&nx1p,   g_nx1);
    cudaGetSymbolAddress((void**)&ball1p, g_ball1);
    cudaGetSymbolAddress((void**)&f1p,    g_f1);
    cudaGetSymbolAddress((void**)&nx2p,   g_nx2);
    cudaGetSymbolAddress((void**)&ball2p, g_ball2);
    cudaGetSymbolAddress((void**)&f2p,    g_f2);
    cudaGetSymbolAddress((void**)&gp,     g_g);
    cudaGetSymbolAddress((void**)&a0p,    g_a0);
    cudaGetSymbolAddress((void**)&h0p,    g_h0);
    cudaGetSymbolAddress((void**)&h1p,    g_h1);
    cudaGetSymbolAddress((void**)&w30hp,  g_w30h);
    cudaGetSymbolAddress((void**)&w31hp,  g_w31h);
    cudaGetSymbolAddress((void**)&w32hp,  g_w32h);

    cudaFuncSetAttribute(sa1m_kernel, cudaFuncAttributeMaxDynamicSharedMemorySize, S1_SMEM);
    cudaFuncSetAttribute(sa2m_kernel, cudaFuncAttributeMaxDynamicSharedMemorySize, SA2M_SMEM);
    cudaFuncSetAttribute(gemm_kernel<0>, cudaFuncAttributeMaxDynamicSharedMemorySize, GM_SMEM);
    cudaFuncSetAttribute(gemm_kernel<1>, cudaFuncAttributeMaxDynamicSharedMemorySize, GM_SMEM);

    // 1: weight prep
    prep_all_kernel<<<1024, 256>>>(w11, w12, w20, w21, w22, w30, w31, w32);
    // 2-3: FPS1 + ball1
    fps1_kernel<<<B_TOT, 512>>>(x, nx1p);
    ball1_kernel<<<B_TOT, 1024>>>(x, nx1p, ball1p);
    // 4: SA1
    sa1m_kernel<<<B_TOT * M1 / 4, 256, S1_SMEM>>>(x, nx1p, ball1p,
                                                  w10, b10, b11, b12, f1p);
    // 5-7: FPS2 + ball2 + SA2
    fps2_kernel<<<(B_TOT * 32 + 127) / 128, 128>>>(nx1p, nx2p);
    ball2_kernel<<<B_TOT, 512>>>(nx1p, nx2p, ball2p);
    sa2m_kernel<<<B_TOT * M2 / 4, 256, SA2M_SMEM>>>(nx1p, f1p, nx2p, ball2p,
                                                    b20, b21, b22, f2p);
    // 8: head input gather
    gather_a0_kernel<<<32768 / 256, 256>>>(nx2p, f2p);
    // 9-11: head GEMMs
    gemm_kernel<0><<<dim3(512, 2), 256, GM_SMEM>>>(
        a0p, 288, 9, w30hp, b30, h0p, 256, nullptr);
    gemm_kernel<0><<<dim3(512, 4), 256, GM_SMEM>>>(
        h0p, 256, 8, w31hp, b31, h1p, 512, nullptr);
    gemm_kernel<1><<<dim3(512, 6), 256, GM_SMEM>>>(
        h1p, 512, 16, w32hp, b32, nullptr, 0, gp);
    // 12: FC
    fc_kernel<<<B_TOT / 16, 192>>>(gp, fcw, fcb, out);
}

// round 14
// speedup vs baseline: 2.6420x; 1.4054x over previous
#include <cuda_runtime.h>
#include <cuda_fp16.h>
#include <math.h>
#include <stdint.h>

// ---------------------------------------------------------------------------
// PointNet++ encoder forward. B=2048 clouds, N=1024 pts, 6 ch.
// MLP stages on HMMA fp16 (fp32 accum). Index paths exact fp32.
// R14: sa1m strides padded 128B -> 144B (conflict-free ldmatrix).
// ---------------------------------------------------------------------------

#define B_TOT 2048
#define N1    1024
#define M1    32
#define M2    16
#define NSMP  32

__device__ float g_nx1  [B_TOT * M1 * 3];
__device__ int   g_ball1[B_TOT * M1 * NSMP];
__device__ float g_f1   [B_TOT * M1 * 128];
__device__ float g_nx2  [B_TOT * M2 * 3];
__device__ int   g_ball2[B_TOT * M2 * NSMP];
__device__ float g_f2   [B_TOT * M2 * 256];
__device__ float g_g    [B_TOT * 768];

// Weights: [N][Kpad] fp16.  (w11/w12 use Kpad=72 -> 144B rows)
__device__ __align__(16) __half g_w11h[64 * 72];
__device__ __align__(16) __half g_w12h[128 * 72];
__device__ __align__(16) __half g_w20h[128 * 152];
__device__ __align__(16) __half g_w21h[128 * 136];
__device__ __align__(16) __half g_w22h[256 * 136];
__device__ __align__(16) __half g_w30h[256 * 288];
__device__ __align__(16) __half g_w31h[512 * 256];
__device__ __align__(16) __half g_w32h[768 * 512];

// Head activations, [32768 rows][Kpad] fp16.
__device__ __align__(16) __half g_a0[32768 * 288];
__device__ __align__(16) __half g_h0[32768 * 256];
__device__ __align__(16) __half g_h1[32768 * 512];

// ---- packed f32x2 helpers (FC kernel) ----------------------------------------
typedef unsigned long long ull_t;
__device__ __forceinline__ ull_t dup2(float v) {
    ull_t r; unsigned u = __float_as_uint(v);
    asm("mov.b64 %0, {%1, %1};" : "=l"(r) : "r"(u));
    return r;
}
__device__ __forceinline__ float2 unpk(ull_t p) {
    unsigned lo, hi;
    asm("mov.b64 {%0, %1}, %2;" : "=r"(lo), "=r"(hi) : "l"(p));
    return make_float2(__uint_as_float(lo), __uint_as_float(hi));
}
#define FMA2(d, a, b, c) \
    asm("fma.rn.f32x2 %0, %1, %2, %3;" : "=l"(d) : "l"(a), "l"(b), "l"(c))

#define BNS_F 0.99999500003749968f   // 1/sqrt(1+1e-5)

// ---- mma.sync / ldmatrix / cp.async helpers ----------------------------------
__device__ __forceinline__ uint32_t smem_to_u32(const void* p) {
    uint32_t a;
    asm("{ .reg .u64 t; cvta.to.shared.u64 t, %1; cvt.u32.u64 %0, t; }"
        : "=r"(a) : "l"(p));
    return a;
}
#define LDSM4(r, a) \
    asm volatile("ldmatrix.sync.aligned.m8n8.x4.shared.b16 {%0,%1,%2,%3}, [%4];" \
                 : "=r"((r)[0]), "=r"((r)[1]), "=r"((r)[2]), "=r"((r)[3]) : "r"(a))

__device__ __forceinline__ void mma_f16(float* c, const uint32_t* a,
                                        const uint32_t* b) {
    asm volatile(
        "mma.sync.aligned.m16n8k16.row.col.f32.f16.f16.f32 "
        "{%0,%1,%2,%3}, {%4,%5,%6,%7}, {%8,%9}, {%0,%1,%2,%3};"
        : "+f"(c[0]), "+f"(c[1]), "+f"(c[2]), "+f"(c[3])
        : "r"(a[0]), "r"(a[1]), "r"(a[2]), "r"(a[3]), "r"(b[0]), "r"(b[1]));
}

#define CP_A16(dst, src) \
    asm volatile("cp.async.cg.shared.global [%0], [%1], 16;" \
                 :: "r"(dst), "l"(src) : "memory")
#define CP_COMMIT() asm volatile("cp.async.commit_group;" ::: "memory")
#define CP_WAIT0()  asm volatile("cp.async.wait_group 0;" ::: "memory")
#define CP_WAIT1()  asm volatile("cp.async.wait_group 1;" ::: "memory")

__device__ __forceinline__ void cp_copy(uint32_t dst, const void* src, int bytes) {
    const char* s = (const char*)src;
    for (int i = threadIdx.x * 16; i < bytes; i += 256 * 16)
        CP_A16(dst + i, s + i);
}

__device__ __forceinline__ uint32_t pk2h(float v0, float v1) {
    __half2 h = __floats2half2_rn(v0, v1);
    return *(const uint32_t*)&h;
}

extern __shared__ float dynsmem[];

// fp16 GEMM pass.
template <int KS, int PN>
__device__ __forceinline__ void gp_t(uint32_t aBase, uint32_t aStride,
                                     uint32_t bBase, uint32_t bStride,
                                     int mrow, int nbase, int lane,
                                     float (&c)[2 * PN][4]) {
    const uint32_t aAddr = aBase + (uint32_t)(mrow + (lane & 15)) * aStride +
                           (uint32_t)((lane >> 4) << 4);
    const uint32_t nrow  = (lane & 7) + ((lane >> 4) << 3);
    const uint32_t kcolB = ((lane >> 3) & 1) << 4;
    const uint32_t bAddr = bBase + (uint32_t)(nbase + nrow) * bStride + kcolB;
    #pragma unroll 1
    for (int ks = 0; ks < KS; ++ks) {
        uint32_t ah[4];
        LDSM4(ah, aAddr + ks * 32);
        #pragma unroll
        for (int p = 0; p < PN; ++p) {
            uint32_t bh[4];
            LDSM4(bh, bAddr + (uint32_t)p * 16u * bStride + ks * 32);
            mma_f16(c[2*p],   ah, bh);
            mma_f16(c[2*p+1], ah, bh + 2);
        }
    }
}

// Epilogue into smem (bias+BNS+relu, fp16).
template <int PN>
__device__ __forceinline__ void epi_t(char* smem, uint32_t outOff,
                                      uint32_t outStride, const float* bias, int cbase,
                                      float (&c)[2 * PN][4], int mrow, int lane) {
    const int r0  = mrow + (lane >> 2);
    const int ccb = 2 * (lane & 3);
    #pragma unroll
    for (int f = 0; f < 2 * PN; ++f) {
        const int col = cbase + (f >> 1) * 16 + (f & 1) * 8 + ccb;
        const float bv0 = bias[col], bv1 = bias[col + 1];
        const float v00 = fmaxf((c[f][0] + bv0) * BNS_F, 0.0f);
        const float v01 = fmaxf((c[f][1] + bv1) * BNS_F, 0.0f);
        const float v10 = fmaxf((c[f][2] + bv0) * BNS_F, 0.0f);
        const float v11 = fmaxf((c[f][3] + bv1) * BNS_F, 0.0f);
        const uint32_t o0 = outOff + (uint32_t)r0 * outStride + (uint32_t)col * 2u;
        const uint32_t o1 = o0 + 8u * outStride;
        *(uint32_t*)(smem + o0) = pk2h(v00, v01);
        *(uint32_t*)(smem + o1) = pk2h(v10, v11);
    }
}

// ---------------------------------------------------------------------------
// Merged weight prep.
// ---------------------------------------------------------------------------
__device__ __forceinline__ void prep_one(const float* w, __half* out,
                                         int idx, int Cin, int Cout, int Kpad) {
    const int n = idx / Kpad, kp = idx % Kpad;
    const float v = (kp < Cin) ? w[(size_t)kp * Cout + n] : 0.0f;
    out[idx] = __float2half_rn(v);
}

__global__ void prep_all_kernel(const float* w11, const float* w12,
                                const float* w20, const float* w21, const float* w22,
                                const float* w30, const float* w31, const float* w32) {
    const int s1 = 64*72, s2 = 128*72, s3 = 128*152, s4 = 128*136,
              s5 = 256*136, s6 = 256*288, s7 = 512*256, s8 = 768*512;
    const int total = s1+s2+s3+s4+s5+s6+s7+s8;
    for (int i = blockIdx.x * blockDim.x + threadIdx.x; i < total;
         i += gridDim.x * blockDim.x) {
        int idx = i;
        if (idx < s1) { prep_one(w11, g_w11h, idx, 64, 64, 72); continue; }  idx -= s1;
        if (idx < s2) { prep_one(w12, g_w12h, idx, 64, 128, 72); continue; } idx -= s2;
        if (idx < s3) { prep_one(w20, g_w20h, idx, 131, 128, 152); continue; } idx -= s3;
        if (idx < s4) { prep_one(w21, g_w21h, idx, 128, 128, 136); continue; } idx -= s4;
        if (idx < s5) { prep_one(w22, g_w22h, idx, 128, 256, 136); continue; } idx -= s5;
        if (idx < s6) { prep_one(w30, g_w30h, idx, 259, 256, 288); continue; } idx -= s6;
        if (idx < s7) { prep_one(w31, g_w31h, idx, 256, 512, 256); continue; } idx -= s7;
        prep_one(w32, g_w32h, idx, 512, 768, 512);
    }
}

// ---------------------------------------------------------------------------
// FPS stage 1 (512 thr, 2 pts/thread), FPS stage 2, ball1/ball2 (unchanged).
// ---------------------------------------------------------------------------
__global__ void __launch_bounds__(512)
fps1_kernel(const float* __restrict__ x, float* __restrict__ nxyz) {
    __shared__ float swv[16];
    __shared__ int   swi[16];
    __shared__ float cur[3];
    const int b = blockIdx.x;
    const int t = threadIdx.x;
    const int warp = t >> 5, lane = t & 31;
    const float* p0 = x + ((size_t)b * N1 + t) * 6;
    const float* p1 = p0 + 512 * 6;
    const float px0 = p0[0], py0 = p0[1], pz0 = p0[2];
    const float px1 = p1[0], py1 = p1[1], pz1 = p1[2];
    float d0 = 1e10f, d1 = 1e10f;
    if (t == 0) {
        float* o = nxyz + (size_t)b * M1 * 3;
        o[0] = px0; o[1] = py0; o[2] = pz0;
    }
    int last = 0;
    for (int it = 1; it < M1; ++it) {
        if (t == (last & 511)) {
            if (last < 512) { cur[0] = px0; cur[1] = py0; cur[2] = pz0; }
            else            { cur[0] = px1; cur[1] = py1; cur[2] = pz1; }
        }
        __syncthreads();
        const float cx = cur[0], cy = cur[1], cz = cur[2];
        {
            float dx = __fsub_rn(px0, cx), dy = __fsub_rn(py0, cy),
                  dz = __fsub_rn(pz0, cz);
            d0 = fminf(d0, __fadd_rn(__fadd_rn(__fmul_rn(dx, dx), __fmul_rn(dy, dy)),
                                     __fmul_rn(dz, dz)));
        }
        {
            float dx = __fsub_rn(px1, cx), dy = __fsub_rn(py1, cy),
                  dz = __fsub_rn(pz1, cz);
            d1 = fminf(d1, __fadd_rn(__fadd_rn(__fmul_rn(dx, dx), __fmul_rn(dy, dy)),
                                     __fmul_rn(dz, dz)));
        }
        float v; int vi;
        if (d0 >= d1) { v = d0; vi = t; } else { v = d1; vi = t + 512; }
        #pragma unroll
        for (int off = 16; off; off >>= 1) {
            float v2 = __shfl_xor_sync(0xffffffffu, v, off);
            int   i2 = __shfl_xor_sync(0xffffffffu, vi, off);
            if (v2 > v || (v2 == v && i2 < vi)) { v = v2; vi = i2; }
        }
        if (lane == 0) { swv[warp] = v; swi[warp] = vi; }
        __syncthreads();
        float wv = (lane < 16) ? swv[lane] : -1.0e30f;
        int   wi = (lane < 16) ? swi[lane] : 0x7fffffff;
        #pragma unroll
        for (int off = 16; off; off >>= 1) {
            float v2 = __shfl_xor_sync(0xffffffffu, wv, off);
            int   i2 = __shfl_xor_sync(0xffffffffu, wi, off);
            if (v2 > wv || (v2 == wv && i2 < wi)) { wv = v2; wi = i2; }
        }
        last = wi;
        if (t == (last & 511)) {
            float* o = nxyz + ((size_t)b * M1 + it) * 3;
            if (last < 512) { o[0] = px0; o[1] = py0; o[2] = pz0; }
            else            { o[0] = px1; o[1] = py1; o[2] = pz1; }
        }
    }
}

__global__ void fps2_kernel(const float* __restrict__ pts,
                            float* __restrict__ nxyz) {
    const int gw   = (blockIdx.x * blockDim.x + threadIdx.x) >> 5;
    const int lane = threadIdx.x & 31;
    if (gw >= B_TOT) return;
    const float* pb = pts + (size_t)gw * M1 * 3;
    const float px = pb[lane * 3 + 0], py = pb[lane * 3 + 1], pz = pb[lane * 3 + 2];
    float dist = 1e10f;
    if (lane == 0) {
        float* o = nxyz + (size_t)gw * M2 * 3;
        o[0] = px; o[1] = py; o[2] = pz;
    }
    int last = 0;
    for (int it = 1; it < M2; ++it) {
        const float cx = __shfl_sync(0xffffffffu, px, last);
        const float cy = __shfl_sync(0xffffffffu, py, last);
        const float cz = __shfl_sync(0xffffffffu, pz, last);
        float dx = __fsub_rn(px, cx), dy = __fsub_rn(py, cy), dz = __fsub_rn(pz, cz);
        float d  = __fadd_rn(__fadd_rn(__fmul_rn(dx, dx), __fmul_rn(dy, dy)),
                             __fmul_rn(dz, dz));
        dist = fminf(dist, d);
        float v = dist; int vi = lane;
        #pragma unroll
        for (int off = 16; off; off >>= 1) {
            float v2 = __shfl_xor_sync(0xffffffffu, v, off);
            int   i2 = __shfl_xor_sync(0xffffffffu, vi, off);
            if (v2 > v || (v2 == v && i2 < vi)) { v = v2; vi = i2; }
        }
        last = vi;
        if (lane == last) {
            float* o = nxyz + ((size_t)gw * M2 + it) * 3;
            o[0] = px; o[1] = py; o[2] = pz;
        }
    }
}

__global__ void __launch_bounds__(1024)
ball1_kernel(const float* __restrict__ x, const float* __restrict__ centers,
             int* __restrict__ out) {
    __shared__ float xs[N1], ys[N1], zs[N1];
    const int b = blockIdx.x, t = threadIdx.x;
    const float* p = x + ((size_t)b * N1 + t) * 6;
    xs[t] = p[0]; ys[t] = p[1]; zs[t] = p[2];
    __syncthreads();
    const int wid = t >> 5, lane = t & 31;
    const float* c = centers + ((size_t)b * M1 + wid) * 3;
    const float cx = c[0], cy = c[1], cz = c[2];
    const float cn = __fadd_rn(__fadd_rn(__fmul_rn(cx, cx), __fmul_rn(cy, cy)),
                               __fmul_rn(cz, cz));
    const float r2 = (float)(0.2 * 0.2);
    int* o = out + ((size_t)b * M1 + wid) * NSMP;
    int cnt = 0, first = -1;
    for (int base = 0; base < N1 && cnt < NSMP; base += 32) {
        const float px = xs[base + lane], py = ys[base + lane], pz = zs[base + lane];
        const float pn = __fadd_rn(__fadd_rn(__fmul_rn(px, px), __fmul_rn(py, py)),
                                   __fmul_rn(pz, pz));
        const float dt = __fadd_rn(__fadd_rn(__fmul_rn(cx, px), __fmul_rn(cy, py)),
                                   __fmul_rn(cz, pz));
        const float d2 = __fsub_rn(__fadd_rn(cn, pn), __fmul_rn(2.0f, dt));
        const bool hit = d2 < r2;
        const unsigned mask = __ballot_sync(0xffffffffu, hit);
        if (first < 0 && mask) first = base + __ffs(mask) - 1;
        const int pos = cnt + __popc(mask & ((1u << lane) - 1u));
        if (hit && pos < NSMP) o[pos] = base + lane;
        cnt += __popc(mask);
    }
    if (cnt > NSMP) cnt = NSMP;
    for (int k = cnt + lane; k < NSMP; k += 32) o[k] = first;
}

__global__ void __launch_bounds__(512)
ball2_kernel(const float* __restrict__ pts, const float* __restrict__ centers,
             int* __restrict__ out) {
    __shared__ float xs[M1], ys[M1], zs[M1];
    const int b = blockIdx.x, t = threadIdx.x;
    if (t < M1) {
        const float* p = pts + ((size_t)b * M1 + t) * 3;
        xs[t] = p[0]; ys[t] = p[1]; zs[t] = p[2];
    }
    __syncthreads();
    const int wid = t >> 5, lane = t & 31;
    const float* c = centers + ((size_t)b * M2 + wid) * 3;
    const float cx = c[0], cy = c[1], cz = c[2];
    const float cn = __fadd_rn(__fadd_rn(__fmul_rn(cx, cx), __fmul_rn(cy, cy)),
                               __fmul_rn(cz, cz));
    const float r2 = (float)(0.4 * 0.4);
    int* o = out + ((size_t)b * M2 + wid) * NSMP;
    const float px = xs[lane], py = ys[lane], pz = zs[lane];
    const float pn = __fadd_rn(__fadd_rn(__fmul_rn(px, px), __fmul_rn(py, py)),
                               __fmul_rn(pz, pz));
    const float dt = __fadd_rn(__fadd_rn(__fmul_rn(cx, px), __fmul_rn(cy, py)),
                               __fmul_rn(cz, pz));
    const float d2 = __fsub_rn(__fadd_rn(cn, pn), __fmul_rn(2.0f, dt));
    const bool hit = d2 < r2;
    const unsigned mask = __ballot_sync(0xffffffffu, hit);
    const int first = mask ? (__ffs(mask) - 1) : -1;
    const int pos = __popc(mask & ((1u << lane) - 1u));
    if (hit) o[pos] = lane;
    const int cnt = __popc(mask);
    for (int k = cnt + lane; k < NSMP; k += 32) o[k] = first;
}

// ---------------------------------------------------------------------------
// SA1: 4 centers/block (M=128). L0 scalar fp32 (w0 in smem); L1/L2 HMMA.
// All tile strides 144B (conflict-free ldmatrix).
// A1@0 (18432); A2@18432 (18432); B1@36864 (9216); B2@46080 (18432);
// w0s@64512 (1792); bias@66304 (768). part overlays A1.
// ---------------------------------------------------------------------------
#define S1_A1   0u
#define S1_A2   18432u
#define S1_B1   36864u
#define S1_B2   46080u
#define S1_W0   64512u
#define S1_BIAS 66304u
#define S1_SMEM 67072

__global__ void __launch_bounds__(256)
sa1m_kernel(const float* __restrict__ x, const float* __restrict__ nx1,
            const int* __restrict__ ball,
            const float* __restrict__ w0g, const float* __restrict__ b0g,
            const float* __restrict__ b1_, const float* __restrict__ b2_,
            float* __restrict__ out) {
    char* smem = (char*)dynsmem;
    const uint32_t su = smem_to_u32(smem);
    const int tid = threadIdx.x;
    const int wid = tid >> 5, lane = tid & 31;
    const int mrow = wid * 16;
    float* w0s  = (float*)(smem + S1_W0);
    float* bias = (float*)(smem + S1_BIAS);
    float* part = (float*)smem;          // overlays A1 (dead by then)
    const int bm0 = blockIdx.x * 4;
    const int b   = bm0 / M1;

    cp_copy(su + S1_B1, g_w11h, 9216);
    cp_copy(su + S1_B2, g_w12h, 18432);
    CP_COMMIT();

    for (int i = tid; i < 384; i += 256) w0s[i] = w0g[i];
    if (tid < 64)  { w0s[384 + tid] = b0g[tid]; bias[tid] = b1_[tid]; }
    if (tid < 128) bias[64 + tid] = b2_[tid];
    __syncthreads();

    // Gather + scalar L0 (fp32 exact): 2 threads per row, 32 cols each.
    {
        const int row = tid >> 1, seg = tid & 1;
        const int center = bm0 + (row >> 5);
        const int p = ball[center * NSMP + (row & 31)];
        const float* xr  = x + ((size_t)b * N1 + p) * 6;
        const float* ctr = nx1 + (size_t)center * 3;
        float in[6];
        #pragma unroll
        for (int k = 0; k < 6; ++k)
            in[k] = (k < 3) ? xr[k] - ctr[k] : xr[k];
        uint32_t* dh = (uint32_t*)(smem + S1_A1 + row * 144 + seg * 64);
        #pragma unroll 4
        for (int j = 0; j < 16; ++j) {
            const int c0 = seg * 32 + 2 * j;
            float a0 = w0s[384 + c0], a1 = w0s[384 + c0 + 1];
            #pragma unroll
            for (int k = 0; k < 6; ++k) {
                a0 = fmaf(in[k], w0s[k * 64 + c0], a0);
                a1 = fmaf(in[k], w0s[k * 64 + c0 + 1], a1);
            }
            dh[j] = pk2h(fmaxf(a0 * BNS_F, 0.0f), fmaxf(a1 * BNS_F, 0.0f));
        }
    }
    CP_WAIT0();
    __syncthreads();

    {   // L1: K=64 (4 ks), N=64
        float c[8][4];
        #pragma unroll
        for (int f = 0; f < 8; ++f)
            #pragma unroll
            for (int j = 0; j < 4; ++j) c[f][j] = 0.0f;
        gp_t<4, 4>(su + S1_A1, 144u, su + S1_B1, 144u, mrow, 0, lane, c);
        epi_t<4>(smem, S1_A2, 144u, bias, 0, c, mrow, lane);
    }
    __syncthreads();

    {   // L2: K=64, N=128 + fused max over 32 rows/center
        float c[16][4];
        #pragma unroll
        for (int f = 0; f < 16; ++f)
            #pragma unroll
            for (int j = 0; j < 4; ++j) c[f][j] = 0.0f;
        gp_t<4, 8>(su + S1_A2, 144u, su + S1_B2, 144u, mrow, 0, lane, c);
        __syncthreads();
        #pragma unroll
        for (int f = 0; f < 16; ++f) {
            float m0 = fmaxf(c[f][0], c[f][2]);
            float m1 = fmaxf(c[f][1], c[f][3]);
            #pragma unroll
            for (int off = 4; off <= 16; off <<= 1) {
                m0 = fmaxf(m0, __shfl_xor_sync(0xffffffffu, m0, off));
                m1 = fmaxf(m1, __shfl_xor_sync(0xffffffffu, m1, off));
            }
            if (lane < 4) {
                const int cc = (f >> 1) * 16 + (f & 1) * 8 + 2 * lane;
                part[wid * 128 + cc] = m0;
                part[wid * 128 + cc + 1] = m1;
            }
        }
        __syncthreads();
        for (int i = tid; i < 512; i += 256) {
            const int ci = i >> 7, n = i & 127;
            const float v = fmaxf(part[(2 * ci) * 128 + n],
                                  part[(2 * ci + 1) * 128 + n]);
            out[(size_t)(bm0 + ci) * 128 + n] =
                fmaxf((v + bias[64 + n]) * BNS_F, 0.0f);
        }
    }
}

// ---------------------------------------------------------------------------
// SA2: 4 centers/block (M=128), cp.async-prefetched fp16 weights (unchanged).
// ---------------------------------------------------------------------------
#define A2_A      0u
#define A2_B0     38912u
#define A2_B1     77824u
#define A2_BIAS   112640u
#define A2_PART   114688u
#define SA2M_SMEM 118784

__global__ void __launch_bounds__(256)
sa2m_kernel(const float* __restrict__ nx1, const float* __restrict__ f1,
            const float* __restrict__ nx2, const int* __restrict__ ball,
            const float* __restrict__ b0_, const float* __restrict__ b1_,
            const float* __restrict__ b2_, float* __restrict__ out) {
    char* smem = (char*)dynsmem;
    const uint32_t su = smem_to_u32(smem);
    const int tid = threadIdx.x;
    const int wid = tid >> 5, lane = tid & 31;
    const int mw  = wid * 16;
    float* bs = (float*)(smem + A2_BIAS);
    float* part = (float*)(smem + A2_PART);
    const int bm0 = blockIdx.x * 4;
    const int b   = bm0 / M2;

    cp_copy(su + A2_B0, g_w20h, 38912);
    CP_COMMIT();
    cp_copy(su + A2_B1, g_w21h, 34816);
    CP_COMMIT();

    if (tid < 128) { bs[tid] = b0_[tid]; bs[128 + tid] = b1_[tid]; }
    bs[256 + tid] = b2_[tid];

    {
        const int row = tid >> 1, seg = tid & 1;
        const int center = bm0 + (row >> 5);
        const int p = ball[center * NSMP + (row & 31)];
        const float* nx1r = nx1 + ((size_t)b * M1 + p) * 3;
        const float* ctr  = nx2 + (size_t)center * 3;
        const float* f1r  = f1 + ((size_t)b * M1 + p) * 128;
        #pragma unroll 1
        for (int i = 0; i < 36; ++i) {
            const int k = seg * 72 + 2 * i;
            float v0, v1;
            if (k < 3)        v0 = nx1r[k] - ctr[k];
            else if (k < 131) v0 = f1r[k - 3];
            else              v0 = 0.0f;
            const int k1 = k + 1;
            if (k1 < 3)        v1 = nx1r[k1] - ctr[k1];
            else if (k1 < 131) v1 = f1r[k1 - 3];
            else               v1 = 0.0f;
            *(uint32_t*)(smem + A2_A + (uint32_t)row * 304u + (uint32_t)k * 2u) =
                pk2h(v0, v1);
        }
    }
    CP_WAIT1();
    __syncthreads();

    float c[16][4];
    #pragma unroll
    for (int f = 0; f < 16; ++f)
        #pragma unroll
        for (int j = 0; j < 4; ++j) c[f][j] = 0.0f;
    gp_t<9, 8>(su + A2_A, 304u, su + A2_B0, 304u, mw, 0, lane, c);
    __syncthreads();
    cp_copy(su + A2_B0, g_w22h, 34816);
    CP_COMMIT();
    epi_t<8>(smem, A2_A, 272u, bs, 0, c, mw, lane);
    CP_WAIT1();
    __syncthreads();

    #pragma unroll
    for (int f = 0; f < 16; ++f)
        #pragma unroll
        for (int j = 0; j < 4; ++j) c[f][j] = 0.0f;
    gp_t<8, 8>(su + A2_A, 272u, su + A2_B1, 272u, mw, 0, lane, c);
    __syncthreads();
    cp_copy(su + A2_B1, g_w22h + 128 * 136, 34816);
    CP_COMMIT();
    epi_t<8>(smem, A2_A, 272u, bs + 128, 0, c, mw, lane);
    CP_WAIT1();
    __syncthreads();

    #pragma unroll 1
    for (int h = 0; h < 2; ++h) {
        const uint32_t bBase = h ? (su + A2_B1) : (su + A2_B0);
        #pragma unroll
        for (int f = 0; f < 16; ++f)
            #pragma unroll
            for (int j = 0; j < 4; ++j) c[f][j] = 0.0f;
        gp_t<8, 8>(su + A2_A, 272u, bBase, 272u, mw, 0, lane, c);
        #pragma unroll
        for (int f = 0; f < 16; ++f) {
            float m0 = fmaxf(c[f][0], c[f][2]);
            float m1 = fmaxf(c[f][1], c[f][3]);
            #pragma unroll
            for (int off = 4; off <= 16; off <<= 1) {
                m0 = fmaxf(m0, __shfl_xor_sync(0xffffffffu, m0, off));
                m1 = fmaxf(m1, __shfl_xor_sync(0xffffffffu, m1, off));
            }
            if (lane < 4) {
                const int cc = (f >> 1) * 16 + (f & 1) * 8 + 2 * lane;
                part[wid * 128 + cc] = m0;
                part[wid * 128 + cc + 1] = m1;
            }
        }
        __syncthreads();
        for (int i = tid; i < 512; i += 256) {
            const int ci = i >> 7, n = i & 127;
            const float v = fmaxf(part[(2 * ci) * 128 + n],
                                  part[(2 * ci + 1) * 128 + n]);
            out[(size_t)(bm0 + ci) * 256 + h * 128 + n] =
                fmaxf((v + bs[256 + h * 128 + n]) * BNS_F, 0.0f);
        }
        if (h == 0) CP_WAIT0();
        __syncthreads();
    }
}

// ---------------------------------------------------------------------------
// Head input gather (fp16).
// ---------------------------------------------------------------------------
__global__ void gather_a0_kernel(const float* __restrict__ nx2,
                                 const float* __restrict__ f2) {
    const int row = blockIdx.x * blockDim.x + threadIdx.x;
    if (row >= 32768) return;
    const float* nr = nx2 + (size_t)row * 3;
    const float* fr = f2 + (size_t)row * 256;
    uint32_t* dh = (uint32_t*)(g_a0 + (size_t)row * 288);
    #pragma unroll 4
    for (int j = 0; j < 144; ++j) {
        const int k = 2 * j;
        float v0, v1;
        if (k < 3)        v0 = nr[k];
        else if (k < 259) v0 = fr[k - 3];
        else              v0 = 0.0f;
        const int k1 = k + 1;
        if (k1 < 3)        v1 = nr[k1];
        else if (k1 < 259) v1 = fr[k1 - 3];
        else               v1 = 0.0f;
        dh[j] = pk2h(v0, v1);
    }
}

// ---------------------------------------------------------------------------
// Pipelined tiled GEMM (fp16): C[64 x 128], K chunked by 32, double-buffered.
// ---------------------------------------------------------------------------
#define GM_BUF  15360u
#define GM_BIAS 30720u
#define GM_SMEM 31232

__device__ __forceinline__ void gm_load(uint32_t bufBase,
                                        const __half* A, const __half* Bw,
                                        int Kpad, int Mbase, int Nbase, int kc) {
    const int tid = threadIdx.x;
    if (tid < 128) {
        const int row = tid >> 1, prt = tid & 1;
        const char* s = (const char*)(A + (size_t)(Mbase + row) * Kpad + kc * 32)
                        + prt * 32;
        const uint32_t d = bufBase + row * 80u + prt * 32u;
        CP_A16(d, s);
        CP_A16(d + 16, s + 16);
    }
    {
        const int row = tid >> 1, prt = tid & 1;
        const char* s = (const char*)(Bw + (size_t)(Nbase + row) * Kpad + kc * 32)
                        + prt * 32;
        const uint32_t d = bufBase + 5120u + row * 80u + prt * 32u;
        CP_A16(d, s);
        CP_A16(d + 16, s + 16);
    }
}

template <int MODE>
__global__ void __launch_bounds__(256, 2)
gemm_kernel(const __half* __restrict__ A, int Kpad, int KC,
            const __half* __restrict__ Bw,
            const float* __restrict__ biasG,
            __half* __restrict__ O, int KpadO,
            float* __restrict__ gout) {
    char* smem = (char*)dynsmem;
    const uint32_t su = smem_to_u32(smem);
    const int tid = threadIdx.x;
    const int wid = tid >> 5, lane = tid & 31;
    const int Mbase = blockIdx.x * 64;
    const int Nbase = blockIdx.y * 128;
    float* bias = (float*)(smem + GM_BIAS);

    gm_load(su, A, Bw, Kpad, Mbase, Nbase, 0);
    CP_COMMIT();
    if (tid < 128) bias[tid] = biasG[Nbase + tid];

    float c[8][4];
    #pragma unroll
    for (int f = 0; f < 8; ++f)
        #pragma unroll
        for (int j = 0; j < 4; ++j) c[f][j] = 0.0f;

    #pragma unroll 1
    for (int kc = 0; kc < KC; ++kc) {
        CP_WAIT0();
        __syncthreads();
        if (kc + 1 < KC) {
            gm_load(su + ((kc + 1) & 1) * GM_BUF, A, Bw, Kpad, Mbase, Nbase, kc + 1);
            CP_COMMIT();
        }
        const uint32_t buf = su + (kc & 1) * GM_BUF;
        gp_t<2, 4>(buf, 80u, buf + 5120u, 80u,
                   (wid & 3) * 16, (wid >> 2) * 64, lane, c);
    }

    if (MODE == 0) {
        const int r0 = Mbase + (wid & 3) * 16 + (lane >> 2);
        const int cb = (wid >> 2) * 64 + 2 * (lane & 3);
        #pragma unroll
        for (int f = 0; f < 8; ++f) {
            const int cl = cb + (f >> 1) * 16 + (f & 1) * 8;
            const int col = Nbase + cl;
            const float bv0 = bias[cl], bv1 = bias[cl + 1];
            const float v00 = fmaxf((c[f][0] + bv0) * BNS_F, 0.0f);
            const float v01 = fmaxf((c[f][1] + bv1) * BNS_F, 0.0f);
            const float v10 = fmaxf((c[f][2] + bv0) * BNS_F, 0.0f);
            const float v11 = fmaxf((c[f][3] + bv1) * BNS_F, 0.0f);
            *(uint32_t*)(O + (size_t)r0 * KpadO + col) = pk2h(v00, v01);
            *(uint32_t*)(O + (size_t)(r0 + 8) * KpadO + col) = pk2h(v10, v11);
        }
    } else {
        const int batch = blockIdx.x * 4 + (wid & 3);
        const int cb = (wid >> 2) * 64;
        #pragma unroll
        for (int f = 0; f < 8; ++f) {
            float m0 = fmaxf(c[f][0], c[f][2]);
            float m1 = fmaxf(c[f][1], c[f][3]);
            #pragma unroll
            for (int off = 4; off <= 16; off <<= 1) {
                m0 = fmaxf(m0, __shfl_xor_sync(0xffffffffu, m0, off));
                m1 = fmaxf(m1, __shfl_xor_sync(0xffffffffu, m1, off));
            }
            if (lane < 4) {
                const int cl = cb + (f >> 1) * 16 + (f & 1) * 8 + 2 * lane;
                const int col = Nbase + cl;
                gout[(size_t)batch * 768 + col] =
                    fmaxf((m0 + bias[cl]) * BNS_F, 0.0f);
                gout[(size_t)batch * 768 + col + 1] =
                    fmaxf((m1 + bias[cl + 1]) * BNS_F, 0.0f);
            }
        }
    }
}

// ---------------------------------------------------------------------------
// FC: 16 batches/block share fc_w loads.
// ---------------------------------------------------------------------------
__global__ void __launch_bounds__(192)
fc_kernel(const float* __restrict__ g_in, const float* __restrict__ fcw,
          const float* __restrict__ fcb, float* __restrict__ out) {
    constexpr int FCB = 16, C = 768, NT = 192;
    __shared__ float gs[FCB * C];
    const int b0 = blockIdx.x * FCB;
    for (int i = threadIdx.x; i < FCB * C; i += NT)
        gs[i] = g_in[(size_t)b0 * C + i];
    __syncthreads();
    const int og = threadIdx.x;
    const float4 bv = *reinterpret_cast<const float4*>(fcb + 4 * og);
    ull_t a01[FCB], a23[FCB];
    #pragma unroll
    for (int i = 0; i < FCB; ++i) { a01[i] = 0ull; a23[i] = 0ull; }
    const float* wp = fcw + 4 * og;
    #pragma unroll 2
    for (int k = 0; k < C; ++k) {
        const ulonglong2 wq =
            *reinterpret_cast<const ulonglong2*>(wp + (size_t)k * C);
        #pragma unroll
        for (int i = 0; i < FCB; ++i) {
            const ull_t hh = dup2(gs[i * C + k]);
            FMA2(a01[i], hh, wq.x, a01[i]);
            FMA2(a23[i], hh, wq.y, a23[i]);
        }
    }
    #pragma unroll
    for (int i = 0; i < FCB; ++i) {
        const float2 p0 = unpk(a01[i]);
        const float2 p1 = unpk(a23[i]);
        float4 r = make_float4(p0.x + bv.x, p0.y + bv.y, p1.x + bv.z, p1.y + bv.w);
        *reinterpret_cast<float4*>(out + (size_t)(b0 + i) * C + 4 * og) = r;
    }
}

// ---------------------------------------------------------------------------
// Host launcher
// ---------------------------------------------------------------------------
extern "C" void kernel_launch(void* const* d_in, const int* in_sizes, int n_in,
                              void* d_out, int out_size) {
    const float* x   = (const float*)d_in[0];
    const float* w10 = (const float*)d_in[1];  const float* b10 = (const float*)d_in[2];
    const float* w11 = (const float*)d_in[3];  const float* b11 = (const float*)d_in[4];
    const float* w12 = (const float*)d_in[5];  const float* b12 = (const float*)d_in[6];
    const float* w20 = (const float*)d_in[7];  const float* b20 = (const float*)d_in[8];
    const float* w21 = (const float*)d_in[9];  const float* b21 = (const float*)d_in[10];
    const float* w22 = (const float*)d_in[11]; const float* b22 = (const float*)d_in[12];
    const float* w30 = (const float*)d_in[13]; const float* b30 = (const float*)d_in[14];
    const float* w31 = (const float*)d_in[15]; const float* b31 = (const float*)d_in[16];
    const float* w32 = (const float*)d_in[17]; const float* b32 = (const float*)d_in[18];
    const float* fcw = (const float*)d_in[19]; const float* fcb = (const float*)d_in[20];
    float* out = (float*)d_out;

    int *ball1p, *ball2p;
    float *nx1p, *f1p, *nx2p, *f2p, *gp;
    __half *a0p, *h0p, *h1p, *w30hp, *w31hp, *w32hp;
    cudaGetSymbolAddress((void**)&nx1p,   g_nx1);
    cudaGetSymbolAddress((void**)&ball1p, g_ball1);
    cudaGetSymbolAddress((void**)&f1p,    g_f1);
    cudaGetSymbolAddress((void**)&nx2p,   g_nx2);
    cudaGetSymbolAddress((void**)&ball2p, g_ball2);
    cudaGetSymbolAddress((void**)&f2p,    g_f2);
    cudaGetSymbolAddress((void**)&gp,     g_g);
    cudaGetSymbolAddress((void**)&a0p,    g_a0);
    cudaGetSymbolAddress((void**)&h0p,    g_h0);
    cudaGetSymbolAddress((void**)&h1p,    g_h1);
    cudaGetSymbolAddress((void**)&w30hp,  g_w30h);
    cudaGetSymbolAddress((void**)&w31hp,  g_w31h);
    cudaGetSymbolAddress((void**)&w32hp,  g_w32h);

    cudaFuncSetAttribute(sa1m_kernel, cudaFuncAttributeMaxDynamicSharedMemorySize, S1_SMEM);
    cudaFuncSetAttribute(sa2m_kernel, cudaFuncAttributeMaxDynamicSharedMemorySize, SA2M_SMEM);
    cudaFuncSetAttribute(gemm_kernel<0>, cudaFuncAttributeMaxDynamicSharedMemorySize, GM_SMEM);
    cudaFuncSetAttribute(gemm_kernel<1>, cudaFuncAttributeMaxDynamicSharedMemorySize, GM_SMEM);

    // 1: weight prep
    prep_all_kernel<<<1024, 256>>>(w11, w12, w20, w21, w22, w30, w31, w32);
    // 2-3: FPS1 + ball1
    fps1_kernel<<<B_TOT, 512>>>(x, nx1p);
    ball1_kernel<<<B_TOT, 1024>>>(x, nx1p, ball1p);
    // 4: SA1
    sa1m_kernel<<<B_TOT * M1 / 4, 256, S1_SMEM>>>(x, nx1p, ball1p,
                                                  w10, b10, b11, b12, f1p);
    // 5-7: FPS2 + ball2 + SA2
    fps2_kernel<<<(B_TOT * 32 + 127) / 128, 128>>>(nx1p, nx2p);
    ball2_kernel<<<B_TOT, 512>>>(nx1p, nx2p, ball2p);
    sa2m_kernel<<<B_TOT * M2 / 4, 256, SA2M_SMEM>>>(nx1p, f1p, nx2p, ball2p,
                                                    b20, b21, b22, f2p);
    // 8: head input gather
    gather_a0_kernel<<<32768 / 256, 256>>>(nx2p, f2p);
    // 9-11: head GEMMs
    gemm_kernel<0><<<dim3(512, 2), 256, GM_SMEM>>>(
        a0p, 288, 9, w30hp, b30, h0p, 256, nullptr);
    gemm_kernel<0><<<dim3(512, 4), 256, GM_SMEM>>>(
        h0p, 256, 8, w31hp, b31, h1p, 512, nullptr);
    gemm_kernel<1><<<dim3(512, 6), 256, GM_SMEM>>>(
        h1p, 512, 16, w32hp, b32, nullptr, 0, gp);
    // 12: FC
    fc_kernel<<<B_TOT / 16, 192>>>(gp, fcw, fcb, out);
}

// round 15
// speedup vs baseline: 2.7927x; 1.0570x over previous
#include <cuda_runtime.h>
#include <cuda_fp16.h>
#include <math.h>
#include <stdint.h>

// ---------------------------------------------------------------------------
// PointNet++ encoder forward. B=2048 clouds, N=1024 pts, 6 ch.
// MLP stages on HMMA fp16 (fp32 accum). Index paths exact fp32.
// R15: sa1m L0 moved onto HMMA (K=16, 48B conflict-free stride).
// ---------------------------------------------------------------------------

#define B_TOT 2048
#define N1    1024
#define M1    32
#define M2    16
#define NSMP  32

__device__ float g_nx1  [B_TOT * M1 * 3];
__device__ int   g_ball1[B_TOT * M1 * NSMP];
__device__ float g_f1   [B_TOT * M1 * 128];
__device__ float g_nx2  [B_TOT * M2 * 3];
__device__ int   g_ball2[B_TOT * M2 * NSMP];
__device__ float g_f2   [B_TOT * M2 * 256];
__device__ float g_g    [B_TOT * 768];

// Weights: [N][Kpad] fp16.
__device__ __align__(16) __half g_w10h[64 * 24];
__device__ __align__(16) __half g_w11h[64 * 72];
__device__ __align__(16) __half g_w12h[128 * 72];
__device__ __align__(16) __half g_w20h[128 * 152];
__device__ __align__(16) __half g_w21h[128 * 136];
__device__ __align__(16) __half g_w22h[256 * 136];
__device__ __align__(16) __half g_w30h[256 * 288];
__device__ __align__(16) __half g_w31h[512 * 256];
__device__ __align__(16) __half g_w32h[768 * 512];

// Head activations, [32768 rows][Kpad] fp16.
__device__ __align__(16) __half g_a0[32768 * 288];
__device__ __align__(16) __half g_h0[32768 * 256];
__device__ __align__(16) __half g_h1[32768 * 512];

// ---- packed f32x2 helpers (FC kernel) ----------------------------------------
typedef unsigned long long ull_t;
__device__ __forceinline__ ull_t dup2(float v) {
    ull_t r; unsigned u = __float_as_uint(v);
    asm("mov.b64 %0, {%1, %1};" : "=l"(r) : "r"(u));
    return r;
}
__device__ __forceinline__ float2 unpk(ull_t p) {
    unsigned lo, hi;
    asm("mov.b64 {%0, %1}, %2;" : "=r"(lo), "=r"(hi) : "l"(p));
    return make_float2(__uint_as_float(lo), __uint_as_float(hi));
}
#define FMA2(d, a, b, c) \
    asm("fma.rn.f32x2 %0, %1, %2, %3;" : "=l"(d) : "l"(a), "l"(b), "l"(c))

#define BNS_F 0.99999500003749968f   // 1/sqrt(1+1e-5)

// ---- mma.sync / ldmatrix / cp.async helpers ----------------------------------
__device__ __forceinline__ uint32_t smem_to_u32(const void* p) {
    uint32_t a;
    asm("{ .reg .u64 t; cvta.to.shared.u64 t, %1; cvt.u32.u64 %0, t; }"
        : "=r"(a) : "l"(p));
    return a;
}
#define LDSM4(r, a) \
    asm volatile("ldmatrix.sync.aligned.m8n8.x4.shared.b16 {%0,%1,%2,%3}, [%4];" \
                 : "=r"((r)[0]), "=r"((r)[1]), "=r"((r)[2]), "=r"((r)[3]) : "r"(a))

__device__ __forceinline__ void mma_f16(float* c, const uint32_t* a,
                                        const uint32_t* b) {
    asm volatile(
        "mma.sync.aligned.m16n8k16.row.col.f32.f16.f16.f32 "
        "{%0,%1,%2,%3}, {%4,%5,%6,%7}, {%8,%9}, {%0,%1,%2,%3};"
        : "+f"(c[0]), "+f"(c[1]), "+f"(c[2]), "+f"(c[3])
        : "r"(a[0]), "r"(a[1]), "r"(a[2]), "r"(a[3]), "r"(b[0]), "r"(b[1]));
}

#define CP_A16(dst, src) \
    asm volatile("cp.async.cg.shared.global [%0], [%1], 16;" \
                 :: "r"(dst), "l"(src) : "memory")
#define CP_COMMIT() asm volatile("cp.async.commit_group;" ::: "memory")
#define CP_WAIT0()  asm volatile("cp.async.wait_group 0;" ::: "memory")
#define CP_WAIT1()  asm volatile("cp.async.wait_group 1;" ::: "memory")

__device__ __forceinline__ void cp_copy(uint32_t dst, const void* src, int bytes) {
    const char* s = (const char*)src;
    for (int i = threadIdx.x * 16; i < bytes; i += 256 * 16)
        CP_A16(dst + i, s + i);
}

__device__ __forceinline__ uint32_t pk2h(float v0, float v1) {
    __half2 h = __floats2half2_rn(v0, v1);
    return *(const uint32_t*)&h;
}

extern __shared__ float dynsmem[];

// fp16 GEMM pass.
template <int KS, int PN>
__device__ __forceinline__ void gp_t(uint32_t aBase, uint32_t aStride,
                                     uint32_t bBase, uint32_t bStride,
                                     int mrow, int nbase, int lane,
                                     float (&c)[2 * PN][4]) {
    const uint32_t aAddr = aBase + (uint32_t)(mrow + (lane & 15)) * aStride +
                           (uint32_t)((lane >> 4) << 4);
    const uint32_t nrow  = (lane & 7) + ((lane >> 4) << 3);
    const uint32_t kcolB = ((lane >> 3) & 1) << 4;
    const uint32_t bAddr = bBase + (uint32_t)(nbase + nrow) * bStride + kcolB;
    #pragma unroll 1
    for (int ks = 0; ks < KS; ++ks) {
        uint32_t ah[4];
        LDSM4(ah, aAddr + ks * 32);
        #pragma unroll
        for (int p = 0; p < PN; ++p) {
            uint32_t bh[4];
            LDSM4(bh, bAddr + (uint32_t)p * 16u * bStride + ks * 32);
            mma_f16(c[2*p],   ah, bh);
            mma_f16(c[2*p+1], ah, bh + 2);
        }
    }
}

// Epilogue into smem (bias+BNS+relu, fp16).
template <int PN>
__device__ __forceinline__ void epi_t(char* smem, uint32_t outOff,
                                      uint32_t outStride, const float* bias, int cbase,
                                      float (&c)[2 * PN][4], int mrow, int lane) {
    const int r0  = mrow + (lane >> 2);
    const int ccb = 2 * (lane & 3);
    #pragma unroll
    for (int f = 0; f < 2 * PN; ++f) {
        const int col = cbase + (f >> 1) * 16 + (f & 1) * 8 + ccb;
        const float bv0 = bias[col], bv1 = bias[col + 1];
        const float v00 = fmaxf((c[f][0] + bv0) * BNS_F, 0.0f);
        const float v01 = fmaxf((c[f][1] + bv1) * BNS_F, 0.0f);
        const float v10 = fmaxf((c[f][2] + bv0) * BNS_F, 0.0f);
        const float v11 = fmaxf((c[f][3] + bv1) * BNS_F, 0.0f);
        const uint32_t o0 = outOff + (uint32_t)r0 * outStride + (uint32_t)col * 2u;
        const uint32_t o1 = o0 + 8u * outStride;
        *(uint32_t*)(smem + o0) = pk2h(v00, v01);
        *(uint32_t*)(smem + o1) = pk2h(v10, v11);
    }
}

// ---------------------------------------------------------------------------
// Merged weight prep.
// ---------------------------------------------------------------------------
__device__ __forceinline__ void prep_one(const float* w, __half* out,
                                         int idx, int Cin, int Cout, int Kpad) {
    const int n = idx / Kpad, kp = idx % Kpad;
    const float v = (kp < Cin) ? w[(size_t)kp * Cout + n] : 0.0f;
    out[idx] = __float2half_rn(v);
}

__global__ void prep_all_kernel(const float* w10,
                                const float* w11, const float* w12,
                                const float* w20, const float* w21, const float* w22,
                                const float* w30, const float* w31, const float* w32) {
    const int s0 = 64*24, s1 = 64*72, s2 = 128*72, s3 = 128*152, s4 = 128*136,
              s5 = 256*136, s6 = 256*288, s7 = 512*256, s8 = 768*512;
    const int total = s0+s1+s2+s3+s4+s5+s6+s7+s8;
    for (int i = blockIdx.x * blockDim.x + threadIdx.x; i < total;
         i += gridDim.x * blockDim.x) {
        int idx = i;
        if (idx < s0) { prep_one(w10, g_w10h, idx, 6, 64, 24); continue; }   idx -= s0;
        if (idx < s1) { prep_one(w11, g_w11h, idx, 64, 64, 72); continue; }  idx -= s1;
        if (idx < s2) { prep_one(w12, g_w12h, idx, 64, 128, 72); continue; } idx -= s2;
        if (idx < s3) { prep_one(w20, g_w20h, idx, 131, 128, 152); continue; } idx -= s3;
        if (idx < s4) { prep_one(w21, g_w21h, idx, 128, 128, 136); continue; } idx -= s4;
        if (idx < s5) { prep_one(w22, g_w22h, idx, 128, 256, 136); continue; } idx -= s5;
        if (idx < s6) { prep_one(w30, g_w30h, idx, 259, 256, 288); continue; } idx -= s6;
        if (idx < s7) { prep_one(w31, g_w31h, idx, 256, 512, 256); continue; } idx -= s7;
        prep_one(w32, g_w32h, idx, 512, 768, 512);
    }
}

// ---------------------------------------------------------------------------
// FPS stage 1 (512 thr, 2 pts/thread), FPS stage 2, ball1/ball2 (unchanged).
// ---------------------------------------------------------------------------
__global__ void __launch_bounds__(512)
fps1_kernel(const float* __restrict__ x, float* __restrict__ nxyz) {
    __shared__ float swv[16];
    __shared__ int   swi[16];
    __shared__ float cur[3];
    const int b = blockIdx.x;
    const int t = threadIdx.x;
    const int warp = t >> 5, lane = t & 31;
    const float* p0 = x + ((size_t)b * N1 + t) * 6;
    const float* p1 = p0 + 512 * 6;
    const float px0 = p0[0], py0 = p0[1], pz0 = p0[2];
    const float px1 = p1[0], py1 = p1[1], pz1 = p1[2];
    float d0 = 1e10f, d1 = 1e10f;
    if (t == 0) {
        float* o = nxyz + (size_t)b * M1 * 3;
        o[0] = px0; o[1] = py0; o[2] = pz0;
    }
    int last = 0;
    for (int it = 1; it < M1; ++it) {
        if (t == (last & 511)) {
            if (last < 512) { cur[0] = px0; cur[1] = py0; cur[2] = pz0; }
            else            { cur[0] = px1; cur[1] = py1; cur[2] = pz1; }
        }
        __syncthreads();
        const float cx = cur[0], cy = cur[1], cz = cur[2];
        {
            float dx = __fsub_rn(px0, cx), dy = __fsub_rn(py0, cy),
                  dz = __fsub_rn(pz0, cz);
            d0 = fminf(d0, __fadd_rn(__fadd_rn(__fmul_rn(dx, dx), __fmul_rn(dy, dy)),
                                     __fmul_rn(dz, dz)));
        }
        {
            float dx = __fsub_rn(px1, cx), dy = __fsub_rn(py1, cy),
                  dz = __fsub_rn(pz1, cz);
            d1 = fminf(d1, __fadd_rn(__fadd_rn(__fmul_rn(dx, dx), __fmul_rn(dy, dy)),
                                     __fmul_rn(dz, dz)));
        }
        float v; int vi;
        if (d0 >= d1) { v = d0; vi = t; } else { v = d1; vi = t + 512; }
        #pragma unroll
        for (int off = 16; off; off >>= 1) {
            float v2 = __shfl_xor_sync(0xffffffffu, v, off);
            int   i2 = __shfl_xor_sync(0xffffffffu, vi, off);
            if (v2 > v || (v2 == v && i2 < vi)) { v = v2; vi = i2; }
        }
        if (lane == 0) { swv[warp] = v; swi[warp] = vi; }
        __syncthreads();
        float wv = (lane < 16) ? swv[lane] : -1.0e30f;
        int   wi = (lane < 16) ? swi[lane] : 0x7fffffff;
        #pragma unroll
        for (int off = 16; off; off >>= 1) {
            float v2 = __shfl_xor_sync(0xffffffffu, wv, off);
            int   i2 = __shfl_xor_sync(0xffffffffu, wi, off);
            if (v2 > wv || (v2 == wv && i2 < wi)) { wv = v2; wi = i2; }
        }
        last = wi;
        if (t == (last & 511)) {
            float* o = nxyz + ((size_t)b * M1 + it) * 3;
            if (last < 512) { o[0] = px0; o[1] = py0; o[2] = pz0; }
            else            { o[0] = px1; o[1] = py1; o[2] = pz1; }
        }
    }
}

__global__ void fps2_kernel(const float* __restrict__ pts,
                            float* __restrict__ nxyz) {
    const int gw   = (blockIdx.x * blockDim.x + threadIdx.x) >> 5;
    const int lane = threadIdx.x & 31;
    if (gw >= B_TOT) return;
    const float* pb = pts + (size_t)gw * M1 * 3;
    const float px = pb[lane * 3 + 0], py = pb[lane * 3 + 1], pz = pb[lane * 3 + 2];
    float dist = 1e10f;
    if (lane == 0) {
        float* o = nxyz + (size_t)gw * M2 * 3;
        o[0] = px; o[1] = py; o[2] = pz;
    }
    int last = 0;
    for (int it = 1; it < M2; ++it) {
        const float cx = __shfl_sync(0xffffffffu, px, last);
        const float cy = __shfl_sync(0xffffffffu, py, last);
        const float cz = __shfl_sync(0xffffffffu, pz, last);
        float dx = __fsub_rn(px, cx), dy = __fsub_rn(py, cy), dz = __fsub_rn(pz, cz);
        float d  = __fadd_rn(__fadd_rn(__fmul_rn(dx, dx), __fmul_rn(dy, dy)),
                             __fmul_rn(dz, dz));
        dist = fminf(dist, d);
        float v = dist; int vi = lane;
        #pragma unroll
        for (int off = 16; off; off >>= 1) {
            float v2 = __shfl_xor_sync(0xffffffffu, v, off);
            int   i2 = __shfl_xor_sync(0xffffffffu, vi, off);
            if (v2 > v || (v2 == v && i2 < vi)) { v = v2; vi = i2; }
        }
        last = vi;
        if (lane == last) {
            float* o = nxyz + ((size_t)gw * M2 + it) * 3;
            o[0] = px; o[1] = py; o[2] = pz;
        }
    }
}

__global__ void __launch_bounds__(1024)
ball1_kernel(const float* __restrict__ x, const float* __restrict__ centers,
             int* __restrict__ out) {
    __shared__ float xs[N1], ys[N1], zs[N1];
    const int b = blockIdx.x, t = threadIdx.x;
    const float* p = x + ((size_t)b * N1 + t) * 6;
    xs[t] = p[0]; ys[t] = p[1]; zs[t] = p[2];
    __syncthreads();
    const int wid = t >> 5, lane = t & 31;
    const float* c = centers + ((size_t)b * M1 + wid) * 3;
    const float cx = c[0], cy = c[1], cz = c[2];
    const float cn = __fadd_rn(__fadd_rn(__fmul_rn(cx, cx), __fmul_rn(cy, cy)),
                               __fmul_rn(cz, cz));
    const float r2 = (float)(0.2 * 0.2);
    int* o = out + ((size_t)b * M1 + wid) * NSMP;
    int cnt = 0, first = -1;
    for (int base = 0; base < N1 && cnt < NSMP; base += 32) {
        const float px = xs[base + lane], py = ys[base + lane], pz = zs[base + lane];
        const float pn = __fadd_rn(__fadd_rn(__fmul_rn(px, px), __fmul_rn(py, py)),
                                   __fmul_rn(pz, pz));
        const float dt = __fadd_rn(__fadd_rn(__fmul_rn(cx, px), __fmul_rn(cy, py)),
                                   __fmul_rn(cz, pz));
        const float d2 = __fsub_rn(__fadd_rn(cn, pn), __fmul_rn(2.0f, dt));
        const bool hit = d2 < r2;
        const unsigned mask = __ballot_sync(0xffffffffu, hit);
        if (first < 0 && mask) first = base + __ffs(mask) - 1;
        const int pos = cnt + __popc(mask & ((1u << lane) - 1u));
        if (hit && pos < NSMP) o[pos] = base + lane;
        cnt += __popc(mask);
    }
    if (cnt > NSMP) cnt = NSMP;
    for (int k = cnt + lane; k < NSMP; k += 32) o[k] = first;
}

__global__ void __launch_bounds__(512)
ball2_kernel(const float* __restrict__ pts, const float* __restrict__ centers,
             int* __restrict__ out) {
    __shared__ float xs[M1], ys[M1], zs[M1];
    const int b = blockIdx.x, t = threadIdx.x;
    if (t < M1) {
        const float* p = pts + ((size_t)b * M1 + t) * 3;
        xs[t] = p[0]; ys[t] = p[1]; zs[t] = p[2];
    }
    __syncthreads();
    const int wid = t >> 5, lane = t & 31;
    const float* c = centers + ((size_t)b * M2 + wid) * 3;
    const float cx = c[0], cy = c[1], cz = c[2];
    const float cn = __fadd_rn(__fadd_rn(__fmul_rn(cx, cx), __fmul_rn(cy, cy)),
                               __fmul_rn(cz, cz));
    const float r2 = (float)(0.4 * 0.4);
    int* o = out + ((size_t)b * M2 + wid) * NSMP;
    const float px = xs[lane], py = ys[lane], pz = zs[lane];
    const float pn = __fadd_rn(__fadd_rn(__fmul_rn(px, px), __fmul_rn(py, py)),
                               __fmul_rn(pz, pz));
    const float dt = __fadd_rn(__fadd_rn(__fmul_rn(cx, px), __fmul_rn(cy, py)),
                               __fmul_rn(cz, pz));
    const float d2 = __fsub_rn(__fadd_rn(cn, pn), __fmul_rn(2.0f, dt));
    const bool hit = d2 < r2;
    const unsigned mask = __ballot_sync(0xffffffffu, hit);
    const int first = mask ? (__ffs(mask) - 1) : -1;
    const int pos = __popc(mask & ((1u << lane) - 1u));
    if (hit) o[pos] = lane;
    const int cnt = __popc(mask);
    for (int k = cnt + lane; k < NSMP; k += 32) o[k] = first;
}

// ---------------------------------------------------------------------------
// SA1: 4 centers/block (M=128), all 3 layers HMMA.
// A0@0 (48B str, 6144); A1@6144 (144B str, 18432); A2@24576 (18432);
// B0@43008 (3072); B1@46080 (9216); B2@55296 (18432); bias@73728 (1024).
// part overlays A0/A1.
// ---------------------------------------------------------------------------
#define S1_A0   0u
#define S1_A1   6144u
#define S1_A2   24576u
#define S1_B0   43008u
#define S1_B1   46080u
#define S1_B2   55296u
#define S1_BIAS 73728u
#define S1_SMEM 74752

__global__ void __launch_bounds__(256)
sa1m_kernel(const float* __restrict__ x, const float* __restrict__ nx1,
            const int* __restrict__ ball,
            const float* __restrict__ b0_, const float* __restrict__ b1_,
            const float* __restrict__ b2_, float* __restrict__ out) {
    char* smem = (char*)dynsmem;
    const uint32_t su = smem_to_u32(smem);
    const int tid = threadIdx.x;
    const int wid = tid >> 5, lane = tid & 31;
    const int mrow = wid * 16;
    float* bias = (float*)(smem + S1_BIAS);
    float* part = (float*)smem;          // overlays A0/A1 (dead by then)
    const int bm0 = blockIdx.x * 4;
    const int b   = bm0 / M1;

    cp_copy(su + S1_B0, g_w10h, 3072);
    cp_copy(su + S1_B1, g_w11h, 9216);
    cp_copy(su + S1_B2, g_w12h, 18432);
    CP_COMMIT();

    if (tid < 64)  { bias[tid] = b0_[tid]; bias[64 + tid] = b1_[tid]; }
    if (tid < 128) bias[128 + tid] = b2_[tid];

    // Gather A0: 128 rows x 24 cols (6 real), fp16, stride 48B.
    if (tid < 128) {
        const int row = tid;
        const int center = bm0 + (row >> 5);
        const int p = ball[center * NSMP + (row & 31)];
        const float* xr  = x + ((size_t)b * N1 + p) * 6;
        const float* ctr = nx1 + (size_t)center * 3;
        float in[6];
        #pragma unroll
        for (int k = 0; k < 6; ++k)
            in[k] = (k < 3) ? xr[k] - ctr[k] : xr[k];
        uint32_t* d = (uint32_t*)(smem + S1_A0 + row * 48);
        d[0] = pk2h(in[0], in[1]);
        d[1] = pk2h(in[2], in[3]);
        d[2] = pk2h(in[4], in[5]);
        #pragma unroll
        for (int j = 3; j < 12; ++j) d[j] = 0u;
    }
    CP_WAIT0();
    __syncthreads();

    {   // L0: K=16 (1 ks), N=64
        float c[8][4];
        #pragma unroll
        for (int f = 0; f < 8; ++f)
            #pragma unroll
            for (int j = 0; j < 4; ++j) c[f][j] = 0.0f;
        gp_t<1, 4>(su + S1_A0, 48u, su + S1_B0, 48u, mrow, 0, lane, c);
        epi_t<4>(smem, S1_A1, 144u, bias, 0, c, mrow, lane);
    }
    __syncthreads();

    {   // L1: K=64 (4 ks), N=64
        float c[8][4];
        #pragma unroll
        for (int f = 0; f < 8; ++f)
            #pragma unroll
            for (int j = 0; j < 4; ++j) c[f][j] = 0.0f;
        gp_t<4, 4>(su + S1_A1, 144u, su + S1_B1, 144u, mrow, 0, lane, c);
        epi_t<4>(smem, S1_A2, 144u, bias + 64, 0, c, mrow, lane);
    }
    __syncthreads();

    {   // L2: K=64, N=128 + fused max over 32 rows/center
        float c[16][4];
        #pragma unroll
        for (int f = 0; f < 16; ++f)
            #pragma unroll
            for (int j = 0; j < 4; ++j) c[f][j] = 0.0f;
        gp_t<4, 8>(su + S1_A2, 144u, su + S1_B2, 144u, mrow, 0, lane, c);
        __syncthreads();   // A0/A1 region now reused as part[]
        #pragma unroll
        for (int f = 0; f < 16; ++f) {
            float m0 = fmaxf(c[f][0], c[f][2]);
            float m1 = fmaxf(c[f][1], c[f][3]);
            #pragma unroll
            for (int off = 4; off <= 16; off <<= 1) {
                m0 = fmaxf(m0, __shfl_xor_sync(0xffffffffu, m0, off));
                m1 = fmaxf(m1, __shfl_xor_sync(0xffffffffu, m1, off));
            }
            if (lane < 4) {
                const int cc = (f >> 1) * 16 + (f & 1) * 8 + 2 * lane;
                part[wid * 128 + cc] = m0;
                part[wid * 128 + cc + 1] = m1;
            }
        }
        __syncthreads();
        for (int i = tid; i < 512; i += 256) {
            const int ci = i >> 7, n = i & 127;
            const float v = fmaxf(part[(2 * ci) * 128 + n],
                                  part[(2 * ci + 1) * 128 + n]);
            out[(size_t)(bm0 + ci) * 128 + n] =
                fmaxf((v + bias[128 + n]) * BNS_F, 0.0f);
        }
    }
}

// ---------------------------------------------------------------------------
// SA2: 4 centers/block (M=128), cp.async-prefetched fp16 weights (unchanged).
// ---------------------------------------------------------------------------
#define A2_A      0u
#define A2_B0     38912u
#define A2_B1     77824u
#define A2_BIAS   112640u
#define A2_PART   114688u
#define SA2M_SMEM 118784

__global__ void __launch_bounds__(256)
sa2m_kernel(const float* __restrict__ nx1, const float* __restrict__ f1,
            const float* __restrict__ nx2, const int* __restrict__ ball,
            const float* __restrict__ b0_, const float* __restrict__ b1_,
            const float* __restrict__ b2_, float* __restrict__ out) {
    char* smem = (char*)dynsmem;
    const uint32_t su = smem_to_u32(smem);
    const int tid = threadIdx.x;
    const int wid = tid >> 5, lane = tid & 31;
    const int mw  = wid * 16;
    float* bs = (float*)(smem + A2_BIAS);
    float* part = (float*)(smem + A2_PART);
    const int bm0 = blockIdx.x * 4;
    const int b   = bm0 / M2;

    cp_copy(su + A2_B0, g_w20h, 38912);
    CP_COMMIT();
    cp_copy(su + A2_B1, g_w21h, 34816);
    CP_COMMIT();

    if (tid < 128) { bs[tid] = b0_[tid]; bs[128 + tid] = b1_[tid]; }
    bs[256 + tid] = b2_[tid];

    {
        const int row = tid >> 1, seg = tid & 1;
        const int center = bm0 + (row >> 5);
        const int p = ball[center * NSMP + (row & 31)];
        const float* nx1r = nx1 + ((size_t)b * M1 + p) * 3;
        const float* ctr  = nx2 + (size_t)center * 3;
        const float* f1r  = f1 + ((size_t)b * M1 + p) * 128;
        #pragma unroll 1
        for (int i = 0; i < 36; ++i) {
            const int k = seg * 72 + 2 * i;
            float v0, v1;
            if (k < 3)        v0 = nx1r[k] - ctr[k];
            else if (k < 131) v0 = f1r[k - 3];
            else              v0 = 0.0f;
            const int k1 = k + 1;
            if (k1 < 3)        v1 = nx1r[k1] - ctr[k1];
            else if (k1 < 131) v1 = f1r[k1 - 3];
            else               v1 = 0.0f;
            *(uint32_t*)(smem + A2_A + (uint32_t)row * 304u + (uint32_t)k * 2u) =
                pk2h(v0, v1);
        }
    }
    CP_WAIT1();
    __syncthreads();

    float c[16][4];
    #pragma unroll
    for (int f = 0; f < 16; ++f)
        #pragma unroll
        for (int j = 0; j < 4; ++j) c[f][j] = 0.0f;
    gp_t<9, 8>(su + A2_A, 304u, su + A2_B0, 304u, mw, 0, lane, c);
    __syncthreads();
    cp_copy(su + A2_B0, g_w22h, 34816);
    CP_COMMIT();
    epi_t<8>(smem, A2_A, 272u, bs, 0, c, mw, lane);
    CP_WAIT1();
    __syncthreads();

    #pragma unroll
    for (int f = 0; f < 16; ++f)
        #pragma unroll
        for (int j = 0; j < 4; ++j) c[f][j] = 0.0f;
    gp_t<8, 8>(su + A2_A, 272u, su + A2_B1, 272u, mw, 0, lane, c);
    __syncthreads();
    cp_copy(su + A2_B1, g_w22h + 128 * 136, 34816);
    CP_COMMIT();
    epi_t<8>(smem, A2_A, 272u, bs + 128, 0, c, mw, lane);
    CP_WAIT1();
    __syncthreads();

    #pragma unroll 1
    for (int h = 0; h < 2; ++h) {
        const uint32_t bBase = h ? (su + A2_B1) : (su + A2_B0);
        #pragma unroll
        for (int f = 0; f < 16; ++f)
            #pragma unroll
            for (int j = 0; j < 4; ++j) c[f][j] = 0.0f;
        gp_t<8, 8>(su + A2_A, 272u, bBase, 272u, mw, 0, lane, c);
        #pragma unroll
        for (int f = 0; f < 16; ++f) {
            float m0 = fmaxf(c[f][0], c[f][2]);
            float m1 = fmaxf(c[f][1], c[f][3]);
            #pragma unroll
            for (int off = 4; off <= 16; off <<= 1) {
                m0 = fmaxf(m0, __shfl_xor_sync(0xffffffffu, m0, off));
                m1 = fmaxf(m1, __shfl_xor_sync(0xffffffffu, m1, off));
            }
            if (lane < 4) {
                const int cc = (f >> 1) * 16 + (f & 1) * 8 + 2 * lane;
                part[wid * 128 + cc] = m0;
                part[wid * 128 + cc + 1] = m1;
            }
        }
        __syncthreads();
        for (int i = tid; i < 512; i += 256) {
            const int ci = i >> 7, n = i & 127;
            const float v = fmaxf(part[(2 * ci) * 128 + n],
                                  part[(2 * ci + 1) * 128 + n]);
            out[(size_t)(bm0 + ci) * 256 + h * 128 + n] =
                fmaxf((v + bs[256 + h * 128 + n]) * BNS_F, 0.0f);
        }
        if (h == 0) CP_WAIT0();
        __syncthreads();
    }
}

// ---------------------------------------------------------------------------
// Head input gather (fp16).
// ---------------------------------------------------------------------------
__global__ void gather_a0_kernel(const float* __restrict__ nx2,
                                 const float* __restrict__ f2) {
    const int row = blockIdx.x * blockDim.x + threadIdx.x;
    if (row >= 32768) return;
    const float* nr = nx2 + (size_t)row * 3;
    const float* fr = f2 + (size_t)row * 256;
    uint32_t* dh = (uint32_t*)(g_a0 + (size_t)row * 288);
    #pragma unroll 4
    for (int j = 0; j < 144; ++j) {
        const int k = 2 * j;
        float v0, v1;
        if (k < 3)        v0 = nr[k];
        else if (k < 259) v0 = fr[k - 3];
        else              v0 = 0.0f;
        const int k1 = k + 1;
        if (k1 < 3)        v1 = nr[k1];
        else if (k1 < 259) v1 = fr[k1 - 3];
        else               v1 = 0.0f;
        dh[j] = pk2h(v0, v1);
    }
}

// ---------------------------------------------------------------------------
// Pipelined tiled GEMM (fp16): C[64 x 128], K chunked by 32, double-buffered.
// ---------------------------------------------------------------------------
#define GM_BUF  15360u
#define GM_BIAS 30720u
#define GM_SMEM 31232

__device__ __forceinline__ void gm_load(uint32_t bufBase,
                                        const __half* A, const __half* Bw,
                                        int Kpad, int Mbase, int Nbase, int kc) {
    const int tid = threadIdx.x;
    if (tid < 128) {
        const int row = tid >> 1, prt = tid & 1;
        const char* s = (const char*)(A + (size_t)(Mbase + row) * Kpad + kc * 32)
                        + prt * 32;
        const uint32_t d = bufBase + row * 80u + prt * 32u;
        CP_A16(d, s);
        CP_A16(d + 16, s + 16);
    }
    {
        const int row = tid >> 1, prt = tid & 1;
        const char* s = (const char*)(Bw + (size_t)(Nbase + row) * Kpad + kc * 32)
                        + prt * 32;
        const uint32_t d = bufBase + 5120u + row * 80u + prt * 32u;
        CP_A16(d, s);
        CP_A16(d + 16, s + 16);
    }
}

template <int MODE>
__global__ void __launch_bounds__(256, 2)
gemm_kernel(const __half* __restrict__ A, int Kpad, int KC,
            const __half* __restrict__ Bw,
            const float* __restrict__ biasG,
            __half* __restrict__ O, int KpadO,
            float* __restrict__ gout) {
    char* smem = (char*)dynsmem;
    const uint32_t su = smem_to_u32(smem);
    const int tid = threadIdx.x;
    const int wid = tid >> 5, lane = tid & 31;
    const int Mbase = blockIdx.x * 64;
    const int Nbase = blockIdx.y * 128;
    float* bias = (float*)(smem + GM_BIAS);

    gm_load(su, A, Bw, Kpad, Mbase, Nbase, 0);
    CP_COMMIT();
    if (tid < 128) bias[tid] = biasG[Nbase + tid];

    float c[8][4];
    #pragma unroll
    for (int f = 0; f < 8; ++f)
        #pragma unroll
        for (int j = 0; j < 4; ++j) c[f][j] = 0.0f;

    #pragma unroll 1
    for (int kc = 0; kc < KC; ++kc) {
        CP_WAIT0();
        __syncthreads();
        if (kc + 1 < KC) {
            gm_load(su + ((kc + 1) & 1) * GM_BUF, A, Bw, Kpad, Mbase, Nbase, kc + 1);
            CP_COMMIT();
        }
        const uint32_t buf = su + (kc & 1) * GM_BUF;
        gp_t<2, 4>(buf, 80u, buf + 5120u, 80u,
                   (wid & 3) * 16, (wid >> 2) * 64, lane, c);
    }

    if (MODE == 0) {
        const int r0 = Mbase + (wid & 3) * 16 + (lane >> 2);
        const int cb = (wid >> 2) * 64 + 2 * (lane & 3);
        #pragma unroll
        for (int f = 0; f < 8; ++f) {
            const int cl = cb + (f >> 1) * 16 + (f & 1) * 8;
            const int col = Nbase + cl;
            const float bv0 = bias[cl], bv1 = bias[cl + 1];
            const float v00 = fmaxf((c[f][0] + bv0) * BNS_F, 0.0f);
            const float v01 = fmaxf((c[f][1] + bv1) * BNS_F, 0.0f);
            const float v10 = fmaxf((c[f][2] + bv0) * BNS_F, 0.0f);
            const float v11 = fmaxf((c[f][3] + bv1) * BNS_F, 0.0f);
            *(uint32_t*)(O + (size_t)r0 * KpadO + col) = pk2h(v00, v01);
            *(uint32_t*)(O + (size_t)(r0 + 8) * KpadO + col) = pk2h(v10, v11);
        }
    } else {
        const int batch = blockIdx.x * 4 + (wid & 3);
        const int cb = (wid >> 2) * 64;
        #pragma unroll
        for (int f = 0; f < 8; ++f) {
            float m0 = fmaxf(c[f][0], c[f][2]);
            float m1 = fmaxf(c[f][1], c[f][3]);
            #pragma unroll
            for (int off = 4; off <= 16; off <<= 1) {
                m0 = fmaxf(m0, __shfl_xor_sync(0xffffffffu, m0, off));
                m1 = fmaxf(m1, __shfl_xor_sync(0xffffffffu, m1, off));
            }
            if (lane < 4) {
                const int cl = cb + (f >> 1) * 16 + (f & 1) * 8 + 2 * lane;
                const int col = Nbase + cl;
                gout[(size_t)batch * 768 + col] =
                    fmaxf((m0 + bias[cl]) * BNS_F, 0.0f);
                gout[(size_t)batch * 768 + col + 1] =
                    fmaxf((m1 + bias[cl + 1]) * BNS_F, 0.0f);
            }
        }
    }
}

// ---------------------------------------------------------------------------
// FC: 16 batches/block share fc_w loads.
// ---------------------------------------------------------------------------
__global__ void __launch_bounds__(192)
fc_kernel(const float* __restrict__ g_in, const float* __restrict__ fcw,
          const float* __restrict__ fcb, float* __restrict__ out) {
    constexpr int FCB = 16, C = 768, NT = 192;
    __shared__ float gs[FCB * C];
    const int b0 = blockIdx.x * FCB;
    for (int i = threadIdx.x; i < FCB * C; i += NT)
        gs[i] = g_in[(size_t)b0 * C + i];
    __syncthreads();
    const int og = threadIdx.x;
    const float4 bv = *reinterpret_cast<const float4*>(fcb + 4 * og);
    ull_t a01[FCB], a23[FCB];
    #pragma unroll
    for (int i = 0; i < FCB; ++i) { a01[i] = 0ull; a23[i] = 0ull; }
    const float* wp = fcw + 4 * og;
    #pragma unroll 2
    for (int k = 0; k < C; ++k) {
        const ulonglong2 wq =
            *reinterpret_cast<const ulonglong2*>(wp + (size_t)k * C);
        #pragma unroll
        for (int i = 0; i < FCB; ++i) {
            const ull_t hh = dup2(gs[i * C + k]);
            FMA2(a01[i], hh, wq.x, a01[i]);
            FMA2(a23[i], hh, wq.y, a23[i]);
        }
    }
    #pragma unroll
    for (int i = 0; i < FCB; ++i) {
        const float2 p0 = unpk(a01[i]);
        const float2 p1 = unpk(a23[i]);
        float4 r = make_float4(p0.x + bv.x, p0.y + bv.y, p1.x + bv.z, p1.y + bv.w);
        *reinterpret_cast<float4*>(out + (size_t)(b0 + i) * C + 4 * og) = r;
    }
}

// ---------------------------------------------------------------------------
// Host launcher
// ---------------------------------------------------------------------------
extern "C" void kernel_launch(void* const* d_in, const int* in_sizes, int n_in,
                              void* d_out, int out_size) {
    const float* x   = (const float*)d_in[0];
    const float* w10 = (const float*)d_in[1];  const float* b10 = (const float*)d_in[2];
    const float* w11 = (const float*)d_in[3];  const float* b11 = (const float*)d_in[4];
    const float* w12 = (const float*)d_in[5];  const float* b12 = (const float*)d_in[6];
    const float* w20 = (const float*)d_in[7];  const float* b20 = (const float*)d_in[8];
    const float* w21 = (const float*)d_in[9];  const float* b21 = (const float*)d_in[10];
    const float* w22 = (const float*)d_in[11]; const float* b22 = (const float*)d_in[12];
    const float* w30 = (const float*)d_in[13]; const float* b30 = (const float*)d_in[14];
    const float* w31 = (const float*)d_in[15]; const float* b31 = (const float*)d_in[16];
    const float* w32 = (const float*)d_in[17]; const float* b32 = (const float*)d_in[18];
    const float* fcw = (const float*)d_in[19]; const float* fcb = (const float*)d_in[20];
    float* out = (float*)d_out;

    int *ball1p, *ball2p;
    float *nx1p, *f1p, *nx2p, *f2p, *gp;
    __half *a0p, *h0p, *h1p, *w30hp, *w31hp, *w32hp;
    cudaGetSymbolAddress((void**)&nx1p,   g_nx1);
    cudaGetSymbolAddress((void**)&ball1p, g_ball1);
    cudaGetSymbolAddress((void**)&f1p,    g_f1);
    cudaGetSymbolAddress((void**)&nx2p,   g_nx2);
    cudaGetSymbolAddress((void**)&ball2p, g_ball2);
    cudaGetSymbolAddress((void**)&f2p,    g_f2);
    cudaGetSymbolAddress((void**)&gp,     g_g);
    cudaGetSymbolAddress((void**)&a0p,    g_a0);
    cudaGetSymbolAddress((void**)&h0p,    g_h0);
    cudaGetSymbolAddress((void**)&h1p,    g_h1);
    cudaGetSymbolAddress((void**)&w30hp,  g_w30h);
    cudaGetSymbolAddress((void**)&w31hp,  g_w31h);
    cudaGetSymbolAddress((void**)&w32hp,  g_w32h);

    cudaFuncSetAttribute(sa1m_kernel, cudaFuncAttributeMaxDynamicSharedMemorySize, S1_SMEM);
    cudaFuncSetAttribute(sa2m_kernel, cudaFuncAttributeMaxDynamicSharedMemorySize, SA2M_SMEM);
    cudaFuncSetAttribute(gemm_kernel<0>, cudaFuncAttributeMaxDynamicSharedMemorySize, GM_SMEM);
    cudaFuncSetAttribute(gemm_kernel<1>, cudaFuncAttributeMaxDynamicSharedMemorySize, GM_SMEM);

    // 1: weight prep
    prep_all_kernel<<<1024, 256>>>(w10, w11, w12, w20, w21, w22, w30, w31, w32);
    // 2-3: FPS1 + ball1
    fps1_kernel<<<B_TOT, 512>>>(x, nx1p);
    ball1_kernel<<<B_TOT, 1024>>>(x, nx1p, ball1p);
    // 4: SA1
    sa1m_kernel<<<B_TOT * M1 / 4, 256, S1_SMEM>>>(x, nx1p, ball1p,
                                                  b10, b11, b12, f1p);
    // 5-7: FPS2 + ball2 + SA2
    fps2_kernel<<<(B_TOT * 32 + 127) / 128, 128>>>(nx1p, nx2p);
    ball2_kernel<<<B_TOT, 512>>>(nx1p, nx2p, ball2p);
    sa2m_kernel<<<B_TOT * M2 / 4, 256, SA2M_SMEM>>>(nx1p, f1p, nx2p, ball2p,
                                                    b20, b21, b22, f2p);
    // 8: head input gather
    gather_a0_kernel<<<32768 / 256, 256>>>(nx2p, f2p);
    // 9-11: head GEMMs
    gemm_kernel<0><<<dim3(512, 2), 256, GM_SMEM>>>(
        a0p, 288, 9, w30hp, b30, h0p, 256, nullptr);
    gemm_kernel<0><<<dim3(512, 4), 256, GM_SMEM>>>(
        h0p, 256, 8, w31hp, b31, h1p, 512, nullptr);
    gemm_kernel<1><<<dim3(512, 6), 256, GM_SMEM>>>(
        h1p, 512, 16, w32hp, b32, nullptr, 0, gp);
    // 12: FC
    fc_kernel<<<B_TOT / 16, 192>>>(gp, fcw, fcb, out);
}

// round 16
// speedup vs baseline: 2.9327x; 1.0501x over previous
#include <cuda_runtime.h>
#include <cuda_fp16.h>
#include <math.h>
#include <stdint.h>

// ---------------------------------------------------------------------------
// PointNet++ encoder forward. B=2048 clouds, N=1024 pts, 6 ch.
// MLP stages on HMMA fp16 (fp32 accum). Index paths exact fp32.
// R16: sa1m/sa2m 8 centers/block, 2 M-tiles per warp (B-fragment reuse).
// ---------------------------------------------------------------------------

#define B_TOT 2048
#define N1    1024
#define M1    32
#define M2    16
#define NSMP  32

__device__ float g_nx1  [B_TOT * M1 * 3];
__device__ int   g_ball1[B_TOT * M1 * NSMP];
__device__ float g_f1   [B_TOT * M1 * 128];
__device__ float g_nx2  [B_TOT * M2 * 3];
__device__ int   g_ball2[B_TOT * M2 * NSMP];
__device__ float g_f2   [B_TOT * M2 * 256];
__device__ float g_g    [B_TOT * 768];

// Weights: [N][Kpad] fp16.
__device__ __align__(16) __half g_w10h[64 * 24];
__device__ __align__(16) __half g_w11h[64 * 72];
__device__ __align__(16) __half g_w12h[128 * 72];
__device__ __align__(16) __half g_w20h[128 * 152];
__device__ __align__(16) __half g_w21h[128 * 136];
__device__ __align__(16) __half g_w22h[256 * 136];
__device__ __align__(16) __half g_w30h[256 * 288];
__device__ __align__(16) __half g_w31h[512 * 256];
__device__ __align__(16) __half g_w32h[768 * 512];

// Head activations, [32768 rows][Kpad] fp16.
__device__ __align__(16) __half g_a0[32768 * 288];
__device__ __align__(16) __half g_h0[32768 * 256];
__device__ __align__(16) __half g_h1[32768 * 512];

// ---- packed f32x2 helpers (FC kernel) ----------------------------------------
typedef unsigned long long ull_t;
__device__ __forceinline__ ull_t dup2(float v) {
    ull_t r; unsigned u = __float_as_uint(v);
    asm("mov.b64 %0, {%1, %1};" : "=l"(r) : "r"(u));
    return r;
}
__device__ __forceinline__ float2 unpk(ull_t p) {
    unsigned lo, hi;
    asm("mov.b64 {%0, %1}, %2;" : "=r"(lo), "=r"(hi) : "l"(p));
    return make_float2(__uint_as_float(lo), __uint_as_float(hi));
}
#define FMA2(d, a, b, c) \
    asm("fma.rn.f32x2 %0, %1, %2, %3;" : "=l"(d) : "l"(a), "l"(b), "l"(c))

#define BNS_F 0.99999500003749968f   // 1/sqrt(1+1e-5)

// ---- mma.sync / ldmatrix / cp.async helpers ----------------------------------
__device__ __forceinline__ uint32_t smem_to_u32(const void* p) {
    uint32_t a;
    asm("{ .reg .u64 t; cvta.to.shared.u64 t, %1; cvt.u32.u64 %0, t; }"
        : "=r"(a) : "l"(p));
    return a;
}
#define LDSM4(r, a) \
    asm volatile("ldmatrix.sync.aligned.m8n8.x4.shared.b16 {%0,%1,%2,%3}, [%4];" \
                 : "=r"((r)[0]), "=r"((r)[1]), "=r"((r)[2]), "=r"((r)[3]) : "r"(a))

__device__ __forceinline__ void mma_f16(float* c, const uint32_t* a,
                                        const uint32_t* b) {
    asm volatile(
        "mma.sync.aligned.m16n8k16.row.col.f32.f16.f16.f32 "
        "{%0,%1,%2,%3}, {%4,%5,%6,%7}, {%8,%9}, {%0,%1,%2,%3};"
        : "+f"(c[0]), "+f"(c[1]), "+f"(c[2]), "+f"(c[3])
        : "r"(a[0]), "r"(a[1]), "r"(a[2]), "r"(a[3]), "r"(b[0]), "r"(b[1]));
}

#define CP_A16(dst, src) \
    asm volatile("cp.async.cg.shared.global [%0], [%1], 16;" \
                 :: "r"(dst), "l"(src) : "memory")
#define CP_COMMIT() asm volatile("cp.async.commit_group;" ::: "memory")
#define CP_WAIT0()  asm volatile("cp.async.wait_group 0;" ::: "memory")
#define CP_WAIT1()  asm volatile("cp.async.wait_group 1;" ::: "memory")

__device__ __forceinline__ void cp_copy(uint32_t dst, const void* src, int bytes) {
    const char* s = (const char*)src;
    for (int i = threadIdx.x * 16; i < bytes; i += 256 * 16)
        CP_A16(dst + i, s + i);
}

__device__ __forceinline__ uint32_t pk2h(float v0, float v1) {
    __half2 h = __floats2half2_rn(v0, v1);
    return *(const uint32_t*)&h;
}

extern __shared__ float dynsmem[];

// fp16 GEMM pass (single M-tile; used by head GEMMs).
template <int KS, int PN>
__device__ __forceinline__ void gp_t(uint32_t aBase, uint32_t aStride,
                                     uint32_t bBase, uint32_t bStride,
                                     int mrow, int nbase, int lane,
                                     float (&c)[2 * PN][4]) {
    const uint32_t aAddr = aBase + (uint32_t)(mrow + (lane & 15)) * aStride +
                           (uint32_t)((lane >> 4) << 4);
    const uint32_t nrow  = (lane & 7) + ((lane >> 4) << 3);
    const uint32_t kcolB = ((lane >> 3) & 1) << 4;
    const uint32_t bAddr = bBase + (uint32_t)(nbase + nrow) * bStride + kcolB;
    #pragma unroll 1
    for (int ks = 0; ks < KS; ++ks) {
        uint32_t ah[4];
        LDSM4(ah, aAddr + ks * 32);
        #pragma unroll
        for (int p = 0; p < PN; ++p) {
            uint32_t bh[4];
            LDSM4(bh, bAddr + (uint32_t)p * 16u * bStride + ks * 32);
            mma_f16(c[2*p],   ah, bh);
            mma_f16(c[2*p+1], ah, bh + 2);
        }
    }
}

// fp16 GEMM pass, 2 M-tiles per warp (rows mrow and mrow+128): B-frag reuse.
template <int KS, int PN>
__device__ __forceinline__ void gp_t2(uint32_t aBase, uint32_t aStride,
                                      uint32_t bBase, uint32_t bStride,
                                      int mrow, int lane,
                                      float (&c0)[2 * PN][4],
                                      float (&c1)[2 * PN][4]) {
    const uint32_t aAddr0 = aBase + (uint32_t)(mrow + (lane & 15)) * aStride +
                            (uint32_t)((lane >> 4) << 4);
    const uint32_t aAddr1 = aAddr0 + 128u * aStride;
    const uint32_t nrow  = (lane & 7) + ((lane >> 4) << 3);
    const uint32_t kcolB = ((lane >> 3) & 1) << 4;
    const uint32_t bAddr = bBase + nrow * bStride + kcolB;
    #pragma unroll 1
    for (int ks = 0; ks < KS; ++ks) {
        uint32_t ah0[4], ah1[4];
        LDSM4(ah0, aAddr0 + ks * 32);
        LDSM4(ah1, aAddr1 + ks * 32);
        #pragma unroll
        for (int p = 0; p < PN; ++p) {
            uint32_t bh[4];
            LDSM4(bh, bAddr + (uint32_t)p * 16u * bStride + ks * 32);
            mma_f16(c0[2*p],   ah0, bh);
            mma_f16(c0[2*p+1], ah0, bh + 2);
            mma_f16(c1[2*p],   ah1, bh);
            mma_f16(c1[2*p+1], ah1, bh + 2);
        }
    }
}

// Epilogue into smem (bias+BNS+relu, fp16).
template <int PN>
__device__ __forceinline__ void epi_t(char* smem, uint32_t outOff,
                                      uint32_t outStride, const float* bias, int cbase,
                                      float (&c)[2 * PN][4], int mrow, int lane) {
    const int r0  = mrow + (lane >> 2);
    const int ccb = 2 * (lane & 3);
    #pragma unroll
    for (int f = 0; f < 2 * PN; ++f) {
        const int col = cbase + (f >> 1) * 16 + (f & 1) * 8 + ccb;
        const float bv0 = bias[col], bv1 = bias[col + 1];
        const float v00 = fmaxf((c[f][0] + bv0) * BNS_F, 0.0f);
        const float v01 = fmaxf((c[f][1] + bv1) * BNS_F, 0.0f);
        const float v10 = fmaxf((c[f][2] + bv0) * BNS_F, 0.0f);
        const float v11 = fmaxf((c[f][3] + bv1) * BNS_F, 0.0f);
        const uint32_t o0 = outOff + (uint32_t)r0 * outStride + (uint32_t)col * 2u;
        const uint32_t o1 = o0 + 8u * outStride;
        *(uint32_t*)(smem + o0) = pk2h(v00, v01);
        *(uint32_t*)(smem + o1) = pk2h(v10, v11);
    }
}

// Max-reduce one fragment set into part[mt*128 + cc].
template <int PN>
__device__ __forceinline__ void max_t(float* part, int mt,
                                      float (&c)[2 * PN][4], int lane) {
    #pragma unroll
    for (int f = 0; f < 2 * PN; ++f) {
        float m0 = fmaxf(c[f][0], c[f][2]);
        float m1 = fmaxf(c[f][1], c[f][3]);
        #pragma unroll
        for (int off = 4; off <= 16; off <<= 1) {
            m0 = fmaxf(m0, __shfl_xor_sync(0xffffffffu, m0, off));
            m1 = fmaxf(m1, __shfl_xor_sync(0xffffffffu, m1, off));
        }
        if (lane < 4) {
            const int cc = (f >> 1) * 16 + (f & 1) * 8 + 2 * lane;
            part[mt * 128 + cc] = m0;
            part[mt * 128 + cc + 1] = m1;
        }
    }
}

// ---------------------------------------------------------------------------
// Merged weight prep.
// ---------------------------------------------------------------------------
__device__ __forceinline__ void prep_one(const float* w, __half* out,
                                         int idx, int Cin, int Cout, int Kpad) {
    const int n = idx / Kpad, kp = idx % Kpad;
    const float v = (kp < Cin) ? w[(size_t)kp * Cout + n] : 0.0f;
    out[idx] = __float2half_rn(v);
}

__global__ void prep_all_kernel(const float* w10,
                                const float* w11, const float* w12,
                                const float* w20, const float* w21, const float* w22,
                                const float* w30, const float* w31, const float* w32) {
    const int s0 = 64*24, s1 = 64*72, s2 = 128*72, s3 = 128*152, s4 = 128*136,
              s5 = 256*136, s6 = 256*288, s7 = 512*256, s8 = 768*512;
    const int total = s0+s1+s2+s3+s4+s5+s6+s7+s8;
    for (int i = blockIdx.x * blockDim.x + threadIdx.x; i < total;
         i += gridDim.x * blockDim.x) {
        int idx = i;
        if (idx < s0) { prep_one(w10, g_w10h, idx, 6, 64, 24); continue; }   idx -= s0;
        if (idx < s1) { prep_one(w11, g_w11h, idx, 64, 64, 72); continue; }  idx -= s1;
        if (idx < s2) { prep_one(w12, g_w12h, idx, 64, 128, 72); continue; } idx -= s2;
        if (idx < s3) { prep_one(w20, g_w20h, idx, 131, 128, 152); continue; } idx -= s3;
        if (idx < s4) { prep_one(w21, g_w21h, idx, 128, 128, 136); continue; } idx -= s4;
        if (idx < s5) { prep_one(w22, g_w22h, idx, 128, 256, 136); continue; } idx -= s5;
        if (idx < s6) { prep_one(w30, g_w30h, idx, 259, 256, 288); continue; } idx -= s6;
        if (idx < s7) { prep_one(w31, g_w31h, idx, 256, 512, 256); continue; } idx -= s7;
        prep_one(w32, g_w32h, idx, 512, 768, 512);
    }
}

// ---------------------------------------------------------------------------
// FPS stage 1/2, ball1/ball2 (unchanged, index-exact).
// ---------------------------------------------------------------------------
__global__ void __launch_bounds__(512)
fps1_kernel(const float* __restrict__ x, float* __restrict__ nxyz) {
    __shared__ float swv[16];
    __shared__ int   swi[16];
    __shared__ float cur[3];
    const int b = blockIdx.x;
    const int t = threadIdx.x;
    const int warp = t >> 5, lane = t & 31;
    const float* p0 = x + ((size_t)b * N1 + t) * 6;
    const float* p1 = p0 + 512 * 6;
    const float px0 = p0[0], py0 = p0[1], pz0 = p0[2];
    const float px1 = p1[0], py1 = p1[1], pz1 = p1[2];
    float d0 = 1e10f, d1 = 1e10f;
    if (t == 0) {
        float* o = nxyz + (size_t)b * M1 * 3;
        o[0] = px0; o[1] = py0; o[2] = pz0;
    }
    int last = 0;
    for (int it = 1; it < M1; ++it) {
        if (t == (last & 511)) {
            if (last < 512) { cur[0] = px0; cur[1] = py0; cur[2] = pz0; }
            else            { cur[0] = px1; cur[1] = py1; cur[2] = pz1; }
        }
        __syncthreads();
        const float cx = cur[0], cy = cur[1], cz = cur[2];
        {
            float dx = __fsub_rn(px0, cx), dy = __fsub_rn(py0, cy),
                  dz = __fsub_rn(pz0, cz);
            d0 = fminf(d0, __fadd_rn(__fadd_rn(__fmul_rn(dx, dx), __fmul_rn(dy, dy)),
                                     __fmul_rn(dz, dz)));
        }
        {
            float dx = __fsub_rn(px1, cx), dy = __fsub_rn(py1, cy),
                  dz = __fsub_rn(pz1, cz);
            d1 = fminf(d1, __fadd_rn(__fadd_rn(__fmul_rn(dx, dx), __fmul_rn(dy, dy)),
                                     __fmul_rn(dz, dz)));
        }
        float v; int vi;
        if (d0 >= d1) { v = d0; vi = t; } else { v = d1; vi = t + 512; }
        #pragma unroll
        for (int off = 16; off; off >>= 1) {
            float v2 = __shfl_xor_sync(0xffffffffu, v, off);
            int   i2 = __shfl_xor_sync(0xffffffffu, vi, off);
            if (v2 > v || (v2 == v && i2 < vi)) { v = v2; vi = i2; }
        }
        if (lane == 0) { swv[warp] = v; swi[warp] = vi; }
        __syncthreads();
        float wv = (lane < 16) ? swv[lane] : -1.0e30f;
        int   wi = (lane < 16) ? swi[lane] : 0x7fffffff;
        #pragma unroll
        for (int off = 16; off; off >>= 1) {
            float v2 = __shfl_xor_sync(0xffffffffu, wv, off);
            int   i2 = __shfl_xor_sync(0xffffffffu, wi, off);
            if (v2 > wv || (v2 == wv && i2 < wi)) { wv = v2; wi = i2; }
        }
        last = wi;
        if (t == (last & 511)) {
            float* o = nxyz + ((size_t)b * M1 + it) * 3;
            if (last < 512) { o[0] = px0; o[1] = py0; o[2] = pz0; }
            else            { o[0] = px1; o[1] = py1; o[2] = pz1; }
        }
    }
}

__global__ void fps2_kernel(const float* __restrict__ pts,
                            float* __restrict__ nxyz) {
    const int gw   = (blockIdx.x * blockDim.x + threadIdx.x) >> 5;
    const int lane = threadIdx.x & 31;
    if (gw >= B_TOT) return;
    const float* pb = pts + (size_t)gw * M1 * 3;
    const float px = pb[lane * 3 + 0], py = pb[lane * 3 + 1], pz = pb[lane * 3 + 2];
    float dist = 1e10f;
    if (lane == 0) {
        float* o = nxyz + (size_t)gw * M2 * 3;
        o[0] = px; o[1] = py; o[2] = pz;
    }
    int last = 0;
    for (int it = 1; it < M2; ++it) {
        const float cx = __shfl_sync(0xffffffffu, px, last);
        const float cy = __shfl_sync(0xffffffffu, py, last);
        const float cz = __shfl_sync(0xffffffffu, pz, last);
        float dx = __fsub_rn(px, cx), dy = __fsub_rn(py, cy), dz = __fsub_rn(pz, cz);
        float d  = __fadd_rn(__fadd_rn(__fmul_rn(dx, dx), __fmul_rn(dy, dy)),
                             __fmul_rn(dz, dz));
        dist = fminf(dist, d);
        float v = dist; int vi = lane;
        #pragma unroll
        for (int off = 16; off; off >>= 1) {
            float v2 = __shfl_xor_sync(0xffffffffu, v, off);
            int   i2 = __shfl_xor_sync(0xffffffffu, vi, off);
            if (v2 > v || (v2 == v && i2 < vi)) { v = v2; vi = i2; }
        }
        last = vi;
        if (lane == last) {
            float* o = nxyz + ((size_t)gw * M2 + it) * 3;
            o[0] = px; o[1] = py; o[2] = pz;
        }
    }
}

__global__ void __launch_bounds__(1024)
ball1_kernel(const float* __restrict__ x, const float* __restrict__ centers,
             int* __restrict__ out) {
    __shared__ float xs[N1], ys[N1], zs[N1];
    const int b = blockIdx.x, t = threadIdx.x;
    const float* p = x + ((size_t)b * N1 + t) * 6;
    xs[t] = p[0]; ys[t] = p[1]; zs[t] = p[2];
    __syncthreads();
    const int wid = t >> 5, lane = t & 31;
    const float* c = centers + ((size_t)b * M1 + wid) * 3;
    const float cx = c[0], cy = c[1], cz = c[2];
    const float cn = __fadd_rn(__fadd_rn(__fmul_rn(cx, cx), __fmul_rn(cy, cy)),
                               __fmul_rn(cz, cz));
    const float r2 = (float)(0.2 * 0.2);
    int* o = out + ((size_t)b * M1 + wid) * NSMP;
    int cnt = 0, first = -1;
    for (int base = 0; base < N1 && cnt < NSMP; base += 32) {
        const float px = xs[base + lane], py = ys[base + lane], pz = zs[base + lane];
        const float pn = __fadd_rn(__fadd_rn(__fmul_rn(px, px), __fmul_rn(py, py)),
                                   __fmul_rn(pz, pz));
        const float dt = __fadd_rn(__fadd_rn(__fmul_rn(cx, px), __fmul_rn(cy, py)),
                                   __fmul_rn(cz, pz));
        const float d2 = __fsub_rn(__fadd_rn(cn, pn), __fmul_rn(2.0f, dt));
        const bool hit = d2 < r2;
        const unsigned mask = __ballot_sync(0xffffffffu, hit);
        if (first < 0 && mask) first = base + __ffs(mask) - 1;
        const int pos = cnt + __popc(mask & ((1u << lane) - 1u));
        if (hit && pos < NSMP) o[pos] = base + lane;
        cnt += __popc(mask);
    }
    if (cnt > NSMP) cnt = NSMP;
    for (int k = cnt + lane; k < NSMP; k += 32) o[k] = first;
}

__global__ void __launch_bounds__(512)
ball2_kernel(const float* __restrict__ pts, const float* __restrict__ centers,
             int* __restrict__ out) {
    __shared__ float xs[M1], ys[M1], zs[M1];
    const int b = blockIdx.x, t = threadIdx.x;
    if (t < M1) {
        const float* p = pts + ((size_t)b * M1 + t) * 3;
        xs[t] = p[0]; ys[t] = p[1]; zs[t] = p[2];
    }
    __syncthreads();
    const int wid = t >> 5, lane = t & 31;
    const float* c = centers + ((size_t)b * M2 + wid) * 3;
    const float cx = c[0], cy = c[1], cz = c[2];
    const float cn = __fadd_rn(__fadd_rn(__fmul_rn(cx, cx), __fmul_rn(cy, cy)),
                               __fmul_rn(cz, cz));
    const float r2 = (float)(0.4 * 0.4);
    int* o = out + ((size_t)b * M2 + wid) * NSMP;
    const float px = xs[lane], py = ys[lane], pz = zs[lane];
    const float pn = __fadd_rn(__fadd_rn(__fmul_rn(px, px), __fmul_rn(py, py)),
                               __fmul_rn(pz, pz));
    const float dt = __fadd_rn(__fadd_rn(__fmul_rn(cx, px), __fmul_rn(cy, py)),
                               __fmul_rn(cz, pz));
    const float d2 = __fsub_rn(__fadd_rn(cn, pn), __fmul_rn(2.0f, dt));
    const bool hit = d2 < r2;
    const unsigned mask = __ballot_sync(0xffffffffu, hit);
    const int first = mask ? (__ffs(mask) - 1) : -1;
    const int pos = __popc(mask & ((1u << lane) - 1u));
    if (hit) o[pos] = lane;
    const int cnt = __popc(mask);
    for (int k = cnt + lane; k < NSMP; k += 32) o[k] = first;
}

// ---------------------------------------------------------------------------
// SA1: 8 centers/block (M=256), 2 M-tiles/warp, all 3 layers HMMA.
// A0@0 (48B str, 12288); A1@12288 (144B str, 36864); A2@49152 (36864);
// B0@86016 (3072); B1@89088 (9216); B2@98304 (18432); bias@116736 (1024).
// part (16x128 fp32 = 8192) overlays A0.
// ---------------------------------------------------------------------------
#define S1_A0   0u
#define S1_A1   12288u
#define S1_A2   49152u
#define S1_B0   86016u
#define S1_B1   89088u
#define S1_B2   98304u
#define S1_BIAS 116736u
#define S1_SMEM 117760

__global__ void __launch_bounds__(256)
sa1m_kernel(const float* __restrict__ x, const float* __restrict__ nx1,
            const int* __restrict__ ball,
            const float* __restrict__ b0_, const float* __restrict__ b1_,
            const float* __restrict__ b2_, float* __restrict__ out) {
    char* smem = (char*)dynsmem;
    const uint32_t su = smem_to_u32(smem);
    const int tid = threadIdx.x;
    const int wid = tid >> 5, lane = tid & 31;
    const int mrow = wid * 16;
    float* bias = (float*)(smem + S1_BIAS);
    float* part = (float*)smem;          // overlays A0 (dead by then)
    const int bm0 = blockIdx.x * 8;
    const int b   = bm0 / M1;

    cp_copy(su + S1_B0, g_w10h, 3072);
    cp_copy(su + S1_B1, g_w11h, 9216);
    cp_copy(su + S1_B2, g_w12h, 18432);
    CP_COMMIT();

    if (tid < 64)  { bias[tid] = b0_[tid]; bias[64 + tid] = b1_[tid]; }
    if (tid < 128) bias[128 + tid] = b2_[tid];

    // Gather A0: 256 rows x 24 cols (6 real), fp16, stride 48B.
    {
        const int row = tid;
        const int center = bm0 + (row >> 5);
        const int p = ball[center * NSMP + (row & 31)];
        const float* xr  = x + ((size_t)b * N1 + p) * 6;
        const float* ctr = nx1 + (size_t)center * 3;
        float in[6];
        #pragma unroll
        for (int k = 0; k < 6; ++k)
            in[k] = (k < 3) ? xr[k] - ctr[k] : xr[k];
        uint32_t* d = (uint32_t*)(smem + S1_A0 + row * 48);
        d[0] = pk2h(in[0], in[1]);
        d[1] = pk2h(in[2], in[3]);
        d[2] = pk2h(in[4], in[5]);
        #pragma unroll
        for (int j = 3; j < 12; ++j) d[j] = 0u;
    }
    CP_WAIT0();
    __syncthreads();

    {   // L0: K=16 (1 ks), N=64
        float c0[8][4], c1[8][4];
        #pragma unroll
        for (int f = 0; f < 8; ++f)
            #pragma unroll
            for (int j = 0; j < 4; ++j) { c0[f][j] = 0.0f; c1[f][j] = 0.0f; }
        gp_t2<1, 4>(su + S1_A0, 48u, su + S1_B0, 48u, mrow, lane, c0, c1);
        epi_t<4>(smem, S1_A1, 144u, bias, 0, c0, mrow, lane);
        epi_t<4>(smem, S1_A1, 144u, bias, 0, c1, mrow + 128, lane);
    }
    __syncthreads();

    {   // L1: K=64 (4 ks), N=64
        float c0[8][4], c1[8][4];
        #pragma unroll
        for (int f = 0; f < 8; ++f)
            #pragma unroll
            for (int j = 0; j < 4; ++j) { c0[f][j] = 0.0f; c1[f][j] = 0.0f; }
        gp_t2<4, 4>(su + S1_A1, 144u, su + S1_B1, 144u, mrow, lane, c0, c1);
        epi_t<4>(smem, S1_A2, 144u, bias + 64, 0, c0, mrow, lane);
        epi_t<4>(smem, S1_A2, 144u, bias + 64, 0, c1, mrow + 128, lane);
    }
    __syncthreads();

    {   // L2: K=64, N=128 + fused max over 32 rows/center
        float c0[16][4], c1[16][4];
        #pragma unroll
        for (int f = 0; f < 16; ++f)
            #pragma unroll
            for (int j = 0; j < 4; ++j) { c0[f][j] = 0.0f; c1[f][j] = 0.0f; }
        gp_t2<4, 8>(su + S1_A2, 144u, su + S1_B2, 144u, mrow, lane, c0, c1);
        __syncthreads();   // A0 region now reused as part[]
        max_t<8>(part, wid, c0, lane);
        max_t<8>(part, 8 + wid, c1, lane);
        __syncthreads();
        for (int i = tid; i < 1024; i += 256) {
            const int ci = i >> 7, n = i & 127;
            const float v = fmaxf(part[(2 * ci) * 128 + n],
                                  part[(2 * ci + 1) * 128 + n]);
            out[(size_t)(bm0 + ci) * 128 + n] =
                fmaxf((v + bias[128 + n]) * BNS_F, 0.0f);
        }
    }
}

// ---------------------------------------------------------------------------
// SA2: 8 centers/block (M=256), 2 M-tiles/warp, cp.async-prefetched weights.
// A@0 (304B str, 77824); B0@77824 (38912); B1@116736 (34816);
// bias@151552 (2048); part@153600 (8192).
// ---------------------------------------------------------------------------
#define A2_A      0u
#define A2_B0     77824u
#define A2_B1     116736u
#define A2_BIAS   151552u
#define A2_PART   153600u
#define SA2M_SMEM 161792

__global__ void __launch_bounds__(256)
sa2m_kernel(const float* __restrict__ nx1, const float* __restrict__ f1,
            const float* __restrict__ nx2, const int* __restrict__ ball,
            const float* __restrict__ b0_, const float* __restrict__ b1_,
            const float* __restrict__ b2_, float* __restrict__ out) {
    char* smem = (char*)dynsmem;
    const uint32_t su = smem_to_u32(smem);
    const int tid = threadIdx.x;
    const int wid = tid >> 5, lane = tid & 31;
    const int mw  = wid * 16;
    float* bs = (float*)(smem + A2_BIAS);
    float* part = (float*)(smem + A2_PART);
    const int bm0 = blockIdx.x * 8;
    const int b   = bm0 / M2;

    cp_copy(su + A2_B0, g_w20h, 38912);
    CP_COMMIT();
    cp_copy(su + A2_B1, g_w21h, 34816);
    CP_COMMIT();

    if (tid < 128) { bs[tid] = b0_[tid]; bs[128 + tid] = b1_[tid]; }
    bs[256 + tid] = b2_[tid];

    // Gather A(L0): 256 rows x 144 cols, fp16, stride 304B. 1 thread/row.
    {
        const int row = tid;
        const int center = bm0 + (row >> 5);
        const int p = ball[center * NSMP + (row & 31)];
        const float* nx1r = nx1 + ((size_t)b * M1 + p) * 3;
        const float* ctr  = nx2 + (size_t)center * 3;
        const float* f1r  = f1 + ((size_t)b * M1 + p) * 128;
        #pragma unroll 1
        for (int i = 0; i < 72; ++i) {
            const int k = 2 * i;
            float v0, v1;
            if (k < 3)        v0 = nx1r[k] - ctr[k];
            else if (k < 131) v0 = f1r[k - 3];
            else              v0 = 0.0f;
            const int k1 = k + 1;
            if (k1 < 3)        v1 = nx1r[k1] - ctr[k1];
            else if (k1 < 131) v1 = f1r[k1 - 3];
            else               v1 = 0.0f;
            *(uint32_t*)(smem + A2_A + (uint32_t)row * 304u + (uint32_t)k * 2u) =
                pk2h(v0, v1);
        }
    }
    CP_WAIT1();
    __syncthreads();

    {   // Layer 0: K=144 (9 ks), N=128
        float c0[16][4], c1[16][4];
        #pragma unroll
        for (int f = 0; f < 16; ++f)
            #pragma unroll
            for (int j = 0; j < 4; ++j) { c0[f][j] = 0.0f; c1[f][j] = 0.0f; }
        gp_t2<9, 8>(su + A2_A, 304u, su + A2_B0, 304u, mw, lane, c0, c1);
        __syncthreads();
        cp_copy(su + A2_B0, g_w22h, 34816);                 // B2 rows 0..127
        CP_COMMIT();
        epi_t<8>(smem, A2_A, 272u, bs, 0, c0, mw, lane);
        epi_t<8>(smem, A2_A, 272u, bs, 0, c1, mw + 128, lane);
        CP_WAIT1();
        __syncthreads();
    }

    {   // Layer 1: K=128 (8 ks), N=128
        float c0[16][4], c1[16][4];
        #pragma unroll
        for (int f = 0; f < 16; ++f)
            #pragma unroll
            for (int j = 0; j < 4; ++j) { c0[f][j] = 0.0f; c1[f][j] = 0.0f; }
        gp_t2<8, 8>(su + A2_A, 272u, su + A2_B1, 272u, mw, lane, c0, c1);
        __syncthreads();
        cp_copy(su + A2_B1, g_w22h + 128 * 136, 34816);     // B2 rows 128..255
        CP_COMMIT();
        epi_t<8>(smem, A2_A, 272u, bs + 128, 0, c0, mw, lane);
        epi_t<8>(smem, A2_A, 272u, bs + 128, 0, c1, mw + 128, lane);
        CP_WAIT1();
        __syncthreads();
    }

    // Layer 2: K=128, N=256 in two halves; fused max over 32 rows/center.
    #pragma unroll 1
    for (int h = 0; h < 2; ++h) {
        const uint32_t bBase = h ? (su + A2_B1) : (su + A2_B0);
        float c0[16][4], c1[16][4];
        #pragma unroll
        for (int f = 0; f < 16; ++f)
            #pragma unroll
            for (int j = 0; j < 4; ++j) { c0[f][j] = 0.0f; c1[f][j] = 0.0f; }
        gp_t2<8, 8>(su + A2_A, 272u, bBase, 272u, mw, lane, c0, c1);
        max_t<8>(part, wid, c0, lane);
        max_t<8>(part, 8 + wid, c1, lane);
        __syncthreads();
        for (int i = tid; i < 1024; i += 256) {
            const int ci = i >> 7, n = i & 127;
            const float v = fmaxf(part[(2 * ci) * 128 + n],
                                  part[(2 * ci + 1) * 128 + n]);
            out[(size_t)(bm0 + ci) * 256 + h * 128 + n] =
                fmaxf((v + bs[256 + h * 128 + n]) * BNS_F, 0.0f);
        }
        if (h == 0) CP_WAIT0();
        __syncthreads();
    }
}

// ---------------------------------------------------------------------------
// Head input gather (fp16).
// ---------------------------------------------------------------------------
__global__ void gather_a0_kernel(const float* __restrict__ nx2,
                                 const float* __restrict__ f2) {
    const int row = blockIdx.x * blockDim.x + threadIdx.x;
    if (row >= 32768) return;
    const float* nr = nx2 + (size_t)row * 3;
    const float* fr = f2 + (size_t)row * 256;
    uint32_t* dh = (uint32_t*)(g_a0 + (size_t)row * 288);
    #pragma unroll 4
    for (int j = 0; j < 144; ++j) {
        const int k = 2 * j;
        float v0, v1;
        if (k < 3)        v0 = nr[k];
        else if (k < 259) v0 = fr[k - 3];
        else              v0 = 0.0f;
        const int k1 = k + 1;
        if (k1 < 3)        v1 = nr[k1];
        else if (k1 < 259) v1 = fr[k1 - 3];
        else               v1 = 0.0f;
        dh[j] = pk2h(v0, v1);
    }
}

// ---------------------------------------------------------------------------
// Pipelined tiled GEMM (fp16): C[64 x 128], K chunked by 32, double-buffered.
// ---------------------------------------------------------------------------
#define GM_BUF  15360u
#define GM_BIAS 30720u
#define GM_SMEM 31232

__device__ __forceinline__ void gm_load(uint32_t bufBase,
                                        const __half* A, const __half* Bw,
                                        int Kpad, int Mbase, int Nbase, int kc) {
    const int tid = threadIdx.x;
    if (tid < 128) {
        const int row = tid >> 1, prt = tid & 1;
        const char* s = (const char*)(A + (size_t)(Mbase + row) * Kpad + kc * 32)
                        + prt * 32;
        const uint32_t d = bufBase + row * 80u + prt * 32u;
        CP_A16(d, s);
        CP_A16(d + 16, s + 16);
    }
    {
        const int row = tid >> 1, prt = tid & 1;
        const char* s = (const char*)(Bw + (size_t)(Nbase + row) * Kpad + kc * 32)
                        + prt * 32;
        const uint32_t d = bufBase + 5120u + row * 80u + prt * 32u;
        CP_A16(d, s);
        CP_A16(d + 16, s + 16);
    }
}

template <int MODE>
__global__ void __launch_bounds__(256, 2)
gemm_kernel(const __half* __restrict__ A, int Kpad, int KC,
            const __half* __restrict__ Bw,
            const float* __restrict__ biasG,
            __half* __restrict__ O, int KpadO,
            float* __restrict__ gout) {
    char* smem = (char*)dynsmem;
    const uint32_t su = smem_to_u32(smem);
    const int tid = threadIdx.x;
    const int wid = tid >> 5, lane = tid & 31;
    const int Mbase = blockIdx.x * 64;
    const int Nbase = blockIdx.y * 128;
    float* bias = (float*)(smem + GM_BIAS);

    gm_load(su, A, Bw, Kpad, Mbase, Nbase, 0);
    CP_COMMIT();
    if (tid < 128) bias[tid] = biasG[Nbase + tid];

    float c[8][4];
    #pragma unroll
    for (int f = 0; f < 8; ++f)
        #pragma unroll
        for (int j = 0; j < 4; ++j) c[f][j] = 0.0f;

    #pragma unroll 1
    for (int kc = 0; kc < KC; ++kc) {
        CP_WAIT0();
        __syncthreads();
        if (kc + 1 < KC) {
            gm_load(su + ((kc + 1) & 1) * GM_BUF, A, Bw, Kpad, Mbase, Nbase, kc + 1);
            CP_COMMIT();
        }
        const uint32_t buf = su + (kc & 1) * GM_BUF;
        gp_t<2, 4>(buf, 80u, buf + 5120u, 80u,
                   (wid & 3) * 16, (wid >> 2) * 64, lane, c);
    }

    if (MODE == 0) {
        const int r0 = Mbase + (wid & 3) * 16 + (lane >> 2);
        const int cb = (wid >> 2) * 64 + 2 * (lane & 3);
        #pragma unroll
        for (int f = 0; f < 8; ++f) {
            const int cl = cb + (f >> 1) * 16 + (f & 1) * 8;
            const int col = Nbase + cl;
            const float bv0 = bias[cl], bv1 = bias[cl + 1];
            const float v00 = fmaxf((c[f][0] + bv0) * BNS_F, 0.0f);
            const float v01 = fmaxf((c[f][1] + bv1) * BNS_F, 0.0f);
            const float v10 = fmaxf((c[f][2] + bv0) * BNS_F, 0.0f);
            const float v11 = fmaxf((c[f][3] + bv1) * BNS_F, 0.0f);
            *(uint32_t*)(O + (size_t)r0 * KpadO + col) = pk2h(v00, v01);
            *(uint32_t*)(O + (size_t)(r0 + 8) * KpadO + col) = pk2h(v10, v11);
        }
    } else {
        const int batch = blockIdx.x * 4 + (wid & 3);
        const int cb = (wid >> 2) * 64;
        #pragma unroll
        for (int f = 0; f < 8; ++f) {
            float m0 = fmaxf(c[f][0], c[f][2]);
            float m1 = fmaxf(c[f][1], c[f][3]);
            #pragma unroll
            for (int off = 4; off <= 16; off <<= 1) {
                m0 = fmaxf(m0, __shfl_xor_sync(0xffffffffu, m0, off));
                m1 = fmaxf(m1, __shfl_xor_sync(0xffffffffu, m1, off));
            }
            if (lane < 4) {
                const int cl = cb + (f >> 1) * 16 + (f & 1) * 8 + 2 * lane;
                const int col = Nbase + cl;
                gout[(size_t)batch * 768 + col] =
                    fmaxf((m0 + bias[cl]) * BNS_F, 0.0f);
                gout[(size_t)batch * 768 + col + 1] =
                    fmaxf((m1 + bias[cl + 1]) * BNS_F, 0.0f);
            }
        }
    }
}

// ---------------------------------------------------------------------------
// FC: 16 batches/block share fc_w loads.
// ---------------------------------------------------------------------------
__global__ void __launch_bounds__(192)
fc_kernel(const float* __restrict__ g_in, const float* __restrict__ fcw,
          const float* __restrict__ fcb, float* __restrict__ out) {
    constexpr int FCB = 16, C = 768, NT = 192;
    __shared__ float gs[FCB * C];
    const int b0 = blockIdx.x * FCB;
    for (int i = threadIdx.x; i < FCB * C; i += NT)
        gs[i] = g_in[(size_t)b0 * C + i];
    __syncthreads();
    const int og = threadIdx.x;
    const float4 bv = *reinterpret_cast<const float4*>(fcb + 4 * og);
    ull_t a01[FCB], a23[FCB];
    #pragma unroll
    for (int i = 0; i < FCB; ++i) { a01[i] = 0ull; a23[i] = 0ull; }
    const float* wp = fcw + 4 * og;
    #pragma unroll 2
    for (int k = 0; k < C; ++k) {
        const ulonglong2 wq =
            *reinterpret_cast<const ulonglong2*>(wp + (size_t)k * C);
        #pragma unroll
        for (int i = 0; i < FCB; ++i) {
            const ull_t hh = dup2(gs[i * C + k]);
            FMA2(a01[i], hh, wq.x, a01[i]);
            FMA2(a23[i], hh, wq.y, a23[i]);
        }
    }
    #pragma unroll
    for (int i = 0; i < FCB; ++i) {
        const float2 p0 = unpk(a01[i]);
        const float2 p1 = unpk(a23[i]);
        float4 r = make_float4(p0.x + bv.x, p0.y + bv.y, p1.x + bv.z, p1.y + bv.w);
        *reinterpret_cast<float4*>(out + (size_t)(b0 + i) * C + 4 * og) = r;
    }
}

// ---------------------------------------------------------------------------
// Host launcher
// ---------------------------------------------------------------------------
extern "C" void kernel_launch(void* const* d_in, const int* in_sizes, int n_in,
                              void* d_out, int out_size) {
    const float* x   = (const float*)d_in[0];
    const float* w10 = (const float*)d_in[1];  const float* b10 = (const float*)d_in[2];
    const float* w11 = (const float*)d_in[3];  const float* b11 = (const float*)d_in[4];
    const float* w12 = (const float*)d_in[5];  const float* b12 = (const float*)d_in[6];
    const float* w20 = (const float*)d_in[7];  const float* b20 = (const float*)d_in[8];
    const float* w21 = (const float*)d_in[9];  const float* b21 = (const float*)d_in[10];
    const float* w22 = (const float*)d_in[11]; const float* b22 = (const float*)d_in[12];
    const float* w30 = (const float*)d_in[13]; const float* b30 = (const float*)d_in[14];
    const float* w31 = (const float*)d_in[15]; const float* b31 = (const float*)d_in[16];
    const float* w32 = (const float*)d_in[17]; const float* b32 = (const float*)d_in[18];
    const float* fcw = (const float*)d_in[19]; const float* fcb = (const float*)d_in[20];
    float* out = (float*)d_out;

    int *ball1p, *ball2p;
    float *nx1p, *f1p, *nx2p, *f2p, *gp;
    __half *a0p, *h0p, *h1p, *w30hp, *w31hp, *w32hp;
    cudaGetSymbolAddress((void**)&nx1p,   g_nx1);
    cudaGetSymbolAddress((void**)&ball1p, g_ball1);
    cudaGetSymbolAddress((void**)&f1p,    g_f1);
    cudaGetSymbolAddress((void**)&nx2p,   g_nx2);
    cudaGetSymbolAddress((void**)&ball2p, g_ball2);
    cudaGetSymbolAddress((void**)&f2p,    g_f2);
    cudaGetSymbolAddress((void**)&gp,     g_g);
    cudaGetSymbolAddress((void**)&a0p,    g_a0);
    cudaGetSymbolAddress((void**)&h0p,    g_h0);
    cudaGetSymbolAddress((void**)&h1p,    g_h1);
    cudaGetSymbolAddress((void**)&w30hp,  g_w30h);
    cudaGetSymbolAddress((void**)&w31hp,  g_w31h);
    cudaGetSymbolAddress((void**)&w32hp,  g_w32h);

    cudaFuncSetAttribute(sa1m_kernel, cudaFuncAttributeMaxDynamicSharedMemorySize, S1_SMEM);
    cudaFuncSetAttribute(sa2m_kernel, cudaFuncAttributeMaxDynamicSharedMemorySize, SA2M_SMEM);
    cudaFuncSetAttribute(gemm_kernel<0>, cudaFuncAttributeMaxDynamicSharedMemorySize, GM_SMEM);
    cudaFuncSetAttribute(gemm_kernel<1>, cudaFuncAttributeMaxDynamicSharedMemorySize, GM_SMEM);

    // 1: weight prep
    prep_all_kernel<<<1024, 256>>>(w10, w11, w12, w20, w21, w22, w30, w31, w32);
    // 2-3: FPS1 + ball1
    fps1_kernel<<<B_TOT, 512>>>(x, nx1p);
    ball1_kernel<<<B_TOT, 1024>>>(x, nx1p, ball1p);
    // 4: SA1
    sa1m_kernel<<<B_TOT * M1 / 8, 256, S1_SMEM>>>(x, nx1p, ball1p,
                                                  b10, b11, b12, f1p);
    // 5-7: FPS2 + ball2 + SA2
    fps2_kernel<<<(B_TOT * 32 + 127) / 128, 128>>>(nx1p, nx2p);
    ball2_kernel<<<B_TOT, 512>>>(nx1p, nx2p, ball2p);
    sa2m_kernel<<<B_TOT * M2 / 8, 256, SA2M_SMEM>>>(nx1p, f1p, nx2p, ball2p,
                                                    b20, b21, b22, f2p);
    // 8: head input gather
    gather_a0_kernel<<<32768 / 256, 256>>>(nx2p, f2p);
    // 9-11: head GEMMs
    gemm_kernel<0><<<dim3(512, 2), 256, GM_SMEM>>>(
        a0p, 288, 9, w30hp, b30, h0p, 256, nullptr);
    gemm_kernel<0><<<dim3(512, 4), 256, GM_SMEM>>>(
        h0p, 256, 8, w31hp, b31, h1p, 512, nullptr);
    gemm_kernel<1><<<dim3(512, 6), 256, GM_SMEM>>>(
        h1p, 512, 16, w32hp, b32, nullptr, 0, gp);
    // 12: FC
    fc_kernel<<<B_TOT / 16, 192>>>(gp, fcw, fcb, out);
}

// round 17
// speedup vs baseline: 3.0391x; 1.0363x over previous
#include <cuda_runtime.h>
#include <cuda_fp16.h>
#include <math.h>
#include <stdint.h>

// ---------------------------------------------------------------------------
// PointNet++ encoder forward. B=2048 clouds, N=1024 pts, 6 ch.
// MLP stages on HMMA fp16 (fp32 accum). Index paths exact fp32.
// R17: sa2m keeps R16 M-doubling; sa1m reverted to R15 (4 centers/block).
// ---------------------------------------------------------------------------

#define B_TOT 2048
#define N1    1024
#define M1    32
#define M2    16
#define NSMP  32

__device__ float g_nx1  [B_TOT * M1 * 3];
__device__ int   g_ball1[B_TOT * M1 * NSMP];
__device__ float g_f1   [B_TOT * M1 * 128];
__device__ float g_nx2  [B_TOT * M2 * 3];
__device__ int   g_ball2[B_TOT * M2 * NSMP];
__device__ float g_f2   [B_TOT * M2 * 256];
__device__ float g_g    [B_TOT * 768];

// Weights: [N][Kpad] fp16.
__device__ __align__(16) __half g_w10h[64 * 24];
__device__ __align__(16) __half g_w11h[64 * 72];
__device__ __align__(16) __half g_w12h[128 * 72];
__device__ __align__(16) __half g_w20h[128 * 152];
__device__ __align__(16) __half g_w21h[128 * 136];
__device__ __align__(16) __half g_w22h[256 * 136];
__device__ __align__(16) __half g_w30h[256 * 288];
__device__ __align__(16) __half g_w31h[512 * 256];
__device__ __align__(16) __half g_w32h[768 * 512];

// Head activations, [32768 rows][Kpad] fp16.
__device__ __align__(16) __half g_a0[32768 * 288];
__device__ __align__(16) __half g_h0[32768 * 256];
__device__ __align__(16) __half g_h1[32768 * 512];

// ---- packed f32x2 helpers (FC kernel) ----------------------------------------
typedef unsigned long long ull_t;
__device__ __forceinline__ ull_t dup2(float v) {
    ull_t r; unsigned u = __float_as_uint(v);
    asm("mov.b64 %0, {%1, %1};" : "=l"(r) : "r"(u));
    return r;
}
__device__ __forceinline__ float2 unpk(ull_t p) {
    unsigned lo, hi;
    asm("mov.b64 {%0, %1}, %2;" : "=r"(lo), "=r"(hi) : "l"(p));
    return make_float2(__uint_as_float(lo), __uint_as_float(hi));
}
#define FMA2(d, a, b, c) \
    asm("fma.rn.f32x2 %0, %1, %2, %3;" : "=l"(d) : "l"(a), "l"(b), "l"(c))

#define BNS_F 0.99999500003749968f   // 1/sqrt(1+1e-5)

// ---- mma.sync / ldmatrix / cp.async helpers ----------------------------------
__device__ __forceinline__ uint32_t smem_to_u32(const void* p) {
    uint32_t a;
    asm("{ .reg .u64 t; cvta.to.shared.u64 t, %1; cvt.u32.u64 %0, t; }"
        : "=r"(a) : "l"(p));
    return a;
}
#define LDSM4(r, a) \
    asm volatile("ldmatrix.sync.aligned.m8n8.x4.shared.b16 {%0,%1,%2,%3}, [%4];" \
                 : "=r"((r)[0]), "=r"((r)[1]), "=r"((r)[2]), "=r"((r)[3]) : "r"(a))

__device__ __forceinline__ void mma_f16(float* c, const uint32_t* a,
                                        const uint32_t* b) {
    asm volatile(
        "mma.sync.aligned.m16n8k16.row.col.f32.f16.f16.f32 "
        "{%0,%1,%2,%3}, {%4,%5,%6,%7}, {%8,%9}, {%0,%1,%2,%3};"
        : "+f"(c[0]), "+f"(c[1]), "+f"(c[2]), "+f"(c[3])
        : "r"(a[0]), "r"(a[1]), "r"(a[2]), "r"(a[3]), "r"(b[0]), "r"(b[1]));
}

#define CP_A16(dst, src) \
    asm volatile("cp.async.cg.shared.global [%0], [%1], 16;" \
                 :: "r"(dst), "l"(src) : "memory")
#define CP_COMMIT() asm volatile("cp.async.commit_group;" ::: "memory")
#define CP_WAIT0()  asm volatile("cp.async.wait_group 0;" ::: "memory")
#define CP_WAIT1()  asm volatile("cp.async.wait_group 1;" ::: "memory")

__device__ __forceinline__ void cp_copy(uint32_t dst, const void* src, int bytes) {
    const char* s = (const char*)src;
    for (int i = threadIdx.x * 16; i < bytes; i += 256 * 16)
        CP_A16(dst + i, s + i);
}

__device__ __forceinline__ uint32_t pk2h(float v0, float v1) {
    __half2 h = __floats2half2_rn(v0, v1);
    return *(const uint32_t*)&h;
}

extern __shared__ float dynsmem[];

// fp16 GEMM pass (single M-tile).
template <int KS, int PN>
__device__ __forceinline__ void gp_t(uint32_t aBase, uint32_t aStride,
                                     uint32_t bBase, uint32_t bStride,
                                     int mrow, int nbase, int lane,
                                     float (&c)[2 * PN][4]) {
    const uint32_t aAddr = aBase + (uint32_t)(mrow + (lane & 15)) * aStride +
                           (uint32_t)((lane >> 4) << 4);
    const uint32_t nrow  = (lane & 7) + ((lane >> 4) << 3);
    const uint32_t kcolB = ((lane >> 3) & 1) << 4;
    const uint32_t bAddr = bBase + (uint32_t)(nbase + nrow) * bStride + kcolB;
    #pragma unroll 1
    for (int ks = 0; ks < KS; ++ks) {
        uint32_t ah[4];
        LDSM4(ah, aAddr + ks * 32);
        #pragma unroll
        for (int p = 0; p < PN; ++p) {
            uint32_t bh[4];
            LDSM4(bh, bAddr + (uint32_t)p * 16u * bStride + ks * 32);
            mma_f16(c[2*p],   ah, bh);
            mma_f16(c[2*p+1], ah, bh + 2);
        }
    }
}

// fp16 GEMM pass, 2 M-tiles per warp (rows mrow and mrow+128): B-frag reuse.
template <int KS, int PN>
__device__ __forceinline__ void gp_t2(uint32_t aBase, uint32_t aStride,
                                      uint32_t bBase, uint32_t bStride,
                                      int mrow, int lane,
                                      float (&c0)[2 * PN][4],
                                      float (&c1)[2 * PN][4]) {
    const uint32_t aAddr0 = aBase + (uint32_t)(mrow + (lane & 15)) * aStride +
                            (uint32_t)((lane >> 4) << 4);
    const uint32_t aAddr1 = aAddr0 + 128u * aStride;
    const uint32_t nrow  = (lane & 7) + ((lane >> 4) << 3);
    const uint32_t kcolB = ((lane >> 3) & 1) << 4;
    const uint32_t bAddr = bBase + nrow * bStride + kcolB;
    #pragma unroll 1
    for (int ks = 0; ks < KS; ++ks) {
        uint32_t ah0[4], ah1[4];
        LDSM4(ah0, aAddr0 + ks * 32);
        LDSM4(ah1, aAddr1 + ks * 32);
        #pragma unroll
        for (int p = 0; p < PN; ++p) {
            uint32_t bh[4];
            LDSM4(bh, bAddr + (uint32_t)p * 16u * bStride + ks * 32);
            mma_f16(c0[2*p],   ah0, bh);
            mma_f16(c0[2*p+1], ah0, bh + 2);
            mma_f16(c1[2*p],   ah1, bh);
            mma_f16(c1[2*p+1], ah1, bh + 2);
        }
    }
}

// Epilogue into smem (bias+BNS+relu, fp16).
template <int PN>
__device__ __forceinline__ void epi_t(char* smem, uint32_t outOff,
                                      uint32_t outStride, const float* bias, int cbase,
                                      float (&c)[2 * PN][4], int mrow, int lane) {
    const int r0  = mrow + (lane >> 2);
    const int ccb = 2 * (lane & 3);
    #pragma unroll
    for (int f = 0; f < 2 * PN; ++f) {
        const int col = cbase + (f >> 1) * 16 + (f & 1) * 8 + ccb;
        const float bv0 = bias[col], bv1 = bias[col + 1];
        const float v00 = fmaxf((c[f][0] + bv0) * BNS_F, 0.0f);
        const float v01 = fmaxf((c[f][1] + bv1) * BNS_F, 0.0f);
        const float v10 = fmaxf((c[f][2] + bv0) * BNS_F, 0.0f);
        const float v11 = fmaxf((c[f][3] + bv1) * BNS_F, 0.0f);
        const uint32_t o0 = outOff + (uint32_t)r0 * outStride + (uint32_t)col * 2u;
        const uint32_t o1 = o0 + 8u * outStride;
        *(uint32_t*)(smem + o0) = pk2h(v00, v01);
        *(uint32_t*)(smem + o1) = pk2h(v10, v11);
    }
}

// Max-reduce one fragment set into part[mt*128 + cc].
template <int PN>
__device__ __forceinline__ void max_t(float* part, int mt,
                                      float (&c)[2 * PN][4], int lane) {
    #pragma unroll
    for (int f = 0; f < 2 * PN; ++f) {
        float m0 = fmaxf(c[f][0], c[f][2]);
        float m1 = fmaxf(c[f][1], c[f][3]);
        #pragma unroll
        for (int off = 4; off <= 16; off <<= 1) {
            m0 = fmaxf(m0, __shfl_xor_sync(0xffffffffu, m0, off));
            m1 = fmaxf(m1, __shfl_xor_sync(0xffffffffu, m1, off));
        }
        if (lane < 4) {
            const int cc = (f >> 1) * 16 + (f & 1) * 8 + 2 * lane;
            part[mt * 128 + cc] = m0;
            part[mt * 128 + cc + 1] = m1;
        }
    }
}

// ---------------------------------------------------------------------------
// Merged weight prep.
// ---------------------------------------------------------------------------
__device__ __forceinline__ void prep_one(const float* w, __half* out,
                                         int idx, int Cin, int Cout, int Kpad) {
    const int n = idx / Kpad, kp = idx % Kpad;
    const float v = (kp < Cin) ? w[(size_t)kp * Cout + n] : 0.0f;
    out[idx] = __float2half_rn(v);
}

__global__ void prep_all_kernel(const float* w10,
                                const float* w11, const float* w12,
                                const float* w20, const float* w21, const float* w22,
                                const float* w30, const float* w31, const float* w32) {
    const int s0 = 64*24, s1 = 64*72, s2 = 128*72, s3 = 128*152, s4 = 128*136,
              s5 = 256*136, s6 = 256*288, s7 = 512*256, s8 = 768*512;
    const int total = s0+s1+s2+s3+s4+s5+s6+s7+s8;
    for (int i = blockIdx.x * blockDim.x + threadIdx.x; i < total;
         i += gridDim.x * blockDim.x) {
        int idx = i;
        if (idx < s0) { prep_one(w10, g_w10h, idx, 6, 64, 24); continue; }   idx -= s0;
        if (idx < s1) { prep_one(w11, g_w11h, idx, 64, 64, 72); continue; }  idx -= s1;
        if (idx < s2) { prep_one(w12, g_w12h, idx, 64, 128, 72); continue; } idx -= s2;
        if (idx < s3) { prep_one(w20, g_w20h, idx, 131, 128, 152); continue; } idx -= s3;
        if (idx < s4) { prep_one(w21, g_w21h, idx, 128, 128, 136); continue; } idx -= s4;
        if (idx < s5) { prep_one(w22, g_w22h, idx, 128, 256, 136); continue; } idx -= s5;
        if (idx < s6) { prep_one(w30, g_w30h, idx, 259, 256, 288); continue; } idx -= s6;
        if (idx < s7) { prep_one(w31, g_w31h, idx, 256, 512, 256); continue; } idx -= s7;
        prep_one(w32, g_w32h, idx, 512, 768, 512);
    }
}

// ---------------------------------------------------------------------------
// FPS stage 1/2, ball1/ball2 (unchanged, index-exact).
// ---------------------------------------------------------------------------
__global__ void __launch_bounds__(512)
fps1_kernel(const float* __restrict__ x, float* __restrict__ nxyz) {
    __shared__ float swv[16];
    __shared__ int   swi[16];
    __shared__ float cur[3];
    const int b = blockIdx.x;
    const int t = threadIdx.x;
    const int warp = t >> 5, lane = t & 31;
    const float* p0 = x + ((size_t)b * N1 + t) * 6;
    const float* p1 = p0 + 512 * 6;
    const float px0 = p0[0], py0 = p0[1], pz0 = p0[2];
    const float px1 = p1[0], py1 = p1[1], pz1 = p1[2];
    float d0 = 1e10f, d1 = 1e10f;
    if (t == 0) {
        float* o = nxyz + (size_t)b * M1 * 3;
        o[0] = px0; o[1] = py0; o[2] = pz0;
    }
    int last = 0;
    for (int it = 1; it < M1; ++it) {
        if (t == (last & 511)) {
            if (last < 512) { cur[0] = px0; cur[1] = py0; cur[2] = pz0; }
            else            { cur[0] = px1; cur[1] = py1; cur[2] = pz1; }
        }
        __syncthreads();
        const float cx = cur[0], cy = cur[1], cz = cur[2];
        {
            float dx = __fsub_rn(px0, cx), dy = __fsub_rn(py0, cy),
                  dz = __fsub_rn(pz0, cz);
            d0 = fminf(d0, __fadd_rn(__fadd_rn(__fmul_rn(dx, dx), __fmul_rn(dy, dy)),
                                     __fmul_rn(dz, dz)));
        }
        {
            float dx = __fsub_rn(px1, cx), dy = __fsub_rn(py1, cy),
                  dz = __fsub_rn(pz1, cz);
            d1 = fminf(d1, __fadd_rn(__fadd_rn(__fmul_rn(dx, dx), __fmul_rn(dy, dy)),
                                     __fmul_rn(dz, dz)));
        }
        float v; int vi;
        if (d0 >= d1) { v = d0; vi = t; } else { v = d1; vi = t + 512; }
        #pragma unroll
        for (int off = 16; off; off >>= 1) {
            float v2 = __shfl_xor_sync(0xffffffffu, v, off);
            int   i2 = __shfl_xor_sync(0xffffffffu, vi, off);
            if (v2 > v || (v2 == v && i2 < vi)) { v = v2; vi = i2; }
        }
        if (lane == 0) { swv[warp] = v; swi[warp] = vi; }
        __syncthreads();
        float wv = (lane < 16) ? swv[lane] : -1.0e30f;
        int   wi = (lane < 16) ? swi[lane] : 0x7fffffff;
        #pragma unroll
        for (int off = 16; off; off >>= 1) {
            float v2 = __shfl_xor_sync(0xffffffffu, wv, off);
            int   i2 = __shfl_xor_sync(0xffffffffu, wi, off);
            if (v2 > wv || (v2 == wv && i2 < wi)) { wv = v2; wi = i2; }
        }
        last = wi;
        if (t == (last & 511)) {
            float* o = nxyz + ((size_t)b * M1 + it) * 3;
            if (last < 512) { o[0] = px0; o[1] = py0; o[2] = pz0; }
            else            { o[0] = px1; o[1] = py1; o[2] = pz1; }
        }
    }
}

__global__ void fps2_kernel(const float* __restrict__ pts,
                            float* __restrict__ nxyz) {
    const int gw   = (blockIdx.x * blockDim.x + threadIdx.x) >> 5;
    const int lane = threadIdx.x & 31;
    if (gw >= B_TOT) return;
    const float* pb = pts + (size_t)gw * M1 * 3;
    const float px = pb[lane * 3 + 0], py = pb[lane * 3 + 1], pz = pb[lane * 3 + 2];
    float dist = 1e10f;
    if (lane == 0) {
        float* o = nxyz + (size_t)gw * M2 * 3;
        o[0] = px; o[1] = py; o[2] = pz;
    }
    int last = 0;
    for (int it = 1; it < M2; ++it) {
        const float cx = __shfl_sync(0xffffffffu, px, last);
        const float cy = __shfl_sync(0xffffffffu, py, last);
        const float cz = __shfl_sync(0xffffffffu, pz, last);
        float dx = __fsub_rn(px, cx), dy = __fsub_rn(py, cy), dz = __fsub_rn(pz, cz);
        float d  = __fadd_rn(__fadd_rn(__fmul_rn(dx, dx), __fmul_rn(dy, dy)),
                             __fmul_rn(dz, dz));
        dist = fminf(dist, d);
        float v = dist; int vi = lane;
        #pragma unroll
        for (int off = 16; off; off >>= 1) {
            float v2 = __shfl_xor_sync(0xffffffffu, v, off);
            int   i2 = __shfl_xor_sync(0xffffffffu, vi, off);
            if (v2 > v || (v2 == v && i2 < vi)) { v = v2; vi = i2; }
        }
        last = vi;
        if (lane == last) {
            float* o = nxyz + ((size_t)gw * M2 + it) * 3;
            o[0] = px; o[1] = py; o[2] = pz;
        }
    }
}

__global__ void __launch_bounds__(1024)
ball1_kernel(const float* __restrict__ x, const float* __restrict__ centers,
             int* __restrict__ out) {
    __shared__ float xs[N1], ys[N1], zs[N1];
    const int b = blockIdx.x, t = threadIdx.x;
    const float* p = x + ((size_t)b * N1 + t) * 6;
    xs[t] = p[0]; ys[t] = p[1]; zs[t] = p[2];
    __syncthreads();
    const int wid = t >> 5, lane = t & 31;
    const float* c = centers + ((size_t)b * M1 + wid) * 3;
    const float cx = c[0], cy = c[1], cz = c[2];
    const float cn = __fadd_rn(__fadd_rn(__fmul_rn(cx, cx), __fmul_rn(cy, cy)),
                               __fmul_rn(cz, cz));
    const float r2 = (float)(0.2 * 0.2);
    int* o = out + ((size_t)b * M1 + wid) * NSMP;
    int cnt = 0, first = -1;
    for (int base = 0; base < N1 && cnt < NSMP; base += 32) {
        const float px = xs[base + lane], py = ys[base + lane], pz = zs[base + lane];
        const float pn = __fadd_rn(__fadd_rn(__fmul_rn(px, px), __fmul_rn(py, py)),
                                   __fmul_rn(pz, pz));
        const float dt = __fadd_rn(__fadd_rn(__fmul_rn(cx, px), __fmul_rn(cy, py)),
                                   __fmul_rn(cz, pz));
        const float d2 = __fsub_rn(__fadd_rn(cn, pn), __fmul_rn(2.0f, dt));
        const bool hit = d2 < r2;
        const unsigned mask = __ballot_sync(0xffffffffu, hit);
        if (first < 0 && mask) first = base + __ffs(mask) - 1;
        const int pos = cnt + __popc(mask & ((1u << lane) - 1u));
        if (hit && pos < NSMP) o[pos] = base + lane;
        cnt += __popc(mask);
    }
    if (cnt > NSMP) cnt = NSMP;
    for (int k = cnt + lane; k < NSMP; k += 32) o[k] = first;
}

__global__ void __launch_bounds__(512)
ball2_kernel(const float* __restrict__ pts, const float* __restrict__ centers,
             int* __restrict__ out) {
    __shared__ float xs[M1], ys[M1], zs[M1];
    const int b = blockIdx.x, t = threadIdx.x;
    if (t < M1) {
        const float* p = pts + ((size_t)b * M1 + t) * 3;
        xs[t] = p[0]; ys[t] = p[1]; zs[t] = p[2];
    }
    __syncthreads();
    const int wid = t >> 5, lane = t & 31;
    const float* c = centers + ((size_t)b * M2 + wid) * 3;
    const float cx = c[0], cy = c[1], cz = c[2];
    const float cn = __fadd_rn(__fadd_rn(__fmul_rn(cx, cx), __fmul_rn(cy, cy)),
                               __fmul_rn(cz, cz));
    const float r2 = (float)(0.4 * 0.4);
    int* o = out + ((size_t)b * M2 + wid) * NSMP;
    const float px = xs[lane], py = ys[lane], pz = zs[lane];
    const float pn = __fadd_rn(__fadd_rn(__fmul_rn(px, px), __fmul_rn(py, py)),
                               __fmul_rn(pz, pz));
    const float dt = __fadd_rn(__fadd_rn(__fmul_rn(cx, px), __fmul_rn(cy, py)),
                               __fmul_rn(cz, pz));
    const float d2 = __fsub_rn(__fadd_rn(cn, pn), __fmul_rn(2.0f, dt));
    const bool hit = d2 < r2;
    const unsigned mask = __ballot_sync(0xffffffffu, hit);
    const int first = mask ? (__ffs(mask) - 1) : -1;
    const int pos = __popc(mask & ((1u << lane) - 1u));
    if (hit) o[pos] = lane;
    const int cnt = __popc(mask);
    for (int k = cnt + lane; k < NSMP; k += 32) o[k] = first;
}

// ---------------------------------------------------------------------------
// SA1 (R15 form): 4 centers/block (M=128), all 3 layers HMMA.
// A0@0 (48B str, 6144); A1@6144 (144B str, 18432); A2@24576 (18432);
// B0@43008 (3072); B1@46080 (9216); B2@55296 (18432); bias@73728 (1024).
// part overlays A0/A1.
// ---------------------------------------------------------------------------
#define S1_A0   0u
#define S1_A1   6144u
#define S1_A2   24576u
#define S1_B0   43008u
#define S1_B1   46080u
#define S1_B2   55296u
#define S1_BIAS 73728u
#define S1_SMEM 74752

__global__ void __launch_bounds__(256)
sa1m_kernel(const float* __restrict__ x, const float* __restrict__ nx1,
            const int* __restrict__ ball,
            const float* __restrict__ b0_, const float* __restrict__ b1_,
            const float* __restrict__ b2_, float* __restrict__ out) {
    char* smem = (char*)dynsmem;
    const uint32_t su = smem_to_u32(smem);
    const int tid = threadIdx.x;
    const int wid = tid >> 5, lane = tid & 31;
    const int mrow = wid * 16;
    float* bias = (float*)(smem + S1_BIAS);
    float* part = (float*)smem;          // overlays A0/A1 (dead by then)
    const int bm0 = blockIdx.x * 4;
    const int b   = bm0 / M1;

    cp_copy(su + S1_B0, g_w10h, 3072);
    cp_copy(su + S1_B1, g_w11h, 9216);
    cp_copy(su + S1_B2, g_w12h, 18432);
    CP_COMMIT();

    if (tid < 64)  { bias[tid] = b0_[tid]; bias[64 + tid] = b1_[tid]; }
    if (tid < 128) bias[128 + tid] = b2_[tid];

    // Gather A0: 128 rows x 24 cols (6 real), fp16, stride 48B.
    if (tid < 128) {
        const int row = tid;
        const int center = bm0 + (row >> 5);
        const int p = ball[center * NSMP + (row & 31)];
        const float* xr  = x + ((size_t)b * N1 + p) * 6;
        const float* ctr = nx1 + (size_t)center * 3;
        float in[6];
        #pragma unroll
        for (int k = 0; k < 6; ++k)
            in[k] = (k < 3) ? xr[k] - ctr[k] : xr[k];
        uint32_t* d = (uint32_t*)(smem + S1_A0 + row * 48);
        d[0] = pk2h(in[0], in[1]);
        d[1] = pk2h(in[2], in[3]);
        d[2] = pk2h(in[4], in[5]);
        #pragma unroll
        for (int j = 3; j < 12; ++j) d[j] = 0u;
    }
    CP_WAIT0();
    __syncthreads();

    {   // L0: K=16 (1 ks), N=64
        float c[8][4];
        #pragma unroll
        for (int f = 0; f < 8; ++f)
            #pragma unroll
            for (int j = 0; j < 4; ++j) c[f][j] = 0.0f;
        gp_t<1, 4>(su + S1_A0, 48u, su + S1_B0, 48u, mrow, 0, lane, c);
        epi_t<4>(smem, S1_A1, 144u, bias, 0, c, mrow, lane);
    }
    __syncthreads();

    {   // L1: K=64 (4 ks), N=64
        float c[8][4];
        #pragma unroll
        for (int f = 0; f < 8; ++f)
            #pragma unroll
            for (int j = 0; j < 4; ++j) c[f][j] = 0.0f;
        gp_t<4, 4>(su + S1_A1, 144u, su + S1_B1, 144u, mrow, 0, lane, c);
        epi_t<4>(smem, S1_A2, 144u, bias + 64, 0, c, mrow, lane);
    }
    __syncthreads();

    {   // L2: K=64, N=128 + fused max over 32 rows/center
        float c[16][4];
        #pragma unroll
        for (int f = 0; f < 16; ++f)
            #pragma unroll
            for (int j = 0; j < 4; ++j) c[f][j] = 0.0f;
        gp_t<4, 8>(su + S1_A2, 144u, su + S1_B2, 144u, mrow, 0, lane, c);
        __syncthreads();   // A0/A1 region now reused as part[]
        max_t<8>(part, wid, c, lane);
        __syncthreads();
        for (int i = tid; i < 512; i += 256) {
            const int ci = i >> 7, n = i & 127;
            const float v = fmaxf(part[(2 * ci) * 128 + n],
                                  part[(2 * ci + 1) * 128 + n]);
            out[(size_t)(bm0 + ci) * 128 + n] =
                fmaxf((v + bias[128 + n]) * BNS_F, 0.0f);
        }
    }
}

// ---------------------------------------------------------------------------
// SA2 (R16 form): 8 centers/block (M=256), 2 M-tiles/warp, cp.async weights.
// A@0 (304B str, 77824); B0@77824 (38912); B1@116736 (34816);
// bias@151552 (2048); part@153600 (8192).
// ---------------------------------------------------------------------------
#define A2_A      0u
#define A2_B0     77824u
#define A2_B1     116736u
#define A2_BIAS   151552u
#define A2_PART   153600u
#define SA2M_SMEM 161792

__global__ void __launch_bounds__(256)
sa2m_kernel(const float* __restrict__ nx1, const float* __restrict__ f1,
            const float* __restrict__ nx2, const int* __restrict__ ball,
            const float* __restrict__ b0_, const float* __restrict__ b1_,
            const float* __restrict__ b2_, float* __restrict__ out) {
    char* smem = (char*)dynsmem;
    const uint32_t su = smem_to_u32(smem);
    const int tid = threadIdx.x;
    const int wid = tid >> 5, lane = tid & 31;
    const int mw  = wid * 16;
    float* bs = (float*)(smem + A2_BIAS);
    float* part = (float*)(smem + A2_PART);
    const int bm0 = blockIdx.x * 8;
    const int b   = bm0 / M2;

    cp_copy(su + A2_B0, g_w20h, 38912);
    CP_COMMIT();
    cp_copy(su + A2_B1, g_w21h, 34816);
    CP_COMMIT();

    if (tid < 128) { bs[tid] = b0_[tid]; bs[128 + tid] = b1_[tid]; }
    bs[256 + tid] = b2_[tid];

    // Gather A(L0): 256 rows x 144 cols, fp16, stride 304B. 1 thread/row.
    {
        const int row = tid;
        const int center = bm0 + (row >> 5);
        const int p = ball[center * NSMP + (row & 31)];
        const float* nx1r = nx1 + ((size_t)b * M1 + p) * 3;
        const float* ctr  = nx2 + (size_t)center * 3;
        const float* f1r  = f1 + ((size_t)b * M1 + p) * 128;
        #pragma unroll 1
        for (int i = 0; i < 72; ++i) {
            const int k = 2 * i;
            float v0, v1;
            if (k < 3)        v0 = nx1r[k] - ctr[k];
            else if (k < 131) v0 = f1r[k - 3];
            else              v0 = 0.0f;
            const int k1 = k + 1;
            if (k1 < 3)        v1 = nx1r[k1] - ctr[k1];
            else if (k1 < 131) v1 = f1r[k1 - 3];
            else               v1 = 0.0f;
            *(uint32_t*)(smem + A2_A + (uint32_t)row * 304u + (uint32_t)k * 2u) =
                pk2h(v0, v1);
        }
    }
    CP_WAIT1();
    __syncthreads();

    {   // Layer 0: K=144 (9 ks), N=128
        float c0[16][4], c1[16][4];
        #pragma unroll
        for (int f = 0; f < 16; ++f)
            #pragma unroll
            for (int j = 0; j < 4; ++j) { c0[f][j] = 0.0f; c1[f][j] = 0.0f; }
        gp_t2<9, 8>(su + A2_A, 304u, su + A2_B0, 304u, mw, lane, c0, c1);
        __syncthreads();
        cp_copy(su + A2_B0, g_w22h, 34816);                 // B2 rows 0..127
        CP_COMMIT();
        epi_t<8>(smem, A2_A, 272u, bs, 0, c0, mw, lane);
        epi_t<8>(smem, A2_A, 272u, bs, 0, c1, mw + 128, lane);
        CP_WAIT1();
        __syncthreads();
    }

    {   // Layer 1: K=128 (8 ks), N=128
        float c0[16][4], c1[16][4];
        #pragma unroll
        for (int f = 0; f < 16; ++f)
            #pragma unroll
            for (int j = 0; j < 4; ++j) { c0[f][j] = 0.0f; c1[f][j] = 0.0f; }
        gp_t2<8, 8>(su + A2_A, 272u, su + A2_B1, 272u, mw, lane, c0, c1);
        __syncthreads();
        cp_copy(su + A2_B1, g_w22h + 128 * 136, 34816);     // B2 rows 128..255
        CP_COMMIT();
        epi_t<8>(smem, A2_A, 272u, bs + 128, 0, c0, mw, lane);
        epi_t<8>(smem, A2_A, 272u, bs + 128, 0, c1, mw + 128, lane);
        CP_WAIT1();
        __syncthreads();
    }

    // Layer 2: K=128, N=256 in two halves; fused max over 32 rows/center.
    #pragma unroll 1
    for (int h = 0; h < 2; ++h) {
        const uint32_t bBase = h ? (su + A2_B1) : (su + A2_B0);
        float c0[16][4], c1[16][4];
        #pragma unroll
        for (int f = 0; f < 16; ++f)
            #pragma unroll
            for (int j = 0; j < 4; ++j) { c0[f][j] = 0.0f; c1[f][j] = 0.0f; }
        gp_t2<8, 8>(su + A2_A, 272u, bBase, 272u, mw, lane, c0, c1);
        max_t<8>(part, wid, c0, lane);
        max_t<8>(part, 8 + wid, c1, lane);
        __syncthreads();
        for (int i = tid; i < 1024; i += 256) {
            const int ci = i >> 7, n = i & 127;
            const float v = fmaxf(part[(2 * ci) * 128 + n],
                                  part[(2 * ci + 1) * 128 + n]);
            out[(size_t)(bm0 + ci) * 256 + h * 128 + n] =
                fmaxf((v + bs[256 + h * 128 + n]) * BNS_F, 0.0f);
        }
        if (h == 0) CP_WAIT0();
        __syncthreads();
    }
}

// ---------------------------------------------------------------------------
// Head input gather (fp16).
// ---------------------------------------------------------------------------
__global__ void gather_a0_kernel(const float* __restrict__ nx2,
                                 const float* __restrict__ f2) {
    const int row = blockIdx.x * blockDim.x + threadIdx.x;
    if (row >= 32768) return;
    const float* nr = nx2 + (size_t)row * 3;
    const float* fr = f2 + (size_t)row * 256;
    uint32_t* dh = (uint32_t*)(g_a0 + (size_t)row * 288);
    #pragma unroll 4
    for (int j = 0; j < 144; ++j) {
        const int k = 2 * j;
        float v0, v1;
        if (k < 3)        v0 = nr[k];
        else if (k < 259) v0 = fr[k - 3];
        else              v0 = 0.0f;
        const int k1 = k + 1;
        if (k1 < 3)        v1 = nr[k1];
        else if (k1 < 259) v1 = fr[k1 - 3];
        else               v1 = 0.0f;
        dh[j] = pk2h(v0, v1);
    }
}

// ---------------------------------------------------------------------------
// Pipelined tiled GEMM (fp16): C[64 x 128], K chunked by 32, double-buffered.
// ---------------------------------------------------------------------------
#define GM_BUF  15360u
#define GM_BIAS 30720u
#define GM_SMEM 31232

__device__ __forceinline__ void gm_load(uint32_t bufBase,
                                        const __half* A, const __half* Bw,
                                        int Kpad, int Mbase, int Nbase, int kc) {
    const int tid = threadIdx.x;
    if (tid < 128) {
        const int row = tid >> 1, prt = tid & 1;
        const char* s = (const char*)(A + (size_t)(Mbase + row) * Kpad + kc * 32)
                        + prt * 32;
        const uint32_t d = bufBase + row * 80u + prt * 32u;
        CP_A16(d, s);
        CP_A16(d + 16, s + 16);
    }
    {
        const int row = tid >> 1, prt = tid & 1;
        const char* s = (const char*)(Bw + (size_t)(Nbase + row) * Kpad + kc * 32)
                        + prt * 32;
        const uint32_t d = bufBase + 5120u + row * 80u + prt * 32u;
        CP_A16(d, s);
        CP_A16(d + 16, s + 16);
    }
}

template <int MODE>
__global__ void __launch_bounds__(256, 2)
gemm_kernel(const __half* __restrict__ A, int Kpad, int KC,
            const __half* __restrict__ Bw,
            const float* __restrict__ biasG,
            __half* __restrict__ O, int KpadO,
            float* __restrict__ gout) {
    char* smem = (char*)dynsmem;
    const uint32_t su = smem_to_u32(smem);
    const int tid = threadIdx.x;
    const int wid = tid >> 5, lane = tid & 31;
    const int Mbase = blockIdx.x * 64;
    const int Nbase = blockIdx.y * 128;
    float* bias = (float*)(smem + GM_BIAS);

    gm_load(su, A, Bw, Kpad, Mbase, Nbase, 0);
    CP_COMMIT();
    if (tid < 128) bias[tid] = biasG[Nbase + tid];

    float c[8][4];
    #pragma unroll
    for (int f = 0; f < 8; ++f)
        #pragma unroll
        for (int j = 0; j < 4; ++j) c[f][j] = 0.0f;

    #pragma unroll 1
    for (int kc = 0; kc < KC; ++kc) {
        CP_WAIT0();
        __syncthreads();
        if (kc + 1 < KC) {
            gm_load(su + ((kc + 1) & 1) * GM_BUF, A, Bw, Kpad, Mbase, Nbase, kc + 1);
            CP_COMMIT();
        }
        const uint32_t buf = su + (kc & 1) * GM_BUF;
        gp_t<2, 4>(buf, 80u, buf + 5120u, 80u,
                   (wid & 3) * 16, (wid >> 2) * 64, lane, c);
    }

    if (MODE == 0) {
        const int r0 = Mbase + (wid & 3) * 16 + (lane >> 2);
        const int cb = (wid >> 2) * 64 + 2 * (lane & 3);
        #pragma unroll
        for (int f = 0; f < 8; ++f) {
            const int cl = cb + (f >> 1) * 16 + (f & 1) * 8;
            const int col = Nbase + cl;
            const float bv0 = bias[cl], bv1 = bias[cl + 1];
            const float v00 = fmaxf((c[f][0] + bv0) * BNS_F, 0.0f);
            const float v01 = fmaxf((c[f][1] + bv1) * BNS_F, 0.0f);
            const float v10 = fmaxf((c[f][2] + bv0) * BNS_F, 0.0f);
            const float v11 = fmaxf((c[f][3] + bv1) * BNS_F, 0.0f);
            *(uint32_t*)(O + (size_t)r0 * KpadO + col) = pk2h(v00, v01);
            *(uint32_t*)(O + (size_t)(r0 + 8) * KpadO + col) = pk2h(v10, v11);
        }
    } else {
        const int batch = blockIdx.x * 4 + (wid & 3);
        const int cb = (wid >> 2) * 64;
        #pragma unroll
        for (int f = 0; f < 8; ++f) {
            float m0 = fmaxf(c[f][0], c[f][2]);
            float m1 = fmaxf(c[f][1], c[f][3]);
            #pragma unroll
            for (int off = 4; off <= 16; off <<= 1) {
                m0 = fmaxf(m0, __shfl_xor_sync(0xffffffffu, m0, off));
                m1 = fmaxf(m1, __shfl_xor_sync(0xffffffffu, m1, off));
            }
            if (lane < 4) {
                const int cl = cb + (f >> 1) * 16 + (f & 1) * 8 + 2 * lane;
                const int col = Nbase + cl;
                gout[(size_t)batch * 768 + col] =
                    fmaxf((m0 + bias[cl]) * BNS_F, 0.0f);
                gout[(size_t)batch * 768 + col + 1] =
                    fmaxf((m1 + bias[cl + 1]) * BNS_F, 0.0f);
            }
        }
    }
}

// ---------------------------------------------------------------------------
// FC: 16 batches/block share fc_w loads.
// ---------------------------------------------------------------------------
__global__ void __launch_bounds__(192)
fc_kernel(const float* __restrict__ g_in, const float* __restrict__ fcw,
          const float* __restrict__ fcb, float* __restrict__ out) {
    constexpr int FCB = 16, C = 768, NT = 192;
    __shared__ float gs[FCB * C];
    const int b0 = blockIdx.x * FCB;
    for (int i = threadIdx.x; i < FCB * C; i += NT)
        gs[i] = g_in[(size_t)b0 * C + i];
    __syncthreads();
    const int og = threadIdx.x;
    const float4 bv = *reinterpret_cast<const float4*>(fcb + 4 * og);
    ull_t a01[FCB], a23[FCB];
    #pragma unroll
    for (int i = 0; i < FCB; ++i) { a01[i] = 0ull; a23[i] = 0ull; }
    const float* wp = fcw + 4 * og;
    #pragma unroll 2
    for (int k = 0; k < C; ++k) {
        const ulonglong2 wq =
            *reinterpret_cast<const ulonglong2*>(wp + (size_t)k * C);
        #pragma unroll
        for (int i = 0; i < FCB; ++i) {
            const ull_t hh = dup2(gs[i * C + k]);
            FMA2(a01[i], hh, wq.x, a01[i]);
            FMA2(a23[i], hh, wq.y, a23[i]);
        }
    }
    #pragma unroll
    for (int i = 0; i < FCB; ++i) {
        const float2 p0 = unpk(a01[i]);
        const float2 p1 = unpk(a23[i]);
        float4 r = make_float4(p0.x + bv.x, p0.y + bv.y, p1.x + bv.z, p1.y + bv.w);
        *reinterpret_cast<float4*>(out + (size_t)(b0 + i) * C + 4 * og) = r;
    }
}

// ---------------------------------------------------------------------------
// Host launcher
// ---------------------------------------------------------------------------
extern "C" void kernel_launch(void* const* d_in, const int* in_sizes, int n_in,
                              void* d_out, int out_size) {
    const float* x   = (const float*)d_in[0];
    const float* w10 = (const float*)d_in[1];  const float* b10 = (const float*)d_in[2];
    const float* w11 = (const float*)d_in[3];  const float* b11 = (const float*)d_in[4];
    const float* w12 = (const float*)d_in[5];  const float* b12 = (const float*)d_in[6];
    const float* w20 = (const float*)d_in[7];  const float* b20 = (const float*)d_in[8];
    const float* w21 = (const float*)d_in[9];  const float* b21 = (const float*)d_in[10];
    const float* w22 = (const float*)d_in[11]; const float* b22 = (const float*)d_in[12];
    const float* w30 = (const float*)d_in[13]; const float* b30 = (const float*)d_in[14];
    const float* w31 = (const float*)d_in[15]; const float* b31 = (const float*)d_in[16];
    const float* w32 = (const float*)d_in[17]; const float* b32 = (const float*)d_in[18];
    const float* fcw = (const float*)d_in[19]; const float* fcb = (const float*)d_in[20];
    float* out = (float*)d_out;

    int *ball1p, *ball2p;
    float *nx1p, *f1p, *nx2p, *f2p, *gp;
    __half *a0p, *h0p, *h1p, *w30hp, *w31hp, *w32hp;
    cudaGetSymbolAddress((void**)&nx1p,   g_nx1);
    cudaGetSymbolAddress((void**)&ball1p, g_ball1);
    cudaGetSymbolAddress((void**)&f1p,    g_f1);
    cudaGetSymbolAddress((void**)&nx2p,   g_nx2);
    cudaGetSymbolAddress((void**)&ball2p, g_ball2);
    cudaGetSymbolAddress((void**)&f2p,    g_f2);
    cudaGetSymbolAddress((void**)&gp,     g_g);
    cudaGetSymbolAddress((void**)&a0p,    g_a0);
    cudaGetSymbolAddress((void**)&h0p,    g_h0);
    cudaGetSymbolAddress((void**)&h1p,    g_h1);
    cudaGetSymbolAddress((void**)&w30hp,  g_w30h);
    cudaGetSymbolAddress((void**)&w31hp,  g_w31h);
    cudaGetSymbolAddress((void**)&w32hp,  g_w32h);

    cudaFuncSetAttribute(sa1m_kernel, cudaFuncAttributeMaxDynamicSharedMemorySize, S1_SMEM);
    cudaFuncSetAttribute(sa2m_kernel, cudaFuncAttributeMaxDynamicSharedMemorySize, SA2M_SMEM);
    cudaFuncSetAttribute(gemm_kernel<0>, cudaFuncAttributeMaxDynamicSharedMemorySize, GM_SMEM);
    cudaFuncSetAttribute(gemm_kernel<1>, cudaFuncAttributeMaxDynamicSharedMemorySize, GM_SMEM);

    // 1: weight prep
    prep_all_kernel<<<1024, 256>>>(w10, w11, w12, w20, w21, w22, w30, w31, w32);
    // 2-3: FPS1 + ball1
    fps1_kernel<<<B_TOT, 512>>>(x, nx1p);
    ball1_kernel<<<B_TOT, 1024>>>(x, nx1p, ball1p);
    // 4: SA1
    sa1m_kernel<<<B_TOT * M1 / 4, 256, S1_SMEM>>>(x, nx1p, ball1p,
                                                  b10, b11, b12, f1p);
    // 5-7: FPS2 + ball2 + SA2
    fps2_kernel<<<(B_TOT * 32 + 127) / 128, 128>>>(nx1p, nx2p);
    ball2_kernel<<<B_TOT, 512>>>(nx1p, nx2p, ball2p);
    sa2m_kernel<<<B_TOT * M2 / 8, 256, SA2M_SMEM>>>(nx1p, f1p, nx2p, ball2p,
                                                    b20, b21, b22, f2p);
    // 8: head input gather
    gather_a0_kernel<<<32768 / 256, 256>>>(nx2p, f2p);
    // 9-11: head GEMMs
    gemm_kernel<0><<<dim3(512, 2), 256, GM_SMEM>>>(
        a0p, 288, 9, w30hp, b30, h0p, 256, nullptr);
    gemm_kernel<0><<<dim3(512, 4), 256, GM_SMEM>>>(
        h0p, 256, 8, w31hp, b31, h1p, 512, nullptr);
    gemm_kernel<1><<<dim3(512, 6), 256, GM_SMEM>>>(
        h1p, 512, 16, w32hp, b32, nullptr, 0, gp);
    // 12: FC
    fc_kernel<<<B_TOT / 16, 192>>>(gp, fcw, fcb, out);
}